// round 1
// baseline (speedup 1.0000x reference)
#include <cuda_runtime.h>
#include <cuda_bf16.h>
#include <math.h>

// Problem constants
#define Bv   8
#define Cv   384
#define Hv   14
#define Wv_  14
#define HEADS 12
#define HC   32
#define Nv   196         // H*W tokens
#define Sv   49          // rH*rW
#define rHv  7
#define rWv  7
#define KKv  9
#define TS   58          // S + KK
#define BNROWS (Bv*Nv)   // 1568

// Scratch (device globals; no allocation allowed)
__device__ float g_xh[Bv*Nv*Cv];
__device__ float g_q [Bv*Nv*Cv];
__device__ float g_xK[Bv*Nv*Cv];
__device__ float g_xV[Bv*Nv*Cv];
__device__ float g_t1[Bv*Nv*Cv];
__device__ float g_t3[Bv*Sv*Cv];
__device__ float g_off[Bv*Sv*2*Nv];
__device__ float g_co [Bv*Nv*2*KKv];
__device__ float g_qk [(size_t)Bv*HEADS*Nv*Nv];
__device__ float g_ao [Bv*Nv*Cv];

__constant__ float c_offm[9][2] = {
    {0.f,-1.f},{-1.f,-1.f},{-1.f,0.f},{-1.f,1.f},{0.f,1.f},{1.f,1.f},{1.f,0.f},{1.f,-1.f},{0.f,0.f}
};

__device__ __forceinline__ float gelu_exact(float v) {
    return 0.5f * v * (1.0f + erff(v * 0.7071067811865476f));
}

// ---------------- transpose x (B,C,H,W) -> xh[b*N+n][c] ----------------
__global__ void transpose_x(const float* __restrict__ x) {
    __shared__ float tile[32][33];
    int b = blockIdx.z;
    int c0 = blockIdx.y * 32, n0 = blockIdx.x * 32;
    int tx = threadIdx.x, ty = threadIdx.y;
    for (int i = ty; i < 32; i += 8) {
        int c = c0 + i, n = n0 + tx;
        tile[i][tx] = (n < Nv) ? x[((size_t)b*Cv + c)*Nv + n] : 0.0f;
    }
    __syncthreads();
    for (int i = ty; i < 32; i += 8) {
        int n = n0 + i, c = c0 + tx;
        if (n < Nv) g_xh[((size_t)b*Nv + n)*Cv + c] = tile[tx][i];
    }
}

// ---------------- generic tiled fp32 GEMM: C[m][o] = sum_k A[m][k]*Wt[o][k] (+bias) ---------
// EPI 0: plain (+bias if non-null)
// EPI 1: gelu(x + bias)
// EPI 2: tanh(x) * scale
// EPI 3: (x + bias), transposed store to NCHW: out[((m/196)*384 + o)*196 + m%196]
template<int EPI>
__global__ void gemm_kernel(const float* __restrict__ A, const float* __restrict__ Wt,
                            const float* __restrict__ bias, float* __restrict__ Co,
                            int M, int No, int Kd, float scale)
{
    __shared__ float As[16][68];
    __shared__ float Bs[16][68];
    const int bm = blockIdx.y * 64;
    const int bn = blockIdx.x * 64;
    const int tid = threadIdx.x;
    const int lk = tid & 15, lm = tid >> 4;
    const int ty = tid >> 4, tx = tid & 15;
    float acc[4][4] = {};
    for (int k0 = 0; k0 < Kd; k0 += 16) {
        #pragma unroll
        for (int i = 0; i < 4; i++) {
            int m = bm + lm + i*16;
            As[lk][lm + i*16] = (m < M) ? A[(size_t)m*Kd + k0 + lk] : 0.0f;
            int n = bn + lm + i*16;
            Bs[lk][lm + i*16] = (n < No) ? Wt[(size_t)n*Kd + k0 + lk] : 0.0f;
        }
        __syncthreads();
        #pragma unroll
        for (int k = 0; k < 16; k++) {
            float ar[4], br[4];
            #pragma unroll
            for (int i = 0; i < 4; i++) ar[i] = As[k][ty*4 + i];
            #pragma unroll
            for (int j = 0; j < 4; j++) br[j] = Bs[k][tx*4 + j];
            #pragma unroll
            for (int i = 0; i < 4; i++)
                #pragma unroll
                for (int j = 0; j < 4; j++)
                    acc[i][j] = fmaf(ar[i], br[j], acc[i][j]);
        }
        __syncthreads();
    }
    #pragma unroll
    for (int i = 0; i < 4; i++) {
        int m = bm + ty*4 + i;
        if (m >= M) continue;
        #pragma unroll
        for (int j = 0; j < 4; j++) {
            int n = bn + tx*4 + j;
            if (n >= No) continue;
            float v = acc[i][j];
            if (EPI == 0 || EPI == 1 || EPI == 3) { if (bias) v += bias[n]; }
            if (EPI == 1) v = gelu_exact(v);
            if (EPI == 2) v = tanhf(v) * scale;
            if (EPI == 3) {
                Co[((size_t)((m / Nv) * Cv + n)) * Nv + (m % Nv)] = v;
            } else {
                Co[(size_t)m * No + n] = v;
            }
        }
    }
}

// ---------------- depthwise 3x3 stride-2 conv + LayerNorm + GELU ----------------
__global__ void dwln_kernel(const float* __restrict__ Wdw, const float* __restrict__ bdw,
                            const float* __restrict__ lng, const float* __restrict__ lnb)
{
    int bs = blockIdx.x;
    int b = bs / Sv, s = bs % Sv;
    int oy = s / rWv, ox = s % rWv;
    int c = threadIdx.x;
    float acc = bdw[c];
    #pragma unroll
    for (int ky = 0; ky < 3; ky++) {
        int y = oy*2 - 1 + ky;
        if (y < 0 || y >= Hv) continue;
        #pragma unroll
        for (int kx = 0; kx < 3; kx++) {
            int x = ox*2 - 1 + kx;
            if (x < 0 || x >= Wv_) continue;
            acc = fmaf(g_t1[((size_t)b*Nv + y*Wv_ + x)*Cv + c], Wdw[c*9 + ky*3 + kx], acc);
        }
    }
    float s1 = acc, s2 = acc*acc;
    #pragma unroll
    for (int o = 16; o > 0; o >>= 1) {
        s1 += __shfl_xor_sync(0xffffffffu, s1, o);
        s2 += __shfl_xor_sync(0xffffffffu, s2, o);
    }
    __shared__ float w1[12], w2[12];
    __shared__ float s_mu, s_rstd;
    if ((c & 31) == 0) { w1[c >> 5] = s1; w2[c >> 5] = s2; }
    __syncthreads();
    if (c == 0) {
        float t1s = 0.f, t2s = 0.f;
        #pragma unroll
        for (int i = 0; i < 12; i++) { t1s += w1[i]; t2s += w2[i]; }
        float mu = t1s / (float)Cv;
        float var = t2s / (float)Cv - mu*mu;
        s_mu = mu; s_rstd = rsqrtf(var + 1e-5f);
    }
    __syncthreads();
    float v = (acc - s_mu) * s_rstd * lng[c] + lnb[c];
    g_t3[(size_t)bs*Cv + c] = gelu_exact(v);
}

// ---------------- per-head score maps QK[b,h,n,p] = q[b,n,h,:].xK[b,p,h,:] ----------------
__global__ void qk_kernel()
{
    int bh = blockIdx.z;
    int b = bh / HEADS, h = bh % HEADS;
    int n0 = blockIdx.y * 32, p0 = blockIdx.x * 32;
    __shared__ float qs[32][33], ks[32][33];
    int tid = threadIdx.x;
    int lr = tid >> 5, lc = tid & 31;
    #pragma unroll
    for (int i = 0; i < 4; i++) {
        int n = n0 + lr + i*8;
        qs[lr + i*8][lc] = (n < Nv) ? g_q[((size_t)b*Nv + n)*Cv + h*HC + lc] : 0.0f;
        int p = p0 + lr + i*8;
        ks[lr + i*8][lc] = (p < Nv) ? g_xK[((size_t)b*Nv + p)*Cv + h*HC + lc] : 0.0f;
    }
    __syncthreads();
    int pcol = tid & 31, ng = tid >> 5;
    float acc[4] = {0.f, 0.f, 0.f, 0.f};
    #pragma unroll
    for (int d = 0; d < 32; d++) {
        float kv = ks[pcol][d];
        #pragma unroll
        for (int i = 0; i < 4; i++) acc[i] = fmaf(qs[ng*4 + i][d], kv, acc[i]);
    }
    #pragma unroll
    for (int i = 0; i < 4; i++) {
        int n = n0 + ng*4 + i, p = p0 + pcol;
        if (n < Nv && p < Nv)
            g_qk[(((size_t)bh)*Nv + n)*Nv + p] = acc[i];
    }
}

// ---------------- fused attention: scores (QK bilinear + pos-bias bilinear), softmax, AV ------
__global__ void attn_kernel(const float* __restrict__ posembed, const float* __restrict__ bv)
{
    const int bn = blockIdx.x;
    const int b = bn / Nv, n = bn % Nv;
    const int ny = n / Wv_, nx = n % Wv_;
    __shared__ float sc[HEADS*TS];
    __shared__ int   sp[TS*4];
    __shared__ float swt[TS*4];

    for (int item = threadIdx.x; item < HEADS*TS; item += blockDim.x) {
        const int h = item / TS, s = item % TS;
        float py, px, tpy, tpx;
        if (s < Sv) {
            int rh = s / rWv, rw = s % rWv;
            float offy = g_off[((size_t)b*Sv + s)*(2*Nv) + 0*Nv + n];
            float offx = g_off[((size_t)b*Sv + s)*(2*Nv) + 1*Nv + n];
            float refy = (float)(rh*2) * (2.0f/13.0f) - 1.0f;
            float refx = (float)(rw*2) * (2.0f/13.0f) - 1.0f;
            py = (offy + refy + 1.0f) * 6.5f;
            px = (offx + refx + 1.0f) * 6.5f;
            tpy = ((float)(2*rh - ny) * (1.0f/13.0f) - offy + 1.0f) * 13.0f;
            tpx = ((float)(2*rw - nx) * (1.0f/13.0f) - offx + 1.0f) * 13.0f;
        } else {
            int j = s - Sv;
            float coy = g_co[((size_t)b*Nv + n)*(2*KKv) + j*2 + 0];
            float cox = g_co[((size_t)b*Nv + n)*(2*KKv) + j*2 + 1];
            float cy = (float)ny + c_offm[j][0];
            float cx = (float)nx + c_offm[j][1];
            float cny = fminf(fmaxf(cy, 0.0f), 14.0f) * (2.0f/13.0f) - 1.0f;
            float cnx = fminf(fmaxf(cx, 0.0f), 14.0f) * (2.0f/13.0f) - 1.0f;
            py = (coy + cny + 1.0f) * 6.5f;
            px = (cox + cnx + 1.0f) * 6.5f;
            tpy = (coy - (float)ny + 1.0f) * 13.0f;
            tpx = (cox - (float)nx + 1.0f) * 13.0f;
        }
        // bilinear on QK map (14x14, zero padding, align_corners semantics pre-applied)
        float y0 = floorf(py), x0 = floorf(px);
        float wy1 = py - y0, wx1 = px - x0;
        const float* qkb = g_qk + (((size_t)(b*HEADS + h))*Nv + n)*Nv;
        float val = 0.0f;
        #pragma unroll
        for (int ccy = 0; ccy < 2; ccy++) {
            #pragma unroll
            for (int ccx = 0; ccx < 2; ccx++) {
                float yf = y0 + (float)ccy, xf = x0 + (float)ccx;
                float w = (ccy ? wy1 : 1.0f - wy1) * (ccx ? wx1 : 1.0f - wx1);
                bool valid = (yf >= 0.0f) && (yf <= 13.0f) && (xf >= 0.0f) && (xf <= 13.0f);
                if (!valid) w = 0.0f;
                int yi = (int)fminf(fmaxf(yf, 0.0f), 13.0f);
                int xi = (int)fminf(fmaxf(xf, 0.0f), 13.0f);
                int pix = yi*Wv_ + xi;
                val += w * qkb[pix];
                if (h == 0) { sp[s*4 + ccy*2 + ccx] = pix; swt[s*4 + ccy*2 + ccx] = w; }
            }
        }
        // bilinear on pos table (27x27)
        float by0 = floorf(tpy), bx0 = floorf(tpx);
        float bwy = tpy - by0, bwx = tpx - bx0;
        const float* tb = posembed + (size_t)h * (27*27);
        float bval = 0.0f;
        #pragma unroll
        for (int ccy = 0; ccy < 2; ccy++) {
            #pragma unroll
            for (int ccx = 0; ccx < 2; ccx++) {
                float yf = by0 + (float)ccy, xf = bx0 + (float)ccx;
                float w = (ccy ? bwy : 1.0f - bwy) * (ccx ? bwx : 1.0f - bwx);
                bool valid = (yf >= 0.0f) && (yf <= 26.0f) && (xf >= 0.0f) && (xf <= 26.0f);
                if (!valid) w = 0.0f;
                int yi = (int)fminf(fmaxf(yf, 0.0f), 26.0f);
                int xi = (int)fminf(fmaxf(xf, 0.0f), 26.0f);
                bval += w * tb[yi*27 + xi];
            }
        }
        sc[h*TS + s] = val + bval;
    }
    __syncthreads();
    if (threadIdx.x < HEADS) {
        int h = threadIdx.x;
        float m = -1e30f;
        for (int s = 0; s < TS; s++) m = fmaxf(m, sc[h*TS + s]);
        float sum = 0.0f;
        for (int s = 0; s < TS; s++) { float e = expf(sc[h*TS + s] - m); sc[h*TS + s] = e; sum += e; }
        float inv = 1.0f / sum;
        for (int s = 0; s < TS; s++) sc[h*TS + s] *= inv;
    }
    __syncthreads();
    int c = threadIdx.x;
    int h = c >> 5;
    const float* xvb = g_xV + (size_t)b * Nv * Cv;
    float acc = bv[c];
    #pragma unroll 2
    for (int s = 0; s < TS; s++) {
        float iv = swt[s*4+0] * xvb[sp[s*4+0]*Cv + c]
                 + swt[s*4+1] * xvb[sp[s*4+1]*Cv + c]
                 + swt[s*4+2] * xvb[sp[s*4+2]*Cv + c]
                 + swt[s*4+3] * xvb[sp[s*4+3]*Cv + c];
        acc = fmaf(sc[h*TS + s], iv, acc);
    }
    g_ao[((size_t)b*Nv + n)*Cv + c] = acc;
}

extern "C" void kernel_launch(void* const* d_in, const int* in_sizes, int n_in,
                              void* d_out, int out_size)
{
    const float* x    = (const float*)d_in[0];
    const float* Wq   = (const float*)d_in[1];
    const float* bq   = (const float*)d_in[2];
    const float* Wk   = (const float*)d_in[3];
    // bk (d_in[4]) cancels in softmax — unused
    const float* Wvv  = (const float*)d_in[5];
    const float* bvv  = (const float*)d_in[6];
    const float* Wo1  = (const float*)d_in[7];
    const float* bo1  = (const float*)d_in[8];
    const float* Wdw  = (const float*)d_in[9];
    const float* bdw  = (const float*)d_in[10];
    const float* lng  = (const float*)d_in[11];
    const float* lnb  = (const float*)d_in[12];
    const float* Wo2  = (const float*)d_in[13];
    const float* Wco  = (const float*)d_in[14];
    const float* pos  = (const float*)d_in[15];
    const float* Wp   = (const float*)d_in[16];
    const float* bp   = (const float*)d_in[17];
    float* out = (float*)d_out;

    float* p_xh;  cudaGetSymbolAddress((void**)&p_xh,  g_xh);
    float* p_q;   cudaGetSymbolAddress((void**)&p_q,   g_q);
    float* p_xK;  cudaGetSymbolAddress((void**)&p_xK,  g_xK);
    float* p_xV;  cudaGetSymbolAddress((void**)&p_xV,  g_xV);
    float* p_t1;  cudaGetSymbolAddress((void**)&p_t1,  g_t1);
    float* p_t3;  cudaGetSymbolAddress((void**)&p_t3,  g_t3);
    float* p_off; cudaGetSymbolAddress((void**)&p_off, g_off);
    float* p_co;  cudaGetSymbolAddress((void**)&p_co,  g_co);
    float* p_ao;  cudaGetSymbolAddress((void**)&p_ao,  g_ao);

    transpose_x<<<dim3(7, 12, Bv), dim3(32, 8)>>>(x);

    gemm_kernel<0><<<dim3(6, 25), 256>>>(p_xh, Wq,  bq,      p_q,  BNROWS, Cv,     Cv, 0.f);
    gemm_kernel<0><<<dim3(6, 25), 256>>>(p_xh, Wk,  nullptr, p_xK, BNROWS, Cv,     Cv, 0.f);
    gemm_kernel<0><<<dim3(6, 25), 256>>>(p_xh, Wvv, nullptr, p_xV, BNROWS, Cv,     Cv, 0.f);
    gemm_kernel<1><<<dim3(6, 25), 256>>>(p_q,  Wo1, bo1,     p_t1, BNROWS, Cv,     Cv, 0.f);
    gemm_kernel<2><<<dim3(1, 25), 256>>>(p_q,  Wco, nullptr, p_co, BNROWS, 2*KKv,  Cv, 1.0f/14.0f);

    dwln_kernel<<<Bv*Sv, Cv>>>(Wdw, bdw, lng, lnb);

    gemm_kernel<2><<<dim3(7, 7), 256>>>(p_t3, Wo2, nullptr, p_off, Bv*Sv, 2*Nv, Cv, 2.0f/14.0f);

    qk_kernel<<<dim3(7, 7, Bv*HEADS), 256>>>();

    attn_kernel<<<Bv*Nv, Cv>>>(pos, bvv);

    gemm_kernel<3><<<dim3(6, 25), 256>>>(p_ao, Wp, bp, out, BNROWS, Cv, Cv, 0.f);
}

// round 2
// speedup vs baseline: 1.0393x; 1.0393x over previous
#include <cuda_runtime.h>
#include <cuda_bf16.h>
#include <math.h>

#define Bv   8
#define Cv   384
#define Hv   14
#define Wv_  14
#define HEADS 12
#define HC   32
#define Nv   196
#define Sv   49
#define rHv  7
#define rWv  7
#define KKv  9
#define TS   58
#define BNROWS (Bv*Nv)   // 1568
#define QKVC 1152

// Scratch
__device__ float g_qkv[BNROWS*QKVC];          // q | xK | xV   (stride 1152)
__device__ float g_t1 [BNROWS*Cv];
__device__ float g_t3 [Bv*Sv*Cv];
__device__ float g_off[Bv*Sv*2*Nv];
__device__ float g_co [BNROWS*2*KKv];
__device__ float g_qk [(size_t)Bv*HEADS*Nv*Nv];
__device__ float g_A  [(size_t)Bv*HEADS*Nv*Nv];
__device__ float g_ao [BNROWS*Cv];

__constant__ float c_offm[9][2] = {
    {0.f,-1.f},{-1.f,-1.f},{-1.f,0.f},{-1.f,1.f},{0.f,1.f},{1.f,1.f},{1.f,0.f},{1.f,-1.f},{0.f,0.f}
};

__device__ __forceinline__ float gelu_exact(float v) {
    return 0.5f * v * (1.0f + erff(v * 0.7071067811865476f));
}

// ---- f32x2 packed math helpers (sm_100+) ----
__device__ __forceinline__ unsigned long long pk2(float lo, float hi) {
    unsigned long long r;
    asm("mov.b64 %0, {%1,%2};" : "=l"(r) : "f"(lo), "f"(hi));
    return r;
}
__device__ __forceinline__ void fma2(unsigned long long &c, unsigned long long a, unsigned long long b) {
    asm("fma.rn.f32x2 %0, %1, %2, %3;" : "=l"(c) : "l"(a), "l"(b), "l"(c));
}
__device__ __forceinline__ float2 upk(unsigned long long v) {
    float2 f;
    asm("mov.b64 {%0,%1}, %2;" : "=f"(f.x), "=f"(f.y) : "l"(v));
    return f;
}

// ================= fused QKV GEMM (A loaded transposed from NCHW x) =================
// out[m][0:384)=x@Wq^T+bq, [384:768)=x@Wk^T, [768:1152)=x@Wv^T, m = b*196+n
__global__ void gemm_qkv(const float* __restrict__ x,
                         const float* __restrict__ Wq, const float* __restrict__ bq,
                         const float* __restrict__ Wk, const float* __restrict__ Wvv)
{
    __shared__ float As[16][68];
    __shared__ float Bs[16][68];
    const int bm = blockIdx.y * 64;
    const int bn = blockIdx.x * 64;
    const int region = bn / Cv;           // 0:Wq 1:Wk 2:Wv
    const int bnl = bn - region * Cv;
    const float* Wt = (region == 0) ? Wq : (region == 1 ? Wk : Wvv);
    const int tid = threadIdx.x;
    const int mloc = tid & 63, kl = tid >> 6;        // A load (m-fast, coalesced over NCHW)
    const int lk = tid & 15, lm = tid >> 4;          // B load (k-fast, coalesced)
    const int ty = tid >> 4, tx = tid & 15;

    unsigned long long acc[4][2];
    #pragma unroll
    for (int i = 0; i < 4; i++) { acc[i][0] = 0ull; acc[i][1] = 0ull; }

    for (int k0 = 0; k0 < Cv; k0 += 16) {
        #pragma unroll
        for (int i = 0; i < 4; i++) {
            int k = k0 + kl * 4 + i;
            int m = bm + mloc;
            float v = 0.0f;
            if (m < BNROWS) {
                int b = m / Nv, nn = m - b * Nv;
                v = x[((size_t)(b * Cv + k)) * Nv + nn];
            }
            As[kl * 4 + i][mloc] = v;
        }
        #pragma unroll
        for (int i = 0; i < 4; i++) {
            int n = bnl + lm + i * 16;
            Bs[lk][lm + i * 16] = Wt[(size_t)n * Cv + k0 + lk];
        }
        __syncthreads();
        #pragma unroll
        for (int k = 0; k < 16; k++) {
            unsigned long long a2[4], b2[2];
            #pragma unroll
            for (int i = 0; i < 4; i++) { float a = As[k][ty * 4 + i]; a2[i] = pk2(a, a); }
            #pragma unroll
            for (int j = 0; j < 2; j++) b2[j] = *(const unsigned long long*)&Bs[k][tx * 4 + j * 2];
            #pragma unroll
            for (int i = 0; i < 4; i++)
                #pragma unroll
                for (int j = 0; j < 2; j++)
                    fma2(acc[i][j], a2[i], b2[j]);
        }
        __syncthreads();
    }
    #pragma unroll
    for (int i = 0; i < 4; i++) {
        int m = bm + ty * 4 + i;
        if (m >= BNROWS) continue;
        #pragma unroll
        for (int j = 0; j < 2; j++) {
            float2 f = upk(acc[i][j]);
            int n0 = bn + tx * 4 + j * 2;
            if (region == 0) { f.x += bq[n0]; f.y += bq[n0 + 1]; }
            g_qkv[(size_t)m * QKVC + n0]     = f.x;
            g_qkv[(size_t)m * QKVC + n0 + 1] = f.y;
        }
    }
}

// ================= fused t1 (gelu(q@Wo1+bo1)) + co (tanh(q@Wco)/14) =================
__global__ void gemm_t1co(const float* __restrict__ Wo1, const float* __restrict__ bo1,
                          const float* __restrict__ Wco)
{
    __shared__ float As[16][34];
    __shared__ float Bs[16][66];
    const int bm = blockIdx.y * 32;
    const int bn = blockIdx.x * 64;
    const int region = (bn >= Cv);
    const int tid = threadIdx.x;
    const int lk = tid & 15, lm = tid >> 4;
    const int ty = tid >> 4, tx = tid & 15;

    unsigned long long acc[4];
    #pragma unroll
    for (int j = 0; j < 4; j++) acc[j] = 0ull;

    for (int k0 = 0; k0 < Cv; k0 += 16) {
        #pragma unroll
        for (int i = 0; i < 2; i++) {
            int m = bm + lm + i * 16;
            As[lk][lm + i * 16] = (m < BNROWS) ? g_qkv[(size_t)m * QKVC + k0 + lk] : 0.0f;
        }
        #pragma unroll
        for (int i = 0; i < 4; i++) {
            int n = bn + lm + i * 16;
            float v = 0.0f;
            if (!region) v = Wo1[(size_t)n * Cv + k0 + lk];
            else { int n2 = n - Cv; if (n2 < 2 * KKv) v = Wco[(size_t)n2 * Cv + k0 + lk]; }
            Bs[lk][lm + i * 16] = v;
        }
        __syncthreads();
        #pragma unroll
        for (int k = 0; k < 16; k++) {
            unsigned long long a2 = *(const unsigned long long*)&As[k][ty * 2];
            #pragma unroll
            for (int j = 0; j < 4; j++) {
                float b = Bs[k][tx * 4 + j];
                fma2(acc[j], a2, pk2(b, b));
            }
        }
        __syncthreads();
    }
    #pragma unroll
    for (int j = 0; j < 4; j++) {
        float2 f = upk(acc[j]);
        int n = bn + tx * 4 + j;
        #pragma unroll
        for (int ii = 0; ii < 2; ii++) {
            int m = bm + ty * 2 + ii;
            if (m >= BNROWS) continue;
            float v = (ii == 0) ? f.x : f.y;
            if (!region) {
                g_t1[(size_t)m * Cv + n] = gelu_exact(v + bo1[n]);
            } else {
                int n2 = n - Cv;
                if (n2 < 2 * KKv) g_co[(size_t)m * (2 * KKv) + n2] = tanhf(v) * (1.0f / 14.0f);
            }
        }
    }
}

// ================= generic 32x64 GEMM, K=384 =================
// EPI 2: tanh(v)*scale -> out[m*ldc+n];  EPI 3: (v+bias[n]) -> NCHW out
template<int EPI>
__global__ void gemm32(const float* __restrict__ A, int lda,
                       const float* __restrict__ Wt, const float* __restrict__ bias,
                       float* __restrict__ out, int M, int N, int ldc, float scale)
{
    __shared__ float As[16][34];
    __shared__ float Bs[16][66];
    const int bm = blockIdx.y * 32;
    const int bn = blockIdx.x * 64;
    const int tid = threadIdx.x;
    const int lk = tid & 15, lm = tid >> 4;
    const int ty = tid >> 4, tx = tid & 15;

    unsigned long long acc[4];
    #pragma unroll
    for (int j = 0; j < 4; j++) acc[j] = 0ull;

    for (int k0 = 0; k0 < Cv; k0 += 16) {
        #pragma unroll
        for (int i = 0; i < 2; i++) {
            int m = bm + lm + i * 16;
            As[lk][lm + i * 16] = (m < M) ? A[(size_t)m * lda + k0 + lk] : 0.0f;
        }
        #pragma unroll
        for (int i = 0; i < 4; i++) {
            int n = bn + lm + i * 16;
            Bs[lk][lm + i * 16] = (n < N) ? Wt[(size_t)n * Cv + k0 + lk] : 0.0f;
        }
        __syncthreads();
        #pragma unroll
        for (int k = 0; k < 16; k++) {
            unsigned long long a2 = *(const unsigned long long*)&As[k][ty * 2];
            #pragma unroll
            for (int j = 0; j < 4; j++) {
                float b = Bs[k][tx * 4 + j];
                fma2(acc[j], a2, pk2(b, b));
            }
        }
        __syncthreads();
    }
    #pragma unroll
    for (int j = 0; j < 4; j++) {
        float2 f = upk(acc[j]);
        int n = bn + tx * 4 + j;
        if (n >= N) continue;
        #pragma unroll
        for (int ii = 0; ii < 2; ii++) {
            int m = bm + ty * 2 + ii;
            if (m >= M) continue;
            float v = (ii == 0) ? f.x : f.y;
            if (EPI == 2) {
                out[(size_t)m * ldc + n] = tanhf(v) * scale;
            } else {
                v += bias[n];
                out[((size_t)((m / Nv) * Cv + n)) * Nv + (m % Nv)] = v;
            }
        }
    }
}

// ================= depthwise 3x3 s2 conv + LN + GELU =================
__global__ void dwln_kernel(const float* __restrict__ Wdw, const float* __restrict__ bdw,
                            const float* __restrict__ lng, const float* __restrict__ lnb)
{
    int bs = blockIdx.x;
    int b = bs / Sv, s = bs % Sv;
    int oy = s / rWv, ox = s % rWv;
    int c = threadIdx.x;
    float acc = bdw[c];
    #pragma unroll
    for (int ky = 0; ky < 3; ky++) {
        int y = oy*2 - 1 + ky;
        if (y < 0 || y >= Hv) continue;
        #pragma unroll
        for (int kx = 0; kx < 3; kx++) {
            int x = ox*2 - 1 + kx;
            if (x < 0 || x >= Wv_) continue;
            acc = fmaf(g_t1[((size_t)b*Nv + y*Wv_ + x)*Cv + c], Wdw[c*9 + ky*3 + kx], acc);
        }
    }
    float s1 = acc, s2 = acc*acc;
    #pragma unroll
    for (int o = 16; o > 0; o >>= 1) {
        s1 += __shfl_xor_sync(0xffffffffu, s1, o);
        s2 += __shfl_xor_sync(0xffffffffu, s2, o);
    }
    __shared__ float w1[12], w2[12];
    __shared__ float s_mu, s_rstd;
    if ((c & 31) == 0) { w1[c >> 5] = s1; w2[c >> 5] = s2; }
    __syncthreads();
    if (c == 0) {
        float t1s = 0.f, t2s = 0.f;
        #pragma unroll
        for (int i = 0; i < 12; i++) { t1s += w1[i]; t2s += w2[i]; }
        float mu = t1s / (float)Cv;
        float var = t2s / (float)Cv - mu*mu;
        s_mu = mu; s_rstd = rsqrtf(var + 1e-5f);
    }
    __syncthreads();
    float v = (acc - s_mu) * s_rstd * lng[c] + lnb[c];
    g_t3[(size_t)bs*Cv + c] = gelu_exact(v);
}

// ================= per-head score maps QK[b,h,n,p] = q.xK =================
__global__ void qk_kernel()
{
    int bh = blockIdx.z;
    int b = bh / HEADS, h = bh % HEADS;
    int n0 = blockIdx.y * 32, p0 = blockIdx.x * 32;
    __shared__ float qs[32][33], ks[32][33];
    int tid = threadIdx.x;
    int lr = tid >> 5, lc = tid & 31;
    #pragma unroll
    for (int i = 0; i < 4; i++) {
        int n = n0 + lr + i*8;
        qs[lr + i*8][lc] = (n < Nv) ? g_qkv[((size_t)b*Nv + n)*QKVC + h*HC + lc] : 0.0f;
        int p = p0 + lr + i*8;
        ks[lr + i*8][lc] = (p < Nv) ? g_qkv[((size_t)b*Nv + p)*QKVC + Cv + h*HC + lc] : 0.0f;
    }
    __syncthreads();
    int pcol = tid & 31, ng = tid >> 5;
    float acc[4] = {0.f, 0.f, 0.f, 0.f};
    #pragma unroll
    for (int d = 0; d < 32; d++) {
        float kv = ks[pcol][d];
        #pragma unroll
        for (int i = 0; i < 4; i++) acc[i] = fmaf(qs[ng*4 + i][d], kv, acc[i]);
    }
    #pragma unroll
    for (int i = 0; i < 4; i++) {
        int n = n0 + ng*4 + i, p = p0 + pcol;
        if (n < Nv && p < Nv)
            g_qk[(((size_t)bh)*Nv + n)*Nv + p] = acc[i];
    }
}

// ================= scores + softmax + fold probs into dense A[b,h,n,:] =================
__global__ void score_kernel(const float* __restrict__ posembed)
{
    const int bn = blockIdx.x;
    const int b = bn / Nv, n = bn % Nv;
    const int ny = n / Wv_, nx = n % Wv_;
    __shared__ float sc[HEADS*TS];
    __shared__ int   sp[TS*4];
    __shared__ float swt[TS*4];
    __shared__ float sA[HEADS][Nv];

    for (int item = threadIdx.x; item < HEADS*TS; item += blockDim.x) {
        const int h = item / TS, s = item % TS;
        float py, px, tpy, tpx;
        if (s < Sv) {
            int rh = s / rWv, rw = s % rWv;
            float offy = g_off[((size_t)b*Sv + s)*(2*Nv) + 0*Nv + n];
            float offx = g_off[((size_t)b*Sv + s)*(2*Nv) + 1*Nv + n];
            float refy = (float)(rh*2) * (2.0f/13.0f) - 1.0f;
            float refx = (float)(rw*2) * (2.0f/13.0f) - 1.0f;
            py = (offy + refy + 1.0f) * 6.5f;
            px = (offx + refx + 1.0f) * 6.5f;
            tpy = ((float)(2*rh - ny) * (1.0f/13.0f) - offy + 1.0f) * 13.0f;
            tpx = ((float)(2*rw - nx) * (1.0f/13.0f) - offx + 1.0f) * 13.0f;
        } else {
            int j = s - Sv;
            float coy = g_co[((size_t)b*Nv + n)*(2*KKv) + j*2 + 0];
            float cox = g_co[((size_t)b*Nv + n)*(2*KKv) + j*2 + 1];
            float cy = (float)ny + c_offm[j][0];
            float cx = (float)nx + c_offm[j][1];
            float cny = fminf(fmaxf(cy, 0.0f), 14.0f) * (2.0f/13.0f) - 1.0f;
            float cnx = fminf(fmaxf(cx, 0.0f), 14.0f) * (2.0f/13.0f) - 1.0f;
            py = (coy + cny + 1.0f) * 6.5f;
            px = (cox + cnx + 1.0f) * 6.5f;
            tpy = (coy - (float)ny + 1.0f) * 13.0f;
            tpx = (cox - (float)nx + 1.0f) * 13.0f;
        }
        float y0 = floorf(py), x0 = floorf(px);
        float wy1 = py - y0, wx1 = px - x0;
        const float* qkb = g_qk + (((size_t)(b*HEADS + h))*Nv + n)*Nv;
        float val = 0.0f;
        #pragma unroll
        for (int ccy = 0; ccy < 2; ccy++) {
            #pragma unroll
            for (int ccx = 0; ccx < 2; ccx++) {
                float yf = y0 + (float)ccy, xf = x0 + (float)ccx;
                float w = (ccy ? wy1 : 1.0f - wy1) * (ccx ? wx1 : 1.0f - wx1);
                bool valid = (yf >= 0.0f) && (yf <= 13.0f) && (xf >= 0.0f) && (xf <= 13.0f);
                if (!valid) w = 0.0f;
                int yi = (int)fminf(fmaxf(yf, 0.0f), 13.0f);
                int xi = (int)fminf(fmaxf(xf, 0.0f), 13.0f);
                int pix = yi*Wv_ + xi;
                val += w * qkb[pix];
                if (h == 0) { sp[s*4 + ccy*2 + ccx] = pix; swt[s*4 + ccy*2 + ccx] = w; }
            }
        }
        float by0 = floorf(tpy), bx0 = floorf(tpx);
        float bwy = tpy - by0, bwx = tpx - bx0;
        const float* tb = posembed + (size_t)h * (27*27);
        float bval = 0.0f;
        #pragma unroll
        for (int ccy = 0; ccy < 2; ccy++) {
            #pragma unroll
            for (int ccx = 0; ccx < 2; ccx++) {
                float yf = by0 + (float)ccy, xf = bx0 + (float)ccx;
                float w = (ccy ? bwy : 1.0f - bwy) * (ccx ? bwx : 1.0f - bwx);
                bool valid = (yf >= 0.0f) && (yf <= 26.0f) && (xf >= 0.0f) && (xf <= 26.0f);
                if (!valid) w = 0.0f;
                int yi = (int)fminf(fmaxf(yf, 0.0f), 26.0f);
                int xi = (int)fminf(fmaxf(xf, 0.0f), 26.0f);
                bval += w * tb[yi*27 + xi];
            }
        }
        sc[h*TS + s] = val + bval;
    }
    __syncthreads();

    // softmax: warp w handles head w
    const int wid = threadIdx.x >> 5, lane = threadIdx.x & 31;
    {
        float m = -1e30f;
        for (int s = lane; s < TS; s += 32) m = fmaxf(m, sc[wid*TS + s]);
        #pragma unroll
        for (int o = 16; o > 0; o >>= 1) m = fmaxf(m, __shfl_xor_sync(0xffffffffu, m, o));
        float sum = 0.0f;
        for (int s = lane; s < TS; s += 32) {
            float e = expf(sc[wid*TS + s] - m);
            sc[wid*TS + s] = e;
            sum += e;
        }
        #pragma unroll
        for (int o = 16; o > 0; o >>= 1) sum += __shfl_xor_sync(0xffffffffu, sum, o);
        float inv = 1.0f / sum;
        for (int s = lane; s < TS; s += 32) sc[wid*TS + s] *= inv;
    }

    // zero sA
    for (int idx = threadIdx.x; idx < HEADS*Nv; idx += blockDim.x)
        ((float*)sA)[idx] = 0.0f;
    __syncthreads();

    // scatter: A[h][pix] += prob[h,s] * w[s,corner]
    for (int i = lane; i < TS*4; i += 32) {
        atomicAdd(&sA[wid][sp[i]], sc[wid*TS + (i >> 2)] * swt[i]);
    }
    __syncthreads();

    for (int idx = threadIdx.x; idx < HEADS*Nv; idx += blockDim.x) {
        int h = idx / Nv, p = idx - h * Nv;
        g_A[(((size_t)(b*HEADS + h))*Nv + n)*Nv + p] = sA[h][p];
    }
}

// ================= AV GEMM: out[b,n,h,:] = A[b,h,n,:] @ xV[b,:,h,:] (+bv) =================
__global__ void av_kernel(const float* __restrict__ bvv)
{
    const int n0 = blockIdx.x * 32;
    const int bh = blockIdx.y;
    const int b = bh / HEADS, h = bh - b * HEADS;
    __shared__ float As[32][33], Vs[32][33];
    const int tid = threadIdx.x;
    const int lr = tid >> 5, lc = tid & 31;
    float acc[4] = {0.f, 0.f, 0.f, 0.f};
    const float* Arow = g_A + ((size_t)bh * Nv) * Nv;

    for (int p0 = 0; p0 < Nv; p0 += 32) {
        #pragma unroll
        for (int i = 0; i < 4; i++) {
            int r = lr + 8*i;
            int n = n0 + r;
            As[r][lc] = (n < Nv && p0 + lc < Nv) ? Arow[(size_t)n*Nv + p0 + lc] : 0.0f;
            int p = p0 + r;
            Vs[r][lc] = (p < Nv) ? g_qkv[((size_t)(b*Nv + p))*QKVC + 2*Cv + h*HC + lc] : 0.0f;
        }
        __syncthreads();
        #pragma unroll
        for (int pp = 0; pp < 32; pp++) {
            float vv = Vs[pp][lc];
            #pragma unroll
            for (int i = 0; i < 4; i++) acc[i] = fmaf(As[lr*4 + i][pp], vv, acc[i]);
        }
        __syncthreads();
    }
    float bb = bvv[h*HC + lc];
    #pragma unroll
    for (int i = 0; i < 4; i++) {
        int n = n0 + lr*4 + i;
        if (n < Nv) g_ao[((size_t)(b*Nv + n))*Cv + h*HC + lc] = acc[i] + bb;
    }
}

extern "C" void kernel_launch(void* const* d_in, const int* in_sizes, int n_in,
                              void* d_out, int out_size)
{
    const float* x    = (const float*)d_in[0];
    const float* Wq   = (const float*)d_in[1];
    const float* bq   = (const float*)d_in[2];
    const float* Wk   = (const float*)d_in[3];
    // bk cancels in softmax — unused
    const float* Wvv  = (const float*)d_in[5];
    const float* bvv  = (const float*)d_in[6];
    const float* Wo1  = (const float*)d_in[7];
    const float* bo1  = (const float*)d_in[8];
    const float* Wdw  = (const float*)d_in[9];
    const float* bdw  = (const float*)d_in[10];
    const float* lng  = (const float*)d_in[11];
    const float* lnb  = (const float*)d_in[12];
    const float* Wo2  = (const float*)d_in[13];
    const float* Wco  = (const float*)d_in[14];
    const float* pos  = (const float*)d_in[15];
    const float* Wp   = (const float*)d_in[16];
    const float* bp   = (const float*)d_in[17];
    float* out = (float*)d_out;

    float* p_t3;  cudaGetSymbolAddress((void**)&p_t3,  g_t3);
    float* p_off; cudaGetSymbolAddress((void**)&p_off, g_off);
    float* p_ao;  cudaGetSymbolAddress((void**)&p_ao,  g_ao);

    // qkv: 18x25 = 450 blocks
    gemm_qkv<<<dim3(18, 25), 256>>>(x, Wq, bq, Wk, Wvv);
    // t1 + co fused: 7x49 = 343 blocks
    gemm_t1co<<<dim3(7, 49), 256>>>(Wo1, bo1, Wco);
    // per-head QK maps
    qk_kernel<<<dim3(7, 7, Bv*HEADS), 256>>>();
    // offset net tail
    dwln_kernel<<<Bv*Sv, Cv>>>(Wdw, bdw, lng, lnb);
    gemm32<2><<<dim3(7, 13), 256>>>(p_t3, Cv, Wo2, nullptr, p_off, Bv*Sv, 2*Nv, 2*Nv, 2.0f/14.0f);
    // scores -> probs -> dense A
    score_kernel<<<Bv*Nv, 384>>>(pos);
    // AV
    av_kernel<<<dim3(7, Bv*HEADS), 256>>>(bvv);
    // final projection -> NCHW
    gemm32<3><<<dim3(6, 49), 256>>>(p_ao, Cv, Wp, bp, out, BNROWS, Cv, Nv, 0.f);
}

// round 3
// speedup vs baseline: 1.3184x; 1.2684x over previous
#include <cuda_runtime.h>
#include <cuda_bf16.h>
#include <math.h>

#define Bv   8
#define Cv   384
#define Hv   14
#define Wv_  14
#define HEADS 12
#define HC   32
#define Nv   196
#define Sv   49
#define rHv  7
#define rWv  7
#define KKv  9
#define TS   58
#define BNROWS (Bv*Nv)   // 1568
#define QKVC 1152

// Scratch
__device__ float g_qkv[BNROWS*QKVC];          // q | xK | xV   (stride 1152)
__device__ float g_t1 [BNROWS*Cv];
__device__ float g_t3 [Bv*Sv*Cv];
__device__ float g_off[Bv*Sv*2*Nv];
__device__ float g_co [BNROWS*2*KKv];
__device__ float g_qk [(size_t)Bv*HEADS*Nv*Nv];
__device__ float g_A  [(size_t)Bv*HEADS*Nv*Nv];
__device__ float g_ao [BNROWS*Cv];

__constant__ float c_offm[9][2] = {
    {0.f,-1.f},{-1.f,-1.f},{-1.f,0.f},{-1.f,1.f},{0.f,1.f},{1.f,1.f},{1.f,0.f},{1.f,-1.f},{0.f,0.f}
};

__device__ __forceinline__ float gelu_exact(float v) {
    return 0.5f * v * (1.0f + erff(v * 0.7071067811865476f));
}

// ---- f32x2 packed math helpers (sm_100+) ----
__device__ __forceinline__ unsigned long long pk2(float lo, float hi) {
    unsigned long long r;
    asm("mov.b64 %0, {%1,%2};" : "=l"(r) : "f"(lo), "f"(hi));
    return r;
}
__device__ __forceinline__ void fma2(unsigned long long &c, unsigned long long a, unsigned long long b) {
    asm("fma.rn.f32x2 %0, %1, %2, %3;" : "=l"(c) : "l"(a), "l"(b), "l"(c));
}
__device__ __forceinline__ float2 upk(unsigned long long v) {
    float2 f;
    asm("mov.b64 {%0,%1}, %2;" : "=f"(f.x), "=f"(f.y) : "l"(v));
    return f;
}

// =====================================================================================
// Big GEMM: 128x64 block tile, BK=16, double-buffered, 256 threads, 8m x 4n per thread,
// f32x2 accumulation over m-pairs.
// MODE 0: qkv   — A = x (NCHW, transposed load), W in {Wq,Wk,Wv} by n-region, out g_qkv
// MODE 1: t1co  — A = g_qkv(q cols, lda=1152), W = Wo1 | Wco, out g_t1 (gelu) / g_co (tanh/14)
// MODE 2: proj  — C[m=c][n'=(b,nn)] = sum_k Wp[c][k]*g_ao[n'][k]; out NCHW coalesced, +bp[c]
// =====================================================================================
template<int MODE>
__global__ __launch_bounds__(256, 2)
void gemm_big(const float* __restrict__ Asrc,
              const float* __restrict__ W0, const float* __restrict__ W1, const float* __restrict__ W2,
              const float* __restrict__ bias, float* __restrict__ outp, int M, int N)
{
    __shared__ float As[2][16][132];
    __shared__ float Bs[2][16][68];

    const int tid = threadIdx.x;
    const int bm = blockIdx.y * 128;
    const int bn = blockIdx.x * 64;
    const int ty = tid >> 4;      // 0..15  -> m = ty*8
    const int tx = tid & 15;      // 0..15  -> n = tx*4

    unsigned long long acc[4][4];
    #pragma unroll
    for (int i = 0; i < 4; i++)
        #pragma unroll
        for (int j = 0; j < 4; j++) acc[i][j] = 0ull;

    // ---- load helpers (registers) ----
    float  ra[8];
    float4 ra4[2];
    float4 rb4;

    const int k4  = (tid & 3) * 4;
    const int mo4 = tid >> 2;            // 0..63
    const int no4 = tid >> 2;            // 0..63

    auto ldgA = [&](int k0) {
        if (MODE == 0) {
            #pragma unroll
            for (int i = 0; i < 8; i++) {
                int mo = (tid & 63) + ((i & 1) << 6);
                int ko = (tid >> 6) + ((i >> 1) << 2);
                int m = bm + mo;
                float v = 0.0f;
                if (m < M) {
                    int b = m / Nv, nn = m - b * Nv;
                    v = Asrc[((size_t)(b * Cv + k0 + ko)) * Nv + nn];
                }
                ra[i] = v;
            }
        } else {
            const int lda = (MODE == 1) ? QKVC : Cv;
            #pragma unroll
            for (int i = 0; i < 2; i++) {
                int m = bm + mo4 + i * 64;
                if (m < M) ra4[i] = *(const float4*)&Asrc[(size_t)m * lda + k0 + k4];
                else       ra4[i] = make_float4(0.f, 0.f, 0.f, 0.f);
            }
        }
    };
    auto ldgB = [&](int k0) {
        int n = bn + no4;
        const float* row = nullptr;
        if (MODE == 0) {
            int region = n / Cv;
            int nl = n - region * Cv;
            const float* Wt = (region == 0) ? W0 : (region == 1 ? W1 : W2);
            row = Wt + (size_t)nl * Cv;
        } else if (MODE == 1) {
            if (n < Cv) row = W0 + (size_t)n * Cv;
            else if (n - Cv < 2 * KKv) row = W1 + (size_t)(n - Cv) * Cv;
        } else {
            if (n < N) row = Asrc ? (W0 + 0) : nullptr, row = W0; // placeholder (unused)
        }
        if (MODE == 2) {
            // B = g_ao[n'][k]
            if (n < N) rb4 = *(const float4*)&g_ao[(size_t)n * Cv + k0 + k4];
            else       rb4 = make_float4(0.f, 0.f, 0.f, 0.f);
        } else {
            if (row) rb4 = *(const float4*)&row[k0 + k4];
            else     rb4 = make_float4(0.f, 0.f, 0.f, 0.f);
        }
    };
    auto sts = [&](int buf) {
        if (MODE == 0) {
            #pragma unroll
            for (int i = 0; i < 8; i++) {
                int mo = (tid & 63) + ((i & 1) << 6);
                int ko = (tid >> 6) + ((i >> 1) << 2);
                As[buf][ko][mo] = ra[i];
            }
        } else {
            #pragma unroll
            for (int i = 0; i < 2; i++) {
                As[buf][k4 + 0][mo4 + i * 64] = ra4[i].x;
                As[buf][k4 + 1][mo4 + i * 64] = ra4[i].y;
                As[buf][k4 + 2][mo4 + i * 64] = ra4[i].z;
                As[buf][k4 + 3][mo4 + i * 64] = ra4[i].w;
            }
        }
        Bs[buf][k4 + 0][no4] = rb4.x;
        Bs[buf][k4 + 1][no4] = rb4.y;
        Bs[buf][k4 + 2][no4] = rb4.z;
        Bs[buf][k4 + 3][no4] = rb4.w;
    };

    const int NT = Cv / 16;   // 24 K-tiles
    ldgA(0); ldgB(0);
    sts(0);
    __syncthreads();

    for (int kt = 0; kt < NT; kt++) {
        const int cur = kt & 1;
        if (kt + 1 < NT) { ldgA((kt + 1) * 16); ldgB((kt + 1) * 16); }
        #pragma unroll
        for (int k = 0; k < 16; k++) {
            unsigned long long a2[4];
            #pragma unroll
            for (int j = 0; j < 4; j++)
                a2[j] = *(const unsigned long long*)&As[cur][k][ty * 8 + j * 2];
            float4 bv = *(const float4*)&Bs[cur][k][tx * 4];
            unsigned long long b2[4];
            b2[0] = pk2(bv.x, bv.x); b2[1] = pk2(bv.y, bv.y);
            b2[2] = pk2(bv.z, bv.z); b2[3] = pk2(bv.w, bv.w);
            #pragma unroll
            for (int i = 0; i < 4; i++)
                #pragma unroll
                for (int j = 0; j < 4; j++)
                    fma2(acc[i][j], a2[i], b2[j]);
        }
        if (kt + 1 < NT) {
            __syncthreads();
            sts(1 - cur);
            __syncthreads();
        }
    }

    // ---- epilogue ----
    #pragma unroll
    for (int i = 0; i < 4; i++) {
        #pragma unroll
        for (int j = 0; j < 4; j++) {
            float2 f = upk(acc[i][j]);
            int n = bn + tx * 4 + j;
            #pragma unroll
            for (int half = 0; half < 2; half++) {
                int m = bm + ty * 8 + i * 2 + half;
                float v = half ? f.y : f.x;
                if (m >= M) continue;
                if (MODE == 0) {
                    if (n < Cv) v += bias[n];
                    g_qkv[(size_t)m * QKVC + n] = v;
                } else if (MODE == 1) {
                    if (n < Cv) {
                        g_t1[(size_t)m * Cv + n] = gelu_exact(v + bias[n]);
                    } else if (n - Cv < 2 * KKv) {
                        g_co[(size_t)m * (2 * KKv) + (n - Cv)] = tanhf(v) * (1.0f / 14.0f);
                    }
                } else {
                    if (n >= N) continue;
                    int b = n / Nv, nn = n - b * Nv;
                    outp[((size_t)(b * Cv + m)) * Nv + nn] = v + bias[m];
                }
            }
        }
    }
}

// ================= generic 32x64 GEMM, K=384 (offset net only) =================
__global__ void gemm32(const float* __restrict__ A, int lda,
                       const float* __restrict__ Wt, float* __restrict__ out,
                       int M, int N, int ldc, float scale)
{
    __shared__ float As[16][34];
    __shared__ float Bs[16][66];
    const int bm = blockIdx.y * 32;
    const int bn = blockIdx.x * 64;
    const int tid = threadIdx.x;
    const int lk = tid & 15, lm = tid >> 4;
    const int ty = tid >> 4, tx = tid & 15;

    unsigned long long acc[4];
    #pragma unroll
    for (int j = 0; j < 4; j++) acc[j] = 0ull;

    for (int k0 = 0; k0 < Cv; k0 += 16) {
        #pragma unroll
        for (int i = 0; i < 2; i++) {
            int m = bm + lm + i * 16;
            As[lk][lm + i * 16] = (m < M) ? A[(size_t)m * lda + k0 + lk] : 0.0f;
        }
        #pragma unroll
        for (int i = 0; i < 4; i++) {
            int n = bn + lm + i * 16;
            Bs[lk][lm + i * 16] = (n < N) ? Wt[(size_t)n * Cv + k0 + lk] : 0.0f;
        }
        __syncthreads();
        #pragma unroll
        for (int k = 0; k < 16; k++) {
            unsigned long long a2 = *(const unsigned long long*)&As[k][ty * 2];
            #pragma unroll
            for (int j = 0; j < 4; j++) {
                float b = Bs[k][tx * 4 + j];
                fma2(acc[j], a2, pk2(b, b));
            }
        }
        __syncthreads();
    }
    #pragma unroll
    for (int j = 0; j < 4; j++) {
        float2 f = upk(acc[j]);
        int n = bn + tx * 4 + j;
        if (n >= N) continue;
        #pragma unroll
        for (int ii = 0; ii < 2; ii++) {
            int m = bm + ty * 2 + ii;
            if (m >= M) continue;
            float v = (ii == 0) ? f.x : f.y;
            out[(size_t)m * ldc + n] = tanhf(v) * scale;
        }
    }
}

// ================= depthwise 3x3 s2 conv + LN + GELU =================
__global__ void dwln_kernel(const float* __restrict__ Wdw, const float* __restrict__ bdw,
                            const float* __restrict__ lng, const float* __restrict__ lnb)
{
    int bs = blockIdx.x;
    int b = bs / Sv, s = bs % Sv;
    int oy = s / rWv, ox = s % rWv;
    int c = threadIdx.x;
    float acc = bdw[c];
    #pragma unroll
    for (int ky = 0; ky < 3; ky++) {
        int y = oy*2 - 1 + ky;
        if (y < 0 || y >= Hv) continue;
        #pragma unroll
        for (int kx = 0; kx < 3; kx++) {
            int x = ox*2 - 1 + kx;
            if (x < 0 || x >= Wv_) continue;
            acc = fmaf(g_t1[((size_t)b*Nv + y*Wv_ + x)*Cv + c], Wdw[c*9 + ky*3 + kx], acc);
        }
    }
    float s1 = acc, s2 = acc*acc;
    #pragma unroll
    for (int o = 16; o > 0; o >>= 1) {
        s1 += __shfl_xor_sync(0xffffffffu, s1, o);
        s2 += __shfl_xor_sync(0xffffffffu, s2, o);
    }
    __shared__ float w1[12], w2[12];
    __shared__ float s_mu, s_rstd;
    if ((c & 31) == 0) { w1[c >> 5] = s1; w2[c >> 5] = s2; }
    __syncthreads();
    if (c == 0) {
        float t1s = 0.f, t2s = 0.f;
        #pragma unroll
        for (int i = 0; i < 12; i++) { t1s += w1[i]; t2s += w2[i]; }
        float mu = t1s / (float)Cv;
        float var = t2s / (float)Cv - mu*mu;
        s_mu = mu; s_rstd = rsqrtf(var + 1e-5f);
    }
    __syncthreads();
    float v = (acc - s_mu) * s_rstd * lng[c] + lnb[c];
    g_t3[(size_t)bs*Cv + c] = gelu_exact(v);
}

// ================= per-head score maps QK[b,h,n,p] = q.xK =================
__global__ void qk_kernel()
{
    int bh = blockIdx.z;
    int b = bh / HEADS, h = bh % HEADS;
    int n0 = blockIdx.y * 32, p0 = blockIdx.x * 32;
    __shared__ float qs[32][33], ks[32][33];
    int tid = threadIdx.x;
    int lr = tid >> 5, lc = tid & 31;
    #pragma unroll
    for (int i = 0; i < 4; i++) {
        int n = n0 + lr + i*8;
        qs[lr + i*8][lc] = (n < Nv) ? g_qkv[((size_t)b*Nv + n)*QKVC + h*HC + lc] : 0.0f;
        int p = p0 + lr + i*8;
        ks[lr + i*8][lc] = (p < Nv) ? g_qkv[((size_t)b*Nv + p)*QKVC + Cv + h*HC + lc] : 0.0f;
    }
    __syncthreads();
    int pcol = tid & 31, ng = tid >> 5;
    float acc[4] = {0.f, 0.f, 0.f, 0.f};
    #pragma unroll
    for (int d = 0; d < 32; d++) {
        float kv = ks[pcol][d];
        #pragma unroll
        for (int i = 0; i < 4; i++) acc[i] = fmaf(qs[ng*4 + i][d], kv, acc[i]);
    }
    #pragma unroll
    for (int i = 0; i < 4; i++) {
        int n = n0 + ng*4 + i, p = p0 + pcol;
        if (n < Nv && p < Nv)
            g_qk[(((size_t)bh)*Nv + n)*Nv + p] = acc[i];
    }
}

// ================= scores + softmax + fold probs into dense A[b,h,n,:] =================
__global__ void score_kernel(const float* __restrict__ posembed)
{
    const int bn = blockIdx.x;
    const int b = bn / Nv, n = bn % Nv;
    const int ny = n / Wv_, nx = n % Wv_;
    __shared__ float sc[HEADS*TS];
    __shared__ int   sp[TS*4];
    __shared__ float swt[TS*4];
    __shared__ float sA[HEADS][Nv];

    for (int item = threadIdx.x; item < HEADS*TS; item += blockDim.x) {
        const int h = item / TS, s = item % TS;
        float py, px, tpy, tpx;
        if (s < Sv) {
            int rh = s / rWv, rw = s % rWv;
            float offy = g_off[((size_t)b*Sv + s)*(2*Nv) + 0*Nv + n];
            float offx = g_off[((size_t)b*Sv + s)*(2*Nv) + 1*Nv + n];
            float refy = (float)(rh*2) * (2.0f/13.0f) - 1.0f;
            float refx = (float)(rw*2) * (2.0f/13.0f) - 1.0f;
            py = (offy + refy + 1.0f) * 6.5f;
            px = (offx + refx + 1.0f) * 6.5f;
            tpy = ((float)(2*rh - ny) * (1.0f/13.0f) - offy + 1.0f) * 13.0f;
            tpx = ((float)(2*rw - nx) * (1.0f/13.0f) - offx + 1.0f) * 13.0f;
        } else {
            int j = s - Sv;
            float coy = g_co[((size_t)b*Nv + n)*(2*KKv) + j*2 + 0];
            float cox = g_co[((size_t)b*Nv + n)*(2*KKv) + j*2 + 1];
            float cy = (float)ny + c_offm[j][0];
            float cx = (float)nx + c_offm[j][1];
            float cny = fminf(fmaxf(cy, 0.0f), 14.0f) * (2.0f/13.0f) - 1.0f;
            float cnx = fminf(fmaxf(cx, 0.0f), 14.0f) * (2.0f/13.0f) - 1.0f;
            py = (coy + cny + 1.0f) * 6.5f;
            px = (cox + cnx + 1.0f) * 6.5f;
            tpy = (coy - (float)ny + 1.0f) * 13.0f;
            tpx = (cox - (float)nx + 1.0f) * 13.0f;
        }
        float y0 = floorf(py), x0 = floorf(px);
        float wy1 = py - y0, wx1 = px - x0;
        const float* qkb = g_qk + (((size_t)(b*HEADS + h))*Nv + n)*Nv;
        float val = 0.0f;
        #pragma unroll
        for (int ccy = 0; ccy < 2; ccy++) {
            #pragma unroll
            for (int ccx = 0; ccx < 2; ccx++) {
                float yf = y0 + (float)ccy, xf = x0 + (float)ccx;
                float w = (ccy ? wy1 : 1.0f - wy1) * (ccx ? wx1 : 1.0f - wx1);
                bool valid = (yf >= 0.0f) && (yf <= 13.0f) && (xf >= 0.0f) && (xf <= 13.0f);
                if (!valid) w = 0.0f;
                int yi = (int)fminf(fmaxf(yf, 0.0f), 13.0f);
                int xi = (int)fminf(fmaxf(xf, 0.0f), 13.0f);
                int pix = yi*Wv_ + xi;
                val += w * qkb[pix];
                if (h == 0) { sp[s*4 + ccy*2 + ccx] = pix; swt[s*4 + ccy*2 + ccx] = w; }
            }
        }
        float by0 = floorf(tpy), bx0 = floorf(tpx);
        float bwy = tpy - by0, bwx = tpx - bx0;
        const float* tb = posembed + (size_t)h * (27*27);
        float bval = 0.0f;
        #pragma unroll
        for (int ccy = 0; ccy < 2; ccy++) {
            #pragma unroll
            for (int ccx = 0; ccx < 2; ccx++) {
                float yf = by0 + (float)ccy, xf = bx0 + (float)ccx;
                float w = (ccy ? bwy : 1.0f - bwy) * (ccx ? bwx : 1.0f - bwx);
                bool valid = (yf >= 0.0f) && (yf <= 26.0f) && (xf >= 0.0f) && (xf <= 26.0f);
                if (!valid) w = 0.0f;
                int yi = (int)fminf(fmaxf(yf, 0.0f), 26.0f);
                int xi = (int)fminf(fmaxf(xf, 0.0f), 26.0f);
                bval += w * tb[yi*27 + xi];
            }
        }
        sc[h*TS + s] = val + bval;
    }
    __syncthreads();

    const int wid = threadIdx.x >> 5, lane = threadIdx.x & 31;
    {
        float m = -1e30f;
        for (int s = lane; s < TS; s += 32) m = fmaxf(m, sc[wid*TS + s]);
        #pragma unroll
        for (int o = 16; o > 0; o >>= 1) m = fmaxf(m, __shfl_xor_sync(0xffffffffu, m, o));
        float sum = 0.0f;
        for (int s = lane; s < TS; s += 32) {
            float e = expf(sc[wid*TS + s] - m);
            sc[wid*TS + s] = e;
            sum += e;
        }
        #pragma unroll
        for (int o = 16; o > 0; o >>= 1) sum += __shfl_xor_sync(0xffffffffu, sum, o);
        float inv = 1.0f / sum;
        for (int s = lane; s < TS; s += 32) sc[wid*TS + s] *= inv;
    }

    for (int idx = threadIdx.x; idx < HEADS*Nv; idx += blockDim.x)
        ((float*)sA)[idx] = 0.0f;
    __syncthreads();

    for (int i = lane; i < TS*4; i += 32) {
        atomicAdd(&sA[wid][sp[i]], sc[wid*TS + (i >> 2)] * swt[i]);
    }
    __syncthreads();

    for (int idx = threadIdx.x; idx < HEADS*Nv; idx += blockDim.x) {
        int h = idx / Nv, p = idx - h * Nv;
        g_A[(((size_t)(b*HEADS + h))*Nv + n)*Nv + p] = sA[h][p];
    }
}

// ================= AV GEMM: out[b,n,h,:] = A[b,h,n,:] @ xV[b,:,h,:] (+bv) =================
__global__ void av_kernel(const float* __restrict__ bvv)
{
    const int n0 = blockIdx.x * 32;
    const int bh = blockIdx.y;
    const int b = bh / HEADS, h = bh - b * HEADS;
    __shared__ float As[32][33], Vs[32][33];
    const int tid = threadIdx.x;
    const int lr = tid >> 5, lc = tid & 31;
    float acc[4] = {0.f, 0.f, 0.f, 0.f};
    const float* Arow = g_A + ((size_t)bh * Nv) * Nv;

    for (int p0 = 0; p0 < Nv; p0 += 32) {
        #pragma unroll
        for (int i = 0; i < 4; i++) {
            int r = lr + 8*i;
            int n = n0 + r;
            As[r][lc] = (n < Nv && p0 + lc < Nv) ? Arow[(size_t)n*Nv + p0 + lc] : 0.0f;
            int p = p0 + r;
            Vs[r][lc] = (p < Nv) ? g_qkv[((size_t)(b*Nv + p))*QKVC + 2*Cv + h*HC + lc] : 0.0f;
        }
        __syncthreads();
        #pragma unroll
        for (int pp = 0; pp < 32; pp++) {
            float vv = Vs[pp][lc];
            #pragma unroll
            for (int i = 0; i < 4; i++) acc[i] = fmaf(As[lr*4 + i][pp], vv, acc[i]);
        }
        __syncthreads();
    }
    float bb = bvv[h*HC + lc];
    #pragma unroll
    for (int i = 0; i < 4; i++) {
        int n = n0 + lr*4 + i;
        if (n < Nv) g_ao[((size_t)(b*Nv + n))*Cv + h*HC + lc] = acc[i] + bb;
    }
}

extern "C" void kernel_launch(void* const* d_in, const int* in_sizes, int n_in,
                              void* d_out, int out_size)
{
    const float* x    = (const float*)d_in[0];
    const float* Wq   = (const float*)d_in[1];
    const float* bq   = (const float*)d_in[2];
    const float* Wk   = (const float*)d_in[3];
    // bk cancels in softmax — unused
    const float* Wvv  = (const float*)d_in[5];
    const float* bvv  = (const float*)d_in[6];
    const float* Wo1  = (const float*)d_in[7];
    const float* bo1  = (const float*)d_in[8];
    const float* Wdw  = (const float*)d_in[9];
    const float* bdw  = (const float*)d_in[10];
    const float* lng  = (const float*)d_in[11];
    const float* lnb  = (const float*)d_in[12];
    const float* Wo2  = (const float*)d_in[13];
    const float* Wco  = (const float*)d_in[14];
    const float* pos  = (const float*)d_in[15];
    const float* Wp   = (const float*)d_in[16];
    const float* bp   = (const float*)d_in[17];
    float* out = (float*)d_out;

    float* p_qkv; cudaGetSymbolAddress((void**)&p_qkv, g_qkv);
    float* p_t3;  cudaGetSymbolAddress((void**)&p_t3,  g_t3);
    float* p_off; cudaGetSymbolAddress((void**)&p_off, g_off);

    // qkv: N=1152, M=1568 -> 18 x 13 blocks
    gemm_big<0><<<dim3(18, 13), 256>>>(x, Wq, Wk, Wvv, bq, nullptr, BNROWS, QKVC);
    // t1 + co: N=402 -> 7 x 13 blocks  (A = q columns of g_qkv)
    gemm_big<1><<<dim3(7, 13), 256>>>(p_qkv, Wo1, Wco, nullptr, bo1, nullptr, BNROWS, Cv + 2*KKv);
    // per-head QK maps
    qk_kernel<<<dim3(7, 7, Bv*HEADS), 256>>>();
    // offset net tail
    dwln_kernel<<<Bv*Sv, Cv>>>(Wdw, bdw, lng, lnb);
    gemm32<<<dim3(7, 13), 256>>>(p_t3, Cv, Wo2, p_off, Bv*Sv, 2*Nv, 2*Nv, 2.0f/14.0f);
    // scores -> probs -> dense A
    score_kernel<<<Bv*Nv, 384>>>(pos);
    // AV
    av_kernel<<<dim3(7, Bv*HEADS), 256>>>(bvv);
    // final projection: M=384 (channels), N=1568 -> 25 x 3 blocks, coalesced NCHW stores
    gemm_big<2><<<dim3(25, 3), 256>>>(Wp, Wp, nullptr, nullptr, bp, out, Cv, BNROWS);
}

// round 4
// speedup vs baseline: 1.3922x; 1.0560x over previous
#include <cuda_runtime.h>
#include <cuda_bf16.h>
#include <math.h>

#define Bv   8
#define Cv   384
#define Hv   14
#define Wv_  14
#define HEADS 12
#define HC   32
#define Nv   196
#define Sv   49
#define rHv  7
#define rWv  7
#define KKv  9
#define TS   58
#define BNROWS (Bv*Nv)   // 1568
#define QKVC 1152

// Scratch
__device__ float g_qkv[BNROWS*QKVC];          // q | xK | xV   (stride 1152)
__device__ float g_t1 [BNROWS*Cv];
__device__ float g_t3 [Bv*Sv*Cv];
__device__ float g_off[Bv*Sv*2*Nv];
__device__ float g_co [BNROWS*2*KKv];
__device__ float g_qk [(size_t)Bv*HEADS*Nv*Nv];
__device__ float g_A  [(size_t)Bv*HEADS*Nv*Nv];
__device__ float g_ao [BNROWS*Cv];

__constant__ float c_offm[9][2] = {
    {0.f,-1.f},{-1.f,-1.f},{-1.f,0.f},{-1.f,1.f},{0.f,1.f},{1.f,1.f},{1.f,0.f},{1.f,-1.f},{0.f,0.f}
};

__device__ __forceinline__ float gelu_exact(float v) {
    return 0.5f * v * (1.0f + erff(v * 0.7071067811865476f));
}

// ---- f32x2 packed math helpers (sm_100+) ----
__device__ __forceinline__ unsigned long long pk2(float lo, float hi) {
    unsigned long long r;
    asm("mov.b64 %0, {%1,%2};" : "=l"(r) : "f"(lo), "f"(hi));
    return r;
}
__device__ __forceinline__ void fma2(unsigned long long &c, unsigned long long a, unsigned long long b) {
    asm("fma.rn.f32x2 %0, %1, %2, %3;" : "=l"(c) : "l"(a), "l"(b), "l"(c));
}
__device__ __forceinline__ float2 upk(unsigned long long v) {
    float2 f;
    asm("mov.b64 {%0,%1}, %2;" : "=f"(f.x), "=f"(f.y) : "l"(v));
    return f;
}

// =====================================================================================
// GEMM core: 128x64 tile, BK=16, double-buffered, 256 threads, 8m x 4n, f32x2 acc.
// MODE 0: qkv, MODE 1: t1co, MODE 2: proj (coalesced NCHW store)
// =====================================================================================
template<int MODE>
__device__ __forceinline__
void gemm_core(float As[2][16][132], float Bs[2][16][68], int bxx, int byy,
               const float* __restrict__ Asrc,
               const float* __restrict__ W0, const float* __restrict__ W1, const float* __restrict__ W2,
               const float* __restrict__ bias, float* __restrict__ outp, int M, int N)
{
    const int tid = threadIdx.x;
    const int bm = byy * 128;
    const int bn = bxx * 64;
    const int ty = tid >> 4;
    const int tx = tid & 15;

    unsigned long long acc[4][4];
    #pragma unroll
    for (int i = 0; i < 4; i++)
        #pragma unroll
        for (int j = 0; j < 4; j++) acc[i][j] = 0ull;

    float  ra[8];
    float4 ra4[2];
    float4 rb4;

    const int k4  = (tid & 3) * 4;
    const int mo4 = tid >> 2;
    const int no4 = tid >> 2;

    auto ldgA = [&](int k0) {
        if (MODE == 0) {
            #pragma unroll
            for (int i = 0; i < 8; i++) {
                int mo = (tid & 63) + ((i & 1) << 6);
                int ko = (tid >> 6) + ((i >> 1) << 2);
                int m = bm + mo;
                float v = 0.0f;
                if (m < M) {
                    int b = m / Nv, nn = m - b * Nv;
                    v = Asrc[((size_t)(b * Cv + k0 + ko)) * Nv + nn];
                }
                ra[i] = v;
            }
        } else {
            const int lda = (MODE == 1) ? QKVC : Cv;
            #pragma unroll
            for (int i = 0; i < 2; i++) {
                int m = bm + mo4 + i * 64;
                if (m < M) ra4[i] = *(const float4*)&Asrc[(size_t)m * lda + k0 + k4];
                else       ra4[i] = make_float4(0.f, 0.f, 0.f, 0.f);
            }
        }
    };
    auto ldgB = [&](int k0) {
        int n = bn + no4;
        if (MODE == 2) {
            if (n < N) rb4 = *(const float4*)&g_ao[(size_t)n * Cv + k0 + k4];
            else       rb4 = make_float4(0.f, 0.f, 0.f, 0.f);
        } else {
            const float* row = nullptr;
            if (MODE == 0) {
                int region = n / Cv;
                int nl = n - region * Cv;
                const float* Wt = (region == 0) ? W0 : (region == 1 ? W1 : W2);
                row = Wt + (size_t)nl * Cv;
            } else {
                if (n < Cv) row = W0 + (size_t)n * Cv;
                else if (n - Cv < 2 * KKv) row = W1 + (size_t)(n - Cv) * Cv;
            }
            if (row) rb4 = *(const float4*)&row[k0 + k4];
            else     rb4 = make_float4(0.f, 0.f, 0.f, 0.f);
        }
    };
    auto sts = [&](int buf) {
        if (MODE == 0) {
            #pragma unroll
            for (int i = 0; i < 8; i++) {
                int mo = (tid & 63) + ((i & 1) << 6);
                int ko = (tid >> 6) + ((i >> 1) << 2);
                As[buf][ko][mo] = ra[i];
            }
        } else {
            #pragma unroll
            for (int i = 0; i < 2; i++) {
                As[buf][k4 + 0][mo4 + i * 64] = ra4[i].x;
                As[buf][k4 + 1][mo4 + i * 64] = ra4[i].y;
                As[buf][k4 + 2][mo4 + i * 64] = ra4[i].z;
                As[buf][k4 + 3][mo4 + i * 64] = ra4[i].w;
            }
        }
        Bs[buf][k4 + 0][no4] = rb4.x;
        Bs[buf][k4 + 1][no4] = rb4.y;
        Bs[buf][k4 + 2][no4] = rb4.z;
        Bs[buf][k4 + 3][no4] = rb4.w;
    };

    const int NT = Cv / 16;
    ldgA(0); ldgB(0);
    sts(0);
    __syncthreads();

    for (int kt = 0; kt < NT; kt++) {
        const int cur = kt & 1;
        if (kt + 1 < NT) { ldgA((kt + 1) * 16); ldgB((kt + 1) * 16); }
        #pragma unroll
        for (int k = 0; k < 16; k++) {
            unsigned long long a2[4];
            #pragma unroll
            for (int j = 0; j < 4; j++)
                a2[j] = *(const unsigned long long*)&As[cur][k][ty * 8 + j * 2];
            float4 bv = *(const float4*)&Bs[cur][k][tx * 4];
            unsigned long long b2[4];
            b2[0] = pk2(bv.x, bv.x); b2[1] = pk2(bv.y, bv.y);
            b2[2] = pk2(bv.z, bv.z); b2[3] = pk2(bv.w, bv.w);
            #pragma unroll
            for (int i = 0; i < 4; i++)
                #pragma unroll
                for (int j = 0; j < 4; j++)
                    fma2(acc[i][j], a2[i], b2[j]);
        }
        if (kt + 1 < NT) {
            __syncthreads();
            sts(1 - cur);
            __syncthreads();
        }
    }

    #pragma unroll
    for (int i = 0; i < 4; i++) {
        #pragma unroll
        for (int j = 0; j < 4; j++) {
            float2 f = upk(acc[i][j]);
            int n = bn + tx * 4 + j;
            #pragma unroll
            for (int half = 0; half < 2; half++) {
                int m = bm + ty * 8 + i * 2 + half;
                float v = half ? f.y : f.x;
                if (m >= M) continue;
                if (MODE == 0) {
                    if (n < Cv) v += bias[n];
                    g_qkv[(size_t)m * QKVC + n] = v;
                } else if (MODE == 1) {
                    if (n < Cv) {
                        g_t1[(size_t)m * Cv + n] = gelu_exact(v + bias[n]);
                    } else if (n - Cv < 2 * KKv) {
                        g_co[(size_t)m * (2 * KKv) + (n - Cv)] = tanhf(v) * (1.0f / 14.0f);
                    }
                } else {
                    if (n >= N) continue;
                    int b = n / Nv, nn = n - b * Nv;
                    outp[((size_t)(b * Cv + m)) * Nv + nn] = v + bias[m];
                }
            }
        }
    }
}

template<int MODE>
__global__ __launch_bounds__(256, 2)
void gemm_big(const float* __restrict__ Asrc,
              const float* __restrict__ W0, const float* __restrict__ W1, const float* __restrict__ W2,
              const float* __restrict__ bias, float* __restrict__ outp, int M, int N)
{
    __shared__ float As[2][16][132];
    __shared__ float Bs[2][16][68];
    gemm_core<MODE>(As, Bs, blockIdx.x, blockIdx.y, Asrc, W0, W1, W2, bias, outp, M, N);
}

// ================= fused: t1co GEMM (91 blocks) + qk maps (4704 blocks) =================
#define T1CO_BLOCKS 91
__global__ __launch_bounds__(256, 2)
void fused_t1co_qk(const float* __restrict__ Wo1, const float* __restrict__ bo1,
                   const float* __restrict__ Wco, const float* __restrict__ q_src)
{
    const int idx = blockIdx.x;
    if (idx < T1CO_BLOCKS) {
        __shared__ float As[2][16][132];
        __shared__ float Bs[2][16][68];
        gemm_core<1>(As, Bs, idx % 7, idx / 7, q_src, Wo1, Wco, nullptr, bo1, nullptr,
                     BNROWS, Cv + 2 * KKv);
    } else {
        const int idx2 = idx - T1CO_BLOCKS;
        const int bxq = idx2 % 7;
        const int byq = (idx2 / 7) % 7;
        const int bh  = idx2 / 49;
        const int b = bh / HEADS, h = bh - b * HEADS;
        const int n0 = byq * 32, p0 = bxq * 32;
        __shared__ float qs[32][33], ks[32][33];
        int tid = threadIdx.x;
        int lr = tid >> 5, lc = tid & 31;
        #pragma unroll
        for (int i = 0; i < 4; i++) {
            int n = n0 + lr + i * 8;
            qs[lr + i*8][lc] = (n < Nv) ? g_qkv[((size_t)b*Nv + n)*QKVC + h*HC + lc] : 0.0f;
            int p = p0 + lr + i * 8;
            ks[lr + i*8][lc] = (p < Nv) ? g_qkv[((size_t)b*Nv + p)*QKVC + Cv + h*HC + lc] : 0.0f;
        }
        __syncthreads();
        int pcol = tid & 31, ng = tid >> 5;
        float acc[4] = {0.f, 0.f, 0.f, 0.f};
        #pragma unroll
        for (int d = 0; d < 32; d++) {
            float kv = ks[pcol][d];
            #pragma unroll
            for (int i = 0; i < 4; i++) acc[i] = fmaf(qs[ng*4 + i][d], kv, acc[i]);
        }
        #pragma unroll
        for (int i = 0; i < 4; i++) {
            int n = n0 + ng*4 + i, p = p0 + pcol;
            if (n < Nv && p < Nv)
                g_qk[(((size_t)bh)*Nv + n)*Nv + p] = acc[i];
        }
    }
}

// ================= generic 32x64 GEMM (offset net only) =================
__global__ void gemm32(const float* __restrict__ A, int lda,
                       const float* __restrict__ Wt, float* __restrict__ out,
                       int M, int N, int ldc, float scale)
{
    __shared__ float As[16][34];
    __shared__ float Bs[16][66];
    const int bm = blockIdx.y * 32;
    const int bn = blockIdx.x * 64;
    const int tid = threadIdx.x;
    const int lk = tid & 15, lm = tid >> 4;
    const int ty = tid >> 4, tx = tid & 15;

    unsigned long long acc[4];
    #pragma unroll
    for (int j = 0; j < 4; j++) acc[j] = 0ull;

    for (int k0 = 0; k0 < Cv; k0 += 16) {
        #pragma unroll
        for (int i = 0; i < 2; i++) {
            int m = bm + lm + i * 16;
            As[lk][lm + i * 16] = (m < M) ? A[(size_t)m * lda + k0 + lk] : 0.0f;
        }
        #pragma unroll
        for (int i = 0; i < 4; i++) {
            int n = bn + lm + i * 16;
            Bs[lk][lm + i * 16] = (n < N) ? Wt[(size_t)n * Cv + k0 + lk] : 0.0f;
        }
        __syncthreads();
        #pragma unroll
        for (int k = 0; k < 16; k++) {
            unsigned long long a2 = *(const unsigned long long*)&As[k][ty * 2];
            #pragma unroll
            for (int j = 0; j < 4; j++) {
                float b = Bs[k][tx * 4 + j];
                fma2(acc[j], a2, pk2(b, b));
            }
        }
        __syncthreads();
    }
    #pragma unroll
    for (int j = 0; j < 4; j++) {
        float2 f = upk(acc[j]);
        int n = bn + tx * 4 + j;
        if (n >= N) continue;
        #pragma unroll
        for (int ii = 0; ii < 2; ii++) {
            int m = bm + ty * 2 + ii;
            if (m >= M) continue;
            float v = (ii == 0) ? f.x : f.y;
            out[(size_t)m * ldc + n] = tanhf(v) * scale;
        }
    }
}

// ================= depthwise 3x3 s2 conv + LN + GELU =================
__global__ void dwln_kernel(const float* __restrict__ Wdw, const float* __restrict__ bdw,
                            const float* __restrict__ lng, const float* __restrict__ lnb)
{
    int bs = blockIdx.x;
    int b = bs / Sv, s = bs % Sv;
    int oy = s / rWv, ox = s % rWv;
    int c = threadIdx.x;
    float acc = bdw[c];
    #pragma unroll
    for (int ky = 0; ky < 3; ky++) {
        int y = oy*2 - 1 + ky;
        if (y < 0 || y >= Hv) continue;
        #pragma unroll
        for (int kx = 0; kx < 3; kx++) {
            int x = ox*2 - 1 + kx;
            if (x < 0 || x >= Wv_) continue;
            acc = fmaf(g_t1[((size_t)b*Nv + y*Wv_ + x)*Cv + c], Wdw[c*9 + ky*3 + kx], acc);
        }
    }
    float s1 = acc, s2 = acc*acc;
    #pragma unroll
    for (int o = 16; o > 0; o >>= 1) {
        s1 += __shfl_xor_sync(0xffffffffu, s1, o);
        s2 += __shfl_xor_sync(0xffffffffu, s2, o);
    }
    __shared__ float w1[12], w2[12];
    __shared__ float s_mu, s_rstd;
    if ((c & 31) == 0) { w1[c >> 5] = s1; w2[c >> 5] = s2; }
    __syncthreads();
    if (c == 0) {
        float t1s = 0.f, t2s = 0.f;
        #pragma unroll
        for (int i = 0; i < 12; i++) { t1s += w1[i]; t2s += w2[i]; }
        float mu = t1s / (float)Cv;
        float var = t2s / (float)Cv - mu*mu;
        s_mu = mu; s_rstd = rsqrtf(var + 1e-5f);
    }
    __syncthreads();
    float v = (acc - s_mu) * s_rstd * lng[c] + lnb[c];
    g_t3[(size_t)bs*Cv + c] = gelu_exact(v);
}

// ================= scores + softmax + fold probs into dense A[b,h,n,:] =================
__global__ void score_kernel(const float* __restrict__ posembed)
{
    const int bn = blockIdx.x;
    const int b = bn / Nv, n = bn % Nv;
    const int ny = n / Wv_, nx = n % Wv_;
    __shared__ float sc[HEADS*TS];
    __shared__ int   sp[TS*4];
    __shared__ float swt[TS*4];
    __shared__ __align__(16) float sA[HEADS][Nv];

    // zero sA up front (float4)
    for (int idx = threadIdx.x; idx < HEADS*Nv/4; idx += blockDim.x)
        ((float4*)sA)[idx] = make_float4(0.f, 0.f, 0.f, 0.f);

    for (int item = threadIdx.x; item < HEADS*TS; item += blockDim.x) {
        const int h = item / TS, s = item % TS;
        float py, px, tpy, tpx;
        if (s < Sv) {
            int rh = s / rWv, rw = s % rWv;
            float offy = g_off[((size_t)b*Sv + s)*(2*Nv) + 0*Nv + n];
            float offx = g_off[((size_t)b*Sv + s)*(2*Nv) + 1*Nv + n];
            float refy = (float)(rh*2) * (2.0f/13.0f) - 1.0f;
            float refx = (float)(rw*2) * (2.0f/13.0f) - 1.0f;
            py = (offy + refy + 1.0f) * 6.5f;
            px = (offx + refx + 1.0f) * 6.5f;
            tpy = ((float)(2*rh - ny) * (1.0f/13.0f) - offy + 1.0f) * 13.0f;
            tpx = ((float)(2*rw - nx) * (1.0f/13.0f) - offx + 1.0f) * 13.0f;
        } else {
            int j = s - Sv;
            float coy = g_co[((size_t)b*Nv + n)*(2*KKv) + j*2 + 0];
            float cox = g_co[((size_t)b*Nv + n)*(2*KKv) + j*2 + 1];
            float cy = (float)ny + c_offm[j][0];
            float cx = (float)nx + c_offm[j][1];
            float cny = fminf(fmaxf(cy, 0.0f), 14.0f) * (2.0f/13.0f) - 1.0f;
            float cnx = fminf(fmaxf(cx, 0.0f), 14.0f) * (2.0f/13.0f) - 1.0f;
            py = (coy + cny + 1.0f) * 6.5f;
            px = (cox + cnx + 1.0f) * 6.5f;
            tpy = (coy - (float)ny + 1.0f) * 13.0f;
            tpx = (cox - (float)nx + 1.0f) * 13.0f;
        }
        float y0 = floorf(py), x0 = floorf(px);
        float wy1 = py - y0, wx1 = px - x0;
        const float* qkb = g_qk + (((size_t)(b*HEADS + h))*Nv + n)*Nv;
        float val = 0.0f;
        #pragma unroll
        for (int ccy = 0; ccy < 2; ccy++) {
            #pragma unroll
            for (int ccx = 0; ccx < 2; ccx++) {
                float yf = y0 + (float)ccy, xf = x0 + (float)ccx;
                float w = (ccy ? wy1 : 1.0f - wy1) * (ccx ? wx1 : 1.0f - wx1);
                bool valid = (yf >= 0.0f) && (yf <= 13.0f) && (xf >= 0.0f) && (xf <= 13.0f);
                if (!valid) w = 0.0f;
                int yi = (int)fminf(fmaxf(yf, 0.0f), 13.0f);
                int xi = (int)fminf(fmaxf(xf, 0.0f), 13.0f);
                int pix = yi*Wv_ + xi;
                val += w * qkb[pix];
                if (h == 0) { sp[s*4 + ccy*2 + ccx] = pix; swt[s*4 + ccy*2 + ccx] = w; }
            }
        }
        float by0 = floorf(tpy), bx0 = floorf(tpx);
        float bwy = tpy - by0, bwx = tpx - bx0;
        const float* tb = posembed + (size_t)h * (27*27);
        float bval = 0.0f;
        #pragma unroll
        for (int ccy = 0; ccy < 2; ccy++) {
            #pragma unroll
            for (int ccx = 0; ccx < 2; ccx++) {
                float yf = by0 + (float)ccy, xf = bx0 + (float)ccx;
                float w = (ccy ? bwy : 1.0f - bwy) * (ccx ? bwx : 1.0f - bwx);
                bool valid = (yf >= 0.0f) && (yf <= 26.0f) && (xf >= 0.0f) && (xf <= 26.0f);
                if (!valid) w = 0.0f;
                int yi = (int)fminf(fmaxf(yf, 0.0f), 26.0f);
                int xi = (int)fminf(fmaxf(xf, 0.0f), 26.0f);
                bval += w * tb[yi*27 + xi];
            }
        }
        sc[h*TS + s] = val + bval;
    }
    __syncthreads();

    // softmax (warp w -> head w) then scatter into sA (no extra sync needed between)
    const int wid = threadIdx.x >> 5, lane = threadIdx.x & 31;
    {
        float m = -1e30f;
        for (int s = lane; s < TS; s += 32) m = fmaxf(m, sc[wid*TS + s]);
        #pragma unroll
        for (int o = 16; o > 0; o >>= 1) m = fmaxf(m, __shfl_xor_sync(0xffffffffu, m, o));
        float sum = 0.0f;
        for (int s = lane; s < TS; s += 32) {
            float e = expf(sc[wid*TS + s] - m);
            sc[wid*TS + s] = e;
            sum += e;
        }
        #pragma unroll
        for (int o = 16; o > 0; o >>= 1) sum += __shfl_xor_sync(0xffffffffu, sum, o);
        float inv = 1.0f / sum;
        for (int s = lane; s < TS; s += 32) sc[wid*TS + s] *= inv;
    }
    // scatter: A[h][pix] += prob[h,s] * w[s,corner]   (sp/swt covered by first sync)
    for (int i = lane; i < TS*4; i += 32) {
        atomicAdd(&sA[wid][sp[i]], sc[wid*TS + (i >> 2)] * swt[i]);
    }
    __syncthreads();

    // writeback (float4)
    float4* dst = (float4*)(g_A + ((size_t)(b*HEADS))*Nv*Nv);
    for (int idx = threadIdx.x; idx < HEADS*(Nv/4); idx += blockDim.x) {
        int h = idx / (Nv/4), p4 = idx - h * (Nv/4);
        dst[((size_t)h*Nv + n)*(Nv/4) + p4] = ((float4*)sA)[h*(Nv/4) + p4];
    }
}

// ================= AV GEMM (f32x2): out[b,n,h,:] = A[b,h,n,:] @ xV[b,:,h,:] + bv ========
__global__ __launch_bounds__(128, 4)
void av_kernel(const float* __restrict__ bvv)
{
    const int n0 = blockIdx.x * 64;
    const int bh = blockIdx.y;
    const int b = bh / HEADS, h = bh - b * HEADS;
    __shared__ __align__(16) float Vs[Nv][HC];      // 25088 B
    __shared__ __align__(16) float As[32][68];      // A^T tile: [k=p][n]

    const int tid = threadIdx.x;
    const int tx = tid & 7;        // c-group: c = tx*4
    const int ng = tid >> 3;       // 0..15 : n = n0 + ng*4

    // load V strip (196 x 32) once
    {
        const float* vbase = g_qkv + (size_t)b * Nv * QKVC + 2 * Cv + h * HC;
        for (int i = tid; i < Nv * (HC/4); i += 128) {
            int p = i >> 3, c4 = (i & 7) * 4;
            *(float4*)&Vs[p][c4] = *(const float4*)&vbase[(size_t)p * QKVC + c4];
        }
    }

    unsigned long long acc[2][4];
    #pragma unroll
    for (int i = 0; i < 2; i++)
        #pragma unroll
        for (int j = 0; j < 4; j++) acc[i][j] = 0ull;

    const float* Arow = g_A + ((size_t)bh * Nv) * Nv;
    const int r = tid >> 1, halfq = tid & 1;

    for (int p0 = 0; p0 < Nv; p0 += 32) {
        const int kt = min(32, Nv - p0);
        __syncthreads();
        // transposed load: As[k][n] = A[n0+n][p0+k]
        {
            int nrow = n0 + r;
            #pragma unroll
            for (int q = 0; q < 4; q++) {
                int pl = halfq * 16 + q * 4;
                float4 v = make_float4(0.f, 0.f, 0.f, 0.f);
                if (nrow < Nv && p0 + pl < Nv)
                    v = *(const float4*)&Arow[(size_t)nrow * Nv + p0 + pl];
                As[pl + 0][r] = v.x;
                As[pl + 1][r] = v.y;
                As[pl + 2][r] = v.z;
                As[pl + 3][r] = v.w;
            }
        }
        __syncthreads();
        for (int k = 0; k < kt; k++) {
            float4 af = *(const float4*)&As[k][ng * 4];
            unsigned long long a0 = pk2(af.x, af.y);
            unsigned long long a1 = pk2(af.z, af.w);
            float4 bf = *(const float4*)&Vs[p0 + k][tx * 4];
            unsigned long long b2[4];
            b2[0] = pk2(bf.x, bf.x); b2[1] = pk2(bf.y, bf.y);
            b2[2] = pk2(bf.z, bf.z); b2[3] = pk2(bf.w, bf.w);
            #pragma unroll
            for (int j = 0; j < 4; j++) { fma2(acc[0][j], a0, b2[j]); fma2(acc[1][j], a1, b2[j]); }
        }
    }

    #pragma unroll
    for (int j = 0; j < 4; j++) {
        int c = tx * 4 + j;
        float bb = bvv[h * HC + c];
        #pragma unroll
        for (int i = 0; i < 2; i++) {
            float2 f = upk(acc[i][j]);
            int n = n0 + ng * 4 + i * 2;
            if (n < Nv)     g_ao[((size_t)(b*Nv + n  ))*Cv + h*HC + c] = f.x + bb;
            if (n + 1 < Nv) g_ao[((size_t)(b*Nv + n+1))*Cv + h*HC + c] = f.y + bb;
        }
    }
}

extern "C" void kernel_launch(void* const* d_in, const int* in_sizes, int n_in,
                              void* d_out, int out_size)
{
    const float* x    = (const float*)d_in[0];
    const float* Wq   = (const float*)d_in[1];
    const float* bq   = (const float*)d_in[2];
    const float* Wk   = (const float*)d_in[3];
    // bk cancels in softmax — unused
    const float* Wvv  = (const float*)d_in[5];
    const float* bvv  = (const float*)d_in[6];
    const float* Wo1  = (const float*)d_in[7];
    const float* bo1  = (const float*)d_in[8];
    const float* Wdw  = (const float*)d_in[9];
    const float* bdw  = (const float*)d_in[10];
    const float* lng  = (const float*)d_in[11];
    const float* lnb  = (const float*)d_in[12];
    const float* Wo2  = (const float*)d_in[13];
    const float* Wco  = (const float*)d_in[14];
    const float* pos  = (const float*)d_in[15];
    const float* Wp   = (const float*)d_in[16];
    const float* bp   = (const float*)d_in[17];
    float* out = (float*)d_out;

    float* p_qkv; cudaGetSymbolAddress((void**)&p_qkv, g_qkv);
    float* p_t3;  cudaGetSymbolAddress((void**)&p_t3,  g_t3);
    float* p_off; cudaGetSymbolAddress((void**)&p_off, g_off);

    // 1) qkv: N=1152, M=1568 -> 18 x 13 blocks
    gemm_big<0><<<dim3(18, 13), 256>>>(x, Wq, Wk, Wvv, bq, nullptr, BNROWS, QKVC);
    // 2) fused t1co (91) + qk (4704)
    fused_t1co_qk<<<T1CO_BLOCKS + 7*7*Bv*HEADS, 256>>>(Wo1, bo1, Wco, p_qkv);
    // 3) offset net tail
    dwln_kernel<<<Bv*Sv, Cv>>>(Wdw, bdw, lng, lnb);
    gemm32<<<dim3(7, 13), 256>>>(p_t3, Cv, Wo2, p_off, Bv*Sv, 2*Nv, 2*Nv, 2.0f/14.0f);
    // 4) scores -> probs -> dense A
    score_kernel<<<Bv*Nv, 384>>>(pos);
    // 5) AV
    av_kernel<<<dim3(4, Bv*HEADS), 128>>>(bvv);
    // 6) final projection (coalesced NCHW stores)
    gemm_big<2><<<dim3(25, 3), 256>>>(Wp, Wp, nullptr, nullptr, bp, out, Cv, BNROWS);
}

// round 5
// speedup vs baseline: 1.4113x; 1.0137x over previous
#include <cuda_runtime.h>
#include <cuda_bf16.h>
#include <math.h>

#define Bv   8
#define Cv   384
#define Hv   14
#define Wv_  14
#define HEADS 12
#define HC   32
#define Nv   196
#define Sv   49
#define rHv  7
#define rWv  7
#define KKv  9
#define TS   58
#define BNROWS (Bv*Nv)   // 1568
#define QKVC 1152

// Scratch
__device__ float g_qkv[BNROWS*QKVC];          // q | xK | xV   (stride 1152)
__device__ float g_t1 [BNROWS*Cv];
__device__ float g_t3 [Bv*Sv*Cv];
__device__ float g_off[Bv*Sv*2*Nv];
__device__ float g_co [BNROWS*2*KKv];
__device__ float g_qk [(size_t)Bv*HEADS*Nv*Nv];
__device__ float g_A  [(size_t)Bv*HEADS*Nv*Nv];
__device__ float g_ao [BNROWS*Cv];

__constant__ float c_offm[9][2] = {
    {0.f,-1.f},{-1.f,-1.f},{-1.f,0.f},{-1.f,1.f},{0.f,1.f},{1.f,1.f},{1.f,0.f},{1.f,-1.f},{0.f,0.f}
};

__device__ __forceinline__ float gelu_exact(float v) {
    return 0.5f * v * (1.0f + erff(v * 0.7071067811865476f));
}

// ---- f32x2 packed math helpers (sm_100+) ----
__device__ __forceinline__ unsigned long long pk2(float lo, float hi) {
    unsigned long long r;
    asm("mov.b64 %0, {%1,%2};" : "=l"(r) : "f"(lo), "f"(hi));
    return r;
}
__device__ __forceinline__ void fma2(unsigned long long &c, unsigned long long a, unsigned long long b) {
    asm("fma.rn.f32x2 %0, %1, %2, %3;" : "=l"(c) : "l"(a), "l"(b), "l"(c));
}
__device__ __forceinline__ float2 upk(unsigned long long v) {
    float2 f;
    asm("mov.b64 {%0,%1}, %2;" : "=f"(f.x), "=f"(f.y) : "l"(v));
    return f;
}

// =====================================================================================
// GEMM core: 128x64 tile, BK=16, double-buffered, 256 threads, 8m x 4n, f32x2 acc.
// MODE 0: qkv, MODE 1: t1co, MODE 2: proj (coalesced NCHW store)
// =====================================================================================
template<int MODE>
__device__ __forceinline__
void gemm_core(float As[2][16][132], float Bs[2][16][68], int bxx, int byy,
               const float* __restrict__ Asrc,
               const float* __restrict__ W0, const float* __restrict__ W1, const float* __restrict__ W2,
               const float* __restrict__ bias, float* __restrict__ outp, int M, int N)
{
    const int tid = threadIdx.x;
    const int bm = byy * 128;
    const int bn = bxx * 64;
    const int ty = tid >> 4;
    const int tx = tid & 15;

    unsigned long long acc[4][4];
    #pragma unroll
    for (int i = 0; i < 4; i++)
        #pragma unroll
        for (int j = 0; j < 4; j++) acc[i][j] = 0ull;

    float  ra[8];
    float4 ra4[2];
    float4 rb4;

    const int k4  = (tid & 3) * 4;
    const int mo4 = tid >> 2;
    const int no4 = tid >> 2;

    auto ldgA = [&](int k0) {
        if (MODE == 0) {
            #pragma unroll
            for (int i = 0; i < 8; i++) {
                int mo = (tid & 63) + ((i & 1) << 6);
                int ko = (tid >> 6) + ((i >> 1) << 2);
                int m = bm + mo;
                float v = 0.0f;
                if (m < M) {
                    int b = m / Nv, nn = m - b * Nv;
                    v = Asrc[((size_t)(b * Cv + k0 + ko)) * Nv + nn];
                }
                ra[i] = v;
            }
        } else {
            const int lda = (MODE == 1) ? QKVC : Cv;
            #pragma unroll
            for (int i = 0; i < 2; i++) {
                int m = bm + mo4 + i * 64;
                if (m < M) ra4[i] = *(const float4*)&Asrc[(size_t)m * lda + k0 + k4];
                else       ra4[i] = make_float4(0.f, 0.f, 0.f, 0.f);
            }
        }
    };
    auto ldgB = [&](int k0) {
        int n = bn + no4;
        if (MODE == 2) {
            if (n < N) rb4 = *(const float4*)&g_ao[(size_t)n * Cv + k0 + k4];
            else       rb4 = make_float4(0.f, 0.f, 0.f, 0.f);
        } else {
            const float* row = nullptr;
            if (MODE == 0) {
                int region = n / Cv;
                int nl = n - region * Cv;
                const float* Wt = (region == 0) ? W0 : (region == 1 ? W1 : W2);
                row = Wt + (size_t)nl * Cv;
            } else {
                if (n < Cv) row = W0 + (size_t)n * Cv;
                else if (n - Cv < 2 * KKv) row = W1 + (size_t)(n - Cv) * Cv;
            }
            if (row) rb4 = *(const float4*)&row[k0 + k4];
            else     rb4 = make_float4(0.f, 0.f, 0.f, 0.f);
        }
    };
    auto sts = [&](int buf) {
        if (MODE == 0) {
            #pragma unroll
            for (int i = 0; i < 8; i++) {
                int mo = (tid & 63) + ((i & 1) << 6);
                int ko = (tid >> 6) + ((i >> 1) << 2);
                As[buf][ko][mo] = ra[i];
            }
        } else {
            #pragma unroll
            for (int i = 0; i < 2; i++) {
                As[buf][k4 + 0][mo4 + i * 64] = ra4[i].x;
                As[buf][k4 + 1][mo4 + i * 64] = ra4[i].y;
                As[buf][k4 + 2][mo4 + i * 64] = ra4[i].z;
                As[buf][k4 + 3][mo4 + i * 64] = ra4[i].w;
            }
        }
        Bs[buf][k4 + 0][no4] = rb4.x;
        Bs[buf][k4 + 1][no4] = rb4.y;
        Bs[buf][k4 + 2][no4] = rb4.z;
        Bs[buf][k4 + 3][no4] = rb4.w;
    };

    const int NT = Cv / 16;
    ldgA(0); ldgB(0);
    sts(0);
    __syncthreads();

    for (int kt = 0; kt < NT; kt++) {
        const int cur = kt & 1;
        if (kt + 1 < NT) { ldgA((kt + 1) * 16); ldgB((kt + 1) * 16); }
        #pragma unroll
        for (int k = 0; k < 16; k++) {
            unsigned long long a2[4];
            #pragma unroll
            for (int j = 0; j < 4; j++)
                a2[j] = *(const unsigned long long*)&As[cur][k][ty * 8 + j * 2];
            float4 bv = *(const float4*)&Bs[cur][k][tx * 4];
            unsigned long long b2[4];
            b2[0] = pk2(bv.x, bv.x); b2[1] = pk2(bv.y, bv.y);
            b2[2] = pk2(bv.z, bv.z); b2[3] = pk2(bv.w, bv.w);
            #pragma unroll
            for (int i = 0; i < 4; i++)
                #pragma unroll
                for (int j = 0; j < 4; j++)
                    fma2(acc[i][j], a2[i], b2[j]);
        }
        if (kt + 1 < NT) {
            __syncthreads();
            sts(1 - cur);
            __syncthreads();
        }
    }

    #pragma unroll
    for (int i = 0; i < 4; i++) {
        #pragma unroll
        for (int j = 0; j < 4; j++) {
            float2 f = upk(acc[i][j]);
            int n = bn + tx * 4 + j;
            #pragma unroll
            for (int half = 0; half < 2; half++) {
                int m = bm + ty * 8 + i * 2 + half;
                float v = half ? f.y : f.x;
                if (m >= M) continue;
                if (MODE == 0) {
                    if (n < Cv) v += bias[n];
                    g_qkv[(size_t)m * QKVC + n] = v;
                } else if (MODE == 1) {
                    if (n < Cv) {
                        g_t1[(size_t)m * Cv + n] = gelu_exact(v + bias[n]);
                    } else if (n - Cv < 2 * KKv) {
                        g_co[(size_t)m * (2 * KKv) + (n - Cv)] = tanhf(v) * (1.0f / 14.0f);
                    }
                } else {
                    if (n >= N) continue;
                    int b = n / Nv, nn = n - b * Nv;
                    outp[((size_t)(b * Cv + m)) * Nv + nn] = v + bias[m];
                }
            }
        }
    }
}

template<int MODE>
__global__ __launch_bounds__(256, 2)
void gemm_big(const float* __restrict__ Asrc,
              const float* __restrict__ W0, const float* __restrict__ W1, const float* __restrict__ W2,
              const float* __restrict__ bias, float* __restrict__ outp, int M, int N)
{
    __shared__ float As[2][16][132];
    __shared__ float Bs[2][16][68];
    gemm_core<MODE>(As, Bs, blockIdx.x, blockIdx.y, Asrc, W0, W1, W2, bias, outp, M, N);
}

// ================= fused: t1co GEMM (91 blocks) + qk maps (4704 blocks) =================
#define T1CO_BLOCKS 91
__global__ __launch_bounds__(256, 2)
void fused_t1co_qk(const float* __restrict__ Wo1, const float* __restrict__ bo1,
                   const float* __restrict__ Wco, const float* __restrict__ q_src)
{
    const int idx = blockIdx.x;
    if (idx < T1CO_BLOCKS) {
        __shared__ float As[2][16][132];
        __shared__ float Bs[2][16][68];
        gemm_core<1>(As, Bs, idx % 7, idx / 7, q_src, Wo1, Wco, nullptr, bo1, nullptr,
                     BNROWS, Cv + 2 * KKv);
    } else {
        const int idx2 = idx - T1CO_BLOCKS;
        const int bxq = idx2 % 7;
        const int byq = (idx2 / 7) % 7;
        const int bh  = idx2 / 49;
        const int b = bh / HEADS, h = bh - b * HEADS;
        const int n0 = byq * 32, p0 = bxq * 32;
        __shared__ float qs[32][33], ks[32][33];
        int tid = threadIdx.x;
        int lr = tid >> 5, lc = tid & 31;
        #pragma unroll
        for (int i = 0; i < 4; i++) {
            int n = n0 + lr + i * 8;
            qs[lr + i*8][lc] = (n < Nv) ? g_qkv[((size_t)b*Nv + n)*QKVC + h*HC + lc] : 0.0f;
            int p = p0 + lr + i * 8;
            ks[lr + i*8][lc] = (p < Nv) ? g_qkv[((size_t)b*Nv + p)*QKVC + Cv + h*HC + lc] : 0.0f;
        }
        __syncthreads();
        int pcol = tid & 31, ng = tid >> 5;
        float acc[4] = {0.f, 0.f, 0.f, 0.f};
        #pragma unroll
        for (int d = 0; d < 32; d++) {
            float kv = ks[pcol][d];
            #pragma unroll
            for (int i = 0; i < 4; i++) acc[i] = fmaf(qs[ng*4 + i][d], kv, acc[i]);
        }
        #pragma unroll
        for (int i = 0; i < 4; i++) {
            int n = n0 + ng*4 + i, p = p0 + pcol;
            if (n < Nv && p < Nv)
                g_qk[(((size_t)bh)*Nv + n)*Nv + p] = acc[i];
        }
    }
}

// ================= offset GEMM: g_off = tanh(t3 @ Wo2^T) * 2/14 =================
// 64x64 tile, BK=16, double-buffered, 256 threads, 4m x 4n per thread, f32x2 acc.
__global__ __launch_bounds__(256, 2)
void gemm_off(const float* __restrict__ Wo2)
{
    __shared__ float As[2][16][68];
    __shared__ float Bs[2][16][68];
    const int M = Bv * Sv;      // 392
    const int N = 2 * Nv;       // 392
    const int bm = blockIdx.y * 64;
    const int bn = blockIdx.x * 64;
    const int tid = threadIdx.x;
    const int ty = tid >> 4, tx = tid & 15;
    const int k4 = (tid & 3) * 4;
    const int ro = tid >> 2;      // 0..63

    unsigned long long acc[2][4];
    #pragma unroll
    for (int i = 0; i < 2; i++)
        #pragma unroll
        for (int j = 0; j < 4; j++) acc[i][j] = 0ull;

    float4 ra4, rb4;
    auto ldg = [&](int k0) {
        int m = bm + ro;
        if (m < M) ra4 = *(const float4*)&g_t3[(size_t)m * Cv + k0 + k4];
        else       ra4 = make_float4(0.f, 0.f, 0.f, 0.f);
        int n = bn + ro;
        if (n < N) rb4 = *(const float4*)&Wo2[(size_t)n * Cv + k0 + k4];
        else       rb4 = make_float4(0.f, 0.f, 0.f, 0.f);
    };
    auto sts = [&](int buf) {
        As[buf][k4 + 0][ro] = ra4.x;
        As[buf][k4 + 1][ro] = ra4.y;
        As[buf][k4 + 2][ro] = ra4.z;
        As[buf][k4 + 3][ro] = ra4.w;
        Bs[buf][k4 + 0][ro] = rb4.x;
        Bs[buf][k4 + 1][ro] = rb4.y;
        Bs[buf][k4 + 2][ro] = rb4.z;
        Bs[buf][k4 + 3][ro] = rb4.w;
    };

    const int NT = Cv / 16;
    ldg(0);
    sts(0);
    __syncthreads();

    for (int kt = 0; kt < NT; kt++) {
        const int cur = kt & 1;
        if (kt + 1 < NT) ldg((kt + 1) * 16);
        #pragma unroll
        for (int k = 0; k < 16; k++) {
            unsigned long long a2[2];
            a2[0] = *(const unsigned long long*)&As[cur][k][ty * 4];
            a2[1] = *(const unsigned long long*)&As[cur][k][ty * 4 + 2];
            float4 bv = *(const float4*)&Bs[cur][k][tx * 4];
            unsigned long long b2[4];
            b2[0] = pk2(bv.x, bv.x); b2[1] = pk2(bv.y, bv.y);
            b2[2] = pk2(bv.z, bv.z); b2[3] = pk2(bv.w, bv.w);
            #pragma unroll
            for (int i = 0; i < 2; i++)
                #pragma unroll
                for (int j = 0; j < 4; j++)
                    fma2(acc[i][j], a2[i], b2[j]);
        }
        if (kt + 1 < NT) {
            __syncthreads();
            sts(1 - cur);
            __syncthreads();
        }
    }

    #pragma unroll
    for (int i = 0; i < 2; i++) {
        #pragma unroll
        for (int j = 0; j < 4; j++) {
            float2 f = upk(acc[i][j]);
            int n = bn + tx * 4 + j;
            if (n >= N) continue;
            #pragma unroll
            for (int half = 0; half < 2; half++) {
                int m = bm + ty * 4 + i * 2 + half;
                if (m >= M) continue;
                float v = half ? f.y : f.x;
                g_off[(size_t)m * N + n] = tanhf(v) * (2.0f / 14.0f);
            }
        }
    }
}

// ================= depthwise 3x3 s2 conv + LN + GELU =================
__global__ void dwln_kernel(const float* __restrict__ Wdw, const float* __restrict__ bdw,
                            const float* __restrict__ lng, const float* __restrict__ lnb)
{
    int bs = blockIdx.x;
    int b = bs / Sv, s = bs % Sv;
    int oy = s / rWv, ox = s % rWv;
    int c = threadIdx.x;
    float acc = bdw[c];
    #pragma unroll
    for (int ky = 0; ky < 3; ky++) {
        int y = oy*2 - 1 + ky;
        if (y < 0 || y >= Hv) continue;
        #pragma unroll
        for (int kx = 0; kx < 3; kx++) {
            int x = ox*2 - 1 + kx;
            if (x < 0 || x >= Wv_) continue;
            acc = fmaf(g_t1[((size_t)b*Nv + y*Wv_ + x)*Cv + c], Wdw[c*9 + ky*3 + kx], acc);
        }
    }
    float s1 = acc, s2 = acc*acc;
    #pragma unroll
    for (int o = 16; o > 0; o >>= 1) {
        s1 += __shfl_xor_sync(0xffffffffu, s1, o);
        s2 += __shfl_xor_sync(0xffffffffu, s2, o);
    }
    __shared__ float w1[12], w2[12];
    __shared__ float s_mu, s_rstd;
    if ((c & 31) == 0) { w1[c >> 5] = s1; w2[c >> 5] = s2; }
    __syncthreads();
    if (c == 0) {
        float t1s = 0.f, t2s = 0.f;
        #pragma unroll
        for (int i = 0; i < 12; i++) { t1s += w1[i]; t2s += w2[i]; }
        float mu = t1s / (float)Cv;
        float var = t2s / (float)Cv - mu*mu;
        s_mu = mu; s_rstd = rsqrtf(var + 1e-5f);
    }
    __syncthreads();
    float v = (acc - s_mu) * s_rstd * lng[c] + lnb[c];
    g_t3[(size_t)bs*Cv + c] = gelu_exact(v);
}

// ================= scores + softmax + fold probs into dense A[b,h,n,:] =================
__global__ void score_kernel(const float* __restrict__ posembed)
{
    const int bn = blockIdx.x;
    const int b = bn / Nv, n = bn % Nv;
    const int ny = n / Wv_, nx = n % Wv_;
    __shared__ float sc[HEADS*TS];
    __shared__ int   sp[TS*4];
    __shared__ float swt[TS*4];
    __shared__ __align__(16) float sA[HEADS][Nv];

    for (int idx = threadIdx.x; idx < HEADS*Nv/4; idx += blockDim.x)
        ((float4*)sA)[idx] = make_float4(0.f, 0.f, 0.f, 0.f);

    for (int item = threadIdx.x; item < HEADS*TS; item += blockDim.x) {
        const int h = item / TS, s = item % TS;
        float py, px, tpy, tpx;
        if (s < Sv) {
            int rh = s / rWv, rw = s % rWv;
            float offy = g_off[((size_t)b*Sv + s)*(2*Nv) + 0*Nv + n];
            float offx = g_off[((size_t)b*Sv + s)*(2*Nv) + 1*Nv + n];
            float refy = (float)(rh*2) * (2.0f/13.0f) - 1.0f;
            float refx = (float)(rw*2) * (2.0f/13.0f) - 1.0f;
            py = (offy + refy + 1.0f) * 6.5f;
            px = (offx + refx + 1.0f) * 6.5f;
            tpy = ((float)(2*rh - ny) * (1.0f/13.0f) - offy + 1.0f) * 13.0f;
            tpx = ((float)(2*rw - nx) * (1.0f/13.0f) - offx + 1.0f) * 13.0f;
        } else {
            int j = s - Sv;
            float coy = g_co[((size_t)b*Nv + n)*(2*KKv) + j*2 + 0];
            float cox = g_co[((size_t)b*Nv + n)*(2*KKv) + j*2 + 1];
            float cy = (float)ny + c_offm[j][0];
            float cx = (float)nx + c_offm[j][1];
            float cny = fminf(fmaxf(cy, 0.0f), 14.0f) * (2.0f/13.0f) - 1.0f;
            float cnx = fminf(fmaxf(cx, 0.0f), 14.0f) * (2.0f/13.0f) - 1.0f;
            py = (coy + cny + 1.0f) * 6.5f;
            px = (cox + cnx + 1.0f) * 6.5f;
            tpy = (coy - (float)ny + 1.0f) * 13.0f;
            tpx = (cox - (float)nx + 1.0f) * 13.0f;
        }
        float y0 = floorf(py), x0 = floorf(px);
        float wy1 = py - y0, wx1 = px - x0;
        const float* qkb = g_qk + (((size_t)(b*HEADS + h))*Nv + n)*Nv;
        float val = 0.0f;
        #pragma unroll
        for (int ccy = 0; ccy < 2; ccy++) {
            #pragma unroll
            for (int ccx = 0; ccx < 2; ccx++) {
                float yf = y0 + (float)ccy, xf = x0 + (float)ccx;
                float w = (ccy ? wy1 : 1.0f - wy1) * (ccx ? wx1 : 1.0f - wx1);
                bool valid = (yf >= 0.0f) && (yf <= 13.0f) && (xf >= 0.0f) && (xf <= 13.0f);
                if (!valid) w = 0.0f;
                int yi = (int)fminf(fmaxf(yf, 0.0f), 13.0f);
                int xi = (int)fminf(fmaxf(xf, 0.0f), 13.0f);
                int pix = yi*Wv_ + xi;
                val += w * qkb[pix];
                if (h == 0) { sp[s*4 + ccy*2 + ccx] = pix; swt[s*4 + ccy*2 + ccx] = w; }
            }
        }
        float by0 = floorf(tpy), bx0 = floorf(tpx);
        float bwy = tpy - by0, bwx = tpx - bx0;
        const float* tb = posembed + (size_t)h * (27*27);
        float bval = 0.0f;
        #pragma unroll
        for (int ccy = 0; ccy < 2; ccy++) {
            #pragma unroll
            for (int ccx = 0; ccx < 2; ccx++) {
                float yf = by0 + (float)ccy, xf = bx0 + (float)ccx;
                float w = (ccy ? bwy : 1.0f - bwy) * (ccx ? bwx : 1.0f - bwx);
                bool valid = (yf >= 0.0f) && (yf <= 26.0f) && (xf >= 0.0f) && (xf <= 26.0f);
                if (!valid) w = 0.0f;
                int yi = (int)fminf(fmaxf(yf, 0.0f), 26.0f);
                int xi = (int)fminf(fmaxf(xf, 0.0f), 26.0f);
                bval += w * tb[yi*27 + xi];
            }
        }
        sc[h*TS + s] = val + bval;
    }
    __syncthreads();

    const int wid = threadIdx.x >> 5, lane = threadIdx.x & 31;
    {
        float m = -1e30f;
        for (int s = lane; s < TS; s += 32) m = fmaxf(m, sc[wid*TS + s]);
        #pragma unroll
        for (int o = 16; o > 0; o >>= 1) m = fmaxf(m, __shfl_xor_sync(0xffffffffu, m, o));
        float sum = 0.0f;
        for (int s = lane; s < TS; s += 32) {
            float e = expf(sc[wid*TS + s] - m);
            sc[wid*TS + s] = e;
            sum += e;
        }
        #pragma unroll
        for (int o = 16; o > 0; o >>= 1) sum += __shfl_xor_sync(0xffffffffu, sum, o);
        float inv = 1.0f / sum;
        for (int s = lane; s < TS; s += 32) sc[wid*TS + s] *= inv;
    }
    for (int i = lane; i < TS*4; i += 32) {
        atomicAdd(&sA[wid][sp[i]], sc[wid*TS + (i >> 2)] * swt[i]);
    }
    __syncthreads();

    float4* dst = (float4*)(g_A + ((size_t)(b*HEADS))*Nv*Nv);
    for (int idx = threadIdx.x; idx < HEADS*(Nv/4); idx += blockDim.x) {
        int h = idx / (Nv/4), p4 = idx - h * (Nv/4);
        dst[((size_t)h*Nv + n)*(Nv/4) + p4] = ((float4*)sA)[h*(Nv/4) + p4];
    }
}

// ================= AV GEMM (f32x2): out[b,n,h,:] = A[b,h,n,:] @ xV[b,:,h,:] + bv ========
__global__ __launch_bounds__(128, 4)
void av_kernel(const float* __restrict__ bvv)
{
    const int n0 = blockIdx.x * 64;
    const int bh = blockIdx.y;
    const int b = bh / HEADS, h = bh - b * HEADS;
    __shared__ __align__(16) float Vs[Nv][HC];
    __shared__ __align__(16) float As[32][68];

    const int tid = threadIdx.x;
    const int tx = tid & 7;
    const int ng = tid >> 3;

    {
        const float* vbase = g_qkv + (size_t)b * Nv * QKVC + 2 * Cv + h * HC;
        for (int i = tid; i < Nv * (HC/4); i += 128) {
            int p = i >> 3, c4 = (i & 7) * 4;
            *(float4*)&Vs[p][c4] = *(const float4*)&vbase[(size_t)p * QKVC + c4];
        }
    }

    unsigned long long acc[2][4];
    #pragma unroll
    for (int i = 0; i < 2; i++)
        #pragma unroll
        for (int j = 0; j < 4; j++) acc[i][j] = 0ull;

    const float* Arow = g_A + ((size_t)bh * Nv) * Nv;
    const int r = tid >> 1, halfq = tid & 1;

    for (int p0 = 0; p0 < Nv; p0 += 32) {
        const int kt = min(32, Nv - p0);
        __syncthreads();
        {
            int nrow = n0 + r;
            #pragma unroll
            for (int q = 0; q < 4; q++) {
                int pl = halfq * 16 + q * 4;
                float4 v = make_float4(0.f, 0.f, 0.f, 0.f);
                if (nrow < Nv && p0 + pl < Nv)
                    v = *(const float4*)&Arow[(size_t)nrow * Nv + p0 + pl];
                As[pl + 0][r] = v.x;
                As[pl + 1][r] = v.y;
                As[pl + 2][r] = v.z;
                As[pl + 3][r] = v.w;
            }
        }
        __syncthreads();
        for (int k = 0; k < kt; k++) {
            float4 af = *(const float4*)&As[k][ng * 4];
            unsigned long long a0 = pk2(af.x, af.y);
            unsigned long long a1 = pk2(af.z, af.w);
            float4 bf = *(const float4*)&Vs[p0 + k][tx * 4];
            unsigned long long b2[4];
            b2[0] = pk2(bf.x, bf.x); b2[1] = pk2(bf.y, bf.y);
            b2[2] = pk2(bf.z, bf.z); b2[3] = pk2(bf.w, bf.w);
            #pragma unroll
            for (int j = 0; j < 4; j++) { fma2(acc[0][j], a0, b2[j]); fma2(acc[1][j], a1, b2[j]); }
        }
    }

    #pragma unroll
    for (int j = 0; j < 4; j++) {
        int c = tx * 4 + j;
        float bb = bvv[h * HC + c];
        #pragma unroll
        for (int i = 0; i < 2; i++) {
            float2 f = upk(acc[i][j]);
            int n = n0 + ng * 4 + i * 2;
            if (n < Nv)     g_ao[((size_t)(b*Nv + n  ))*Cv + h*HC + c] = f.x + bb;
            if (n + 1 < Nv) g_ao[((size_t)(b*Nv + n+1))*Cv + h*HC + c] = f.y + bb;
        }
    }
}

extern "C" void kernel_launch(void* const* d_in, const int* in_sizes, int n_in,
                              void* d_out, int out_size)
{
    const float* x    = (const float*)d_in[0];
    const float* Wq   = (const float*)d_in[1];
    const float* bq   = (const float*)d_in[2];
    const float* Wk   = (const float*)d_in[3];
    // bk cancels in softmax — unused
    const float* Wvv  = (const float*)d_in[5];
    const float* bvv  = (const float*)d_in[6];
    const float* Wo1  = (const float*)d_in[7];
    const float* bo1  = (const float*)d_in[8];
    const float* Wdw  = (const float*)d_in[9];
    const float* bdw  = (const float*)d_in[10];
    const float* lng  = (const float*)d_in[11];
    const float* lnb  = (const float*)d_in[12];
    const float* Wo2  = (const float*)d_in[13];
    const float* Wco  = (const float*)d_in[14];
    const float* pos  = (const float*)d_in[15];
    const float* Wp   = (const float*)d_in[16];
    const float* bp   = (const float*)d_in[17];
    float* out = (float*)d_out;

    float* p_qkv; cudaGetSymbolAddress((void**)&p_qkv, g_qkv);

    // 1) qkv: N=1152, M=1568 -> 18 x 13 blocks
    gemm_big<0><<<dim3(18, 13), 256>>>(x, Wq, Wk, Wvv, bq, nullptr, BNROWS, QKVC);
    // 2) fused t1co (91) + qk (4704)
    fused_t1co_qk<<<T1CO_BLOCKS + 7*7*Bv*HEADS, 256>>>(Wo1, bo1, Wco, p_qkv);
    // 3) offset net tail
    dwln_kernel<<<Bv*Sv, Cv>>>(Wdw, bdw, lng, lnb);
    gemm_off<<<dim3(7, 7), 256>>>(Wo2);
    // 4) scores -> probs -> dense A
    score_kernel<<<Bv*Nv, 384>>>(pos);
    // 5) AV
    av_kernel<<<dim3(4, Bv*HEADS), 128>>>(bvv);
    // 6) final projection (coalesced NCHW stores)
    gemm_big<2><<<dim3(25, 3), 256>>>(Wp, Wp, nullptr, nullptr, bp, out, Cv, BNROWS);
}

// round 6
// speedup vs baseline: 1.4749x; 1.0451x over previous
#include <cuda_runtime.h>
#include <cuda_bf16.h>
#include <math.h>

#define Bv   8
#define Cv   384
#define Hv   14
#define Wv_  14
#define HEADS 12
#define HC   32
#define Nv   196
#define Sv   49
#define rHv  7
#define rWv  7
#define KKv  9
#define TS   58
#define BNROWS (Bv*Nv)   // 1568
#define QKVC 1152

// Scratch
__device__ float g_qkv[BNROWS*QKVC];          // q | xK | xV   (stride 1152)
__device__ float g_t1 [BNROWS*Cv];
__device__ float g_t3 [Bv*Sv*Cv];
__device__ float g_off[Bv*Sv*2*Nv];
__device__ float g_co [BNROWS*2*KKv];
__device__ float g_qk [(size_t)Bv*HEADS*Nv*Nv];
__device__ float g_A  [(size_t)Bv*HEADS*Nv*Nv];
__device__ float g_ao [BNROWS*Cv];

__constant__ float c_offm[9][2] = {
    {0.f,-1.f},{-1.f,-1.f},{-1.f,0.f},{-1.f,1.f},{0.f,1.f},{1.f,1.f},{1.f,0.f},{1.f,-1.f},{0.f,0.f}
};

__device__ __forceinline__ float gelu_exact(float v) {
    return 0.5f * v * (1.0f + erff(v * 0.7071067811865476f));
}

// ---- f32x2 packed math helpers (sm_100+) ----
__device__ __forceinline__ unsigned long long pk2(float lo, float hi) {
    unsigned long long r;
    asm("mov.b64 %0, {%1,%2};" : "=l"(r) : "f"(lo), "f"(hi));
    return r;
}
__device__ __forceinline__ void fma2(unsigned long long &c, unsigned long long a, unsigned long long b) {
    asm("fma.rn.f32x2 %0, %1, %2, %3;" : "=l"(c) : "l"(a), "l"(b), "l"(c));
}
__device__ __forceinline__ float2 upk(unsigned long long v) {
    float2 f;
    asm("mov.b64 {%0,%1}, %2;" : "=f"(f.x), "=f"(f.y) : "l"(v));
    return f;
}

// =====================================================================================
// GEMM core: 128x64 tile, BK=16, double-buffered, 256 threads, 8m x 4n, f32x2 acc.
// MODE 0: qkv, MODE 1: t1co, MODE 2: proj (coalesced NCHW store)
// =====================================================================================
template<int MODE>
__device__ __forceinline__
void gemm_core(float As[2][16][132], float Bs[2][16][68], int bxx, int byy,
               const float* __restrict__ Asrc,
               const float* __restrict__ W0, const float* __restrict__ W1, const float* __restrict__ W2,
               const float* __restrict__ bias, float* __restrict__ outp, int M, int N)
{
    const int tid = threadIdx.x;
    const int bm = byy * 128;
    const int bn = bxx * 64;
    const int ty = tid >> 4;
    const int tx = tid & 15;

    unsigned long long acc[4][4];
    #pragma unroll
    for (int i = 0; i < 4; i++)
        #pragma unroll
        for (int j = 0; j < 4; j++) acc[i][j] = 0ull;

    float  ra[8];
    float4 ra4[2];
    float4 rb4;

    const int k4  = (tid & 3) * 4;
    const int mo4 = tid >> 2;
    const int no4 = tid >> 2;

    auto ldgA = [&](int k0) {
        if (MODE == 0) {
            #pragma unroll
            for (int i = 0; i < 8; i++) {
                int mo = (tid & 63) + ((i & 1) << 6);
                int ko = (tid >> 6) + ((i >> 1) << 2);
                int m = bm + mo;
                float v = 0.0f;
                if (m < M) {
                    int b = m / Nv, nn = m - b * Nv;
                    v = Asrc[((size_t)(b * Cv + k0 + ko)) * Nv + nn];
                }
                ra[i] = v;
            }
        } else {
            const int lda = (MODE == 1) ? QKVC : Cv;
            #pragma unroll
            for (int i = 0; i < 2; i++) {
                int m = bm + mo4 + i * 64;
                if (m < M) ra4[i] = *(const float4*)&Asrc[(size_t)m * lda + k0 + k4];
                else       ra4[i] = make_float4(0.f, 0.f, 0.f, 0.f);
            }
        }
    };
    auto ldgB = [&](int k0) {
        int n = bn + no4;
        if (MODE == 2) {
            if (n < N) rb4 = *(const float4*)&g_ao[(size_t)n * Cv + k0 + k4];
            else       rb4 = make_float4(0.f, 0.f, 0.f, 0.f);
        } else {
            const float* row = nullptr;
            if (MODE == 0) {
                int region = n / Cv;
                int nl = n - region * Cv;
                const float* Wt = (region == 0) ? W0 : (region == 1 ? W1 : W2);
                row = Wt + (size_t)nl * Cv;
            } else {
                if (n < Cv) row = W0 + (size_t)n * Cv;
                else if (n - Cv < 2 * KKv) row = W1 + (size_t)(n - Cv) * Cv;
            }
            if (row) rb4 = *(const float4*)&row[k0 + k4];
            else     rb4 = make_float4(0.f, 0.f, 0.f, 0.f);
        }
    };
    auto sts = [&](int buf) {
        if (MODE == 0) {
            #pragma unroll
            for (int i = 0; i < 8; i++) {
                int mo = (tid & 63) + ((i & 1) << 6);
                int ko = (tid >> 6) + ((i >> 1) << 2);
                As[buf][ko][mo] = ra[i];
            }
        } else {
            #pragma unroll
            for (int i = 0; i < 2; i++) {
                As[buf][k4 + 0][mo4 + i * 64] = ra4[i].x;
                As[buf][k4 + 1][mo4 + i * 64] = ra4[i].y;
                As[buf][k4 + 2][mo4 + i * 64] = ra4[i].z;
                As[buf][k4 + 3][mo4 + i * 64] = ra4[i].w;
            }
        }
        Bs[buf][k4 + 0][no4] = rb4.x;
        Bs[buf][k4 + 1][no4] = rb4.y;
        Bs[buf][k4 + 2][no4] = rb4.z;
        Bs[buf][k4 + 3][no4] = rb4.w;
    };

    const int NT = Cv / 16;
    ldgA(0); ldgB(0);
    sts(0);
    __syncthreads();

    for (int kt = 0; kt < NT; kt++) {
        const int cur = kt & 1;
        if (kt + 1 < NT) { ldgA((kt + 1) * 16); ldgB((kt + 1) * 16); }
        #pragma unroll
        for (int k = 0; k < 16; k++) {
            unsigned long long a2[4];
            #pragma unroll
            for (int j = 0; j < 4; j++)
                a2[j] = *(const unsigned long long*)&As[cur][k][ty * 8 + j * 2];
            float4 bv = *(const float4*)&Bs[cur][k][tx * 4];
            unsigned long long b2[4];
            b2[0] = pk2(bv.x, bv.x); b2[1] = pk2(bv.y, bv.y);
            b2[2] = pk2(bv.z, bv.z); b2[3] = pk2(bv.w, bv.w);
            #pragma unroll
            for (int i = 0; i < 4; i++)
                #pragma unroll
                for (int j = 0; j < 4; j++)
                    fma2(acc[i][j], a2[i], b2[j]);
        }
        if (kt + 1 < NT) {
            __syncthreads();
            sts(1 - cur);
            __syncthreads();
        }
    }

    #pragma unroll
    for (int i = 0; i < 4; i++) {
        #pragma unroll
        for (int j = 0; j < 4; j++) {
            float2 f = upk(acc[i][j]);
            int n = bn + tx * 4 + j;
            #pragma unroll
            for (int half = 0; half < 2; half++) {
                int m = bm + ty * 8 + i * 2 + half;
                float v = half ? f.y : f.x;
                if (m >= M) continue;
                if (MODE == 0) {
                    if (n < Cv) v += bias[n];
                    g_qkv[(size_t)m * QKVC + n] = v;
                } else if (MODE == 1) {
                    if (n < Cv) {
                        g_t1[(size_t)m * Cv + n] = gelu_exact(v + bias[n]);
                    } else if (n - Cv < 2 * KKv) {
                        g_co[(size_t)m * (2 * KKv) + (n - Cv)] = tanhf(v) * (1.0f / 14.0f);
                    }
                } else {
                    if (n >= N) continue;
                    int b = n / Nv, nn = n - b * Nv;
                    outp[((size_t)(b * Cv + m)) * Nv + nn] = v + bias[m];
                }
            }
        }
    }
}

template<int MODE>
__global__ __launch_bounds__(256, 2)
void gemm_big(const float* __restrict__ Asrc,
              const float* __restrict__ W0, const float* __restrict__ W1, const float* __restrict__ W2,
              const float* __restrict__ bias, float* __restrict__ outp, int M, int N)
{
    __shared__ float As[2][16][132];
    __shared__ float Bs[2][16][68];
    gemm_core<MODE>(As, Bs, blockIdx.x, blockIdx.y, Asrc, W0, W1, W2, bias, outp, M, N);
}

// ================= fused: t1co GEMM (91 blocks) + qk maps (4704 blocks) =================
#define T1CO_BLOCKS 91
__global__ __launch_bounds__(256, 2)
void fused_t1co_qk(const float* __restrict__ Wo1, const float* __restrict__ bo1,
                   const float* __restrict__ Wco, const float* __restrict__ q_src)
{
    const int idx = blockIdx.x;
    if (idx < T1CO_BLOCKS) {
        __shared__ float As[2][16][132];
        __shared__ float Bs[2][16][68];
        gemm_core<1>(As, Bs, idx % 7, idx / 7, q_src, Wo1, Wco, nullptr, bo1, nullptr,
                     BNROWS, Cv + 2 * KKv);
    } else {
        const int idx2 = idx - T1CO_BLOCKS;
        const int bxq = idx2 % 7;
        const int byq = (idx2 / 7) % 7;
        const int bh  = idx2 / 49;
        const int b = bh / HEADS, h = bh - b * HEADS;
        const int n0 = byq * 32, p0 = bxq * 32;
        __shared__ float qs[32][33], ks[32][33];
        int tid = threadIdx.x;
        int lr = tid >> 5, lc = tid & 31;
        #pragma unroll
        for (int i = 0; i < 4; i++) {
            int n = n0 + lr + i * 8;
            qs[lr + i*8][lc] = (n < Nv) ? g_qkv[((size_t)b*Nv + n)*QKVC + h*HC + lc] : 0.0f;
            int p = p0 + lr + i * 8;
            ks[lr + i*8][lc] = (p < Nv) ? g_qkv[((size_t)b*Nv + p)*QKVC + Cv + h*HC + lc] : 0.0f;
        }
        __syncthreads();
        int pcol = tid & 31, ng = tid >> 5;
        float acc[4] = {0.f, 0.f, 0.f, 0.f};
        #pragma unroll
        for (int d = 0; d < 32; d++) {
            float kv = ks[pcol][d];
            #pragma unroll
            for (int i = 0; i < 4; i++) acc[i] = fmaf(qs[ng*4 + i][d], kv, acc[i]);
        }
        #pragma unroll
        for (int i = 0; i < 4; i++) {
            int n = n0 + ng*4 + i, p = p0 + pcol;
            if (n < Nv && p < Nv)
                g_qk[(((size_t)bh)*Nv + n)*Nv + p] = acc[i];
        }
    }
}

// ================= offset GEMM: g_off = tanh(t3 @ Wo2^T) * 2/14 =================
// 32x64 tile, BK=32, double-buffered, 128 threads, 4m x 4n per thread, f32x2 acc.
// grid (7, 13) = 91 blocks — latency hidden by BK=32 stage depth + multi-CTA/SM.
__global__ __launch_bounds__(128, 4)
void gemm_off(const float* __restrict__ Wo2)
{
    __shared__ float As[2][32][36];
    __shared__ float Bs[2][32][68];
    const int M = Bv * Sv;      // 392
    const int N = 2 * Nv;       // 392
    const int bm = blockIdx.y * 32;
    const int bn = blockIdx.x * 64;
    const int tid = threadIdx.x;
    const int ty = tid >> 4;      // 0..7 -> m = ty*4
    const int tx = tid & 15;      // 0..15 -> n = tx*4
    const int k4 = (tid & 7) * 4;
    const int rowg = tid >> 3;    // 0..15

    unsigned long long acc[2][4];
    #pragma unroll
    for (int i = 0; i < 2; i++)
        #pragma unroll
        for (int j = 0; j < 4; j++) acc[i][j] = 0ull;

    float4 ra4[2], rb4[4];
    auto ldg = [&](int k0) {
        #pragma unroll
        for (int i = 0; i < 2; i++) {
            int m = bm + rowg + i * 16;
            if (m < M) ra4[i] = *(const float4*)&g_t3[(size_t)m * Cv + k0 + k4];
            else       ra4[i] = make_float4(0.f, 0.f, 0.f, 0.f);
        }
        #pragma unroll
        for (int i = 0; i < 4; i++) {
            int n = bn + rowg + i * 16;
            if (n < N) rb4[i] = *(const float4*)&Wo2[(size_t)n * Cv + k0 + k4];
            else       rb4[i] = make_float4(0.f, 0.f, 0.f, 0.f);
        }
    };
    auto sts = [&](int buf) {
        #pragma unroll
        for (int i = 0; i < 2; i++) {
            As[buf][k4 + 0][rowg + i * 16] = ra4[i].x;
            As[buf][k4 + 1][rowg + i * 16] = ra4[i].y;
            As[buf][k4 + 2][rowg + i * 16] = ra4[i].z;
            As[buf][k4 + 3][rowg + i * 16] = ra4[i].w;
        }
        #pragma unroll
        for (int i = 0; i < 4; i++) {
            Bs[buf][k4 + 0][rowg + i * 16] = rb4[i].x;
            Bs[buf][k4 + 1][rowg + i * 16] = rb4[i].y;
            Bs[buf][k4 + 2][rowg + i * 16] = rb4[i].z;
            Bs[buf][k4 + 3][rowg + i * 16] = rb4[i].w;
        }
    };

    const int NT = Cv / 32;   // 12 stages
    ldg(0);
    sts(0);
    __syncthreads();

    for (int kt = 0; kt < NT; kt++) {
        const int cur = kt & 1;
        if (kt + 1 < NT) ldg((kt + 1) * 32);
        #pragma unroll
        for (int k = 0; k < 32; k++) {
            unsigned long long a2[2];
            a2[0] = *(const unsigned long long*)&As[cur][k][ty * 4];
            a2[1] = *(const unsigned long long*)&As[cur][k][ty * 4 + 2];
            float4 bv = *(const float4*)&Bs[cur][k][tx * 4];
            unsigned long long b2[4];
            b2[0] = pk2(bv.x, bv.x); b2[1] = pk2(bv.y, bv.y);
            b2[2] = pk2(bv.z, bv.z); b2[3] = pk2(bv.w, bv.w);
            #pragma unroll
            for (int i = 0; i < 2; i++)
                #pragma unroll
                for (int j = 0; j < 4; j++)
                    fma2(acc[i][j], a2[i], b2[j]);
        }
        if (kt + 1 < NT) {
            __syncthreads();
            sts(1 - cur);
            __syncthreads();
        }
    }

    #pragma unroll
    for (int i = 0; i < 2; i++) {
        #pragma unroll
        for (int j = 0; j < 4; j++) {
            float2 f = upk(acc[i][j]);
            int n = bn + tx * 4 + j;
            if (n >= N) continue;
            #pragma unroll
            for (int half = 0; half < 2; half++) {
                int m = bm + ty * 4 + i * 2 + half;
                if (m >= M) continue;
                float v = half ? f.y : f.x;
                g_off[(size_t)m * N + n] = tanhf(v) * (2.0f / 14.0f);
            }
        }
    }
}

// ================= depthwise 3x3 s2 conv + LN + GELU =================
__global__ void dwln_kernel(const float* __restrict__ Wdw, const float* __restrict__ bdw,
                            const float* __restrict__ lng, const float* __restrict__ lnb)
{
    int bs = blockIdx.x;
    int b = bs / Sv, s = bs % Sv;
    int oy = s / rWv, ox = s % rWv;
    int c = threadIdx.x;
    float acc = bdw[c];
    #pragma unroll
    for (int ky = 0; ky < 3; ky++) {
        int y = oy*2 - 1 + ky;
        if (y < 0 || y >= Hv) continue;
        #pragma unroll
        for (int kx = 0; kx < 3; kx++) {
            int x = ox*2 - 1 + kx;
            if (x < 0 || x >= Wv_) continue;
            acc = fmaf(g_t1[((size_t)b*Nv + y*Wv_ + x)*Cv + c], Wdw[c*9 + ky*3 + kx], acc);
        }
    }
    float s1 = acc, s2 = acc*acc;
    #pragma unroll
    for (int o = 16; o > 0; o >>= 1) {
        s1 += __shfl_xor_sync(0xffffffffu, s1, o);
        s2 += __shfl_xor_sync(0xffffffffu, s2, o);
    }
    __shared__ float w1[12], w2[12];
    __shared__ float s_mu, s_rstd;
    if ((c & 31) == 0) { w1[c >> 5] = s1; w2[c >> 5] = s2; }
    __syncthreads();
    if (c == 0) {
        float t1s = 0.f, t2s = 0.f;
        #pragma unroll
        for (int i = 0; i < 12; i++) { t1s += w1[i]; t2s += w2[i]; }
        float mu = t1s / (float)Cv;
        float var = t2s / (float)Cv - mu*mu;
        s_mu = mu; s_rstd = rsqrtf(var + 1e-5f);
    }
    __syncthreads();
    float v = (acc - s_mu) * s_rstd * lng[c] + lnb[c];
    g_t3[(size_t)bs*Cv + c] = gelu_exact(v);
}

// ================= scores + softmax + fold probs into dense A[b,h,n,:] =================
__global__ void score_kernel(const float* __restrict__ posembed)
{
    const int bn = blockIdx.x;
    const int b = bn / Nv, n = bn % Nv;
    const int ny = n / Wv_, nx = n % Wv_;
    __shared__ float sc[HEADS*TS];
    __shared__ int   sp[TS*4];
    __shared__ float swt[TS*4];
    __shared__ __align__(16) float sA[HEADS][Nv];

    for (int idx = threadIdx.x; idx < HEADS*Nv/4; idx += blockDim.x)
        ((float4*)sA)[idx] = make_float4(0.f, 0.f, 0.f, 0.f);

    for (int item = threadIdx.x; item < HEADS*TS; item += blockDim.x) {
        const int h = item / TS, s = item % TS;
        float py, px, tpy, tpx;
        if (s < Sv) {
            int rh = s / rWv, rw = s % rWv;
            float offy = g_off[((size_t)b*Sv + s)*(2*Nv) + 0*Nv + n];
            float offx = g_off[((size_t)b*Sv + s)*(2*Nv) + 1*Nv + n];
            float refy = (float)(rh*2) * (2.0f/13.0f) - 1.0f;
            float refx = (float)(rw*2) * (2.0f/13.0f) - 1.0f;
            py = (offy + refy + 1.0f) * 6.5f;
            px = (offx + refx + 1.0f) * 6.5f;
            tpy = ((float)(2*rh - ny) * (1.0f/13.0f) - offy + 1.0f) * 13.0f;
            tpx = ((float)(2*rw - nx) * (1.0f/13.0f) - offx + 1.0f) * 13.0f;
        } else {
            int j = s - Sv;
            float coy = g_co[((size_t)b*Nv + n)*(2*KKv) + j*2 + 0];
            float cox = g_co[((size_t)b*Nv + n)*(2*KKv) + j*2 + 1];
            float cy = (float)ny + c_offm[j][0];
            float cx = (float)nx + c_offm[j][1];
            float cny = fminf(fmaxf(cy, 0.0f), 14.0f) * (2.0f/13.0f) - 1.0f;
            float cnx = fminf(fmaxf(cx, 0.0f), 14.0f) * (2.0f/13.0f) - 1.0f;
            py = (coy + cny + 1.0f) * 6.5f;
            px = (cox + cnx + 1.0f) * 6.5f;
            tpy = (coy - (float)ny + 1.0f) * 13.0f;
            tpx = (cox - (float)nx + 1.0f) * 13.0f;
        }
        float y0 = floorf(py), x0 = floorf(px);
        float wy1 = py - y0, wx1 = px - x0;
        const float* qkb = g_qk + (((size_t)(b*HEADS + h))*Nv + n)*Nv;
        float val = 0.0f;
        #pragma unroll
        for (int ccy = 0; ccy < 2; ccy++) {
            #pragma unroll
            for (int ccx = 0; ccx < 2; ccx++) {
                float yf = y0 + (float)ccy, xf = x0 + (float)ccx;
                float w = (ccy ? wy1 : 1.0f - wy1) * (ccx ? wx1 : 1.0f - wx1);
                bool valid = (yf >= 0.0f) && (yf <= 13.0f) && (xf >= 0.0f) && (xf <= 13.0f);
                if (!valid) w = 0.0f;
                int yi = (int)fminf(fmaxf(yf, 0.0f), 13.0f);
                int xi = (int)fminf(fmaxf(xf, 0.0f), 13.0f);
                int pix = yi*Wv_ + xi;
                val += w * qkb[pix];
                if (h == 0) { sp[s*4 + ccy*2 + ccx] = pix; swt[s*4 + ccy*2 + ccx] = w; }
            }
        }
        float by0 = floorf(tpy), bx0 = floorf(tpx);
        float bwy = tpy - by0, bwx = tpx - bx0;
        const float* tb = posembed + (size_t)h * (27*27);
        float bval = 0.0f;
        #pragma unroll
        for (int ccy = 0; ccy < 2; ccy++) {
            #pragma unroll
            for (int ccx = 0; ccx < 2; ccx++) {
                float yf = by0 + (float)ccy, xf = bx0 + (float)ccx;
                float w = (ccy ? bwy : 1.0f - bwy) * (ccx ? bwx : 1.0f - bwx);
                bool valid = (yf >= 0.0f) && (yf <= 26.0f) && (xf >= 0.0f) && (xf <= 26.0f);
                if (!valid) w = 0.0f;
                int yi = (int)fminf(fmaxf(yf, 0.0f), 26.0f);
                int xi = (int)fminf(fmaxf(xf, 0.0f), 26.0f);
                bval += w * tb[yi*27 + xi];
            }
        }
        sc[h*TS + s] = val + bval;
    }
    __syncthreads();

    const int wid = threadIdx.x >> 5, lane = threadIdx.x & 31;
    {
        float m = -1e30f;
        for (int s = lane; s < TS; s += 32) m = fmaxf(m, sc[wid*TS + s]);
        #pragma unroll
        for (int o = 16; o > 0; o >>= 1) m = fmaxf(m, __shfl_xor_sync(0xffffffffu, m, o));
        float sum = 0.0f;
        for (int s = lane; s < TS; s += 32) {
            float e = expf(sc[wid*TS + s] - m);
            sc[wid*TS + s] = e;
            sum += e;
        }
        #pragma unroll
        for (int o = 16; o > 0; o >>= 1) sum += __shfl_xor_sync(0xffffffffu, sum, o);
        float inv = 1.0f / sum;
        for (int s = lane; s < TS; s += 32) sc[wid*TS + s] *= inv;
    }
    for (int i = lane; i < TS*4; i += 32) {
        atomicAdd(&sA[wid][sp[i]], sc[wid*TS + (i >> 2)] * swt[i]);
    }
    __syncthreads();

    float4* dst = (float4*)(g_A + ((size_t)(b*HEADS))*Nv*Nv);
    for (int idx = threadIdx.x; idx < HEADS*(Nv/4); idx += blockDim.x) {
        int h = idx / (Nv/4), p4 = idx - h * (Nv/4);
        dst[((size_t)h*Nv + n)*(Nv/4) + p4] = ((float4*)sA)[h*(Nv/4) + p4];
    }
}

// ================= AV GEMM (f32x2): out[b,n,h,:] = A[b,h,n,:] @ xV[b,:,h,:] + bv ========
__global__ __launch_bounds__(128, 4)
void av_kernel(const float* __restrict__ bvv)
{
    const int n0 = blockIdx.x * 64;
    const int bh = blockIdx.y;
    const int b = bh / HEADS, h = bh - b * HEADS;
    __shared__ __align__(16) float Vs[Nv][HC];
    __shared__ __align__(16) float As[32][68];

    const int tid = threadIdx.x;
    const int tx = tid & 7;
    const int ng = tid >> 3;

    {
        const float* vbase = g_qkv + (size_t)b * Nv * QKVC + 2 * Cv + h * HC;
        for (int i = tid; i < Nv * (HC/4); i += 128) {
            int p = i >> 3, c4 = (i & 7) * 4;
            *(float4*)&Vs[p][c4] = *(const float4*)&vbase[(size_t)p * QKVC + c4];
        }
    }

    unsigned long long acc[2][4];
    #pragma unroll
    for (int i = 0; i < 2; i++)
        #pragma unroll
        for (int j = 0; j < 4; j++) acc[i][j] = 0ull;

    const float* Arow = g_A + ((size_t)bh * Nv) * Nv;
    const int r = tid >> 1, halfq = tid & 1;

    for (int p0 = 0; p0 < Nv; p0 += 32) {
        const int kt = min(32, Nv - p0);
        __syncthreads();
        {
            int nrow = n0 + r;
            #pragma unroll
            for (int q = 0; q < 4; q++) {
                int pl = halfq * 16 + q * 4;
                float4 v = make_float4(0.f, 0.f, 0.f, 0.f);
                if (nrow < Nv && p0 + pl < Nv)
                    v = *(const float4*)&Arow[(size_t)nrow * Nv + p0 + pl];
                As[pl + 0][r] = v.x;
                As[pl + 1][r] = v.y;
                As[pl + 2][r] = v.z;
                As[pl + 3][r] = v.w;
            }
        }
        __syncthreads();
        for (int k = 0; k < kt; k++) {
            float4 af = *(const float4*)&As[k][ng * 4];
            unsigned long long a0 = pk2(af.x, af.y);
            unsigned long long a1 = pk2(af.z, af.w);
            float4 bf = *(const float4*)&Vs[p0 + k][tx * 4];
            unsigned long long b2[4];
            b2[0] = pk2(bf.x, bf.x); b2[1] = pk2(bf.y, bf.y);
            b2[2] = pk2(bf.z, bf.z); b2[3] = pk2(bf.w, bf.w);
            #pragma unroll
            for (int j = 0; j < 4; j++) { fma2(acc[0][j], a0, b2[j]); fma2(acc[1][j], a1, b2[j]); }
        }
    }

    #pragma unroll
    for (int j = 0; j < 4; j++) {
        int c = tx * 4 + j;
        float bb = bvv[h * HC + c];
        #pragma unroll
        for (int i = 0; i < 2; i++) {
            float2 f = upk(acc[i][j]);
            int n = n0 + ng * 4 + i * 2;
            if (n < Nv)     g_ao[((size_t)(b*Nv + n  ))*Cv + h*HC + c] = f.x + bb;
            if (n + 1 < Nv) g_ao[((size_t)(b*Nv + n+1))*Cv + h*HC + c] = f.y + bb;
        }
    }
}

extern "C" void kernel_launch(void* const* d_in, const int* in_sizes, int n_in,
                              void* d_out, int out_size)
{
    const float* x    = (const float*)d_in[0];
    const float* Wq   = (const float*)d_in[1];
    const float* bq   = (const float*)d_in[2];
    const float* Wk   = (const float*)d_in[3];
    // bk cancels in softmax — unused
    const float* Wvv  = (const float*)d_in[5];
    const float* bvv  = (const float*)d_in[6];
    const float* Wo1  = (const float*)d_in[7];
    const float* bo1  = (const float*)d_in[8];
    const float* Wdw  = (const float*)d_in[9];
    const float* bdw  = (const float*)d_in[10];
    const float* lng  = (const float*)d_in[11];
    const float* lnb  = (const float*)d_in[12];
    const float* Wo2  = (const float*)d_in[13];
    const float* Wco  = (const float*)d_in[14];
    const float* pos  = (const float*)d_in[15];
    const float* Wp   = (const float*)d_in[16];
    const float* bp   = (const float*)d_in[17];
    float* out = (float*)d_out;

    float* p_qkv; cudaGetSymbolAddress((void**)&p_qkv, g_qkv);

    // 1) qkv: N=1152, M=1568 -> 18 x 13 blocks
    gemm_big<0><<<dim3(18, 13), 256>>>(x, Wq, Wk, Wvv, bq, nullptr, BNROWS, QKVC);
    // 2) fused t1co (91) + qk (4704)
    fused_t1co_qk<<<T1CO_BLOCKS + 7*7*Bv*HEADS, 256>>>(Wo1, bo1, Wco, p_qkv);
    // 3) offset net tail
    dwln_kernel<<<Bv*Sv, Cv>>>(Wdw, bdw, lng, lnb);
    gemm_off<<<dim3(7, 13), 128>>>(Wo2);
    // 4) scores -> probs -> dense A
    score_kernel<<<Bv*Nv, 384>>>(pos);
    // 5) AV
    av_kernel<<<dim3(4, Bv*HEADS), 128>>>(bvv);
    // 6) final projection (coalesced NCHW stores)
    gemm_big<2><<<dim3(25, 3), 256>>>(Wp, Wp, nullptr, nullptr, bp, out, Cv, BNROWS);
}

// round 7
// speedup vs baseline: 1.5087x; 1.0230x over previous
#include <cuda_runtime.h>
#include <cuda_bf16.h>
#include <math.h>

#define Bv   8
#define Cv   384
#define Hv   14
#define Wv_  14
#define HEADS 12
#define HC   32
#define Nv   196
#define Sv   49
#define rHv  7
#define rWv  7
#define KKv  9
#define TS   58
#define BNROWS (Bv*Nv)   // 1568
#define QKVC 1152

// Scratch
__device__ float g_qkv[BNROWS*QKVC];          // q | xK | xV   (stride 1152)
__device__ float g_t1 [BNROWS*Cv];
__device__ float g_t3 [Bv*Sv*Cv];
__device__ float g_off[Bv*Sv*2*Nv];           // RAW (pre-tanh) accumulations
__device__ float g_co [BNROWS*2*KKv];
__device__ float g_qk [(size_t)Bv*HEADS*Nv*Nv];
__device__ float g_A  [(size_t)Bv*HEADS*Nv*Nv];
__device__ float g_ao [BNROWS*Cv];

__constant__ float c_offm[9][2] = {
    {0.f,-1.f},{-1.f,-1.f},{-1.f,0.f},{-1.f,1.f},{0.f,1.f},{1.f,1.f},{1.f,0.f},{1.f,-1.f},{0.f,0.f}
};

__device__ __forceinline__ float gelu_exact(float v) {
    return 0.5f * v * (1.0f + erff(v * 0.7071067811865476f));
}

// ---- f32x2 packed math helpers (sm_100+) ----
__device__ __forceinline__ unsigned long long pk2(float lo, float hi) {
    unsigned long long r;
    asm("mov.b64 %0, {%1,%2};" : "=l"(r) : "f"(lo), "f"(hi));
    return r;
}
__device__ __forceinline__ void fma2(unsigned long long &c, unsigned long long a, unsigned long long b) {
    asm("fma.rn.f32x2 %0, %1, %2, %3;" : "=l"(c) : "l"(a), "l"(b), "l"(c));
}
__device__ __forceinline__ float2 upk(unsigned long long v) {
    float2 f;
    asm("mov.b64 {%0,%1}, %2;" : "=f"(f.x), "=f"(f.y) : "l"(v));
    return f;
}

// =====================================================================================
// GEMM core: 128x64 tile, BK=16, double-buffered, 256 threads, 8m x 4n, f32x2 acc.
// MODE 0: qkv, MODE 1: t1co, MODE 2: proj (coalesced NCHW store)
// =====================================================================================
template<int MODE>
__device__ __forceinline__
void gemm_core(float As[2][16][132], float Bs[2][16][68], int bxx, int byy,
               const float* __restrict__ Asrc,
               const float* __restrict__ W0, const float* __restrict__ W1, const float* __restrict__ W2,
               const float* __restrict__ bias, float* __restrict__ outp, int M, int N)
{
    const int tid = threadIdx.x;
    const int bm = byy * 128;
    const int bn = bxx * 64;
    const int ty = tid >> 4;
    const int tx = tid & 15;

    unsigned long long acc[4][4];
    #pragma unroll
    for (int i = 0; i < 4; i++)
        #pragma unroll
        for (int j = 0; j < 4; j++) acc[i][j] = 0ull;

    float  ra[8];
    float4 ra4[2];
    float4 rb4;

    const int k4  = (tid & 3) * 4;
    const int mo4 = tid >> 2;
    const int no4 = tid >> 2;

    auto ldgA = [&](int k0) {
        if (MODE == 0) {
            #pragma unroll
            for (int i = 0; i < 8; i++) {
                int mo = (tid & 63) + ((i & 1) << 6);
                int ko = (tid >> 6) + ((i >> 1) << 2);
                int m = bm + mo;
                float v = 0.0f;
                if (m < M) {
                    int b = m / Nv, nn = m - b * Nv;
                    v = Asrc[((size_t)(b * Cv + k0 + ko)) * Nv + nn];
                }
                ra[i] = v;
            }
        } else {
            const int lda = (MODE == 1) ? QKVC : Cv;
            #pragma unroll
            for (int i = 0; i < 2; i++) {
                int m = bm + mo4 + i * 64;
                if (m < M) ra4[i] = *(const float4*)&Asrc[(size_t)m * lda + k0 + k4];
                else       ra4[i] = make_float4(0.f, 0.f, 0.f, 0.f);
            }
        }
    };
    auto ldgB = [&](int k0) {
        int n = bn + no4;
        if (MODE == 2) {
            if (n < N) rb4 = *(const float4*)&g_ao[(size_t)n * Cv + k0 + k4];
            else       rb4 = make_float4(0.f, 0.f, 0.f, 0.f);
        } else {
            const float* row = nullptr;
            if (MODE == 0) {
                int region = n / Cv;
                int nl = n - region * Cv;
                const float* Wt = (region == 0) ? W0 : (region == 1 ? W1 : W2);
                row = Wt + (size_t)nl * Cv;
            } else {
                if (n < Cv) row = W0 + (size_t)n * Cv;
                else if (n - Cv < 2 * KKv) row = W1 + (size_t)(n - Cv) * Cv;
            }
            if (row) rb4 = *(const float4*)&row[k0 + k4];
            else     rb4 = make_float4(0.f, 0.f, 0.f, 0.f);
        }
    };
    auto sts = [&](int buf) {
        if (MODE == 0) {
            #pragma unroll
            for (int i = 0; i < 8; i++) {
                int mo = (tid & 63) + ((i & 1) << 6);
                int ko = (tid >> 6) + ((i >> 1) << 2);
                As[buf][ko][mo] = ra[i];
            }
        } else {
            #pragma unroll
            for (int i = 0; i < 2; i++) {
                As[buf][k4 + 0][mo4 + i * 64] = ra4[i].x;
                As[buf][k4 + 1][mo4 + i * 64] = ra4[i].y;
                As[buf][k4 + 2][mo4 + i * 64] = ra4[i].z;
                As[buf][k4 + 3][mo4 + i * 64] = ra4[i].w;
            }
        }
        Bs[buf][k4 + 0][no4] = rb4.x;
        Bs[buf][k4 + 1][no4] = rb4.y;
        Bs[buf][k4 + 2][no4] = rb4.z;
        Bs[buf][k4 + 3][no4] = rb4.w;
    };

    const int NT = Cv / 16;
    ldgA(0); ldgB(0);
    sts(0);
    __syncthreads();

    for (int kt = 0; kt < NT; kt++) {
        const int cur = kt & 1;
        if (kt + 1 < NT) { ldgA((kt + 1) * 16); ldgB((kt + 1) * 16); }
        #pragma unroll
        for (int k = 0; k < 16; k++) {
            unsigned long long a2[4];
            #pragma unroll
            for (int j = 0; j < 4; j++)
                a2[j] = *(const unsigned long long*)&As[cur][k][ty * 8 + j * 2];
            float4 bv = *(const float4*)&Bs[cur][k][tx * 4];
            unsigned long long b2[4];
            b2[0] = pk2(bv.x, bv.x); b2[1] = pk2(bv.y, bv.y);
            b2[2] = pk2(bv.z, bv.z); b2[3] = pk2(bv.w, bv.w);
            #pragma unroll
            for (int i = 0; i < 4; i++)
                #pragma unroll
                for (int j = 0; j < 4; j++)
                    fma2(acc[i][j], a2[i], b2[j]);
        }
        if (kt + 1 < NT) {
            __syncthreads();
            sts(1 - cur);
            __syncthreads();
        }
    }

    #pragma unroll
    for (int i = 0; i < 4; i++) {
        #pragma unroll
        for (int j = 0; j < 4; j++) {
            float2 f = upk(acc[i][j]);
            int n = bn + tx * 4 + j;
            #pragma unroll
            for (int half = 0; half < 2; half++) {
                int m = bm + ty * 8 + i * 2 + half;
                float v = half ? f.y : f.x;
                if (m >= M) continue;
                if (MODE == 0) {
                    if (n < Cv) v += bias[n];
                    g_qkv[(size_t)m * QKVC + n] = v;
                } else if (MODE == 1) {
                    if (n < Cv) {
                        g_t1[(size_t)m * Cv + n] = gelu_exact(v + bias[n]);
                    } else if (n - Cv < 2 * KKv) {
                        g_co[(size_t)m * (2 * KKv) + (n - Cv)] = tanhf(v) * (1.0f / 14.0f);
                    }
                } else {
                    if (n >= N) continue;
                    int b = n / Nv, nn = n - b * Nv;
                    outp[((size_t)(b * Cv + m)) * Nv + nn] = v + bias[m];
                }
            }
        }
    }
}

template<int MODE>
__global__ __launch_bounds__(256, 2)
void gemm_big(const float* __restrict__ Asrc,
              const float* __restrict__ W0, const float* __restrict__ W1, const float* __restrict__ W2,
              const float* __restrict__ bias, float* __restrict__ outp, int M, int N)
{
    __shared__ float As[2][16][132];
    __shared__ float Bs[2][16][68];
    gemm_core<MODE>(As, Bs, blockIdx.x, blockIdx.y, Asrc, W0, W1, W2, bias, outp, M, N);
}

// ================= fused: t1co GEMM (91 blocks) + qk maps (4704 blocks) =================
#define T1CO_BLOCKS 91
__global__ __launch_bounds__(256, 2)
void fused_t1co_qk(const float* __restrict__ Wo1, const float* __restrict__ bo1,
                   const float* __restrict__ Wco, const float* __restrict__ q_src)
{
    const int idx = blockIdx.x;
    if (idx < T1CO_BLOCKS) {
        __shared__ float As[2][16][132];
        __shared__ float Bs[2][16][68];
        gemm_core<1>(As, Bs, idx % 7, idx / 7, q_src, Wo1, Wco, nullptr, bo1, nullptr,
                     BNROWS, Cv + 2 * KKv);
    } else {
        const int idx2 = idx - T1CO_BLOCKS;
        const int bxq = idx2 % 7;
        const int byq = (idx2 / 7) % 7;
        const int bh  = idx2 / 49;
        const int b = bh / HEADS, h = bh - b * HEADS;
        const int n0 = byq * 32, p0 = bxq * 32;
        __shared__ float qs[32][33], ks[32][33];
        int tid = threadIdx.x;
        int lr = tid >> 5, lc = tid & 31;
        #pragma unroll
        for (int i = 0; i < 4; i++) {
            int n = n0 + lr + i * 8;
            qs[lr + i*8][lc] = (n < Nv) ? g_qkv[((size_t)b*Nv + n)*QKVC + h*HC + lc] : 0.0f;
            int p = p0 + lr + i * 8;
            ks[lr + i*8][lc] = (p < Nv) ? g_qkv[((size_t)b*Nv + p)*QKVC + Cv + h*HC + lc] : 0.0f;
        }
        __syncthreads();
        int pcol = tid & 31, ng = tid >> 5;
        float acc[4] = {0.f, 0.f, 0.f, 0.f};
        #pragma unroll
        for (int d = 0; d < 32; d++) {
            float kv = ks[pcol][d];
            #pragma unroll
            for (int i = 0; i < 4; i++) acc[i] = fmaf(qs[ng*4 + i][d], kv, acc[i]);
        }
        #pragma unroll
        for (int i = 0; i < 4; i++) {
            int n = n0 + ng*4 + i, p = p0 + pcol;
            if (n < Nv && p < Nv)
                g_qk[(((size_t)bh)*Nv + n)*Nv + p] = acc[i];
        }
    }
}

// ================= offset GEMM (split-K x4): g_off += t3 @ Wo2^T (raw) =================
// 32x64 tile, K-chunk 96 (3 stages of BK=32), grid (7,13,4)=364 blocks, 128 threads.
// Partial sums combined via atomicAdd; tanh epilogue moved into score_kernel.
__global__ __launch_bounds__(128, 8)
void gemm_off(const float* __restrict__ Wo2)
{
    __shared__ float As[2][32][36];
    __shared__ float Bs[2][32][68];
    const int M = Bv * Sv;      // 392
    const int N = 2 * Nv;       // 392
    const int bm = blockIdx.y * 32;
    const int bn = blockIdx.x * 64;
    const int kbase = blockIdx.z * 96;
    const int tid = threadIdx.x;
    const int ty = tid >> 4;      // 0..7 -> m = ty*4
    const int tx = tid & 15;      // 0..15 -> n = tx*4
    const int k4 = (tid & 7) * 4;
    const int rowg = tid >> 3;    // 0..15

    unsigned long long acc[2][4];
    #pragma unroll
    for (int i = 0; i < 2; i++)
        #pragma unroll
        for (int j = 0; j < 4; j++) acc[i][j] = 0ull;

    float4 ra4[2], rb4[4];
    auto ldg = [&](int k0) {
        #pragma unroll
        for (int i = 0; i < 2; i++) {
            int m = bm + rowg + i * 16;
            if (m < M) ra4[i] = *(const float4*)&g_t3[(size_t)m * Cv + k0 + k4];
            else       ra4[i] = make_float4(0.f, 0.f, 0.f, 0.f);
        }
        #pragma unroll
        for (int i = 0; i < 4; i++) {
            int n = bn + rowg + i * 16;
            if (n < N) rb4[i] = *(const float4*)&Wo2[(size_t)n * Cv + k0 + k4];
            else       rb4[i] = make_float4(0.f, 0.f, 0.f, 0.f);
        }
    };
    auto sts = [&](int buf) {
        #pragma unroll
        for (int i = 0; i < 2; i++) {
            As[buf][k4 + 0][rowg + i * 16] = ra4[i].x;
            As[buf][k4 + 1][rowg + i * 16] = ra4[i].y;
            As[buf][k4 + 2][rowg + i * 16] = ra4[i].z;
            As[buf][k4 + 3][rowg + i * 16] = ra4[i].w;
        }
        #pragma unroll
        for (int i = 0; i < 4; i++) {
            Bs[buf][k4 + 0][rowg + i * 16] = rb4[i].x;
            Bs[buf][k4 + 1][rowg + i * 16] = rb4[i].y;
            Bs[buf][k4 + 2][rowg + i * 16] = rb4[i].z;
            Bs[buf][k4 + 3][rowg + i * 16] = rb4[i].w;
        }
    };

    const int NT = 3;   // 96 / 32
    ldg(kbase);
    sts(0);
    __syncthreads();

    #pragma unroll
    for (int kt = 0; kt < NT; kt++) {
        const int cur = kt & 1;
        if (kt + 1 < NT) ldg(kbase + (kt + 1) * 32);
        #pragma unroll
        for (int k = 0; k < 32; k++) {
            unsigned long long a2[2];
            a2[0] = *(const unsigned long long*)&As[cur][k][ty * 4];
            a2[1] = *(const unsigned long long*)&As[cur][k][ty * 4 + 2];
            float4 bv = *(const float4*)&Bs[cur][k][tx * 4];
            unsigned long long b2[4];
            b2[0] = pk2(bv.x, bv.x); b2[1] = pk2(bv.y, bv.y);
            b2[2] = pk2(bv.z, bv.z); b2[3] = pk2(bv.w, bv.w);
            #pragma unroll
            for (int i = 0; i < 2; i++)
                #pragma unroll
                for (int j = 0; j < 4; j++)
                    fma2(acc[i][j], a2[i], b2[j]);
        }
        if (kt + 1 < NT) {
            __syncthreads();
            sts(1 - cur);
            __syncthreads();
        }
    }

    #pragma unroll
    for (int i = 0; i < 2; i++) {
        #pragma unroll
        for (int j = 0; j < 4; j++) {
            float2 f = upk(acc[i][j]);
            int n = bn + tx * 4 + j;
            if (n >= N) continue;
            int m0 = bm + ty * 4 + i * 2;
            if (m0 < M)     atomicAdd(&g_off[(size_t)m0 * N + n], f.x);
            if (m0 + 1 < M) atomicAdd(&g_off[(size_t)(m0 + 1) * N + n], f.y);
        }
    }
}

// ================= depthwise 3x3 s2 conv + LN + GELU  (+ zero g_off row) =================
__global__ void dwln_kernel(const float* __restrict__ Wdw, const float* __restrict__ bdw,
                            const float* __restrict__ lng, const float* __restrict__ lnb)
{
    int bs = blockIdx.x;
    int b = bs / Sv, s = bs % Sv;
    int oy = s / rWv, ox = s % rWv;
    int c = threadIdx.x;

    // zero the g_off row this (b,s) owns (392 floats) — ready before gemm_off's atomics
    for (int i = c; i < 2 * Nv; i += blockDim.x)
        g_off[(size_t)bs * (2 * Nv) + i] = 0.0f;

    float acc = bdw[c];
    #pragma unroll
    for (int ky = 0; ky < 3; ky++) {
        int y = oy*2 - 1 + ky;
        if (y < 0 || y >= Hv) continue;
        #pragma unroll
        for (int kx = 0; kx < 3; kx++) {
            int x = ox*2 - 1 + kx;
            if (x < 0 || x >= Wv_) continue;
            acc = fmaf(g_t1[((size_t)b*Nv + y*Wv_ + x)*Cv + c], Wdw[c*9 + ky*3 + kx], acc);
        }
    }
    float s1 = acc, s2 = acc*acc;
    #pragma unroll
    for (int o = 16; o > 0; o >>= 1) {
        s1 += __shfl_xor_sync(0xffffffffu, s1, o);
        s2 += __shfl_xor_sync(0xffffffffu, s2, o);
    }
    __shared__ float w1[12], w2[12];
    __shared__ float s_mu, s_rstd;
    if ((c & 31) == 0) { w1[c >> 5] = s1; w2[c >> 5] = s2; }
    __syncthreads();
    if (c == 0) {
        float t1s = 0.f, t2s = 0.f;
        #pragma unroll
        for (int i = 0; i < 12; i++) { t1s += w1[i]; t2s += w2[i]; }
        float mu = t1s / (float)Cv;
        float var = t2s / (float)Cv - mu*mu;
        s_mu = mu; s_rstd = rsqrtf(var + 1e-5f);
    }
    __syncthreads();
    float v = (acc - s_mu) * s_rstd * lng[c] + lnb[c];
    g_t3[(size_t)bs*Cv + c] = gelu_exact(v);
}

// ================= scores + softmax + fold probs into dense A[b,h,n,:] =================
__global__ void score_kernel(const float* __restrict__ posembed)
{
    const int bn = blockIdx.x;
    const int b = bn / Nv, n = bn % Nv;
    const int ny = n / Wv_, nx = n % Wv_;
    __shared__ float sc[HEADS*TS];
    __shared__ int   sp[TS*4];
    __shared__ float swt[TS*4];
    __shared__ __align__(16) float sA[HEADS][Nv];

    for (int idx = threadIdx.x; idx < HEADS*Nv/4; idx += blockDim.x)
        ((float4*)sA)[idx] = make_float4(0.f, 0.f, 0.f, 0.f);

    for (int item = threadIdx.x; item < HEADS*TS; item += blockDim.x) {
        const int h = item / TS, s = item % TS;
        float py, px, tpy, tpx;
        if (s < Sv) {
            int rh = s / rWv, rw = s % rWv;
            // raw accumulations -> apply tanh epilogue here
            float offy = tanhf(g_off[((size_t)b*Sv + s)*(2*Nv) + 0*Nv + n]) * (2.0f/14.0f);
            float offx = tanhf(g_off[((size_t)b*Sv + s)*(2*Nv) + 1*Nv + n]) * (2.0f/14.0f);
            float refy = (float)(rh*2) * (2.0f/13.0f) - 1.0f;
            float refx = (float)(rw*2) * (2.0f/13.0f) - 1.0f;
            py = (offy + refy + 1.0f) * 6.5f;
            px = (offx + refx + 1.0f) * 6.5f;
            tpy = ((float)(2*rh - ny) * (1.0f/13.0f) - offy + 1.0f) * 13.0f;
            tpx = ((float)(2*rw - nx) * (1.0f/13.0f) - offx + 1.0f) * 13.0f;
        } else {
            int j = s - Sv;
            float coy = g_co[((size_t)b*Nv + n)*(2*KKv) + j*2 + 0];
            float cox = g_co[((size_t)b*Nv + n)*(2*KKv) + j*2 + 1];
            float cy = (float)ny + c_offm[j][0];
            float cx = (float)nx + c_offm[j][1];
            float cny = fminf(fmaxf(cy, 0.0f), 14.0f) * (2.0f/13.0f) - 1.0f;
            float cnx = fminf(fmaxf(cx, 0.0f), 14.0f) * (2.0f/13.0f) - 1.0f;
            py = (coy + cny + 1.0f) * 6.5f;
            px = (cox + cnx + 1.0f) * 6.5f;
            tpy = (coy - (float)ny + 1.0f) * 13.0f;
            tpx = (cox - (float)nx + 1.0f) * 13.0f;
        }
        float y0 = floorf(py), x0 = floorf(px);
        float wy1 = py - y0, wx1 = px - x0;
        const float* qkb = g_qk + (((size_t)(b*HEADS + h))*Nv + n)*Nv;
        float val = 0.0f;
        #pragma unroll
        for (int ccy = 0; ccy < 2; ccy++) {
            #pragma unroll
            for (int ccx = 0; ccx < 2; ccx++) {
                float yf = y0 + (float)ccy, xf = x0 + (float)ccx;
                float w = (ccy ? wy1 : 1.0f - wy1) * (ccx ? wx1 : 1.0f - wx1);
                bool valid = (yf >= 0.0f) && (yf <= 13.0f) && (xf >= 0.0f) && (xf <= 13.0f);
                if (!valid) w = 0.0f;
                int yi = (int)fminf(fmaxf(yf, 0.0f), 13.0f);
                int xi = (int)fminf(fmaxf(xf, 0.0f), 13.0f);
                int pix = yi*Wv_ + xi;
                val += w * qkb[pix];
                if (h == 0) { sp[s*4 + ccy*2 + ccx] = pix; swt[s*4 + ccy*2 + ccx] = w; }
            }
        }
        float by0 = floorf(tpy), bx0 = floorf(tpx);
        float bwy = tpy - by0, bwx = tpx - bx0;
        const float* tb = posembed + (size_t)h * (27*27);
        float bval = 0.0f;
        #pragma unroll
        for (int ccy = 0; ccy < 2; ccy++) {
            #pragma unroll
            for (int ccx = 0; ccx < 2; ccx++) {
                float yf = by0 + (float)ccy, xf = bx0 + (float)ccx;
                float w = (ccy ? bwy : 1.0f - bwy) * (ccx ? bwx : 1.0f - bwx);
                bool valid = (yf >= 0.0f) && (yf <= 26.0f) && (xf >= 0.0f) && (xf <= 26.0f);
                if (!valid) w = 0.0f;
                int yi = (int)fminf(fmaxf(yf, 0.0f), 26.0f);
                int xi = (int)fminf(fmaxf(xf, 0.0f), 26.0f);
                bval += w * tb[yi*27 + xi];
            }
        }
        sc[h*TS + s] = val + bval;
    }
    __syncthreads();

    const int wid = threadIdx.x >> 5, lane = threadIdx.x & 31;
    {
        float m = -1e30f;
        for (int s = lane; s < TS; s += 32) m = fmaxf(m, sc[wid*TS + s]);
        #pragma unroll
        for (int o = 16; o > 0; o >>= 1) m = fmaxf(m, __shfl_xor_sync(0xffffffffu, m, o));
        float sum = 0.0f;
        for (int s = lane; s < TS; s += 32) {
            float e = expf(sc[wid*TS + s] - m);
            sc[wid*TS + s] = e;
            sum += e;
        }
        #pragma unroll
        for (int o = 16; o > 0; o >>= 1) sum += __shfl_xor_sync(0xffffffffu, sum, o);
        float inv = 1.0f / sum;
        for (int s = lane; s < TS; s += 32) sc[wid*TS + s] *= inv;
    }
    for (int i = lane; i < TS*4; i += 32) {
        atomicAdd(&sA[wid][sp[i]], sc[wid*TS + (i >> 2)] * swt[i]);
    }
    __syncthreads();

    float4* dst = (float4*)(g_A + ((size_t)(b*HEADS))*Nv*Nv);
    for (int idx = threadIdx.x; idx < HEADS*(Nv/4); idx += blockDim.x) {
        int h = idx / (Nv/4), p4 = idx - h * (Nv/4);
        dst[((size_t)h*Nv + n)*(Nv/4) + p4] = ((float4*)sA)[h*(Nv/4) + p4];
    }
}

// ================= AV GEMM (f32x2): out[b,n,h,:] = A[b,h,n,:] @ xV[b,:,h,:] + bv ========
__global__ __launch_bounds__(128, 4)
void av_kernel(const float* __restrict__ bvv)
{
    const int n0 = blockIdx.x * 64;
    const int bh = blockIdx.y;
    const int b = bh / HEADS, h = bh - b * HEADS;
    __shared__ __align__(16) float Vs[Nv][HC];
    __shared__ __align__(16) float As[32][68];

    const int tid = threadIdx.x;
    const int tx = tid & 7;
    const int ng = tid >> 3;

    {
        const float* vbase = g_qkv + (size_t)b * Nv * QKVC + 2 * Cv + h * HC;
        for (int i = tid; i < Nv * (HC/4); i += 128) {
            int p = i >> 3, c4 = (i & 7) * 4;
            *(float4*)&Vs[p][c4] = *(const float4*)&vbase[(size_t)p * QKVC + c4];
        }
    }

    unsigned long long acc[2][4];
    #pragma unroll
    for (int i = 0; i < 2; i++)
        #pragma unroll
        for (int j = 0; j < 4; j++) acc[i][j] = 0ull;

    const float* Arow = g_A + ((size_t)bh * Nv) * Nv;
    const int r = tid >> 1, halfq = tid & 1;

    for (int p0 = 0; p0 < Nv; p0 += 32) {
        const int kt = min(32, Nv - p0);
        __syncthreads();
        {
            int nrow = n0 + r;
            #pragma unroll
            for (int q = 0; q < 4; q++) {
                int pl = halfq * 16 + q * 4;
                float4 v = make_float4(0.f, 0.f, 0.f, 0.f);
                if (nrow < Nv && p0 + pl < Nv)
                    v = *(const float4*)&Arow[(size_t)nrow * Nv + p0 + pl];
                As[pl + 0][r] = v.x;
                As[pl + 1][r] = v.y;
                As[pl + 2][r] = v.z;
                As[pl + 3][r] = v.w;
            }
        }
        __syncthreads();
        for (int k = 0; k < kt; k++) {
            float4 af = *(const float4*)&As[k][ng * 4];
            unsigned long long a0 = pk2(af.x, af.y);
            unsigned long long a1 = pk2(af.z, af.w);
            float4 bf = *(const float4*)&Vs[p0 + k][tx * 4];
            unsigned long long b2[4];
            b2[0] = pk2(bf.x, bf.x); b2[1] = pk2(bf.y, bf.y);
            b2[2] = pk2(bf.z, bf.z); b2[3] = pk2(bf.w, bf.w);
            #pragma unroll
            for (int j = 0; j < 4; j++) { fma2(acc[0][j], a0, b2[j]); fma2(acc[1][j], a1, b2[j]); }
        }
    }

    #pragma unroll
    for (int j = 0; j < 4; j++) {
        int c = tx * 4 + j;
        float bb = bvv[h * HC + c];
        #pragma unroll
        for (int i = 0; i < 2; i++) {
            float2 f = upk(acc[i][j]);
            int n = n0 + ng * 4 + i * 2;
            if (n < Nv)     g_ao[((size_t)(b*Nv + n  ))*Cv + h*HC + c] = f.x + bb;
            if (n + 1 < Nv) g_ao[((size_t)(b*Nv + n+1))*Cv + h*HC + c] = f.y + bb;
        }
    }
}

extern "C" void kernel_launch(void* const* d_in, const int* in_sizes, int n_in,
                              void* d_out, int out_size)
{
    const float* x    = (const float*)d_in[0];
    const float* Wq   = (const float*)d_in[1];
    const float* bq   = (const float*)d_in[2];
    const float* Wk   = (const float*)d_in[3];
    // bk cancels in softmax — unused
    const float* Wvv  = (const float*)d_in[5];
    const float* bvv  = (const float*)d_in[6];
    const float* Wo1  = (const float*)d_in[7];
    const float* bo1  = (const float*)d_in[8];
    const float* Wdw  = (const float*)d_in[9];
    const float* bdw  = (const float*)d_in[10];
    const float* lng  = (const float*)d_in[11];
    const float* lnb  = (const float*)d_in[12];
    const float* Wo2  = (const float*)d_in[13];
    const float* Wco  = (const float*)d_in[14];
    const float* pos  = (const float*)d_in[15];
    const float* Wp   = (const float*)d_in[16];
    const float* bp   = (const float*)d_in[17];
    float* out = (float*)d_out;

    float* p_qkv; cudaGetSymbolAddress((void**)&p_qkv, g_qkv);

    // 1) qkv: N=1152, M=1568 -> 18 x 13 blocks
    gemm_big<0><<<dim3(18, 13), 256>>>(x, Wq, Wk, Wvv, bq, nullptr, BNROWS, QKVC);
    // 2) fused t1co (91) + qk (4704)
    fused_t1co_qk<<<T1CO_BLOCKS + 7*7*Bv*HEADS, 256>>>(Wo1, bo1, Wco, p_qkv);
    // 3) offset net tail (dwln also zero-fills g_off)
    dwln_kernel<<<Bv*Sv, Cv>>>(Wdw, bdw, lng, lnb);
    gemm_off<<<dim3(7, 13, 4), 128>>>(Wo2);
    // 4) scores -> probs -> dense A (applies tanh epilogue on off)
    score_kernel<<<Bv*Nv, 384>>>(pos);
    // 5) AV
    av_kernel<<<dim3(4, Bv*HEADS), 128>>>(bvv);
    // 6) final projection (coalesced NCHW stores)
    gemm_big<2><<<dim3(25, 3), 256>>>(Wp, Wp, nullptr, nullptr, bp, out, Cv, BNROWS);
}

// round 8
// speedup vs baseline: 1.5921x; 1.0553x over previous
#include <cuda_runtime.h>
#include <cuda_bf16.h>
#include <math.h>

#define Bv   8
#define Cv   384
#define Hv   14
#define Wv_  14
#define HEADS 12
#define HC   32
#define Nv   196
#define Sv   49
#define rHv  7
#define rWv  7
#define KKv  9
#define TS   58
#define BNROWS (Bv*Nv)   // 1568
#define QKVC 1152

// Scratch
__device__ float g_qkv[BNROWS*QKVC];          // q | xK | xV   (stride 1152)
__device__ float g_t1 [BNROWS*Cv];
__device__ float g_t3 [Bv*Sv*Cv];
__device__ float g_off[Bv*Sv*2*Nv];           // RAW (pre-tanh) accumulations
__device__ float g_co [BNROWS*2*KKv];
__device__ float g_qk [(size_t)Bv*HEADS*Nv*Nv];
__device__ float g_A  [(size_t)Bv*HEADS*Nv*Nv];
__device__ float g_ao [BNROWS*Cv];

__constant__ float c_offm[9][2] = {
    {0.f,-1.f},{-1.f,-1.f},{-1.f,0.f},{-1.f,1.f},{0.f,1.f},{1.f,1.f},{1.f,0.f},{1.f,-1.f},{0.f,0.f}
};

__device__ __forceinline__ float gelu_exact(float v) {
    return 0.5f * v * (1.0f + erff(v * 0.7071067811865476f));
}

// ---- f32x2 packed math helpers (sm_100+) ----
__device__ __forceinline__ unsigned long long pk2(float lo, float hi) {
    unsigned long long r;
    asm("mov.b64 %0, {%1,%2};" : "=l"(r) : "f"(lo), "f"(hi));
    return r;
}
__device__ __forceinline__ void fma2(unsigned long long &c, unsigned long long a, unsigned long long b) {
    asm("fma.rn.f32x2 %0, %1, %2, %3;" : "=l"(c) : "l"(a), "l"(b), "l"(c));
}
__device__ __forceinline__ float2 upk(unsigned long long v) {
    float2 f;
    asm("mov.b64 {%0,%1}, %2;" : "=f"(f.x), "=f"(f.y) : "l"(v));
    return f;
}

// =====================================================================================
// GEMM core: 128x64 tile, BK=16, double-buffered, 256 threads, 8m x 4n, f32x2 acc.
// MODE 0: qkv, MODE 1: t1co
// =====================================================================================
template<int MODE>
__device__ __forceinline__
void gemm_core(float As[2][16][132], float Bs[2][16][68], int bxx, int byy,
               const float* __restrict__ Asrc,
               const float* __restrict__ W0, const float* __restrict__ W1, const float* __restrict__ W2,
               const float* __restrict__ bias, int M, int N)
{
    const int tid = threadIdx.x;
    const int bm = byy * 128;
    const int bn = bxx * 64;
    const int ty = tid >> 4;
    const int tx = tid & 15;

    unsigned long long acc[4][4];
    #pragma unroll
    for (int i = 0; i < 4; i++)
        #pragma unroll
        for (int j = 0; j < 4; j++) acc[i][j] = 0ull;

    float  ra[8];
    float4 ra4[2];
    float4 rb4;

    const int k4  = (tid & 3) * 4;
    const int mo4 = tid >> 2;
    const int no4 = tid >> 2;

    auto ldgA = [&](int k0) {
        if (MODE == 0) {
            #pragma unroll
            for (int i = 0; i < 8; i++) {
                int mo = (tid & 63) + ((i & 1) << 6);
                int ko = (tid >> 6) + ((i >> 1) << 2);
                int m = bm + mo;
                float v = 0.0f;
                if (m < M) {
                    int b = m / Nv, nn = m - b * Nv;
                    v = Asrc[((size_t)(b * Cv + k0 + ko)) * Nv + nn];
                }
                ra[i] = v;
            }
        } else {
            #pragma unroll
            for (int i = 0; i < 2; i++) {
                int m = bm + mo4 + i * 64;
                if (m < M) ra4[i] = *(const float4*)&Asrc[(size_t)m * QKVC + k0 + k4];
                else       ra4[i] = make_float4(0.f, 0.f, 0.f, 0.f);
            }
        }
    };
    auto ldgB = [&](int k0) {
        int n = bn + no4;
        const float* row = nullptr;
        if (MODE == 0) {
            int region = n / Cv;
            int nl = n - region * Cv;
            const float* Wt = (region == 0) ? W0 : (region == 1 ? W1 : W2);
            row = Wt + (size_t)nl * Cv;
        } else {
            if (n < Cv) row = W0 + (size_t)n * Cv;
            else if (n - Cv < 2 * KKv) row = W1 + (size_t)(n - Cv) * Cv;
        }
        if (row) rb4 = *(const float4*)&row[k0 + k4];
        else     rb4 = make_float4(0.f, 0.f, 0.f, 0.f);
    };
    auto sts = [&](int buf) {
        if (MODE == 0) {
            #pragma unroll
            for (int i = 0; i < 8; i++) {
                int mo = (tid & 63) + ((i & 1) << 6);
                int ko = (tid >> 6) + ((i >> 1) << 2);
                As[buf][ko][mo] = ra[i];
            }
        } else {
            #pragma unroll
            for (int i = 0; i < 2; i++) {
                As[buf][k4 + 0][mo4 + i * 64] = ra4[i].x;
                As[buf][k4 + 1][mo4 + i * 64] = ra4[i].y;
                As[buf][k4 + 2][mo4 + i * 64] = ra4[i].z;
                As[buf][k4 + 3][mo4 + i * 64] = ra4[i].w;
            }
        }
        Bs[buf][k4 + 0][no4] = rb4.x;
        Bs[buf][k4 + 1][no4] = rb4.y;
        Bs[buf][k4 + 2][no4] = rb4.z;
        Bs[buf][k4 + 3][no4] = rb4.w;
    };

    const int NT = Cv / 16;
    ldgA(0); ldgB(0);
    sts(0);
    __syncthreads();

    for (int kt = 0; kt < NT; kt++) {
        const int cur = kt & 1;
        if (kt + 1 < NT) { ldgA((kt + 1) * 16); ldgB((kt + 1) * 16); }
        #pragma unroll
        for (int k = 0; k < 16; k++) {
            unsigned long long a2[4];
            #pragma unroll
            for (int j = 0; j < 4; j++)
                a2[j] = *(const unsigned long long*)&As[cur][k][ty * 8 + j * 2];
            float4 bv = *(const float4*)&Bs[cur][k][tx * 4];
            unsigned long long b2[4];
            b2[0] = pk2(bv.x, bv.x); b2[1] = pk2(bv.y, bv.y);
            b2[2] = pk2(bv.z, bv.z); b2[3] = pk2(bv.w, bv.w);
            #pragma unroll
            for (int i = 0; i < 4; i++)
                #pragma unroll
                for (int j = 0; j < 4; j++)
                    fma2(acc[i][j], a2[i], b2[j]);
        }
        if (kt + 1 < NT) {
            __syncthreads();
            sts(1 - cur);
            __syncthreads();
        }
    }

    #pragma unroll
    for (int i = 0; i < 4; i++) {
        #pragma unroll
        for (int j = 0; j < 4; j++) {
            float2 f = upk(acc[i][j]);
            int n = bn + tx * 4 + j;
            #pragma unroll
            for (int half = 0; half < 2; half++) {
                int m = bm + ty * 8 + i * 2 + half;
                float v = half ? f.y : f.x;
                if (m >= M) continue;
                if (MODE == 0) {
                    if (n < Cv) v += bias[n];
                    g_qkv[(size_t)m * QKVC + n] = v;
                } else {
                    if (n < Cv) {
                        g_t1[(size_t)m * Cv + n] = gelu_exact(v + bias[n]);
                    } else if (n - Cv < 2 * KKv) {
                        g_co[(size_t)m * (2 * KKv) + (n - Cv)] = tanhf(v) * (1.0f / 14.0f);
                    }
                }
            }
        }
    }
}

template<int MODE>
__global__ __launch_bounds__(256, 2)
void gemm_big(const float* __restrict__ Asrc,
              const float* __restrict__ W0, const float* __restrict__ W1, const float* __restrict__ W2,
              const float* __restrict__ bias, int M, int N)
{
    __shared__ float As[2][16][132];
    __shared__ float Bs[2][16][68];
    gemm_core<MODE>(As, Bs, blockIdx.x, blockIdx.y, Asrc, W0, W1, W2, bias, M, N);
}

// ================= fused: t1co GEMM (91 blocks) + qk maps (1536 blocks, 64x64 f32x2) ======
#define T1CO_BLOCKS 91
__global__ __launch_bounds__(256, 2)
void fused_t1co_qk(const float* __restrict__ Wo1, const float* __restrict__ bo1,
                   const float* __restrict__ Wco, const float* __restrict__ q_src)
{
    const int idx = blockIdx.x;
    if (idx < T1CO_BLOCKS) {
        __shared__ float As[2][16][132];
        __shared__ float Bs[2][16][68];
        gemm_core<1>(As, Bs, idx % 7, idx / 7, q_src, Wo1, Wco, nullptr, bo1,
                     BNROWS, Cv + 2 * KKv);
    } else {
        // qk: per (b,h) 64x64 output tile, K=32, f32x2
        const int idx2 = idx - T1CO_BLOCKS;
        const int bxq = idx2 & 3;           // p tile
        const int byq = (idx2 >> 2) & 3;    // n tile
        const int bh  = idx2 >> 4;          // 0..95
        const int b = bh / HEADS, h = bh - b * HEADS;
        const int n0 = byq * 64, p0 = bxq * 64;
        __shared__ float qs[32][68], ks[32][68];
        const int tid = threadIdx.x;
        const int rowg = tid >> 2;          // 0..63
        const int k8 = (tid & 3) * 8;       // 0,8,16,24

        {
            int n = n0 + rowg;
            float4 v0 = make_float4(0.f,0.f,0.f,0.f), v1 = v0;
            if (n < Nv) {
                const float* qrow = &g_qkv[((size_t)(b*Nv + n))*QKVC + h*HC + k8];
                v0 = *(const float4*)&qrow[0];
                v1 = *(const float4*)&qrow[4];
            }
            qs[k8+0][rowg] = v0.x; qs[k8+1][rowg] = v0.y;
            qs[k8+2][rowg] = v0.z; qs[k8+3][rowg] = v0.w;
            qs[k8+4][rowg] = v1.x; qs[k8+5][rowg] = v1.y;
            qs[k8+6][rowg] = v1.z; qs[k8+7][rowg] = v1.w;

            int p = p0 + rowg;
            float4 w0 = make_float4(0.f,0.f,0.f,0.f), w1 = w0;
            if (p < Nv) {
                const float* krow = &g_qkv[((size_t)(b*Nv + p))*QKVC + Cv + h*HC + k8];
                w0 = *(const float4*)&krow[0];
                w1 = *(const float4*)&krow[4];
            }
            ks[k8+0][rowg] = w0.x; ks[k8+1][rowg] = w0.y;
            ks[k8+2][rowg] = w0.z; ks[k8+3][rowg] = w0.w;
            ks[k8+4][rowg] = w1.x; ks[k8+5][rowg] = w1.y;
            ks[k8+6][rowg] = w1.z; ks[k8+7][rowg] = w1.w;
        }
        __syncthreads();

        const int ty = tid >> 4, tx = tid & 15;
        unsigned long long acc[2][4];
        #pragma unroll
        for (int i = 0; i < 2; i++)
            #pragma unroll
            for (int j = 0; j < 4; j++) acc[i][j] = 0ull;

        #pragma unroll
        for (int k = 0; k < 32; k++) {
            unsigned long long a2[2];
            a2[0] = *(const unsigned long long*)&qs[k][ty * 4];
            a2[1] = *(const unsigned long long*)&qs[k][ty * 4 + 2];
            float4 bv = *(const float4*)&ks[k][tx * 4];
            unsigned long long b2[4];
            b2[0] = pk2(bv.x, bv.x); b2[1] = pk2(bv.y, bv.y);
            b2[2] = pk2(bv.z, bv.z); b2[3] = pk2(bv.w, bv.w);
            #pragma unroll
            for (int i = 0; i < 2; i++)
                #pragma unroll
                for (int j = 0; j < 4; j++)
                    fma2(acc[i][j], a2[i], b2[j]);
        }

        float* qkb = g_qk + ((size_t)bh * Nv) * Nv;
        #pragma unroll
        for (int i = 0; i < 2; i++) {
            #pragma unroll
            for (int j = 0; j < 4; j++) {
                float2 f = upk(acc[i][j]);
                int p = p0 + tx * 4 + j;
                if (p >= Nv) continue;
                int n = n0 + ty * 4 + i * 2;
                if (n < Nv)     qkb[(size_t)n * Nv + p]       = f.x;
                if (n + 1 < Nv) qkb[(size_t)(n + 1) * Nv + p] = f.y;
            }
        }
    }
}

// ================= offset GEMM (split-K x4): g_off += t3 @ Wo2^T (raw) =================
__global__ __launch_bounds__(128, 8)
void gemm_off(const float* __restrict__ Wo2)
{
    __shared__ float As[2][32][36];
    __shared__ float Bs[2][32][68];
    const int M = Bv * Sv;      // 392
    const int N = 2 * Nv;       // 392
    const int bm = blockIdx.y * 32;
    const int bn = blockIdx.x * 64;
    const int kbase = blockIdx.z * 96;
    const int tid = threadIdx.x;
    const int ty = tid >> 4;
    const int tx = tid & 15;
    const int k4 = (tid & 7) * 4;
    const int rowg = tid >> 3;

    unsigned long long acc[2][4];
    #pragma unroll
    for (int i = 0; i < 2; i++)
        #pragma unroll
        for (int j = 0; j < 4; j++) acc[i][j] = 0ull;

    float4 ra4[2], rb4[4];
    auto ldg = [&](int k0) {
        #pragma unroll
        for (int i = 0; i < 2; i++) {
            int m = bm + rowg + i * 16;
            if (m < M) ra4[i] = *(const float4*)&g_t3[(size_t)m * Cv + k0 + k4];
            else       ra4[i] = make_float4(0.f, 0.f, 0.f, 0.f);
        }
        #pragma unroll
        for (int i = 0; i < 4; i++) {
            int n = bn + rowg + i * 16;
            if (n < N) rb4[i] = *(const float4*)&Wo2[(size_t)n * Cv + k0 + k4];
            else       rb4[i] = make_float4(0.f, 0.f, 0.f, 0.f);
        }
    };
    auto sts = [&](int buf) {
        #pragma unroll
        for (int i = 0; i < 2; i++) {
            As[buf][k4 + 0][rowg + i * 16] = ra4[i].x;
            As[buf][k4 + 1][rowg + i * 16] = ra4[i].y;
            As[buf][k4 + 2][rowg + i * 16] = ra4[i].z;
            As[buf][k4 + 3][rowg + i * 16] = ra4[i].w;
        }
        #pragma unroll
        for (int i = 0; i < 4; i++) {
            Bs[buf][k4 + 0][rowg + i * 16] = rb4[i].x;
            Bs[buf][k4 + 1][rowg + i * 16] = rb4[i].y;
            Bs[buf][k4 + 2][rowg + i * 16] = rb4[i].z;
            Bs[buf][k4 + 3][rowg + i * 16] = rb4[i].w;
        }
    };

    const int NT = 3;
    ldg(kbase);
    sts(0);
    __syncthreads();

    #pragma unroll
    for (int kt = 0; kt < NT; kt++) {
        const int cur = kt & 1;
        if (kt + 1 < NT) ldg(kbase + (kt + 1) * 32);
        #pragma unroll
        for (int k = 0; k < 32; k++) {
            unsigned long long a2[2];
            a2[0] = *(const unsigned long long*)&As[cur][k][ty * 4];
            a2[1] = *(const unsigned long long*)&As[cur][k][ty * 4 + 2];
            float4 bv = *(const float4*)&Bs[cur][k][tx * 4];
            unsigned long long b2[4];
            b2[0] = pk2(bv.x, bv.x); b2[1] = pk2(bv.y, bv.y);
            b2[2] = pk2(bv.z, bv.z); b2[3] = pk2(bv.w, bv.w);
            #pragma unroll
            for (int i = 0; i < 2; i++)
                #pragma unroll
                for (int j = 0; j < 4; j++)
                    fma2(acc[i][j], a2[i], b2[j]);
        }
        if (kt + 1 < NT) {
            __syncthreads();
            sts(1 - cur);
            __syncthreads();
        }
    }

    #pragma unroll
    for (int i = 0; i < 2; i++) {
        #pragma unroll
        for (int j = 0; j < 4; j++) {
            float2 f = upk(acc[i][j]);
            int n = bn + tx * 4 + j;
            if (n >= N) continue;
            int m0 = bm + ty * 4 + i * 2;
            if (m0 < M)     atomicAdd(&g_off[(size_t)m0 * N + n], f.x);
            if (m0 + 1 < M) atomicAdd(&g_off[(size_t)(m0 + 1) * N + n], f.y);
        }
    }
}

// ================= proj GEMM (split-K x2): out += Wp @ ao^T, coalesced NCHW atomics =====
// Bias pre-seeded into out by av_kernel.
__global__ __launch_bounds__(128, 8)
void gemm_proj(const float* __restrict__ Wp, float* __restrict__ out)
{
    __shared__ float As[2][32][36];
    __shared__ float Bs[2][32][68];
    const int N = BNROWS;       // 1568
    const int bm = blockIdx.y * 32;      // channel
    const int bn = blockIdx.x * 64;      // token
    const int kbase = blockIdx.z * 192;
    const int tid = threadIdx.x;
    const int ty = tid >> 4;
    const int tx = tid & 15;
    const int k4 = (tid & 7) * 4;
    const int rowg = tid >> 3;

    unsigned long long acc[2][4];
    #pragma unroll
    for (int i = 0; i < 2; i++)
        #pragma unroll
        for (int j = 0; j < 4; j++) acc[i][j] = 0ull;

    float4 ra4[2], rb4[4];
    auto ldg = [&](int k0) {
        #pragma unroll
        for (int i = 0; i < 2; i++) {
            int m = bm + rowg + i * 16;       // < 384 always
            ra4[i] = *(const float4*)&Wp[(size_t)m * Cv + k0 + k4];
        }
        #pragma unroll
        for (int i = 0; i < 4; i++) {
            int n = bn + rowg + i * 16;
            if (n < N) rb4[i] = *(const float4*)&g_ao[(size_t)n * Cv + k0 + k4];
            else       rb4[i] = make_float4(0.f, 0.f, 0.f, 0.f);
        }
    };
    auto sts = [&](int buf) {
        #pragma unroll
        for (int i = 0; i < 2; i++) {
            As[buf][k4 + 0][rowg + i * 16] = ra4[i].x;
            As[buf][k4 + 1][rowg + i * 16] = ra4[i].y;
            As[buf][k4 + 2][rowg + i * 16] = ra4[i].z;
            As[buf][k4 + 3][rowg + i * 16] = ra4[i].w;
        }
        #pragma unroll
        for (int i = 0; i < 4; i++) {
            Bs[buf][k4 + 0][rowg + i * 16] = rb4[i].x;
            Bs[buf][k4 + 1][rowg + i * 16] = rb4[i].y;
            Bs[buf][k4 + 2][rowg + i * 16] = rb4[i].z;
            Bs[buf][k4 + 3][rowg + i * 16] = rb4[i].w;
        }
    };

    const int NT = 6;   // 192 / 32
    ldg(kbase);
    sts(0);
    __syncthreads();

    #pragma unroll
    for (int kt = 0; kt < NT; kt++) {
        const int cur = kt & 1;
        if (kt + 1 < NT) ldg(kbase + (kt + 1) * 32);
        #pragma unroll
        for (int k = 0; k < 32; k++) {
            unsigned long long a2[2];
            a2[0] = *(const unsigned long long*)&As[cur][k][ty * 4];
            a2[1] = *(const unsigned long long*)&As[cur][k][ty * 4 + 2];
            float4 bv = *(const float4*)&Bs[cur][k][tx * 4];
            unsigned long long b2[4];
            b2[0] = pk2(bv.x, bv.x); b2[1] = pk2(bv.y, bv.y);
            b2[2] = pk2(bv.z, bv.z); b2[3] = pk2(bv.w, bv.w);
            #pragma unroll
            for (int i = 0; i < 2; i++)
                #pragma unroll
                for (int j = 0; j < 4; j++)
                    fma2(acc[i][j], a2[i], b2[j]);
        }
        if (kt + 1 < NT) {
            __syncthreads();
            sts(1 - cur);
            __syncthreads();
        }
    }

    #pragma unroll
    for (int i = 0; i < 2; i++) {
        #pragma unroll
        for (int j = 0; j < 4; j++) {
            float2 f = upk(acc[i][j]);
            int n = bn + tx * 4 + j;
            if (n >= N) continue;
            int b = n / Nv, nn = n - b * Nv;
            int m0 = bm + ty * 4 + i * 2;
            atomicAdd(&out[((size_t)(b * Cv + m0))     * Nv + nn], f.x);
            atomicAdd(&out[((size_t)(b * Cv + m0 + 1)) * Nv + nn], f.y);
        }
    }
}

// ================= depthwise 3x3 s2 conv + LN + GELU  (+ zero g_off row) =================
__global__ void dwln_kernel(const float* __restrict__ Wdw, const float* __restrict__ bdw,
                            const float* __restrict__ lng, const float* __restrict__ lnb)
{
    int bs = blockIdx.x;
    int b = bs / Sv, s = bs % Sv;
    int oy = s / rWv, ox = s % rWv;
    int c = threadIdx.x;

    for (int i = c; i < 2 * Nv; i += blockDim.x)
        g_off[(size_t)bs * (2 * Nv) + i] = 0.0f;

    float acc = bdw[c];
    #pragma unroll
    for (int ky = 0; ky < 3; ky++) {
        int y = oy*2 - 1 + ky;
        if (y < 0 || y >= Hv) continue;
        #pragma unroll
        for (int kx = 0; kx < 3; kx++) {
            int x = ox*2 - 1 + kx;
            if (x < 0 || x >= Wv_) continue;
            acc = fmaf(g_t1[((size_t)b*Nv + y*Wv_ + x)*Cv + c], Wdw[c*9 + ky*3 + kx], acc);
        }
    }
    float s1 = acc, s2 = acc*acc;
    #pragma unroll
    for (int o = 16; o > 0; o >>= 1) {
        s1 += __shfl_xor_sync(0xffffffffu, s1, o);
        s2 += __shfl_xor_sync(0xffffffffu, s2, o);
    }
    __shared__ float w1[12], w2[12];
    __shared__ float s_mu, s_rstd;
    if ((c & 31) == 0) { w1[c >> 5] = s1; w2[c >> 5] = s2; }
    __syncthreads();
    if (c == 0) {
        float t1s = 0.f, t2s = 0.f;
        #pragma unroll
        for (int i = 0; i < 12; i++) { t1s += w1[i]; t2s += w2[i]; }
        float mu = t1s / (float)Cv;
        float var = t2s / (float)Cv - mu*mu;
        s_mu = mu; s_rstd = rsqrtf(var + 1e-5f);
    }
    __syncthreads();
    float v = (acc - s_mu) * s_rstd * lng[c] + lnb[c];
    g_t3[(size_t)bs*Cv + c] = gelu_exact(v);
}

// ================= scores + softmax + fold probs into dense A[b,h,n,:] =================
__global__ void score_kernel(const float* __restrict__ posembed)
{
    const int bn = blockIdx.x;
    const int b = bn / Nv, n = bn % Nv;
    const int ny = n / Wv_, nx = n % Wv_;
    __shared__ float sc[HEADS*TS];
    __shared__ int   sp[TS*4];
    __shared__ float swt[TS*4];
    __shared__ __align__(16) float sA[HEADS][Nv];

    for (int idx = threadIdx.x; idx < HEADS*Nv/4; idx += blockDim.x)
        ((float4*)sA)[idx] = make_float4(0.f, 0.f, 0.f, 0.f);

    for (int item = threadIdx.x; item < HEADS*TS; item += blockDim.x) {
        const int h = item / TS, s = item % TS;
        float py, px, tpy, tpx;
        if (s < Sv) {
            int rh = s / rWv, rw = s % rWv;
            float offy = tanhf(g_off[((size_t)b*Sv + s)*(2*Nv) + 0*Nv + n]) * (2.0f/14.0f);
            float offx = tanhf(g_off[((size_t)b*Sv + s)*(2*Nv) + 1*Nv + n]) * (2.0f/14.0f);
            float refy = (float)(rh*2) * (2.0f/13.0f) - 1.0f;
            float refx = (float)(rw*2) * (2.0f/13.0f) - 1.0f;
            py = (offy + refy + 1.0f) * 6.5f;
            px = (offx + refx + 1.0f) * 6.5f;
            tpy = ((float)(2*rh - ny) * (1.0f/13.0f) - offy + 1.0f) * 13.0f;
            tpx = ((float)(2*rw - nx) * (1.0f/13.0f) - offx + 1.0f) * 13.0f;
        } else {
            int j = s - Sv;
            float coy = g_co[((size_t)b*Nv + n)*(2*KKv) + j*2 + 0];
            float cox = g_co[((size_t)b*Nv + n)*(2*KKv) + j*2 + 1];
            float cy = (float)ny + c_offm[j][0];
            float cx = (float)nx + c_offm[j][1];
            float cny = fminf(fmaxf(cy, 0.0f), 14.0f) * (2.0f/13.0f) - 1.0f;
            float cnx = fminf(fmaxf(cx, 0.0f), 14.0f) * (2.0f/13.0f) - 1.0f;
            py = (coy + cny + 1.0f) * 6.5f;
            px = (cox + cnx + 1.0f) * 6.5f;
            tpy = (coy - (float)ny + 1.0f) * 13.0f;
            tpx = (cox - (float)nx + 1.0f) * 13.0f;
        }
        float y0 = floorf(py), x0 = floorf(px);
        float wy1 = py - y0, wx1 = px - x0;
        const float* qkb = g_qk + (((size_t)(b*HEADS + h))*Nv + n)*Nv;
        float val = 0.0f;
        #pragma unroll
        for (int ccy = 0; ccy < 2; ccy++) {
            #pragma unroll
            for (int ccx = 0; ccx < 2; ccx++) {
                float yf = y0 + (float)ccy, xf = x0 + (float)ccx;
                float w = (ccy ? wy1 : 1.0f - wy1) * (ccx ? wx1 : 1.0f - wx1);
                bool valid = (yf >= 0.0f) && (yf <= 13.0f) && (xf >= 0.0f) && (xf <= 13.0f);
                if (!valid) w = 0.0f;
                int yi = (int)fminf(fmaxf(yf, 0.0f), 13.0f);
                int xi = (int)fminf(fmaxf(xf, 0.0f), 13.0f);
                int pix = yi*Wv_ + xi;
                val += w * qkb[pix];
                if (h == 0) { sp[s*4 + ccy*2 + ccx] = pix; swt[s*4 + ccy*2 + ccx] = w; }
            }
        }
        float by0 = floorf(tpy), bx0 = floorf(tpx);
        float bwy = tpy - by0, bwx = tpx - bx0;
        const float* tb = posembed + (size_t)h * (27*27);
        float bval = 0.0f;
        #pragma unroll
        for (int ccy = 0; ccy < 2; ccy++) {
            #pragma unroll
            for (int ccx = 0; ccx < 2; ccx++) {
                float yf = by0 + (float)ccy, xf = bx0 + (float)ccx;
                float w = (ccy ? bwy : 1.0f - bwy) * (ccx ? bwx : 1.0f - bwx);
                bool valid = (yf >= 0.0f) && (yf <= 26.0f) && (xf >= 0.0f) && (xf <= 26.0f);
                if (!valid) w = 0.0f;
                int yi = (int)fminf(fmaxf(yf, 0.0f), 26.0f);
                int xi = (int)fminf(fmaxf(xf, 0.0f), 26.0f);
                bval += w * tb[yi*27 + xi];
            }
        }
        sc[h*TS + s] = val + bval;
    }
    __syncthreads();

    const int wid = threadIdx.x >> 5, lane = threadIdx.x & 31;
    {
        float m = -1e30f;
        for (int s = lane; s < TS; s += 32) m = fmaxf(m, sc[wid*TS + s]);
        #pragma unroll
        for (int o = 16; o > 0; o >>= 1) m = fmaxf(m, __shfl_xor_sync(0xffffffffu, m, o));
        float sum = 0.0f;
        for (int s = lane; s < TS; s += 32) {
            float e = expf(sc[wid*TS + s] - m);
            sc[wid*TS + s] = e;
            sum += e;
        }
        #pragma unroll
        for (int o = 16; o > 0; o >>= 1) sum += __shfl_xor_sync(0xffffffffu, sum, o);
        float inv = 1.0f / sum;
        for (int s = lane; s < TS; s += 32) sc[wid*TS + s] *= inv;
    }
    for (int i = lane; i < TS*4; i += 32) {
        atomicAdd(&sA[wid][sp[i]], sc[wid*TS + (i >> 2)] * swt[i]);
    }
    __syncthreads();

    float4* dst = (float4*)(g_A + ((size_t)(b*HEADS))*Nv*Nv);
    for (int idx = threadIdx.x; idx < HEADS*(Nv/4); idx += blockDim.x) {
        int h = idx / (Nv/4), p4 = idx - h * (Nv/4);
        dst[((size_t)h*Nv + n)*(Nv/4) + p4] = ((float4*)sA)[h*(Nv/4) + p4];
    }
}

// ================= AV GEMM (f32x2) + seed out with bias ========
__global__ __launch_bounds__(128, 4)
void av_kernel(const float* __restrict__ bvv, const float* __restrict__ bp, float* __restrict__ out)
{
    const int n0 = blockIdx.x * 64;
    const int bh = blockIdx.y;
    const int b = bh / HEADS, h = bh - b * HEADS;
    __shared__ __align__(16) float Vs[Nv][HC];
    __shared__ __align__(16) float As[32][68];

    const int tid = threadIdx.x;
    const int tx = tid & 7;
    const int ng = tid >> 3;

    // seed this block's disjoint slab of out with the projection bias
    for (int i = tid; i < 64 * HC; i += 128) {
        int nn = n0 + (i & 63);
        int c  = h * HC + (i >> 6);
        if (nn < Nv) out[((size_t)(b * Cv + c)) * Nv + nn] = bp[c];
    }

    {
        const float* vbase = g_qkv + (size_t)b * Nv * QKVC + 2 * Cv + h * HC;
        for (int i = tid; i < Nv * (HC/4); i += 128) {
            int p = i >> 3, c4 = (i & 7) * 4;
            *(float4*)&Vs[p][c4] = *(const float4*)&vbase[(size_t)p * QKVC + c4];
        }
    }

    unsigned long long acc[2][4];
    #pragma unroll
    for (int i = 0; i < 2; i++)
        #pragma unroll
        for (int j = 0; j < 4; j++) acc[i][j] = 0ull;

    const float* Arow = g_A + ((size_t)bh * Nv) * Nv;
    const int r = tid >> 1, halfq = tid & 1;

    for (int p0 = 0; p0 < Nv; p0 += 32) {
        const int kt = min(32, Nv - p0);
        __syncthreads();
        {
            int nrow = n0 + r;
            #pragma unroll
            for (int q = 0; q < 4; q++) {
                int pl = halfq * 16 + q * 4;
                float4 v = make_float4(0.f, 0.f, 0.f, 0.f);
                if (nrow < Nv && p0 + pl < Nv)
                    v = *(const float4*)&Arow[(size_t)nrow * Nv + p0 + pl];
                As[pl + 0][r] = v.x;
                As[pl + 1][r] = v.y;
                As[pl + 2][r] = v.z;
                As[pl + 3][r] = v.w;
            }
        }
        __syncthreads();
        for (int k = 0; k < kt; k++) {
            float4 af = *(const float4*)&As[k][ng * 4];
            unsigned long long a0 = pk2(af.x, af.y);
            unsigned long long a1 = pk2(af.z, af.w);
            float4 bf = *(const float4*)&Vs[p0 + k][tx * 4];
            unsigned long long b2[4];
            b2[0] = pk2(bf.x, bf.x); b2[1] = pk2(bf.y, bf.y);
            b2[2] = pk2(bf.z, bf.z); b2[3] = pk2(bf.w, bf.w);
            #pragma unroll
            for (int j = 0; j < 4; j++) { fma2(acc[0][j], a0, b2[j]); fma2(acc[1][j], a1, b2[j]); }
        }
    }

    #pragma unroll
    for (int j = 0; j < 4; j++) {
        int c = tx * 4 + j;
        float bb = bvv[h * HC + c];
        #pragma unroll
        for (int i = 0; i < 2; i++) {
            float2 f = upk(acc[i][j]);
            int n = n0 + ng * 4 + i * 2;
            if (n < Nv)     g_ao[((size_t)(b*Nv + n  ))*Cv + h*HC + c] = f.x + bb;
            if (n + 1 < Nv) g_ao[((size_t)(b*Nv + n+1))*Cv + h*HC + c] = f.y + bb;
        }
    }
}

extern "C" void kernel_launch(void* const* d_in, const int* in_sizes, int n_in,
                              void* d_out, int out_size)
{
    const float* x    = (const float*)d_in[0];
    const float* Wq   = (const float*)d_in[1];
    const float* bq   = (const float*)d_in[2];
    const float* Wk   = (const float*)d_in[3];
    // bk cancels in softmax — unused
    const float* Wvv  = (const float*)d_in[5];
    const float* bvv  = (const float*)d_in[6];
    const float* Wo1  = (const float*)d_in[7];
    const float* bo1  = (const float*)d_in[8];
    const float* Wdw  = (const float*)d_in[9];
    const float* bdw  = (const float*)d_in[10];
    const float* lng  = (const float*)d_in[11];
    const float* lnb  = (const float*)d_in[12];
    const float* Wo2  = (const float*)d_in[13];
    const float* Wco  = (const float*)d_in[14];
    const float* pos  = (const float*)d_in[15];
    const float* Wp   = (const float*)d_in[16];
    const float* bp   = (const float*)d_in[17];
    float* out = (float*)d_out;

    float* p_qkv; cudaGetSymbolAddress((void**)&p_qkv, g_qkv);

    // 1) qkv: N=1152, M=1568 -> 18 x 13 blocks
    gemm_big<0><<<dim3(18, 13), 256>>>(x, Wq, Wk, Wvv, bq, BNROWS, QKVC);
    // 2) fused t1co (91) + qk (1536, 64x64 f32x2)
    fused_t1co_qk<<<T1CO_BLOCKS + 16 * Bv * HEADS, 256>>>(Wo1, bo1, Wco, p_qkv);
    // 3) offset net tail (dwln also zero-fills g_off)
    dwln_kernel<<<Bv*Sv, Cv>>>(Wdw, bdw, lng, lnb);
    gemm_off<<<dim3(7, 13, 4), 128>>>(Wo2);
    // 4) scores -> probs -> dense A (applies tanh epilogue on off)
    score_kernel<<<Bv*Nv, 384>>>(pos);
    // 5) AV + seed out with proj bias
    av_kernel<<<dim3(4, Bv*HEADS), 128>>>(bvv, bp, out);
    // 6) final projection: split-K x2, atomics into bias-seeded out
    gemm_proj<<<dim3(25, 12, 2), 128>>>(Wp, out);
}

// round 10
// speedup vs baseline: 1.8261x; 1.1470x over previous
#include <cuda_runtime.h>
#include <cuda_bf16.h>
#include <math.h>
#include <stdint.h>

#define Bv   8
#define Cv   384
#define Hv   14
#define Wv_  14
#define HEADS 12
#define HC   32
#define Nv   196
#define Sv   49
#define rHv  7
#define rWv  7
#define KKv  9
#define TS   58
#define BNROWS (Bv*Nv)   // 1568
#define QKVC 1152

// Scratch
__device__ __align__(16) float g_qkv[BNROWS*QKVC];          // q | xK | xV   (stride 1152)
__device__ __align__(16) float g_t1 [BNROWS*Cv];
__device__ __align__(16) float g_t3 [Bv*Sv*Cv];
__device__ __align__(16) float g_off[Bv*Sv*2*Nv];           // RAW (pre-tanh) accumulations
__device__ __align__(16) float g_co [BNROWS*2*KKv];
__device__ __align__(16) float g_qk [(size_t)Bv*HEADS*Nv*Nv];
__device__ __align__(16) float g_A  [(size_t)Bv*HEADS*Nv*Nv];
__device__ __align__(16) float g_ao [BNROWS*Cv];
// bf16 split operands for tensor-core qkv
__device__ __align__(16) __nv_bfloat16 g_xhi[BNROWS*Cv];
__device__ __align__(16) __nv_bfloat16 g_xlo[BNROWS*Cv];
__device__ __align__(16) __nv_bfloat16 g_whi[QKVC*Cv];
__device__ __align__(16) __nv_bfloat16 g_wlo[QKVC*Cv];

__constant__ float c_offm[9][2] = {
    {0.f,-1.f},{-1.f,-1.f},{-1.f,0.f},{-1.f,1.f},{0.f,1.f},{1.f,1.f},{1.f,0.f},{1.f,-1.f},{0.f,0.f}
};

__device__ __forceinline__ float gelu_exact(float v) {
    return 0.5f * v * (1.0f + erff(v * 0.7071067811865476f));
}

// ---- f32x2 packed math helpers (sm_100+) ----
__device__ __forceinline__ unsigned long long pk2(float lo, float hi) {
    unsigned long long r;
    asm("mov.b64 %0, {%1,%2};" : "=l"(r) : "f"(lo), "f"(hi));
    return r;
}
__device__ __forceinline__ void fma2(unsigned long long &c, unsigned long long a, unsigned long long b) {
    asm("fma.rn.f32x2 %0, %1, %2, %3;" : "=l"(c) : "l"(a), "l"(b), "l"(c));
}
__device__ __forceinline__ float2 upk(unsigned long long v) {
    float2 f;
    asm("mov.b64 {%0,%1}, %2;" : "=f"(f.x), "=f"(f.y) : "l"(v));
    return f;
}

// ---- mma.sync m16n8k16 bf16 (row.col, fp32 accum) ----
__device__ __forceinline__ void mma16816(float* c, const uint32_t* a, const uint32_t* b) {
    asm volatile(
        "mma.sync.aligned.m16n8k16.row.col.f32.bf16.bf16.f32 "
        "{%0,%1,%2,%3}, {%4,%5,%6,%7}, {%8,%9}, {%0,%1,%2,%3};"
        : "+f"(c[0]), "+f"(c[1]), "+f"(c[2]), "+f"(c[3])
        : "r"(a[0]), "r"(a[1]), "r"(a[2]), "r"(a[3]), "r"(b[0]), "r"(b[1]));
}

// ================= prep: x (NCHW) -> token-major bf16 hi/lo; weights -> bf16 hi/lo ========
__global__ void prep_kernel(const float* __restrict__ x,
                            const float* __restrict__ Wq, const float* __restrict__ Wk,
                            const float* __restrict__ Wvv)
{
    const int bid = blockIdx.x;
    const int tid = threadIdx.x;
    if (bid < 672) {
        // x transpose + split: (nt, ct, b)
        int nt = bid % 7, ct = (bid / 7) % 12, b = bid / 84;
        __shared__ float tile[32][33];
        int tx = tid & 31, ty = tid >> 5;   // 32 x 8
        int c0 = ct * 32, n0 = nt * 32;
        for (int i = ty; i < 32; i += 8) {
            int c = c0 + i, n = n0 + tx;
            tile[i][tx] = (n < Nv) ? x[((size_t)b*Cv + c)*Nv + n] : 0.0f;
        }
        __syncthreads();
        for (int i = ty; i < 32; i += 8) {
            int n = n0 + i, c = c0 + tx;
            if (n < Nv) {
                float v = tile[tx][i];
                __nv_bfloat16 h = __float2bfloat16(v);
                float r = v - __bfloat162float(h);
                size_t o = ((size_t)b*Nv + n)*Cv + c;
                g_xhi[o] = h;
                g_xlo[o] = __float2bfloat16(r);
            }
        }
    } else {
        int idx = (bid - 672) * 256 + tid;     // float4 index over 1152x384
        if (idx < QKVC * (Cv/4)) {
            int r = idx / (Cv/4), c4 = idx - r * (Cv/4);
            const float* src = (r < Cv) ? &Wq[(size_t)r*Cv]
                              : (r < 2*Cv ? &Wk[(size_t)(r - Cv)*Cv] : &Wvv[(size_t)(r - 2*Cv)*Cv]);
            float4 v = *(const float4*)&src[c4*4];
            size_t o = (size_t)r*Cv + c4*4;
            float vv[4] = {v.x, v.y, v.z, v.w};
            #pragma unroll
            for (int j = 0; j < 4; j++) {
                __nv_bfloat16 h = __float2bfloat16(vv[j]);
                g_whi[o + j] = h;
                g_wlo[o + j] = __float2bfloat16(vv[j] - __bfloat162float(h));
            }
        }
    }
}

// ================= qkv via HMMA (mma.sync m16n8k16) bf16-split =================
// 64x64 block tile, 8 warps (2m x 4n), warp tile 32x16, KC=32 smem chunks, 12 chunks.
__global__ __launch_bounds__(256, 4)
void qkv_hmma(const float* __restrict__ bq)
{
    __shared__ __align__(16) __nv_bfloat16 sAh[64][40];
    __shared__ __align__(16) __nv_bfloat16 sAl[64][40];
    __shared__ __align__(16) __nv_bfloat16 sBh[64][40];
    __shared__ __align__(16) __nv_bfloat16 sBl[64][40];

    const int tid  = threadIdx.x;
    const int lane = tid & 31;
    const int w    = tid >> 5;
    const int wm   = w >> 2;        // 0..1
    const int wn   = w & 3;         // 0..3
    const int bm = blockIdx.y * 64;
    const int bn = blockIdx.x * 64;

    const int gid = lane >> 2;      // 0..7
    const int tig = lane & 3;       // 0..3
    const int srow = tid >> 2, sc8 = (tid & 3) * 8;

    float acc[2][2][4];
    #pragma unroll
    for (int i = 0; i < 2; i++)
        #pragma unroll
        for (int j = 0; j < 2; j++)
            #pragma unroll
            for (int q = 0; q < 4; q++) acc[i][j][q] = 0.0f;

    for (int kc = 0; kc < 12; kc++) {
        const int k0 = kc * 32;
        // ---- stage 64x32 tiles (hi/lo A + hi/lo B) ----
        {
            int m = bm + srow;
            uint4 vh = make_uint4(0u,0u,0u,0u), vl = vh;
            if (m < BNROWS) {
                size_t o = (size_t)m * Cv + k0 + sc8;
                vh = *(const uint4*)&g_xhi[o];
                vl = *(const uint4*)&g_xlo[o];
            }
            *(uint4*)&sAh[srow][sc8] = vh;
            *(uint4*)&sAl[srow][sc8] = vl;
            size_t ob = (size_t)(bn + srow) * Cv + k0 + sc8;
            *(uint4*)&sBh[srow][sc8] = *(const uint4*)&g_whi[ob];
            *(uint4*)&sBl[srow][sc8] = *(const uint4*)&g_wlo[ob];
        }
        __syncthreads();
        #pragma unroll
        for (int kk = 0; kk < 32; kk += 16) {
            uint32_t ah[2][4], al[2][4], bh[2][2], bl[2][2];
            const int c = kk + tig * 2;
            #pragma unroll
            for (int mt = 0; mt < 2; mt++) {
                int r = wm * 32 + mt * 16 + gid;
                ah[mt][0] = *(const uint32_t*)&sAh[r][c];
                ah[mt][1] = *(const uint32_t*)&sAh[r + 8][c];
                ah[mt][2] = *(const uint32_t*)&sAh[r][c + 8];
                ah[mt][3] = *(const uint32_t*)&sAh[r + 8][c + 8];
                al[mt][0] = *(const uint32_t*)&sAl[r][c];
                al[mt][1] = *(const uint32_t*)&sAl[r + 8][c];
                al[mt][2] = *(const uint32_t*)&sAl[r][c + 8];
                al[mt][3] = *(const uint32_t*)&sAl[r + 8][c + 8];
            }
            #pragma unroll
            for (int nt = 0; nt < 2; nt++) {
                int r = wn * 16 + nt * 8 + gid;
                bh[nt][0] = *(const uint32_t*)&sBh[r][c];
                bh[nt][1] = *(const uint32_t*)&sBh[r][c + 8];
                bl[nt][0] = *(const uint32_t*)&sBl[r][c];
                bl[nt][1] = *(const uint32_t*)&sBl[r][c + 8];
            }
            #pragma unroll
            for (int mt = 0; mt < 2; mt++)
                #pragma unroll
                for (int nt = 0; nt < 2; nt++) {
                    mma16816(acc[mt][nt], ah[mt], bh[nt]);
                    mma16816(acc[mt][nt], ah[mt], bl[nt]);
                    mma16816(acc[mt][nt], al[mt], bh[nt]);
                }
        }
        __syncthreads();
    }

    // ---- epilogue: direct stores (+bq for q region) ----
    #pragma unroll
    for (int mt = 0; mt < 2; mt++) {
        #pragma unroll
        for (int nt = 0; nt < 2; nt++) {
            int n0 = bn + wn * 16 + nt * 8 + tig * 2;
            float b0 = (n0 < Cv) ? bq[n0] : 0.0f;
            float b1 = (n0 + 1 < Cv) ? bq[n0 + 1] : 0.0f;
            int m0 = bm + wm * 32 + mt * 16 + gid;
            if (m0 < BNROWS) {
                g_qkv[(size_t)m0 * QKVC + n0]     = acc[mt][nt][0] + b0;
                g_qkv[(size_t)m0 * QKVC + n0 + 1] = acc[mt][nt][1] + b1;
            }
            if (m0 + 8 < BNROWS) {
                g_qkv[(size_t)(m0 + 8) * QKVC + n0]     = acc[mt][nt][2] + b0;
                g_qkv[(size_t)(m0 + 8) * QKVC + n0 + 1] = acc[mt][nt][3] + b1;
            }
        }
    }
}

// =====================================================================================
// fp32 GEMM core (t1co) — unchanged from round 8
// =====================================================================================
__device__ __forceinline__
void gemm_core1(float As[2][16][132], float Bs[2][16][68], int bxx, int byy,
                const float* __restrict__ Asrc,
                const float* __restrict__ W0, const float* __restrict__ W1,
                const float* __restrict__ bias, int M, int N)
{
    const int tid = threadIdx.x;
    const int bm = byy * 128;
    const int bn = bxx * 64;
    const int ty = tid >> 4;
    const int tx = tid & 15;

    unsigned long long acc[4][4];
    #pragma unroll
    for (int i = 0; i < 4; i++)
        #pragma unroll
        for (int j = 0; j < 4; j++) acc[i][j] = 0ull;

    float4 ra4[2];
    float4 rb4;
    const int k4  = (tid & 3) * 4;
    const int mo4 = tid >> 2;
    const int no4 = tid >> 2;

    auto ldgA = [&](int k0) {
        #pragma unroll
        for (int i = 0; i < 2; i++) {
            int m = bm + mo4 + i * 64;
            if (m < M) ra4[i] = *(const float4*)&Asrc[(size_t)m * QKVC + k0 + k4];
            else       ra4[i] = make_float4(0.f, 0.f, 0.f, 0.f);
        }
    };
    auto ldgB = [&](int k0) {
        int n = bn + no4;
        const float* row = nullptr;
        if (n < Cv) row = W0 + (size_t)n * Cv;
        else if (n - Cv < 2 * KKv) row = W1 + (size_t)(n - Cv) * Cv;
        if (row) rb4 = *(const float4*)&row[k0 + k4];
        else     rb4 = make_float4(0.f, 0.f, 0.f, 0.f);
    };
    auto sts = [&](int buf) {
        #pragma unroll
        for (int i = 0; i < 2; i++) {
            As[buf][k4 + 0][mo4 + i * 64] = ra4[i].x;
            As[buf][k4 + 1][mo4 + i * 64] = ra4[i].y;
            As[buf][k4 + 2][mo4 + i * 64] = ra4[i].z;
            As[buf][k4 + 3][mo4 + i * 64] = ra4[i].w;
        }
        Bs[buf][k4 + 0][no4] = rb4.x;
        Bs[buf][k4 + 1][no4] = rb4.y;
        Bs[buf][k4 + 2][no4] = rb4.z;
        Bs[buf][k4 + 3][no4] = rb4.w;
    };

    const int NT = Cv / 16;
    ldgA(0); ldgB(0);
    sts(0);
    __syncthreads();

    for (int kt = 0; kt < NT; kt++) {
        const int cur = kt & 1;
        if (kt + 1 < NT) { ldgA((kt + 1) * 16); ldgB((kt + 1) * 16); }
        #pragma unroll
        for (int k = 0; k < 16; k++) {
            unsigned long long a2[4];
            #pragma unroll
            for (int j = 0; j < 4; j++)
                a2[j] = *(const unsigned long long*)&As[cur][k][ty * 8 + j * 2];
            float4 bv = *(const float4*)&Bs[cur][k][tx * 4];
            unsigned long long b2[4];
            b2[0] = pk2(bv.x, bv.x); b2[1] = pk2(bv.y, bv.y);
            b2[2] = pk2(bv.z, bv.z); b2[3] = pk2(bv.w, bv.w);
            #pragma unroll
            for (int i = 0; i < 4; i++)
                #pragma unroll
                for (int j = 0; j < 4; j++)
                    fma2(acc[i][j], a2[i], b2[j]);
        }
        if (kt + 1 < NT) {
            __syncthreads();
            sts(1 - cur);
            __syncthreads();
        }
    }

    #pragma unroll
    for (int i = 0; i < 4; i++) {
        #pragma unroll
        for (int j = 0; j < 4; j++) {
            float2 f = upk(acc[i][j]);
            int n = bn + tx * 4 + j;
            #pragma unroll
            for (int half = 0; half < 2; half++) {
                int m = bm + ty * 8 + i * 2 + half;
                float v = half ? f.y : f.x;
                if (m >= M) continue;
                if (n < Cv) {
                    g_t1[(size_t)m * Cv + n] = gelu_exact(v + bias[n]);
                } else if (n - Cv < 2 * KKv) {
                    g_co[(size_t)m * (2 * KKv) + (n - Cv)] = tanhf(v) * (1.0f / 14.0f);
                }
            }
        }
    }
}

// ================= fused: t1co GEMM (91 blocks) + qk maps (1536 blocks, 64x64 f32x2) ======
#define T1CO_BLOCKS 91
__global__ __launch_bounds__(256, 2)
void fused_t1co_qk(const float* __restrict__ Wo1, const float* __restrict__ bo1,
                   const float* __restrict__ Wco, const float* __restrict__ q_src)
{
    const int idx = blockIdx.x;
    if (idx < T1CO_BLOCKS) {
        __shared__ float As[2][16][132];
        __shared__ float Bs[2][16][68];
        gemm_core1(As, Bs, idx % 7, idx / 7, q_src, Wo1, Wco, bo1, BNROWS, Cv + 2 * KKv);
    } else {
        const int idx2 = idx - T1CO_BLOCKS;
        const int bxq = idx2 & 3;
        const int byq = (idx2 >> 2) & 3;
        const int bh  = idx2 >> 4;
        const int b = bh / HEADS, h = bh - b * HEADS;
        const int n0 = byq * 64, p0 = bxq * 64;
        __shared__ float qs[32][68], ks[32][68];
        const int tid = threadIdx.x;
        const int rowg = tid >> 2;
        const int k8 = (tid & 3) * 8;

        {
            int n = n0 + rowg;
            float4 v0 = make_float4(0.f,0.f,0.f,0.f), v1 = v0;
            if (n < Nv) {
                const float* qrow = &g_qkv[((size_t)(b*Nv + n))*QKVC + h*HC + k8];
                v0 = *(const float4*)&qrow[0];
                v1 = *(const float4*)&qrow[4];
            }
            qs[k8+0][rowg] = v0.x; qs[k8+1][rowg] = v0.y;
            qs[k8+2][rowg] = v0.z; qs[k8+3][rowg] = v0.w;
            qs[k8+4][rowg] = v1.x; qs[k8+5][rowg] = v1.y;
            qs[k8+6][rowg] = v1.z; qs[k8+7][rowg] = v1.w;

            int p = p0 + rowg;
            float4 w0 = make_float4(0.f,0.f,0.f,0.f), w1 = w0;
            if (p < Nv) {
                const float* krow = &g_qkv[((size_t)(b*Nv + p))*QKVC + Cv + h*HC + k8];
                w0 = *(const float4*)&krow[0];
                w1 = *(const float4*)&krow[4];
            }
            ks[k8+0][rowg] = w0.x; ks[k8+1][rowg] = w0.y;
            ks[k8+2][rowg] = w0.z; ks[k8+3][rowg] = w0.w;
            ks[k8+4][rowg] = w1.x; ks[k8+5][rowg] = w1.y;
            ks[k8+6][rowg] = w1.z; ks[k8+7][rowg] = w1.w;
        }
        __syncthreads();

        const int ty = tid >> 4, tx = tid & 15;
        unsigned long long acc[2][4];
        #pragma unroll
        for (int i = 0; i < 2; i++)
            #pragma unroll
            for (int j = 0; j < 4; j++) acc[i][j] = 0ull;

        #pragma unroll
        for (int k = 0; k < 32; k++) {
            unsigned long long a2[2];
            a2[0] = *(const unsigned long long*)&qs[k][ty * 4];
            a2[1] = *(const unsigned long long*)&qs[k][ty * 4 + 2];
            float4 bv = *(const float4*)&ks[k][tx * 4];
            unsigned long long b2[4];
            b2[0] = pk2(bv.x, bv.x); b2[1] = pk2(bv.y, bv.y);
            b2[2] = pk2(bv.z, bv.z); b2[3] = pk2(bv.w, bv.w);
            #pragma unroll
            for (int i = 0; i < 2; i++)
                #pragma unroll
                for (int j = 0; j < 4; j++)
                    fma2(acc[i][j], a2[i], b2[j]);
        }

        float* qkb = g_qk + ((size_t)bh * Nv) * Nv;
        #pragma unroll
        for (int i = 0; i < 2; i++) {
            #pragma unroll
            for (int j = 0; j < 4; j++) {
                float2 f = upk(acc[i][j]);
                int p = p0 + tx * 4 + j;
                if (p >= Nv) continue;
                int n = n0 + ty * 4 + i * 2;
                if (n < Nv)     qkb[(size_t)n * Nv + p]       = f.x;
                if (n + 1 < Nv) qkb[(size_t)(n + 1) * Nv + p] = f.y;
            }
        }
    }
}

// ================= offset GEMM (split-K x4): g_off += t3 @ Wo2^T (raw) =================
__global__ __launch_bounds__(128, 8)
void gemm_off(const float* __restrict__ Wo2)
{
    __shared__ float As[2][32][36];
    __shared__ float Bs[2][32][68];
    const int M = Bv * Sv;
    const int N = 2 * Nv;
    const int bm = blockIdx.y * 32;
    const int bn = blockIdx.x * 64;
    const int kbase = blockIdx.z * 96;
    const int tid = threadIdx.x;
    const int ty = tid >> 4;
    const int tx = tid & 15;
    const int k4 = (tid & 7) * 4;
    const int rowg = tid >> 3;

    unsigned long long acc[2][4];
    #pragma unroll
    for (int i = 0; i < 2; i++)
        #pragma unroll
        for (int j = 0; j < 4; j++) acc[i][j] = 0ull;

    float4 ra4[2], rb4[4];
    auto ldg = [&](int k0) {
        #pragma unroll
        for (int i = 0; i < 2; i++) {
            int m = bm + rowg + i * 16;
            if (m < M) ra4[i] = *(const float4*)&g_t3[(size_t)m * Cv + k0 + k4];
            else       ra4[i] = make_float4(0.f, 0.f, 0.f, 0.f);
        }
        #pragma unroll
        for (int i = 0; i < 4; i++) {
            int n = bn + rowg + i * 16;
            if (n < N) rb4[i] = *(const float4*)&Wo2[(size_t)n * Cv + k0 + k4];
            else       rb4[i] = make_float4(0.f, 0.f, 0.f, 0.f);
        }
    };
    auto sts = [&](int buf) {
        #pragma unroll
        for (int i = 0; i < 2; i++) {
            As[buf][k4 + 0][rowg + i * 16] = ra4[i].x;
            As[buf][k4 + 1][rowg + i * 16] = ra4[i].y;
            As[buf][k4 + 2][rowg + i * 16] = ra4[i].z;
            As[buf][k4 + 3][rowg + i * 16] = ra4[i].w;
        }
        #pragma unroll
        for (int i = 0; i < 4; i++) {
            Bs[buf][k4 + 0][rowg + i * 16] = rb4[i].x;
            Bs[buf][k4 + 1][rowg + i * 16] = rb4[i].y;
            Bs[buf][k4 + 2][rowg + i * 16] = rb4[i].z;
            Bs[buf][k4 + 3][rowg + i * 16] = rb4[i].w;
        }
    };

    const int NT = 3;
    ldg(kbase);
    sts(0);
    __syncthreads();

    #pragma unroll
    for (int kt = 0; kt < NT; kt++) {
        const int cur = kt & 1;
        if (kt + 1 < NT) ldg(kbase + (kt + 1) * 32);
        #pragma unroll
        for (int k = 0; k < 32; k++) {
            unsigned long long a2[2];
            a2[0] = *(const unsigned long long*)&As[cur][k][ty * 4];
            a2[1] = *(const unsigned long long*)&As[cur][k][ty * 4 + 2];
            float4 bv = *(const float4*)&Bs[cur][k][tx * 4];
            unsigned long long b2[4];
            b2[0] = pk2(bv.x, bv.x); b2[1] = pk2(bv.y, bv.y);
            b2[2] = pk2(bv.z, bv.z); b2[3] = pk2(bv.w, bv.w);
            #pragma unroll
            for (int i = 0; i < 2; i++)
                #pragma unroll
                for (int j = 0; j < 4; j++)
                    fma2(acc[i][j], a2[i], b2[j]);
        }
        if (kt + 1 < NT) {
            __syncthreads();
            sts(1 - cur);
            __syncthreads();
        }
    }

    #pragma unroll
    for (int i = 0; i < 2; i++) {
        #pragma unroll
        for (int j = 0; j < 4; j++) {
            float2 f = upk(acc[i][j]);
            int n = bn + tx * 4 + j;
            if (n >= N) continue;
            int m0 = bm + ty * 4 + i * 2;
            if (m0 < M)     atomicAdd(&g_off[(size_t)m0 * N + n], f.x);
            if (m0 + 1 < M) atomicAdd(&g_off[(size_t)(m0 + 1) * N + n], f.y);
        }
    }
}

// ================= proj GEMM (split-K x2): out += Wp @ ao^T =================
__global__ __launch_bounds__(128, 8)
void gemm_proj(const float* __restrict__ Wp, float* __restrict__ out)
{
    __shared__ float As[2][32][36];
    __shared__ float Bs[2][32][68];
    const int N = BNROWS;
    const int bm = blockIdx.y * 32;
    const int bn = blockIdx.x * 64;
    const int kbase = blockIdx.z * 192;
    const int tid = threadIdx.x;
    const int ty = tid >> 4;
    const int tx = tid & 15;
    const int k4 = (tid & 7) * 4;
    const int rowg = tid >> 3;

    unsigned long long acc[2][4];
    #pragma unroll
    for (int i = 0; i < 2; i++)
        #pragma unroll
        for (int j = 0; j < 4; j++) acc[i][j] = 0ull;

    float4 ra4[2], rb4[4];
    auto ldg = [&](int k0) {
        #pragma unroll
        for (int i = 0; i < 2; i++) {
            int m = bm + rowg + i * 16;
            ra4[i] = *(const float4*)&Wp[(size_t)m * Cv + k0 + k4];
        }
        #pragma unroll
        for (int i = 0; i < 4; i++) {
            int n = bn + rowg + i * 16;
            if (n < N) rb4[i] = *(const float4*)&g_ao[(size_t)n * Cv + k0 + k4];
            else       rb4[i] = make_float4(0.f, 0.f, 0.f, 0.f);
        }
    };
    auto sts = [&](int buf) {
        #pragma unroll
        for (int i = 0; i < 2; i++) {
            As[buf][k4 + 0][rowg + i * 16] = ra4[i].x;
            As[buf][k4 + 1][rowg + i * 16] = ra4[i].y;
            As[buf][k4 + 2][rowg + i * 16] = ra4[i].z;
            As[buf][k4 + 3][rowg + i * 16] = ra4[i].w;
        }
        #pragma unroll
        for (int i = 0; i < 4; i++) {
            Bs[buf][k4 + 0][rowg + i * 16] = rb4[i].x;
            Bs[buf][k4 + 1][rowg + i * 16] = rb4[i].y;
            Bs[buf][k4 + 2][rowg + i * 16] = rb4[i].z;
            Bs[buf][k4 + 3][rowg + i * 16] = rb4[i].w;
        }
    };

    const int NT = 6;
    ldg(kbase);
    sts(0);
    __syncthreads();

    #pragma unroll
    for (int kt = 0; kt < NT; kt++) {
        const int cur = kt & 1;
        if (kt + 1 < NT) ldg(kbase + (kt + 1) * 32);
        #pragma unroll
        for (int k = 0; k < 32; k++) {
            unsigned long long a2[2];
            a2[0] = *(const unsigned long long*)&As[cur][k][ty * 4];
            a2[1] = *(const unsigned long long*)&As[cur][k][ty * 4 + 2];
            float4 bv = *(const float4*)&Bs[cur][k][tx * 4];
            unsigned long long b2[4];
            b2[0] = pk2(bv.x, bv.x); b2[1] = pk2(bv.y, bv.y);
            b2[2] = pk2(bv.z, bv.z); b2[3] = pk2(bv.w, bv.w);
            #pragma unroll
            for (int i = 0; i < 2; i++)
                #pragma unroll
                for (int j = 0; j < 4; j++)
                    fma2(acc[i][j], a2[i], b2[j]);
        }
        if (kt + 1 < NT) {
            __syncthreads();
            sts(1 - cur);
            __syncthreads();
        }
    }

    #pragma unroll
    for (int i = 0; i < 2; i++) {
        #pragma unroll
        for (int j = 0; j < 4; j++) {
            float2 f = upk(acc[i][j]);
            int n = bn + tx * 4 + j;
            if (n >= N) continue;
            int b = n / Nv, nn = n - b * Nv;
            int m0 = bm + ty * 4 + i * 2;
            atomicAdd(&out[((size_t)(b * Cv + m0))     * Nv + nn], f.x);
            atomicAdd(&out[((size_t)(b * Cv + m0 + 1)) * Nv + nn], f.y);
        }
    }
}

// ================= depthwise 3x3 s2 conv + LN + GELU  (+ zero g_off row) =================
__global__ void dwln_kernel(const float* __restrict__ Wdw, const float* __restrict__ bdw,
                            const float* __restrict__ lng, const float* __restrict__ lnb)
{
    int bs = blockIdx.x;
    int b = bs / Sv, s = bs % Sv;
    int oy = s / rWv, ox = s % rWv;
    int c = threadIdx.x;

    for (int i = c; i < 2 * Nv; i += blockDim.x)
        g_off[(size_t)bs * (2 * Nv) + i] = 0.0f;

    float acc = bdw[c];
    #pragma unroll
    for (int ky = 0; ky < 3; ky++) {
        int y = oy*2 - 1 + ky;
        if (y < 0 || y >= Hv) continue;
        #pragma unroll
        for (int kx = 0; kx < 3; kx++) {
            int x = ox*2 - 1 + kx;
            if (x < 0 || x >= Wv_) continue;
            acc = fmaf(g_t1[((size_t)b*Nv + y*Wv_ + x)*Cv + c], Wdw[c*9 + ky*3 + kx], acc);
        }
    }
    float s1 = acc, s2 = acc*acc;
    #pragma unroll
    for (int o = 16; o > 0; o >>= 1) {
        s1 += __shfl_xor_sync(0xffffffffu, s1, o);
        s2 += __shfl_xor_sync(0xffffffffu, s2, o);
    }
    __shared__ float w1[12], w2[12];
    __shared__ float s_mu, s_rstd;
    if ((c & 31) == 0) { w1[c >> 5] = s1; w2[c >> 5] = s2; }
    __syncthreads();
    if (c == 0) {
        float t1s = 0.f, t2s = 0.f;
        #pragma unroll
        for (int i = 0; i < 12; i++) { t1s += w1[i]; t2s += w2[i]; }
        float mu = t1s / (float)Cv;
        float var = t2s / (float)Cv - mu*mu;
        s_mu = mu; s_rstd = rsqrtf(var + 1e-5f);
    }
    __syncthreads();
    float v = (acc - s_mu) * s_rstd * lng[c] + lnb[c];
    g_t3[(size_t)bs*Cv + c] = gelu_exact(v);
}

// ================= scores + softmax + fold probs into dense A[b,h,n,:] =================
__global__ void score_kernel(const float* __restrict__ posembed)
{
    const int bn = blockIdx.x;
    const int b = bn / Nv, n = bn % Nv;
    const int ny = n / Wv_, nx = n % Wv_;
    __shared__ float sc[HEADS*TS];
    __shared__ int   sp[TS*4];
    __shared__ float swt[TS*4];
    __shared__ __align__(16) float sA[HEADS][Nv];

    for (int idx = threadIdx.x; idx < HEADS*Nv/4; idx += blockDim.x)
        ((float4*)sA)[idx] = make_float4(0.f, 0.f, 0.f, 0.f);

    for (int item = threadIdx.x; item < HEADS*TS; item += blockDim.x) {
        const int h = item / TS, s = item % TS;
        float py, px, tpy, tpx;
        if (s < Sv) {
            int rh = s / rWv, rw = s % rWv;
            float offy = tanhf(g_off[((size_t)b*Sv + s)*(2*Nv) + 0*Nv + n]) * (2.0f/14.0f);
            float offx = tanhf(g_off[((size_t)b*Sv + s)*(2*Nv) + 1*Nv + n]) * (2.0f/14.0f);
            float refy = (float)(rh*2) * (2.0f/13.0f) - 1.0f;
            float refx = (float)(rw*2) * (2.0f/13.0f) - 1.0f;
            py = (offy + refy + 1.0f) * 6.5f;
            px = (offx + refx + 1.0f) * 6.5f;
            tpy = ((float)(2*rh - ny) * (1.0f/13.0f) - offy + 1.0f) * 13.0f;
            tpx = ((float)(2*rw - nx) * (1.0f/13.0f) - offx + 1.0f) * 13.0f;
        } else {
            int j = s - Sv;
            float coy = g_co[((size_t)b*Nv + n)*(2*KKv) + j*2 + 0];
            float cox = g_co[((size_t)b*Nv + n)*(2*KKv) + j*2 + 1];
            float cy = (float)ny + c_offm[j][0];
            float cx = (float)nx + c_offm[j][1];
            float cny = fminf(fmaxf(cy, 0.0f), 14.0f) * (2.0f/13.0f) - 1.0f;
            float cnx = fminf(fmaxf(cx, 0.0f), 14.0f) * (2.0f/13.0f) - 1.0f;
            py = (coy + cny + 1.0f) * 6.5f;
            px = (cox + cnx + 1.0f) * 6.5f;
            tpy = (coy - (float)ny + 1.0f) * 13.0f;
            tpx = (cox - (float)nx + 1.0f) * 13.0f;
        }
        float y0 = floorf(py), x0 = floorf(px);
        float wy1 = py - y0, wx1 = px - x0;
        const float* qkb = g_qk + (((size_t)(b*HEADS + h))*Nv + n)*Nv;
        float val = 0.0f;
        #pragma unroll
        for (int ccy = 0; ccy < 2; ccy++) {
            #pragma unroll
            for (int ccx = 0; ccx < 2; ccx++) {
                float yf = y0 + (float)ccy, xf = x0 + (float)ccx;
                float w = (ccy ? wy1 : 1.0f - wy1) * (ccx ? wx1 : 1.0f - wx1);
                bool valid = (yf >= 0.0f) && (yf <= 13.0f) && (xf >= 0.0f) && (xf <= 13.0f);
                if (!valid) w = 0.0f;
                int yi = (int)fminf(fmaxf(yf, 0.0f), 13.0f);
                int xi = (int)fminf(fmaxf(xf, 0.0f), 13.0f);
                int pix = yi*Wv_ + xi;
                val += w * qkb[pix];
                if (h == 0) { sp[s*4 + ccy*2 + ccx] = pix; swt[s*4 + ccy*2 + ccx] = w; }
            }
        }
        float by0 = floorf(tpy), bx0 = floorf(tpx);
        float bwy = tpy - by0, bwx = tpx - bx0;
        const float* tb = posembed + (size_t)h * (27*27);
        float bval = 0.0f;
        #pragma unroll
        for (int ccy = 0; ccy < 2; ccy++) {
            #pragma unroll
            for (int ccx = 0; ccx < 2; ccx++) {
                float yf = by0 + (float)ccy, xf = bx0 + (float)ccx;
                float w = (ccy ? bwy : 1.0f - bwy) * (ccx ? bwx : 1.0f - bwx);
                bool valid = (yf >= 0.0f) && (yf <= 26.0f) && (xf >= 0.0f) && (xf <= 26.0f);
                if (!valid) w = 0.0f;
                int yi = (int)fminf(fmaxf(yf, 0.0f), 26.0f);
                int xi = (int)fminf(fmaxf(xf, 0.0f), 26.0f);
                bval += w * tb[yi*27 + xi];
            }
        }
        sc[h*TS + s] = val + bval;
    }
    __syncthreads();

    const int wid = threadIdx.x >> 5, lane = threadIdx.x & 31;
    {
        float m = -1e30f;
        for (int s = lane; s < TS; s += 32) m = fmaxf(m, sc[wid*TS + s]);
        #pragma unroll
        for (int o = 16; o > 0; o >>= 1) m = fmaxf(m, __shfl_xor_sync(0xffffffffu, m, o));
        float sum = 0.0f;
        for (int s = lane; s < TS; s += 32) {
            float e = expf(sc[wid*TS + s] - m);
            sc[wid*TS + s] = e;
            sum += e;
        }
        #pragma unroll
        for (int o = 16; o > 0; o >>= 1) sum += __shfl_xor_sync(0xffffffffu, sum, o);
        float inv = 1.0f / sum;
        for (int s = lane; s < TS; s += 32) sc[wid*TS + s] *= inv;
    }
    for (int i = lane; i < TS*4; i += 32) {
        atomicAdd(&sA[wid][sp[i]], sc[wid*TS + (i >> 2)] * swt[i]);
    }
    __syncthreads();

    float4* dst = (float4*)(g_A + ((size_t)(b*HEADS))*Nv*Nv);
    for (int idx = threadIdx.x; idx < HEADS*(Nv/4); idx += blockDim.x) {
        int h = idx / (Nv/4), p4 = idx - h * (Nv/4);
        dst[((size_t)h*Nv + n)*(Nv/4) + p4] = ((float4*)sA)[h*(Nv/4) + p4];
    }
}

// ================= AV GEMM (f32x2) + seed out with bias ========
__global__ __launch_bounds__(128, 4)
void av_kernel(const float* __restrict__ bvv, const float* __restrict__ bp, float* __restrict__ out)
{
    const int n0 = blockIdx.x * 64;
    const int bh = blockIdx.y;
    const int b = bh / HEADS, h = bh - b * HEADS;
    __shared__ __align__(16) float Vs[Nv][HC];
    __shared__ __align__(16) float As[32][68];

    const int tid = threadIdx.x;
    const int tx = tid & 7;
    const int ng = tid >> 3;

    for (int i = tid; i < 64 * HC; i += 128) {
        int nn = n0 + (i & 63);
        int c  = h * HC + (i >> 6);
        if (nn < Nv) out[((size_t)(b * Cv + c)) * Nv + nn] = bp[c];
    }

    {
        const float* vbase = g_qkv + (size_t)b * Nv * QKVC + 2 * Cv + h * HC;
        for (int i = tid; i < Nv * (HC/4); i += 128) {
            int p = i >> 3, c4 = (i & 7) * 4;
            *(float4*)&Vs[p][c4] = *(const float4*)&vbase[(size_t)p * QKVC + c4];
        }
    }

    unsigned long long acc[2][4];
    #pragma unroll
    for (int i = 0; i < 2; i++)
        #pragma unroll
        for (int j = 0; j < 4; j++) acc[i][j] = 0ull;

    const float* Arow = g_A + ((size_t)bh * Nv) * Nv;
    const int r = tid >> 1, halfq = tid & 1;

    for (int p0 = 0; p0 < Nv; p0 += 32) {
        const int kt = min(32, Nv - p0);
        __syncthreads();
        {
            int nrow = n0 + r;
            #pragma unroll
            for (int q = 0; q < 4; q++) {
                int pl = halfq * 16 + q * 4;
                float4 v = make_float4(0.f, 0.f, 0.f, 0.f);
                if (nrow < Nv && p0 + pl < Nv)
                    v = *(const float4*)&Arow[(size_t)nrow * Nv + p0 + pl];
                As[pl + 0][r] = v.x;
                As[pl + 1][r] = v.y;
                As[pl + 2][r] = v.z;
                As[pl + 3][r] = v.w;
            }
        }
        __syncthreads();
        for (int k = 0; k < kt; k++) {
            float4 af = *(const float4*)&As[k][ng * 4];
            unsigned long long a0 = pk2(af.x, af.y);
            unsigned long long a1 = pk2(af.z, af.w);
            float4 bf = *(const float4*)&Vs[p0 + k][tx * 4];
            unsigned long long b2[4];
            b2[0] = pk2(bf.x, bf.x); b2[1] = pk2(bf.y, bf.y);
            b2[2] = pk2(bf.z, bf.z); b2[3] = pk2(bf.w, bf.w);
            #pragma unroll
            for (int j = 0; j < 4; j++) { fma2(acc[0][j], a0, b2[j]); fma2(acc[1][j], a1, b2[j]); }
        }
    }

    #pragma unroll
    for (int j = 0; j < 4; j++) {
        int c = tx * 4 + j;
        float bb = bvv[h * HC + c];
        #pragma unroll
        for (int i = 0; i < 2; i++) {
            float2 f = upk(acc[i][j]);
            int n = n0 + ng * 4 + i * 2;
            if (n < Nv)     g_ao[((size_t)(b*Nv + n  ))*Cv + h*HC + c] = f.x + bb;
            if (n + 1 < Nv) g_ao[((size_t)(b*Nv + n+1))*Cv + h*HC + c] = f.y + bb;
        }
    }
}

extern "C" void kernel_launch(void* const* d_in, const int* in_sizes, int n_in,
                              void* d_out, int out_size)
{
    const float* x    = (const float*)d_in[0];
    const float* Wq   = (const float*)d_in[1];
    const float* bq   = (const float*)d_in[2];
    const float* Wk   = (const float*)d_in[3];
    // bk cancels in softmax — unused
    const float* Wvv  = (const float*)d_in[5];
    const float* bvv  = (const float*)d_in[6];
    const float* Wo1  = (const float*)d_in[7];
    const float* bo1  = (const float*)d_in[8];
    const float* Wdw  = (const float*)d_in[9];
    const float* bdw  = (const float*)d_in[10];
    const float* lng  = (const float*)d_in[11];
    const float* lnb  = (const float*)d_in[12];
    const float* Wo2  = (const float*)d_in[13];
    const float* Wco  = (const float*)d_in[14];
    const float* pos  = (const float*)d_in[15];
    const float* Wp   = (const float*)d_in[16];
    const float* bp   = (const float*)d_in[17];
    float* out = (float*)d_out;

    float* p_qkv; cudaGetSymbolAddress((void**)&p_qkv, g_qkv);

    // 0) split-precision conversion (x transpose + weights)
    prep_kernel<<<672 + 432, 256>>>(x, Wq, Wk, Wvv);
    // 1) qkv via HMMA (mma.sync m16n8k16 bf16-split): 18 x 25 tiles of 64x64
    qkv_hmma<<<dim3(18, 25), 256>>>(bq);
    // 2) fused t1co (91) + qk (1536)
    fused_t1co_qk<<<T1CO_BLOCKS + 16 * Bv * HEADS, 256>>>(Wo1, bo1, Wco, p_qkv);
    // 3) offset net tail (dwln also zero-fills g_off)
    dwln_kernel<<<Bv*Sv, Cv>>>(Wdw, bdw, lng, lnb);
    gemm_off<<<dim3(7, 13, 4), 128>>>(Wo2);
    // 4) scores -> probs -> dense A
    score_kernel<<<Bv*Nv, 384>>>(pos);
    // 5) AV + seed out with proj bias
    av_kernel<<<dim3(4, Bv*HEADS), 128>>>(bvv, bp, out);
    // 6) final projection: split-K x2, atomics into bias-seeded out
    gemm_proj<<<dim3(25, 12, 2), 128>>>(Wp, out);
}

// round 11
// speedup vs baseline: 2.0625x; 1.1294x over previous
#include <cuda_runtime.h>
#include <cuda_bf16.h>
#include <math.h>
#include <stdint.h>

#define Bv   8
#define Cv   384
#define Hv   14
#define Wv_  14
#define HEADS 12
#define HC   32
#define Nv   196
#define Sv   49
#define rHv  7
#define rWv  7
#define KKv  9
#define TS   58
#define BNROWS (Bv*Nv)   // 1568
#define QKVC 1152
#define N2   448         // padded t1co output cols (384 Wo1 + 18 Wco + pad)

// Scratch
__device__ __align__(16) float g_qkv[BNROWS*QKVC];          // q | xK | xV (fp32, for av)
__device__ __align__(16) float g_t1 [BNROWS*Cv];
__device__ __align__(16) float g_t3 [Bv*Sv*Cv];
__device__ __align__(16) float g_off[Bv*Sv*2*Nv];           // RAW (pre-tanh) accumulations
__device__ __align__(16) float g_co [BNROWS*2*KKv];
__device__ __align__(16) float g_qk [(size_t)Bv*HEADS*Nv*Nv];
__device__ __align__(16) float g_A  [(size_t)Bv*HEADS*Nv*Nv];
// bf16 split operands
__device__ __align__(16) __nv_bfloat16 g_xhi[BNROWS*Cv];
__device__ __align__(16) __nv_bfloat16 g_xlo[BNROWS*Cv];
__device__ __align__(16) __nv_bfloat16 g_whi[QKVC*Cv];
__device__ __align__(16) __nv_bfloat16 g_wlo[QKVC*Cv];
__device__ __align__(16) __nv_bfloat16 g_qkvhi[BNROWS*QKVC];
__device__ __align__(16) __nv_bfloat16 g_qkvlo[BNROWS*QKVC];
__device__ __align__(16) __nv_bfloat16 g_w2hi[N2*Cv];
__device__ __align__(16) __nv_bfloat16 g_w2lo[N2*Cv];
__device__ __align__(16) __nv_bfloat16 g_wphi[Cv*Cv];
__device__ __align__(16) __nv_bfloat16 g_wplo[Cv*Cv];
__device__ __align__(16) __nv_bfloat16 g_aohi[BNROWS*Cv];
__device__ __align__(16) __nv_bfloat16 g_aolo[BNROWS*Cv];

__constant__ float c_offm[9][2] = {
    {0.f,-1.f},{-1.f,-1.f},{-1.f,0.f},{-1.f,1.f},{0.f,1.f},{1.f,1.f},{1.f,0.f},{1.f,-1.f},{0.f,0.f}
};

__device__ __forceinline__ float gelu_exact(float v) {
    return 0.5f * v * (1.0f + erff(v * 0.7071067811865476f));
}

// ---- f32x2 packed math helpers ----
__device__ __forceinline__ unsigned long long pk2(float lo, float hi) {
    unsigned long long r;
    asm("mov.b64 %0, {%1,%2};" : "=l"(r) : "f"(lo), "f"(hi));
    return r;
}
__device__ __forceinline__ void fma2(unsigned long long &c, unsigned long long a, unsigned long long b) {
    asm("fma.rn.f32x2 %0, %1, %2, %3;" : "=l"(c) : "l"(a), "l"(b), "l"(c));
}
__device__ __forceinline__ float2 upk(unsigned long long v) {
    float2 f;
    asm("mov.b64 {%0,%1}, %2;" : "=f"(f.x), "=f"(f.y) : "l"(v));
    return f;
}

// ---- mma.sync m16n8k16 bf16 (row.col, fp32 accum) ----
__device__ __forceinline__ void mma16816(float* c, const uint32_t* a, const uint32_t* b) {
    asm volatile(
        "mma.sync.aligned.m16n8k16.row.col.f32.bf16.bf16.f32 "
        "{%0,%1,%2,%3}, {%4,%5,%6,%7}, {%8,%9}, {%0,%1,%2,%3};"
        : "+f"(c[0]), "+f"(c[1]), "+f"(c[2]), "+f"(c[3])
        : "r"(a[0]), "r"(a[1]), "r"(a[2]), "r"(a[3]), "r"(b[0]), "r"(b[1]));
}

__device__ __forceinline__ void split_bf16(float v, __nv_bfloat16& h, __nv_bfloat16& l) {
    h = __float2bfloat16(v);
    l = __float2bfloat16(v - __bfloat162float(h));
}

// ================= prep: x transpose + all weight splits ========
// sections: [0,672) x; [672,1104) Wqkv; [1104,1272) Wo1|Wco; [1272,1416) Wp
__global__ void prep_kernel(const float* __restrict__ x,
                            const float* __restrict__ Wq, const float* __restrict__ Wk,
                            const float* __restrict__ Wvv, const float* __restrict__ Wo1,
                            const float* __restrict__ Wco, const float* __restrict__ Wp)
{
    const int bid = blockIdx.x;
    const int tid = threadIdx.x;
    if (bid < 672) {
        int nt = bid % 7, ct = (bid / 7) % 12, b = bid / 84;
        __shared__ float tile[32][33];
        int tx = tid & 31, ty = tid >> 5;
        int c0 = ct * 32, n0 = nt * 32;
        for (int i = ty; i < 32; i += 8) {
            int c = c0 + i, n = n0 + tx;
            tile[i][tx] = (n < Nv) ? x[((size_t)b*Cv + c)*Nv + n] : 0.0f;
        }
        __syncthreads();
        for (int i = ty; i < 32; i += 8) {
            int n = n0 + i, c = c0 + tx;
            if (n < Nv) {
                size_t o = ((size_t)b*Nv + n)*Cv + c;
                split_bf16(tile[tx][i], g_xhi[o], g_xlo[o]);
            }
        }
    } else if (bid < 1104) {
        int idx = (bid - 672) * 256 + tid;
        if (idx < QKVC * (Cv/4)) {
            int r = idx / (Cv/4), c4 = idx - r * (Cv/4);
            const float* src = (r < Cv) ? &Wq[(size_t)r*Cv]
                              : (r < 2*Cv ? &Wk[(size_t)(r - Cv)*Cv] : &Wvv[(size_t)(r - 2*Cv)*Cv]);
            float4 v = *(const float4*)&src[c4*4];
            size_t o = (size_t)r*Cv + c4*4;
            float vv[4] = {v.x, v.y, v.z, v.w};
            #pragma unroll
            for (int j = 0; j < 4; j++) split_bf16(vv[j], g_whi[o + j], g_wlo[o + j]);
        }
    } else if (bid < 1272) {
        int idx = (bid - 1104) * 256 + tid;
        if (idx < N2 * (Cv/4)) {
            int r = idx / (Cv/4), c4 = idx - r * (Cv/4);
            float4 v = make_float4(0.f, 0.f, 0.f, 0.f);
            if (r < Cv) v = *(const float4*)&Wo1[(size_t)r*Cv + c4*4];
            else if (r < Cv + 2*KKv) v = *(const float4*)&Wco[(size_t)(r - Cv)*Cv + c4*4];
            size_t o = (size_t)r*Cv + c4*4;
            float vv[4] = {v.x, v.y, v.z, v.w};
            #pragma unroll
            for (int j = 0; j < 4; j++) split_bf16(vv[j], g_w2hi[o + j], g_w2lo[o + j]);
        }
    } else {
        int idx = (bid - 1272) * 256 + tid;
        if (idx < Cv * (Cv/4)) {
            int r = idx / (Cv/4), c4 = idx - r * (Cv/4);
            float4 v = *(const float4*)&Wp[(size_t)r*Cv + c4*4];
            size_t o = (size_t)r*Cv + c4*4;
            float vv[4] = {v.x, v.y, v.z, v.w};
            #pragma unroll
            for (int j = 0; j < 4; j++) split_bf16(vv[j], g_wphi[o + j], g_wplo[o + j]);
        }
    }
}

// ================= qkv via HMMA; epilogue also emits bf16 hi/lo =================
__global__ __launch_bounds__(256, 4)
void qkv_hmma(const float* __restrict__ bq)
{
    __shared__ __align__(16) __nv_bfloat16 sAh[64][40];
    __shared__ __align__(16) __nv_bfloat16 sAl[64][40];
    __shared__ __align__(16) __nv_bfloat16 sBh[64][40];
    __shared__ __align__(16) __nv_bfloat16 sBl[64][40];

    const int tid  = threadIdx.x;
    const int lane = tid & 31;
    const int w    = tid >> 5;
    const int wm   = w >> 2;
    const int wn   = w & 3;
    const int bm = blockIdx.y * 64;
    const int bn = blockIdx.x * 64;
    const int gid = lane >> 2;
    const int tig = lane & 3;
    const int srow = tid >> 2, sc8 = (tid & 3) * 8;

    float acc[2][2][4];
    #pragma unroll
    for (int i = 0; i < 2; i++)
        #pragma unroll
        for (int j = 0; j < 2; j++)
            #pragma unroll
            for (int q = 0; q < 4; q++) acc[i][j][q] = 0.0f;

    for (int kc = 0; kc < 12; kc++) {
        const int k0 = kc * 32;
        {
            int m = bm + srow;
            uint4 vh = make_uint4(0u,0u,0u,0u), vl = vh;
            if (m < BNROWS) {
                size_t o = (size_t)m * Cv + k0 + sc8;
                vh = *(const uint4*)&g_xhi[o];
                vl = *(const uint4*)&g_xlo[o];
            }
            *(uint4*)&sAh[srow][sc8] = vh;
            *(uint4*)&sAl[srow][sc8] = vl;
            size_t ob = (size_t)(bn + srow) * Cv + k0 + sc8;
            *(uint4*)&sBh[srow][sc8] = *(const uint4*)&g_whi[ob];
            *(uint4*)&sBl[srow][sc8] = *(const uint4*)&g_wlo[ob];
        }
        __syncthreads();
        #pragma unroll
        for (int kk = 0; kk < 32; kk += 16) {
            uint32_t ah[2][4], al[2][4], bh[2][2], bl[2][2];
            const int c = kk + tig * 2;
            #pragma unroll
            for (int mt = 0; mt < 2; mt++) {
                int r = wm * 32 + mt * 16 + gid;
                ah[mt][0] = *(const uint32_t*)&sAh[r][c];
                ah[mt][1] = *(const uint32_t*)&sAh[r + 8][c];
                ah[mt][2] = *(const uint32_t*)&sAh[r][c + 8];
                ah[mt][3] = *(const uint32_t*)&sAh[r + 8][c + 8];
                al[mt][0] = *(const uint32_t*)&sAl[r][c];
                al[mt][1] = *(const uint32_t*)&sAl[r + 8][c];
                al[mt][2] = *(const uint32_t*)&sAl[r][c + 8];
                al[mt][3] = *(const uint32_t*)&sAl[r + 8][c + 8];
            }
            #pragma unroll
            for (int nt = 0; nt < 2; nt++) {
                int r = wn * 16 + nt * 8 + gid;
                bh[nt][0] = *(const uint32_t*)&sBh[r][c];
                bh[nt][1] = *(const uint32_t*)&sBh[r][c + 8];
                bl[nt][0] = *(const uint32_t*)&sBl[r][c];
                bl[nt][1] = *(const uint32_t*)&sBl[r][c + 8];
            }
            #pragma unroll
            for (int mt = 0; mt < 2; mt++)
                #pragma unroll
                for (int nt = 0; nt < 2; nt++) {
                    mma16816(acc[mt][nt], ah[mt], bh[nt]);
                    mma16816(acc[mt][nt], ah[mt], bl[nt]);
                    mma16816(acc[mt][nt], al[mt], bh[nt]);
                }
        }
        __syncthreads();
    }

    #pragma unroll
    for (int mt = 0; mt < 2; mt++) {
        #pragma unroll
        for (int nt = 0; nt < 2; nt++) {
            int n0 = bn + wn * 16 + nt * 8 + tig * 2;
            float b0 = (n0 < Cv) ? bq[n0] : 0.0f;
            float b1 = (n0 + 1 < Cv) ? bq[n0 + 1] : 0.0f;
            #pragma unroll
            for (int half = 0; half < 2; half++) {
                int m0 = bm + wm * 32 + mt * 16 + gid + half * 8;
                if (m0 >= BNROWS) continue;
                float v0 = acc[mt][nt][half * 2 + 0] + b0;
                float v1 = acc[mt][nt][half * 2 + 1] + b1;
                size_t o = (size_t)m0 * QKVC + n0;
                g_qkv[o]     = v0;
                g_qkv[o + 1] = v1;
                split_bf16(v0, g_qkvhi[o],     g_qkvlo[o]);
                split_bf16(v1, g_qkvhi[o + 1], g_qkvlo[o + 1]);
            }
        }
    }
}

// ================= fused HMMA: t1co (175 blocks) + qk (1536 blocks) =================
#define T1_BLOCKS 175
__global__ __launch_bounds__(256, 4)
void fused_t1qk_hmma(const float* __restrict__ bo1)
{
    __shared__ __align__(16) char smem_buf[20480];
    __nv_bfloat16 (*sAh)[40] = (__nv_bfloat16(*)[40])(smem_buf);
    __nv_bfloat16 (*sAl)[40] = (__nv_bfloat16(*)[40])(smem_buf + 5120);
    __nv_bfloat16 (*sBh)[40] = (__nv_bfloat16(*)[40])(smem_buf + 10240);
    __nv_bfloat16 (*sBl)[40] = (__nv_bfloat16(*)[40])(smem_buf + 15360);

    const int tid  = threadIdx.x;
    const int lane = tid & 31;
    const int w    = tid >> 5;
    const int wm   = w >> 2;
    const int wn   = w & 3;
    const int gid = lane >> 2;
    const int tig = lane & 3;
    const int srow = tid >> 2, sc8 = (tid & 3) * 8;

    float acc[2][2][4];
    #pragma unroll
    for (int i = 0; i < 2; i++)
        #pragma unroll
        for (int j = 0; j < 2; j++)
            #pragma unroll
            for (int q = 0; q < 4; q++) acc[i][j][q] = 0.0f;

    if (blockIdx.x < T1_BLOCKS) {
        // ---- t1co: C[1568 x 448] = q @ [Wo1|Wco]^T ----
        const int bm = (blockIdx.x / 7) * 64;
        const int bn = (blockIdx.x % 7) * 64;
        for (int kc = 0; kc < 12; kc++) {
            const int k0 = kc * 32;
            {
                int m = bm + srow;
                uint4 vh = make_uint4(0u,0u,0u,0u), vl = vh;
                if (m < BNROWS) {
                    size_t o = (size_t)m * QKVC + k0 + sc8;   // q region cols 0..383
                    vh = *(const uint4*)&g_qkvhi[o];
                    vl = *(const uint4*)&g_qkvlo[o];
                }
                *(uint4*)&sAh[srow][sc8] = vh;
                *(uint4*)&sAl[srow][sc8] = vl;
                size_t ob = (size_t)(bn + srow) * Cv + k0 + sc8;
                *(uint4*)&sBh[srow][sc8] = *(const uint4*)&g_w2hi[ob];
                *(uint4*)&sBl[srow][sc8] = *(const uint4*)&g_w2lo[ob];
            }
            __syncthreads();
            #pragma unroll
            for (int kk = 0; kk < 32; kk += 16) {
                uint32_t ah[2][4], al[2][4], bh[2][2], bl[2][2];
                const int c = kk + tig * 2;
                #pragma unroll
                for (int mt = 0; mt < 2; mt++) {
                    int r = wm * 32 + mt * 16 + gid;
                    ah[mt][0] = *(const uint32_t*)&sAh[r][c];
                    ah[mt][1] = *(const uint32_t*)&sAh[r + 8][c];
                    ah[mt][2] = *(const uint32_t*)&sAh[r][c + 8];
                    ah[mt][3] = *(const uint32_t*)&sAh[r + 8][c + 8];
                    al[mt][0] = *(const uint32_t*)&sAl[r][c];
                    al[mt][1] = *(const uint32_t*)&sAl[r + 8][c];
                    al[mt][2] = *(const uint32_t*)&sAl[r][c + 8];
                    al[mt][3] = *(const uint32_t*)&sAl[r + 8][c + 8];
                }
                #pragma unroll
                for (int nt = 0; nt < 2; nt++) {
                    int r = wn * 16 + nt * 8 + gid;
                    bh[nt][0] = *(const uint32_t*)&sBh[r][c];
                    bh[nt][1] = *(const uint32_t*)&sBh[r][c + 8];
                    bl[nt][0] = *(const uint32_t*)&sBl[r][c];
                    bl[nt][1] = *(const uint32_t*)&sBl[r][c + 8];
                }
                #pragma unroll
                for (int mt = 0; mt < 2; mt++)
                    #pragma unroll
                    for (int nt = 0; nt < 2; nt++) {
                        mma16816(acc[mt][nt], ah[mt], bh[nt]);
                        mma16816(acc[mt][nt], ah[mt], bl[nt]);
                        mma16816(acc[mt][nt], al[mt], bh[nt]);
                    }
            }
            __syncthreads();
        }
        #pragma unroll
        for (int mt = 0; mt < 2; mt++) {
            #pragma unroll
            for (int nt = 0; nt < 2; nt++) {
                int n0 = bn + wn * 16 + nt * 8 + tig * 2;
                #pragma unroll
                for (int half = 0; half < 2; half++) {
                    int m0 = bm + wm * 32 + mt * 16 + gid + half * 8;
                    if (m0 >= BNROWS) continue;
                    #pragma unroll
                    for (int jj = 0; jj < 2; jj++) {
                        float v = acc[mt][nt][half * 2 + jj];
                        int n = n0 + jj;
                        if (n < Cv) {
                            g_t1[(size_t)m0 * Cv + n] = gelu_exact(v + bo1[n]);
                        } else if (n < Cv + 2 * KKv) {
                            g_co[(size_t)m0 * (2 * KKv) + (n - Cv)] = tanhf(v) * (1.0f / 14.0f);
                        }
                    }
                }
            }
        }
    } else {
        // ---- qk: per (b,h) 64x64 tile of Q @ K^T, K=32 ----
        const int idx2 = blockIdx.x - T1_BLOCKS;
        const int bxq = idx2 & 3;
        const int byq = (idx2 >> 2) & 3;
        const int bh  = idx2 >> 4;
        const int b = bh / HEADS, h = bh - b * HEADS;
        const int n0b = byq * 64, p0b = bxq * 64;
        // stage: A = q slice, B = xK slice  (64 rows x 32 k)
        {
            int sc8q = (tid & 3) * 8;
            if (sc8q < 32) {
                int n = n0b + srow;
                uint4 vh = make_uint4(0u,0u,0u,0u), vl = vh;
                if (n < Nv) {
                    size_t o = ((size_t)(b*Nv + n))*QKVC + h*HC + sc8q;
                    vh = *(const uint4*)&g_qkvhi[o];
                    vl = *(const uint4*)&g_qkvlo[o];
                }
                *(uint4*)&sAh[srow][sc8q] = vh;
                *(uint4*)&sAl[srow][sc8q] = vl;
                int p = p0b + srow;
                uint4 wh = make_uint4(0u,0u,0u,0u), wl = wh;
                if (p < Nv) {
                    size_t o = ((size_t)(b*Nv + p))*QKVC + Cv + h*HC + sc8q;
                    wh = *(const uint4*)&g_qkvhi[o];
                    wl = *(const uint4*)&g_qkvlo[o];
                }
                *(uint4*)&sBh[srow][sc8q] = wh;
                *(uint4*)&sBl[srow][sc8q] = wl;
            }
        }
        __syncthreads();
        #pragma unroll
        for (int kk = 0; kk < 32; kk += 16) {
            uint32_t ah[2][4], al[2][4], bh2[2][2], bl2[2][2];
            const int c = kk + tig * 2;
            #pragma unroll
            for (int mt = 0; mt < 2; mt++) {
                int r = wm * 32 + mt * 16 + gid;
                ah[mt][0] = *(const uint32_t*)&sAh[r][c];
                ah[mt][1] = *(const uint32_t*)&sAh[r + 8][c];
                ah[mt][2] = *(const uint32_t*)&sAh[r][c + 8];
                ah[mt][3] = *(const uint32_t*)&sAh[r + 8][c + 8];
                al[mt][0] = *(const uint32_t*)&sAl[r][c];
                al[mt][1] = *(const uint32_t*)&sAl[r + 8][c];
                al[mt][2] = *(const uint32_t*)&sAl[r][c + 8];
                al[mt][3] = *(const uint32_t*)&sAl[r + 8][c + 8];
            }
            #pragma unroll
            for (int nt = 0; nt < 2; nt++) {
                int r = wn * 16 + nt * 8 + gid;
                bh2[nt][0] = *(const uint32_t*)&sBh[r][c];
                bh2[nt][1] = *(const uint32_t*)&sBh[r][c + 8];
                bl2[nt][0] = *(const uint32_t*)&sBl[r][c];
                bl2[nt][1] = *(const uint32_t*)&sBl[r][c + 8];
            }
            #pragma unroll
            for (int mt = 0; mt < 2; mt++)
                #pragma unroll
                for (int nt = 0; nt < 2; nt++) {
                    mma16816(acc[mt][nt], ah[mt], bh2[nt]);
                    mma16816(acc[mt][nt], ah[mt], bl2[nt]);
                    mma16816(acc[mt][nt], al[mt], bh2[nt]);
                }
        }
        float* qkb = g_qk + ((size_t)bh * Nv) * Nv;
        #pragma unroll
        for (int mt = 0; mt < 2; mt++) {
            #pragma unroll
            for (int nt = 0; nt < 2; nt++) {
                int p0 = p0b + wn * 16 + nt * 8 + tig * 2;
                #pragma unroll
                for (int half = 0; half < 2; half++) {
                    int n = n0b + wm * 32 + mt * 16 + gid + half * 8;
                    if (n >= Nv) continue;
                    if (p0 < Nv)     qkb[(size_t)n * Nv + p0]     = acc[mt][nt][half * 2 + 0];
                    if (p0 + 1 < Nv) qkb[(size_t)n * Nv + p0 + 1] = acc[mt][nt][half * 2 + 1];
                }
            }
        }
    }
}

// ================= proj HMMA (split-K x2): out += Wp @ ao^T =================
__global__ __launch_bounds__(256, 4)
void proj_hmma(float* __restrict__ out)
{
    __shared__ __align__(16) __nv_bfloat16 sAh[64][40];
    __shared__ __align__(16) __nv_bfloat16 sAl[64][40];
    __shared__ __align__(16) __nv_bfloat16 sBh[64][40];
    __shared__ __align__(16) __nv_bfloat16 sBl[64][40];

    const int tid  = threadIdx.x;
    const int lane = tid & 31;
    const int w    = tid >> 5;
    const int wm   = w >> 2;
    const int wn   = w & 3;
    const int bm = blockIdx.y * 64;       // channel
    const int bn = blockIdx.x * 64;       // token
    const int kbase = blockIdx.z * 192;
    const int gid = lane >> 2;
    const int tig = lane & 3;
    const int srow = tid >> 2, sc8 = (tid & 3) * 8;

    float acc[2][2][4];
    #pragma unroll
    for (int i = 0; i < 2; i++)
        #pragma unroll
        for (int j = 0; j < 2; j++)
            #pragma unroll
            for (int q = 0; q < 4; q++) acc[i][j][q] = 0.0f;

    for (int kc = 0; kc < 6; kc++) {
        const int k0 = kbase + kc * 32;
        {
            size_t oa = (size_t)(bm + srow) * Cv + k0 + sc8;
            *(uint4*)&sAh[srow][sc8] = *(const uint4*)&g_wphi[oa];
            *(uint4*)&sAl[srow][sc8] = *(const uint4*)&g_wplo[oa];
            int n = bn + srow;
            uint4 vh = make_uint4(0u,0u,0u,0u), vl = vh;
            if (n < BNROWS) {
                size_t o = (size_t)n * Cv + k0 + sc8;
                vh = *(const uint4*)&g_aohi[o];
                vl = *(const uint4*)&g_aolo[o];
            }
            *(uint4*)&sBh[srow][sc8] = vh;
            *(uint4*)&sBl[srow][sc8] = vl;
        }
        __syncthreads();
        #pragma unroll
        for (int kk = 0; kk < 32; kk += 16) {
            uint32_t ah[2][4], al[2][4], bh[2][2], bl[2][2];
            const int c = kk + tig * 2;
            #pragma unroll
            for (int mt = 0; mt < 2; mt++) {
                int r = wm * 32 + mt * 16 + gid;
                ah[mt][0] = *(const uint32_t*)&sAh[r][c];
                ah[mt][1] = *(const uint32_t*)&sAh[r + 8][c];
                ah[mt][2] = *(const uint32_t*)&sAh[r][c + 8];
                ah[mt][3] = *(const uint32_t*)&sAh[r + 8][c + 8];
                al[mt][0] = *(const uint32_t*)&sAl[r][c];
                al[mt][1] = *(const uint32_t*)&sAl[r + 8][c];
                al[mt][2] = *(const uint32_t*)&sAl[r][c + 8];
                al[mt][3] = *(const uint32_t*)&sAl[r + 8][c + 8];
            }
            #pragma unroll
            for (int nt = 0; nt < 2; nt++) {
                int r = wn * 16 + nt * 8 + gid;
                bh[nt][0] = *(const uint32_t*)&sBh[r][c];
                bh[nt][1] = *(const uint32_t*)&sBh[r][c + 8];
                bl[nt][0] = *(const uint32_t*)&sBl[r][c];
                bl[nt][1] = *(const uint32_t*)&sBl[r][c + 8];
            }
            #pragma unroll
            for (int mt = 0; mt < 2; mt++)
                #pragma unroll
                for (int nt = 0; nt < 2; nt++) {
                    mma16816(acc[mt][nt], ah[mt], bh[nt]);
                    mma16816(acc[mt][nt], ah[mt], bl[nt]);
                    mma16816(acc[mt][nt], al[mt], bh[nt]);
                }
        }
        __syncthreads();
    }

    #pragma unroll
    for (int mt = 0; mt < 2; mt++) {
        #pragma unroll
        for (int nt = 0; nt < 2; nt++) {
            int n0 = bn + wn * 16 + nt * 8 + tig * 2;
            #pragma unroll
            for (int half = 0; half < 2; half++) {
                int m0 = bm + wm * 32 + mt * 16 + gid + half * 8;
                #pragma unroll
                for (int jj = 0; jj < 2; jj++) {
                    int n = n0 + jj;
                    if (n >= BNROWS) continue;
                    int b = n / Nv, nn = n - b * Nv;
                    atomicAdd(&out[((size_t)(b * Cv + m0)) * Nv + nn], acc[mt][nt][half * 2 + jj]);
                }
            }
        }
    }
}

// ================= offset GEMM (split-K x4, f32x2): g_off += t3 @ Wo2^T (raw) ============
__global__ __launch_bounds__(128, 8)
void gemm_off(const float* __restrict__ Wo2)
{
    __shared__ float As[2][32][36];
    __shared__ float Bs[2][32][68];
    const int M = Bv * Sv;
    const int N = 2 * Nv;
    const int bm = blockIdx.y * 32;
    const int bn = blockIdx.x * 64;
    const int kbase = blockIdx.z * 96;
    const int tid = threadIdx.x;
    const int ty = tid >> 4;
    const int tx = tid & 15;
    const int k4 = (tid & 7) * 4;
    const int rowg = tid >> 3;

    unsigned long long acc[2][4];
    #pragma unroll
    for (int i = 0; i < 2; i++)
        #pragma unroll
        for (int j = 0; j < 4; j++) acc[i][j] = 0ull;

    float4 ra4[2], rb4[4];
    auto ldg = [&](int k0) {
        #pragma unroll
        for (int i = 0; i < 2; i++) {
            int m = bm + rowg + i * 16;
            if (m < M) ra4[i] = *(const float4*)&g_t3[(size_t)m * Cv + k0 + k4];
            else       ra4[i] = make_float4(0.f, 0.f, 0.f, 0.f);
        }
        #pragma unroll
        for (int i = 0; i < 4; i++) {
            int n = bn + rowg + i * 16;
            if (n < N) rb4[i] = *(const float4*)&Wo2[(size_t)n * Cv + k0 + k4];
            else       rb4[i] = make_float4(0.f, 0.f, 0.f, 0.f);
        }
    };
    auto sts = [&](int buf) {
        #pragma unroll
        for (int i = 0; i < 2; i++) {
            As[buf][k4 + 0][rowg + i * 16] = ra4[i].x;
            As[buf][k4 + 1][rowg + i * 16] = ra4[i].y;
            As[buf][k4 + 2][rowg + i * 16] = ra4[i].z;
            As[buf][k4 + 3][rowg + i * 16] = ra4[i].w;
        }
        #pragma unroll
        for (int i = 0; i < 4; i++) {
            Bs[buf][k4 + 0][rowg + i * 16] = rb4[i].x;
            Bs[buf][k4 + 1][rowg + i * 16] = rb4[i].y;
            Bs[buf][k4 + 2][rowg + i * 16] = rb4[i].z;
            Bs[buf][k4 + 3][rowg + i * 16] = rb4[i].w;
        }
    };

    const int NT = 3;
    ldg(kbase);
    sts(0);
    __syncthreads();

    #pragma unroll
    for (int kt = 0; kt < NT; kt++) {
        const int cur = kt & 1;
        if (kt + 1 < NT) ldg(kbase + (kt + 1) * 32);
        #pragma unroll
        for (int k = 0; k < 32; k++) {
            unsigned long long a2[2];
            a2[0] = *(const unsigned long long*)&As[cur][k][ty * 4];
            a2[1] = *(const unsigned long long*)&As[cur][k][ty * 4 + 2];
            float4 bv = *(const float4*)&Bs[cur][k][tx * 4];
            unsigned long long b2[4];
            b2[0] = pk2(bv.x, bv.x); b2[1] = pk2(bv.y, bv.y);
            b2[2] = pk2(bv.z, bv.z); b2[3] = pk2(bv.w, bv.w);
            #pragma unroll
            for (int i = 0; i < 2; i++)
                #pragma unroll
                for (int j = 0; j < 4; j++)
                    fma2(acc[i][j], a2[i], b2[j]);
        }
        if (kt + 1 < NT) {
            __syncthreads();
            sts(1 - cur);
            __syncthreads();
        }
    }

    #pragma unroll
    for (int i = 0; i < 2; i++) {
        #pragma unroll
        for (int j = 0; j < 4; j++) {
            float2 f = upk(acc[i][j]);
            int n = bn + tx * 4 + j;
            if (n >= N) continue;
            int m0 = bm + ty * 4 + i * 2;
            if (m0 < M)     atomicAdd(&g_off[(size_t)m0 * N + n], f.x);
            if (m0 + 1 < M) atomicAdd(&g_off[(size_t)(m0 + 1) * N + n], f.y);
        }
    }
}

// ================= depthwise 3x3 s2 conv + LN + GELU  (+ zero g_off row) =================
__global__ void dwln_kernel(const float* __restrict__ Wdw, const float* __restrict__ bdw,
                            const float* __restrict__ lng, const float* __restrict__ lnb)
{
    int bs = blockIdx.x;
    int b = bs / Sv, s = bs % Sv;
    int oy = s / rWv, ox = s % rWv;
    int c = threadIdx.x;

    for (int i = c; i < 2 * Nv; i += blockDim.x)
        g_off[(size_t)bs * (2 * Nv) + i] = 0.0f;

    float acc = bdw[c];
    #pragma unroll
    for (int ky = 0; ky < 3; ky++) {
        int y = oy*2 - 1 + ky;
        if (y < 0 || y >= Hv) continue;
        #pragma unroll
        for (int kx = 0; kx < 3; kx++) {
            int x = ox*2 - 1 + kx;
            if (x < 0 || x >= Wv_) continue;
            acc = fmaf(g_t1[((size_t)b*Nv + y*Wv_ + x)*Cv + c], Wdw[c*9 + ky*3 + kx], acc);
        }
    }
    float s1 = acc, s2 = acc*acc;
    #pragma unroll
    for (int o = 16; o > 0; o >>= 1) {
        s1 += __shfl_xor_sync(0xffffffffu, s1, o);
        s2 += __shfl_xor_sync(0xffffffffu, s2, o);
    }
    __shared__ float w1[12], w2[12];
    __shared__ float s_mu, s_rstd;
    if ((c & 31) == 0) { w1[c >> 5] = s1; w2[c >> 5] = s2; }
    __syncthreads();
    if (c == 0) {
        float t1s = 0.f, t2s = 0.f;
        #pragma unroll
        for (int i = 0; i < 12; i++) { t1s += w1[i]; t2s += w2[i]; }
        float mu = t1s / (float)Cv;
        float var = t2s / (float)Cv - mu*mu;
        s_mu = mu; s_rstd = rsqrtf(var + 1e-5f);
    }
    __syncthreads();
    float v = (acc - s_mu) * s_rstd * lng[c] + lnb[c];
    g_t3[(size_t)bs*Cv + c] = gelu_exact(v);
}

// ================= scores + softmax + fold probs into dense A[b,h,n,:] =================
__global__ void score_kernel(const float* __restrict__ posembed)
{
    const int bn = blockIdx.x;
    const int b = bn / Nv, n = bn % Nv;
    const int ny = n / Wv_, nx = n % Wv_;
    __shared__ float sc[HEADS*TS];
    __shared__ int   sp[TS*4];
    __shared__ float swt[TS*4];
    __shared__ __align__(16) float sA[HEADS][Nv];

    for (int idx = threadIdx.x; idx < HEADS*Nv/4; idx += blockDim.x)
        ((float4*)sA)[idx] = make_float4(0.f, 0.f, 0.f, 0.f);

    for (int item = threadIdx.x; item < HEADS*TS; item += blockDim.x) {
        const int h = item / TS, s = item % TS;
        float py, px, tpy, tpx;
        if (s < Sv) {
            int rh = s / rWv, rw = s % rWv;
            float offy = tanhf(g_off[((size_t)b*Sv + s)*(2*Nv) + 0*Nv + n]) * (2.0f/14.0f);
            float offx = tanhf(g_off[((size_t)b*Sv + s)*(2*Nv) + 1*Nv + n]) * (2.0f/14.0f);
            float refy = (float)(rh*2) * (2.0f/13.0f) - 1.0f;
            float refx = (float)(rw*2) * (2.0f/13.0f) - 1.0f;
            py = (offy + refy + 1.0f) * 6.5f;
            px = (offx + refx + 1.0f) * 6.5f;
            tpy = ((float)(2*rh - ny) * (1.0f/13.0f) - offy + 1.0f) * 13.0f;
            tpx = ((float)(2*rw - nx) * (1.0f/13.0f) - offx + 1.0f) * 13.0f;
        } else {
            int j = s - Sv;
            float coy = g_co[((size_t)b*Nv + n)*(2*KKv) + j*2 + 0];
            float cox = g_co[((size_t)b*Nv + n)*(2*KKv) + j*2 + 1];
            float cy = (float)ny + c_offm[j][0];
            float cx = (float)nx + c_offm[j][1];
            float cny = fminf(fmaxf(cy, 0.0f), 14.0f) * (2.0f/13.0f) - 1.0f;
            float cnx = fminf(fmaxf(cx, 0.0f), 14.0f) * (2.0f/13.0f) - 1.0f;
            py = (coy + cny + 1.0f) * 6.5f;
            px = (cox + cnx + 1.0f) * 6.5f;
            tpy = (coy - (float)ny + 1.0f) * 13.0f;
            tpx = (cox - (float)nx + 1.0f) * 13.0f;
        }
        float y0 = floorf(py), x0 = floorf(px);
        float wy1 = py - y0, wx1 = px - x0;
        const float* qkb = g_qk + (((size_t)(b*HEADS + h))*Nv + n)*Nv;
        float val = 0.0f;
        #pragma unroll
        for (int ccy = 0; ccy < 2; ccy++) {
            #pragma unroll
            for (int ccx = 0; ccx < 2; ccx++) {
                float yf = y0 + (float)ccy, xf = x0 + (float)ccx;
                float w = (ccy ? wy1 : 1.0f - wy1) * (ccx ? wx1 : 1.0f - wx1);
                bool valid = (yf >= 0.0f) && (yf <= 13.0f) && (xf >= 0.0f) && (xf <= 13.0f);
                if (!valid) w = 0.0f;
                int yi = (int)fminf(fmaxf(yf, 0.0f), 13.0f);
                int xi = (int)fminf(fmaxf(xf, 0.0f), 13.0f);
                int pix = yi*Wv_ + xi;
                val += w * qkb[pix];
                if (h == 0) { sp[s*4 + ccy*2 + ccx] = pix; swt[s*4 + ccy*2 + ccx] = w; }
            }
        }
        float by0 = floorf(tpy), bx0 = floorf(tpx);
        float bwy = tpy - by0, bwx = tpx - bx0;
        const float* tb = posembed + (size_t)h * (27*27);
        float bval = 0.0f;
        #pragma unroll
        for (int ccy = 0; ccy < 2; ccy++) {
            #pragma unroll
            for (int ccx = 0; ccx < 2; ccx++) {
                float yf = by0 + (float)ccy, xf = bx0 + (float)ccx;
                float w = (ccy ? bwy : 1.0f - bwy) * (ccx ? bwx : 1.0f - bwx);
                bool valid = (yf >= 0.0f) && (yf <= 26.0f) && (xf >= 0.0f) && (xf <= 26.0f);
                if (!valid) w = 0.0f;
                int yi = (int)fminf(fmaxf(yf, 0.0f), 26.0f);
                int xi = (int)fminf(fmaxf(xf, 0.0f), 26.0f);
                bval += w * tb[yi*27 + xi];
            }
        }
        sc[h*TS + s] = val + bval;
    }
    __syncthreads();

    const int wid = threadIdx.x >> 5, lane = threadIdx.x & 31;
    {
        float m = -1e30f;
        for (int s = lane; s < TS; s += 32) m = fmaxf(m, sc[wid*TS + s]);
        #pragma unroll
        for (int o = 16; o > 0; o >>= 1) m = fmaxf(m, __shfl_xor_sync(0xffffffffu, m, o));
        float sum = 0.0f;
        for (int s = lane; s < TS; s += 32) {
            float e = expf(sc[wid*TS + s] - m);
            sc[wid*TS + s] = e;
            sum += e;
        }
        #pragma unroll
        for (int o = 16; o > 0; o >>= 1) sum += __shfl_xor_sync(0xffffffffu, sum, o);
        float inv = 1.0f / sum;
        for (int s = lane; s < TS; s += 32) sc[wid*TS + s] *= inv;
    }
    for (int i = lane; i < TS*4; i += 32) {
        atomicAdd(&sA[wid][sp[i]], sc[wid*TS + (i >> 2)] * swt[i]);
    }
    __syncthreads();

    float4* dst = (float4*)(g_A + ((size_t)(b*HEADS))*Nv*Nv);
    for (int idx = threadIdx.x; idx < HEADS*(Nv/4); idx += blockDim.x) {
        int h = idx / (Nv/4), p4 = idx - h * (Nv/4);
        dst[((size_t)h*Nv + n)*(Nv/4) + p4] = ((float4*)sA)[h*(Nv/4) + p4];
    }
}

// ================= AV GEMM (f32x2) -> bf16 hi/lo output + seed out with bias ========
__global__ __launch_bounds__(128, 4)
void av_kernel(const float* __restrict__ bvv, const float* __restrict__ bp, float* __restrict__ out)
{
    const int n0 = blockIdx.x * 64;
    const int bh = blockIdx.y;
    const int b = bh / HEADS, h = bh - b * HEADS;
    __shared__ __align__(16) float Vs[Nv][HC];
    __shared__ __align__(16) float As[32][68];

    const int tid = threadIdx.x;
    const int tx = tid & 7;
    const int ng = tid >> 3;

    for (int i = tid; i < 64 * HC; i += 128) {
        int nn = n0 + (i & 63);
        int c  = h * HC + (i >> 6);
        if (nn < Nv) out[((size_t)(b * Cv + c)) * Nv + nn] = bp[c];
    }

    {
        const float* vbase = g_qkv + (size_t)b * Nv * QKVC + 2 * Cv + h * HC;
        for (int i = tid; i < Nv * (HC/4); i += 128) {
            int p = i >> 3, c4 = (i & 7) * 4;
            *(float4*)&Vs[p][c4] = *(const float4*)&vbase[(size_t)p * QKVC + c4];
        }
    }

    unsigned long long acc[2][4];
    #pragma unroll
    for (int i = 0; i < 2; i++)
        #pragma unroll
        for (int j = 0; j < 4; j++) acc[i][j] = 0ull;

    const float* Arow = g_A + ((size_t)bh * Nv) * Nv;
    const int r = tid >> 1, halfq = tid & 1;

    for (int p0 = 0; p0 < Nv; p0 += 32) {
        const int kt = min(32, Nv - p0);
        __syncthreads();
        {
            int nrow = n0 + r;
            #pragma unroll
            for (int q = 0; q < 4; q++) {
                int pl = halfq * 16 + q * 4;
                float4 v = make_float4(0.f, 0.f, 0.f, 0.f);
                if (nrow < Nv && p0 + pl < Nv)
                    v = *(const float4*)&Arow[(size_t)nrow * Nv + p0 + pl];
                As[pl + 0][r] = v.x;
                As[pl + 1][r] = v.y;
                As[pl + 2][r] = v.z;
                As[pl + 3][r] = v.w;
            }
        }
        __syncthreads();
        for (int k = 0; k < kt; k++) {
            float4 af = *(const float4*)&As[k][ng * 4];
            unsigned long long a0 = pk2(af.x, af.y);
            unsigned long long a1 = pk2(af.z, af.w);
            float4 bf = *(const float4*)&Vs[p0 + k][tx * 4];
            unsigned long long b2[4];
            b2[0] = pk2(bf.x, bf.x); b2[1] = pk2(bf.y, bf.y);
            b2[2] = pk2(bf.z, bf.z); b2[3] = pk2(bf.w, bf.w);
            #pragma unroll
            for (int j = 0; j < 4; j++) { fma2(acc[0][j], a0, b2[j]); fma2(acc[1][j], a1, b2[j]); }
        }
    }

    #pragma unroll
    for (int j = 0; j < 4; j++) {
        int c = tx * 4 + j;
        float bb = bvv[h * HC + c];
        #pragma unroll
        for (int i = 0; i < 2; i++) {
            float2 f = upk(acc[i][j]);
            #pragma unroll
            for (int half = 0; half < 2; half++) {
                int n = n0 + ng * 4 + i * 2 + half;
                if (n >= Nv) continue;
                float v = (half ? f.y : f.x) + bb;
                size_t o = ((size_t)(b*Nv + n))*Cv + h*HC + c;
                split_bf16(v, g_aohi[o], g_aolo[o]);
            }
        }
    }
}

extern "C" void kernel_launch(void* const* d_in, const int* in_sizes, int n_in,
                              void* d_out, int out_size)
{
    const float* x    = (const float*)d_in[0];
    const float* Wq   = (const float*)d_in[1];
    const float* bq   = (const float*)d_in[2];
    const float* Wk   = (const float*)d_in[3];
    // bk cancels in softmax — unused
    const float* Wvv  = (const float*)d_in[5];
    const float* bvv  = (const float*)d_in[6];
    const float* Wo1  = (const float*)d_in[7];
    const float* bo1  = (const float*)d_in[8];
    const float* Wdw  = (const float*)d_in[9];
    const float* bdw  = (const float*)d_in[10];
    const float* lng  = (const float*)d_in[11];
    const float* lnb  = (const float*)d_in[12];
    const float* Wo2  = (const float*)d_in[13];
    const float* Wco  = (const float*)d_in[14];
    const float* pos  = (const float*)d_in[15];
    const float* Wp   = (const float*)d_in[16];
    const float* bp   = (const float*)d_in[17];
    float* out = (float*)d_out;

    // 0) split-precision conversion (x transpose + all weights)
    prep_kernel<<<1416, 256>>>(x, Wq, Wk, Wvv, Wo1, Wco, Wp);
    // 1) qkv via HMMA (also emits bf16 hi/lo)
    qkv_hmma<<<dim3(18, 25), 256>>>(bq);
    // 2) fused HMMA: t1co (175) + qk (1536)
    fused_t1qk_hmma<<<T1_BLOCKS + 16 * Bv * HEADS, 256>>>(bo1);
    // 3) offset net tail
    dwln_kernel<<<Bv*Sv, Cv>>>(Wdw, bdw, lng, lnb);
    gemm_off<<<dim3(7, 13, 4), 128>>>(Wo2);
    // 4) scores -> probs -> dense A
    score_kernel<<<Bv*Nv, 384>>>(pos);
    // 5) AV (bf16 hi/lo output) + seed out with proj bias
    av_kernel<<<dim3(4, Bv*HEADS), 128>>>(bvv, bp, out);
    // 6) final projection via HMMA (split-K x2, atomics into bias-seeded out)
    proj_hmma<<<dim3(25, 6, 2), 256>>>(out);
}

// round 14
// speedup vs baseline: 2.0973x; 1.0169x over previous
#include <cuda_runtime.h>
#include <cuda_bf16.h>
#include <math.h>
#include <stdint.h>

#define Bv   8
#define Cv   384
#define Hv   14
#define Wv_  14
#define HEADS 12
#define HC   32
#define Nv   196
#define Sv   49
#define rHv  7
#define rWv  7
#define KKv  9
#define TS   58
#define BNROWS (Bv*Nv)   // 1568
#define QKVC 1152
#define N2   448         // padded t1co output cols
#define AP   224         // padded p-stride for dense prob matrix / V^T

// fp32 scratch
__device__ __align__(16) float g_t1 [BNROWS*Cv];
__device__ __align__(16) float g_off[Bv*Sv*2*Nv];
__device__ __align__(16) float g_co [BNROWS*2*KKv];
__device__ __align__(16) float g_qk [(size_t)Bv*HEADS*Nv*Nv];
// bf16 split operands
__device__ __align__(16) __nv_bfloat16 g_xhi[BNROWS*Cv];
__device__ __align__(16) __nv_bfloat16 g_xlo[BNROWS*Cv];
__device__ __align__(16) __nv_bfloat16 g_whi[QKVC*Cv];
__device__ __align__(16) __nv_bfloat16 g_wlo[QKVC*Cv];
__device__ __align__(16) __nv_bfloat16 g_qkvhi[BNROWS*QKVC];   // cols 0..767 used (q | xK)
__device__ __align__(16) __nv_bfloat16 g_qkvlo[BNROWS*QKVC];
__device__ __align__(16) __nv_bfloat16 g_w2hi[N2*Cv];
__device__ __align__(16) __nv_bfloat16 g_w2lo[N2*Cv];
__device__ __align__(16) __nv_bfloat16 g_wphi[Cv*Cv];
__device__ __align__(16) __nv_bfloat16 g_wplo[Cv*Cv];
__device__ __align__(16) __nv_bfloat16 g_wo2hi[(Bv*Sv)*Cv];    // 392 x 384
__device__ __align__(16) __nv_bfloat16 g_wo2lo[(Bv*Sv)*Cv];
__device__ __align__(16) __nv_bfloat16 g_t3hi[(Bv*Sv)*Cv];
__device__ __align__(16) __nv_bfloat16 g_t3lo[(Bv*Sv)*Cv];
__device__ __align__(16) __nv_bfloat16 g_aohi[BNROWS*Cv];
__device__ __align__(16) __nv_bfloat16 g_aolo[BNROWS*Cv];
// dense prob matrix [bh][n][p] (p-stride AP, pad zero) + V^T [bh][c][p]
__device__ __align__(16) __nv_bfloat16 g_Ahi[(size_t)Bv*HEADS*Nv*AP];
__device__ __align__(16) __nv_bfloat16 g_Alo[(size_t)Bv*HEADS*Nv*AP];
__device__ __align__(16) __nv_bfloat16 g_vthi[(size_t)Bv*HEADS*HC*AP];
__device__ __align__(16) __nv_bfloat16 g_vtlo[(size_t)Bv*HEADS*HC*AP];

__constant__ float c_offm[9][2] = {
    {0.f,-1.f},{-1.f,-1.f},{-1.f,0.f},{-1.f,1.f},{0.f,1.f},{1.f,1.f},{1.f,0.f},{1.f,-1.f},{0.f,0.f}
};

__device__ __forceinline__ float gelu_exact(float v) {
    return 0.5f * v * (1.0f + erff(v * 0.7071067811865476f));
}
__device__ __forceinline__ void mma16816(float* c, const uint32_t* a, const uint32_t* b) {
    asm volatile(
        "mma.sync.aligned.m16n8k16.row.col.f32.bf16.bf16.f32 "
        "{%0,%1,%2,%3}, {%4,%5,%6,%7}, {%8,%9}, {%0,%1,%2,%3};"
        : "+f"(c[0]), "+f"(c[1]), "+f"(c[2]), "+f"(c[3])
        : "r"(a[0]), "r"(a[1]), "r"(a[2]), "r"(a[3]), "r"(b[0]), "r"(b[1]));
}
__device__ __forceinline__ void split_bf16(float v, __nv_bfloat16& h, __nv_bfloat16& l) {
    h = __float2bfloat16(v);
    l = __float2bfloat16(v - __bfloat162float(h));
}

// ================= prep: x transpose + all weight splits ========
// [0,672) x; [672,1104) Wqkv; [1104,1272) Wo1|Wco; [1272,1416) Wp; [1416,1563) Wo2
__global__ void prep_kernel(const float* __restrict__ x,
                            const float* __restrict__ Wq, const float* __restrict__ Wk,
                            const float* __restrict__ Wvv, const float* __restrict__ Wo1,
                            const float* __restrict__ Wco, const float* __restrict__ Wp,
                            const float* __restrict__ Wo2)
{
    const int bid = blockIdx.x;
    const int tid = threadIdx.x;
    if (bid < 672) {
        int nt = bid % 7, ct = (bid / 7) % 12, b = bid / 84;
        __shared__ float tile[32][33];
        int tx = tid & 31, ty = tid >> 5;
        int c0 = ct * 32, n0 = nt * 32;
        for (int i = ty; i < 32; i += 8) {
            int c = c0 + i, n = n0 + tx;
            tile[i][tx] = (n < Nv) ? x[((size_t)b*Cv + c)*Nv + n] : 0.0f;
        }
        __syncthreads();
        for (int i = ty; i < 32; i += 8) {
            int n = n0 + i, c = c0 + tx;
            if (n < Nv) {
                size_t o = ((size_t)b*Nv + n)*Cv + c;
                split_bf16(tile[tx][i], g_xhi[o], g_xlo[o]);
            }
        }
    } else if (bid < 1104) {
        int idx = (bid - 672) * 256 + tid;
        if (idx < QKVC * (Cv/4)) {
            int r = idx / (Cv/4), c4 = idx - r * (Cv/4);
            const float* src = (r < Cv) ? &Wq[(size_t)r*Cv]
                              : (r < 2*Cv ? &Wk[(size_t)(r - Cv)*Cv] : &Wvv[(size_t)(r - 2*Cv)*Cv]);
            float4 v = *(const float4*)&src[c4*4];
            size_t o = (size_t)r*Cv + c4*4;
            float vv[4] = {v.x, v.y, v.z, v.w};
            #pragma unroll
            for (int j = 0; j < 4; j++) split_bf16(vv[j], g_whi[o + j], g_wlo[o + j]);
        }
    } else if (bid < 1272) {
        int idx = (bid - 1104) * 256 + tid;
        if (idx < N2 * (Cv/4)) {
            int r = idx / (Cv/4), c4 = idx - r * (Cv/4);
            float4 v = make_float4(0.f, 0.f, 0.f, 0.f);
            if (r < Cv) v = *(const float4*)&Wo1[(size_t)r*Cv + c4*4];
            else if (r < Cv + 2*KKv) v = *(const float4*)&Wco[(size_t)(r - Cv)*Cv + c4*4];
            size_t o = (size_t)r*Cv + c4*4;
            float vv[4] = {v.x, v.y, v.z, v.w};
            #pragma unroll
            for (int j = 0; j < 4; j++) split_bf16(vv[j], g_w2hi[o + j], g_w2lo[o + j]);
        }
    } else if (bid < 1416) {
        int idx = (bid - 1272) * 256 + tid;
        if (idx < Cv * (Cv/4)) {
            int r = idx / (Cv/4), c4 = idx - r * (Cv/4);
            float4 v = *(const float4*)&Wp[(size_t)r*Cv + c4*4];
            size_t o = (size_t)r*Cv + c4*4;
            float vv[4] = {v.x, v.y, v.z, v.w};
            #pragma unroll
            for (int j = 0; j < 4; j++) split_bf16(vv[j], g_wphi[o + j], g_wplo[o + j]);
        }
    } else {
        int idx = (bid - 1416) * 256 + tid;
        if (idx < (Bv*Sv) * (Cv/4)) {
            int r = idx / (Cv/4), c4 = idx - r * (Cv/4);
            float4 v = *(const float4*)&Wo2[(size_t)r*Cv + c4*4];
            size_t o = (size_t)r*Cv + c4*4;
            float vv[4] = {v.x, v.y, v.z, v.w};
            #pragma unroll
            for (int j = 0; j < 4; j++) split_bf16(vv[j], g_wo2hi[o + j], g_wo2lo[o + j]);
        }
    }
}

// ================= qkv via HMMA; q|xK -> g_qkvhi/lo, V -> transposed g_vthi/lo ============
__global__ __launch_bounds__(256, 4)
void qkv_hmma(const float* __restrict__ bq)
{
    __shared__ __align__(16) __nv_bfloat16 sAh[64][40];
    __shared__ __align__(16) __nv_bfloat16 sAl[64][40];
    __shared__ __align__(16) __nv_bfloat16 sBh[64][40];
    __shared__ __align__(16) __nv_bfloat16 sBl[64][40];

    const int tid  = threadIdx.x;
    const int lane = tid & 31;
    const int w    = tid >> 5;
    const int wm   = w >> 2;
    const int wn   = w & 3;
    const int bm = blockIdx.y * 64;
    const int bn = blockIdx.x * 64;
    const int gid = lane >> 2;
    const int tig = lane & 3;
    const int srow = tid >> 2, sc8 = (tid & 3) * 8;

    float acc[2][2][4];
    #pragma unroll
    for (int i = 0; i < 2; i++)
        #pragma unroll
        for (int j = 0; j < 2; j++)
            #pragma unroll
            for (int q = 0; q < 4; q++) acc[i][j][q] = 0.0f;

    for (int kc = 0; kc < 12; kc++) {
        const int k0 = kc * 32;
        {
            int m = bm + srow;
            uint4 vh = make_uint4(0u,0u,0u,0u), vl = vh;
            if (m < BNROWS) {
                size_t o = (size_t)m * Cv + k0 + sc8;
                vh = *(const uint4*)&g_xhi[o];
                vl = *(const uint4*)&g_xlo[o];
            }
            *(uint4*)&sAh[srow][sc8] = vh;
            *(uint4*)&sAl[srow][sc8] = vl;
            size_t ob = (size_t)(bn + srow) * Cv + k0 + sc8;
            *(uint4*)&sBh[srow][sc8] = *(const uint4*)&g_whi[ob];
            *(uint4*)&sBl[srow][sc8] = *(const uint4*)&g_wlo[ob];
        }
        __syncthreads();
        #pragma unroll
        for (int kk = 0; kk < 32; kk += 16) {
            uint32_t ah[2][4], al[2][4], bh[2][2], bl[2][2];
            const int c = kk + tig * 2;
            #pragma unroll
            for (int mt = 0; mt < 2; mt++) {
                int r = wm * 32 + mt * 16 + gid;
                ah[mt][0] = *(const uint32_t*)&sAh[r][c];
                ah[mt][1] = *(const uint32_t*)&sAh[r + 8][c];
                ah[mt][2] = *(const uint32_t*)&sAh[r][c + 8];
                ah[mt][3] = *(const uint32_t*)&sAh[r + 8][c + 8];
                al[mt][0] = *(const uint32_t*)&sAl[r][c];
                al[mt][1] = *(const uint32_t*)&sAl[r + 8][c];
                al[mt][2] = *(const uint32_t*)&sAl[r][c + 8];
                al[mt][3] = *(const uint32_t*)&sAl[r + 8][c + 8];
            }
            #pragma unroll
            for (int nt = 0; nt < 2; nt++) {
                int r = wn * 16 + nt * 8 + gid;
                bh[nt][0] = *(const uint32_t*)&sBh[r][c];
                bh[nt][1] = *(const uint32_t*)&sBh[r][c + 8];
                bl[nt][0] = *(const uint32_t*)&sBl[r][c];
                bl[nt][1] = *(const uint32_t*)&sBl[r][c + 8];
            }
            #pragma unroll
            for (int mt = 0; mt < 2; mt++)
                #pragma unroll
                for (int nt = 0; nt < 2; nt++) {
                    mma16816(acc[mt][nt], ah[mt], bh[nt]);
                    mma16816(acc[mt][nt], ah[mt], bl[nt]);
                    mma16816(acc[mt][nt], al[mt], bh[nt]);
                }
        }
        __syncthreads();
    }

    #pragma unroll
    for (int mt = 0; mt < 2; mt++) {
        #pragma unroll
        for (int nt = 0; nt < 2; nt++) {
            int n0 = bn + wn * 16 + nt * 8 + tig * 2;
            #pragma unroll
            for (int half = 0; half < 2; half++) {
                int m0 = bm + wm * 32 + mt * 16 + gid + half * 8;
                if (m0 >= BNROWS) continue;
                #pragma unroll
                for (int jj = 0; jj < 2; jj++) {
                    int n = n0 + jj;
                    float v = acc[mt][nt][half * 2 + jj];
                    if (n < Cv) v += bq[n];
                    if (n < 2 * Cv) {
                        size_t o = (size_t)m0 * QKVC + n;
                        split_bf16(v, g_qkvhi[o], g_qkvlo[o]);
                    } else {
                        int h = (n - 2 * Cv) >> 5, c = (n - 2 * Cv) & 31;
                        int b = m0 / Nv, p = m0 - b * Nv;
                        size_t o = ((size_t)(b * HEADS + h) * HC + c) * AP + p;
                        split_bf16(v, g_vthi[o], g_vtlo[o]);
                    }
                }
            }
        }
    }
}

// ================= fused HMMA: t1co (175 blocks) + qk (1536 blocks) =================
#define T1_BLOCKS 175
__global__ __launch_bounds__(256, 4)
void fused_t1qk_hmma(const float* __restrict__ bo1)
{
    __shared__ __align__(16) char smem_buf[20480];
    __nv_bfloat16 (*sAh)[40] = (__nv_bfloat16(*)[40])(smem_buf);
    __nv_bfloat16 (*sAl)[40] = (__nv_bfloat16(*)[40])(smem_buf + 5120);
    __nv_bfloat16 (*sBh)[40] = (__nv_bfloat16(*)[40])(smem_buf + 10240);
    __nv_bfloat16 (*sBl)[40] = (__nv_bfloat16(*)[40])(smem_buf + 15360);

    const int tid  = threadIdx.x;
    const int lane = tid & 31;
    const int w    = tid >> 5;
    const int wm   = w >> 2;
    const int wn   = w & 3;
    const int gid = lane >> 2;
    const int tig = lane & 3;
    const int srow = tid >> 2, sc8 = (tid & 3) * 8;

    float acc[2][2][4];
    #pragma unroll
    for (int i = 0; i < 2; i++)
        #pragma unroll
        for (int j = 0; j < 2; j++)
            #pragma unroll
            for (int q = 0; q < 4; q++) acc[i][j][q] = 0.0f;

    if (blockIdx.x < T1_BLOCKS) {
        const int bm = (blockIdx.x / 7) * 64;
        const int bn = (blockIdx.x % 7) * 64;
        for (int kc = 0; kc < 12; kc++) {
            const int k0 = kc * 32;
            {
                int m = bm + srow;
                uint4 vh = make_uint4(0u,0u,0u,0u), vl = vh;
                if (m < BNROWS) {
                    size_t o = (size_t)m * QKVC + k0 + sc8;
                    vh = *(const uint4*)&g_qkvhi[o];
                    vl = *(const uint4*)&g_qkvlo[o];
                }
                *(uint4*)&sAh[srow][sc8] = vh;
                *(uint4*)&sAl[srow][sc8] = vl;
                size_t ob = (size_t)(bn + srow) * Cv + k0 + sc8;
                *(uint4*)&sBh[srow][sc8] = *(const uint4*)&g_w2hi[ob];
                *(uint4*)&sBl[srow][sc8] = *(const uint4*)&g_w2lo[ob];
            }
            __syncthreads();
            #pragma unroll
            for (int kk = 0; kk < 32; kk += 16) {
                uint32_t ah[2][4], al[2][4], bh[2][2], bl[2][2];
                const int c = kk + tig * 2;
                #pragma unroll
                for (int mt = 0; mt < 2; mt++) {
                    int r = wm * 32 + mt * 16 + gid;
                    ah[mt][0] = *(const uint32_t*)&sAh[r][c];
                    ah[mt][1] = *(const uint32_t*)&sAh[r + 8][c];
                    ah[mt][2] = *(const uint32_t*)&sAh[r][c + 8];
                    ah[mt][3] = *(const uint32_t*)&sAh[r + 8][c + 8];
                    al[mt][0] = *(const uint32_t*)&sAl[r][c];
                    al[mt][1] = *(const uint32_t*)&sAl[r + 8][c];
                    al[mt][2] = *(const uint32_t*)&sAl[r][c + 8];
                    al[mt][3] = *(const uint32_t*)&sAl[r + 8][c + 8];
                }
                #pragma unroll
                for (int nt = 0; nt < 2; nt++) {
                    int r = wn * 16 + nt * 8 + gid;
                    bh[nt][0] = *(const uint32_t*)&sBh[r][c];
                    bh[nt][1] = *(const uint32_t*)&sBh[r][c + 8];
                    bl[nt][0] = *(const uint32_t*)&sBl[r][c];
                    bl[nt][1] = *(const uint32_t*)&sBl[r][c + 8];
                }
                #pragma unroll
                for (int mt = 0; mt < 2; mt++)
                    #pragma unroll
                    for (int nt = 0; nt < 2; nt++) {
                        mma16816(acc[mt][nt], ah[mt], bh[nt]);
                        mma16816(acc[mt][nt], ah[mt], bl[nt]);
                        mma16816(acc[mt][nt], al[mt], bh[nt]);
                    }
            }
            __syncthreads();
        }
        #pragma unroll
        for (int mt = 0; mt < 2; mt++) {
            #pragma unroll
            for (int nt = 0; nt < 2; nt++) {
                int n0 = bn + wn * 16 + nt * 8 + tig * 2;
                #pragma unroll
                for (int half = 0; half < 2; half++) {
                    int m0 = bm + wm * 32 + mt * 16 + gid + half * 8;
                    if (m0 >= BNROWS) continue;
                    #pragma unroll
                    for (int jj = 0; jj < 2; jj++) {
                        float v = acc[mt][nt][half * 2 + jj];
                        int n = n0 + jj;
                        if (n < Cv) {
                            g_t1[(size_t)m0 * Cv + n] = gelu_exact(v + bo1[n]);
                        } else if (n < Cv + 2 * KKv) {
                            g_co[(size_t)m0 * (2 * KKv) + (n - Cv)] = tanhf(v) * (1.0f / 14.0f);
                        }
                    }
                }
            }
        }
    } else {
        const int idx2 = blockIdx.x - T1_BLOCKS;
        const int bxq = idx2 & 3;
        const int byq = (idx2 >> 2) & 3;
        const int bh  = idx2 >> 4;
        const int b = bh / HEADS, h = bh - b * HEADS;
        const int n0b = byq * 64, p0b = bxq * 64;
        {
            int sc8q = (tid & 3) * 8;
            if (sc8q < 32) {
                int n = n0b + srow;
                uint4 vh = make_uint4(0u,0u,0u,0u), vl = vh;
                if (n < Nv) {
                    size_t o = ((size_t)(b*Nv + n))*QKVC + h*HC + sc8q;
                    vh = *(const uint4*)&g_qkvhi[o];
                    vl = *(const uint4*)&g_qkvlo[o];
                }
                *(uint4*)&sAh[srow][sc8q] = vh;
                *(uint4*)&sAl[srow][sc8q] = vl;
                int p = p0b + srow;
                uint4 wh = make_uint4(0u,0u,0u,0u), wl = wh;
                if (p < Nv) {
                    size_t o = ((size_t)(b*Nv + p))*QKVC + Cv + h*HC + sc8q;
                    wh = *(const uint4*)&g_qkvhi[o];
                    wl = *(const uint4*)&g_qkvlo[o];
                }
                *(uint4*)&sBh[srow][sc8q] = wh;
                *(uint4*)&sBl[srow][sc8q] = wl;
            }
        }
        __syncthreads();
        #pragma unroll
        for (int kk = 0; kk < 32; kk += 16) {
            uint32_t ah[2][4], al[2][4], bh2[2][2], bl2[2][2];
            const int c = kk + tig * 2;
            #pragma unroll
            for (int mt = 0; mt < 2; mt++) {
                int r = wm * 32 + mt * 16 + gid;
                ah[mt][0] = *(const uint32_t*)&sAh[r][c];
                ah[mt][1] = *(const uint32_t*)&sAh[r + 8][c];
                ah[mt][2] = *(const uint32_t*)&sAh[r][c + 8];
                ah[mt][3] = *(const uint32_t*)&sAh[r + 8][c + 8];
                al[mt][0] = *(const uint32_t*)&sAl[r][c];
                al[mt][1] = *(const uint32_t*)&sAl[r + 8][c];
                al[mt][2] = *(const uint32_t*)&sAl[r][c + 8];
                al[mt][3] = *(const uint32_t*)&sAl[r + 8][c + 8];
            }
            #pragma unroll
            for (int nt = 0; nt < 2; nt++) {
                int r = wn * 16 + nt * 8 + gid;
                bh2[nt][0] = *(const uint32_t*)&sBh[r][c];
                bh2[nt][1] = *(const uint32_t*)&sBh[r][c + 8];
                bl2[nt][0] = *(const uint32_t*)&sBl[r][c];
                bl2[nt][1] = *(const uint32_t*)&sBl[r][c + 8];
            }
            #pragma unroll
            for (int mt = 0; mt < 2; mt++)
                #pragma unroll
                for (int nt = 0; nt < 2; nt++) {
                    mma16816(acc[mt][nt], ah[mt], bh2[nt]);
                    mma16816(acc[mt][nt], ah[mt], bl2[nt]);
                    mma16816(acc[mt][nt], al[mt], bh2[nt]);
                }
        }
        float* qkb = g_qk + ((size_t)bh * Nv) * Nv;
        #pragma unroll
        for (int mt = 0; mt < 2; mt++) {
            #pragma unroll
            for (int nt = 0; nt < 2; nt++) {
                int p0 = p0b + wn * 16 + nt * 8 + tig * 2;
                #pragma unroll
                for (int half = 0; half < 2; half++) {
                    int n = n0b + wm * 32 + mt * 16 + gid + half * 8;
                    if (n >= Nv) continue;
                    if (p0 < Nv)     qkb[(size_t)n * Nv + p0]     = acc[mt][nt][half * 2 + 0];
                    if (p0 + 1 < Nv) qkb[(size_t)n * Nv + p0 + 1] = acc[mt][nt][half * 2 + 1];
                }
            }
        }
    }
}

// ================= gemm_off via HMMA (split-K x2): g_off += t3 @ Wo2^T =================
__global__ __launch_bounds__(256, 4)
void off_hmma()
{
    __shared__ __align__(16) __nv_bfloat16 sAh[64][40];
    __shared__ __align__(16) __nv_bfloat16 sAl[64][40];
    __shared__ __align__(16) __nv_bfloat16 sBh[64][40];
    __shared__ __align__(16) __nv_bfloat16 sBl[64][40];

    const int M = Bv * Sv;      // 392
    const int tid  = threadIdx.x;
    const int lane = tid & 31;
    const int w    = tid >> 5;
    const int wm   = w >> 2;
    const int wn   = w & 3;
    const int bm = blockIdx.y * 64;
    const int bn = blockIdx.x * 64;
    const int kbase = blockIdx.z * 192;
    const int gid = lane >> 2;
    const int tig = lane & 3;
    const int srow = tid >> 2, sc8 = (tid & 3) * 8;

    float acc[2][2][4];
    #pragma unroll
    for (int i = 0; i < 2; i++)
        #pragma unroll
        for (int j = 0; j < 2; j++)
            #pragma unroll
            for (int q = 0; q < 4; q++) acc[i][j][q] = 0.0f;

    for (int kc = 0; kc < 6; kc++) {
        const int k0 = kbase + kc * 32;
        {
            int m = bm + srow;
            uint4 vh = make_uint4(0u,0u,0u,0u), vl = vh;
            if (m < M) {
                size_t o = (size_t)m * Cv + k0 + sc8;
                vh = *(const uint4*)&g_t3hi[o];
                vl = *(const uint4*)&g_t3lo[o];
            }
            *(uint4*)&sAh[srow][sc8] = vh;
            *(uint4*)&sAl[srow][sc8] = vl;
            int n = bn + srow;
            uint4 wh = make_uint4(0u,0u,0u,0u), wl = wh;
            if (n < M) {
                size_t o = (size_t)n * Cv + k0 + sc8;
                wh = *(const uint4*)&g_wo2hi[o];
                wl = *(const uint4*)&g_wo2lo[o];
            }
            *(uint4*)&sBh[srow][sc8] = wh;
            *(uint4*)&sBl[srow][sc8] = wl;
        }
        __syncthreads();
        #pragma unroll
        for (int kk = 0; kk < 32; kk += 16) {
            uint32_t ah[2][4], al[2][4], bh[2][2], bl[2][2];
            const int c = kk + tig * 2;
            #pragma unroll
            for (int mt = 0; mt < 2; mt++) {
                int r = wm * 32 + mt * 16 + gid;
                ah[mt][0] = *(const uint32_t*)&sAh[r][c];
                ah[mt][1] = *(const uint32_t*)&sAh[r + 8][c];
                ah[mt][2] = *(const uint32_t*)&sAh[r][c + 8];
                ah[mt][3] = *(const uint32_t*)&sAh[r + 8][c + 8];
                al[mt][0] = *(const uint32_t*)&sAl[r][c];
                al[mt][1] = *(const uint32_t*)&sAl[r + 8][c];
                al[mt][2] = *(const uint32_t*)&sAl[r][c + 8];
                al[mt][3] = *(const uint32_t*)&sAl[r + 8][c + 8];
            }
            #pragma unroll
            for (int nt = 0; nt < 2; nt++) {
                int r = wn * 16 + nt * 8 + gid;
                bh[nt][0] = *(const uint32_t*)&sBh[r][c];
                bh[nt][1] = *(const uint32_t*)&sBh[r][c + 8];
                bl[nt][0] = *(const uint32_t*)&sBl[r][c];
                bl[nt][1] = *(const uint32_t*)&sBl[r][c + 8];
            }
            #pragma unroll
            for (int mt = 0; mt < 2; mt++)
                #pragma unroll
                for (int nt = 0; nt < 2; nt++) {
                    mma16816(acc[mt][nt], ah[mt], bh[nt]);
                    mma16816(acc[mt][nt], ah[mt], bl[nt]);
                    mma16816(acc[mt][nt], al[mt], bh[nt]);
                }
        }
        __syncthreads();
    }

    #pragma unroll
    for (int mt = 0; mt < 2; mt++) {
        #pragma unroll
        for (int nt = 0; nt < 2; nt++) {
            int n0 = bn + wn * 16 + nt * 8 + tig * 2;
            #pragma unroll
            for (int half = 0; half < 2; half++) {
                int m0 = bm + wm * 32 + mt * 16 + gid + half * 8;
                if (m0 >= M) continue;
                #pragma unroll
                for (int jj = 0; jj < 2; jj++) {
                    int n = n0 + jj;
                    if (n < M) atomicAdd(&g_off[(size_t)m0 * (2*Nv) + n], acc[mt][nt][half * 2 + jj]);
                }
            }
        }
    }
}

// ================= proj HMMA (split-K x2): out += Wp @ ao^T =================
__global__ __launch_bounds__(256, 4)
void proj_hmma(float* __restrict__ out)
{
    __shared__ __align__(16) __nv_bfloat16 sAh[64][40];
    __shared__ __align__(16) __nv_bfloat16 sAl[64][40];
    __shared__ __align__(16) __nv_bfloat16 sBh[64][40];
    __shared__ __align__(16) __nv_bfloat16 sBl[64][40];

    const int tid  = threadIdx.x;
    const int lane = tid & 31;
    const int w    = tid >> 5;
    const int wm   = w >> 2;
    const int wn   = w & 3;
    const int bm = blockIdx.y * 64;
    const int bn = blockIdx.x * 64;
    const int kbase = blockIdx.z * 192;
    const int gid = lane >> 2;
    const int tig = lane & 3;
    const int srow = tid >> 2, sc8 = (tid & 3) * 8;

    float acc[2][2][4];
    #pragma unroll
    for (int i = 0; i < 2; i++)
        #pragma unroll
        for (int j = 0; j < 2; j++)
            #pragma unroll
            for (int q = 0; q < 4; q++) acc[i][j][q] = 0.0f;

    for (int kc = 0; kc < 6; kc++) {
        const int k0 = kbase + kc * 32;
        {
            size_t oa = (size_t)(bm + srow) * Cv + k0 + sc8;
            *(uint4*)&sAh[srow][sc8] = *(const uint4*)&g_wphi[oa];
            *(uint4*)&sAl[srow][sc8] = *(const uint4*)&g_wplo[oa];
            int n = bn + srow;
            uint4 vh = make_uint4(0u,0u,0u,0u), vl = vh;
            if (n < BNROWS) {
                size_t o = (size_t)n * Cv + k0 + sc8;
                vh = *(const uint4*)&g_aohi[o];
                vl = *(const uint4*)&g_aolo[o];
            }
            *(uint4*)&sBh[srow][sc8] = vh;
            *(uint4*)&sBl[srow][sc8] = vl;
        }
        __syncthreads();
        #pragma unroll
        for (int kk = 0; kk < 32; kk += 16) {
            uint32_t ah[2][4], al[2][4], bh[2][2], bl[2][2];
            const int c = kk + tig * 2;
            #pragma unroll
            for (int mt = 0; mt < 2; mt++) {
                int r = wm * 32 + mt * 16 + gid;
                ah[mt][0] = *(const uint32_t*)&sAh[r][c];
                ah[mt][1] = *(const uint32_t*)&sAh[r + 8][c];
                ah[mt][2] = *(const uint32_t*)&sAh[r][c + 8];
                ah[mt][3] = *(const uint32_t*)&sAh[r + 8][c + 8];
                al[mt][0] = *(const uint32_t*)&sAl[r][c];
                al[mt][1] = *(const uint32_t*)&sAl[r + 8][c];
                al[mt][2] = *(const uint32_t*)&sAl[r][c + 8];
                al[mt][3] = *(const uint32_t*)&sAl[r + 8][c + 8];
            }
            #pragma unroll
            for (int nt = 0; nt < 2; nt++) {
                int r = wn * 16 + nt * 8 + gid;
                bh[nt][0] = *(const uint32_t*)&sBh[r][c];
                bh[nt][1] = *(const uint32_t*)&sBh[r][c + 8];
                bl[nt][0] = *(const uint32_t*)&sBl[r][c];
                bl[nt][1] = *(const uint32_t*)&sBl[r][c + 8];
            }
            #pragma unroll
            for (int mt = 0; mt < 2; mt++)
                #pragma unroll
                for (int nt = 0; nt < 2; nt++) {
                    mma16816(acc[mt][nt], ah[mt], bh[nt]);
                    mma16816(acc[mt][nt], ah[mt], bl[nt]);
                    mma16816(acc[mt][nt], al[mt], bh[nt]);
                }
        }
        __syncthreads();
    }

    #pragma unroll
    for (int mt = 0; mt < 2; mt++) {
        #pragma unroll
        for (int nt = 0; nt < 2; nt++) {
            int n0 = bn + wn * 16 + nt * 8 + tig * 2;
            #pragma unroll
            for (int half = 0; half < 2; half++) {
                int m0 = bm + wm * 32 + mt * 16 + gid + half * 8;
                #pragma unroll
                for (int jj = 0; jj < 2; jj++) {
                    int n = n0 + jj;
                    if (n >= BNROWS) continue;
                    int b = n / Nv, nn = n - b * Nv;
                    atomicAdd(&out[((size_t)(b * Cv + m0)) * Nv + nn], acc[mt][nt][half * 2 + jj]);
                }
            }
        }
    }
}

// ================= dwln: depthwise conv + LN + GELU -> t3 hi/lo (+ zero g_off row) ========
__global__ void dwln_kernel(const float* __restrict__ Wdw, const float* __restrict__ bdw,
                            const float* __restrict__ lng, const float* __restrict__ lnb)
{
    int bs = blockIdx.x;
    int b = bs / Sv, s = bs % Sv;
    int oy = s / rWv, ox = s % rWv;
    int c = threadIdx.x;

    for (int i = c; i < 2 * Nv; i += blockDim.x)
        g_off[(size_t)bs * (2 * Nv) + i] = 0.0f;

    float acc = bdw[c];
    #pragma unroll
    for (int ky = 0; ky < 3; ky++) {
        int y = oy*2 - 1 + ky;
        if (y < 0 || y >= Hv) continue;
        #pragma unroll
        for (int kx = 0; kx < 3; kx++) {
            int x = ox*2 - 1 + kx;
            if (x < 0 || x >= Wv_) continue;
            acc = fmaf(g_t1[((size_t)b*Nv + y*Wv_ + x)*Cv + c], Wdw[c*9 + ky*3 + kx], acc);
        }
    }
    float s1 = acc, s2 = acc*acc;
    #pragma unroll
    for (int o = 16; o > 0; o >>= 1) {
        s1 += __shfl_xor_sync(0xffffffffu, s1, o);
        s2 += __shfl_xor_sync(0xffffffffu, s2, o);
    }
    __shared__ float w1[12], w2[12];
    __shared__ float s_mu, s_rstd;
    if ((c & 31) == 0) { w1[c >> 5] = s1; w2[c >> 5] = s2; }
    __syncthreads();
    if (c == 0) {
        float t1s = 0.f, t2s = 0.f;
        #pragma unroll
        for (int i = 0; i < 12; i++) { t1s += w1[i]; t2s += w2[i]; }
        float mu = t1s / (float)Cv;
        float var = t2s / (float)Cv - mu*mu;
        s_mu = mu; s_rstd = rsqrtf(var + 1e-5f);
    }
    __syncthreads();
    float v = gelu_exact((acc - s_mu) * s_rstd * lng[c] + lnb[c]);
    split_bf16(v, g_t3hi[(size_t)bs*Cv + c], g_t3lo[(size_t)bs*Cv + c]);
}

// ================= scores + softmax -> dense bf16 prob matrix =================
__global__ void score_kernel(const float* __restrict__ posembed)
{
    const int bn = blockIdx.x;
    const int b = bn / Nv, n = bn % Nv;
    const int ny = n / Wv_, nx = n % Wv_;
    __shared__ float sc[HEADS*TS];
    __shared__ int   sp[TS*4];
    __shared__ float swt[TS*4];
    __shared__ __align__(16) float sA[HEADS][Nv];

    for (int idx = threadIdx.x; idx < HEADS*Nv/4; idx += blockDim.x)
        ((float4*)sA)[idx] = make_float4(0.f, 0.f, 0.f, 0.f);

    for (int item = threadIdx.x; item < HEADS*TS; item += blockDim.x) {
        const int h = item / TS, s = item % TS;
        float py, px, tpy, tpx;
        if (s < Sv) {
            int rh = s / rWv, rw = s % rWv;
            float offy = tanhf(g_off[((size_t)b*Sv + s)*(2*Nv) + 0*Nv + n]) * (2.0f/14.0f);
            float offx = tanhf(g_off[((size_t)b*Sv + s)*(2*Nv) + 1*Nv + n]) * (2.0f/14.0f);
            float refy = (float)(rh*2) * (2.0f/13.0f) - 1.0f;
            float refx = (float)(rw*2) * (2.0f/13.0f) - 1.0f;
            py = (offy + refy + 1.0f) * 6.5f;
            px = (offx + refx + 1.0f) * 6.5f;
            tpy = ((float)(2*rh - ny) * (1.0f/13.0f) - offy + 1.0f) * 13.0f;
            tpx = ((float)(2*rw - nx) * (1.0f/13.0f) - offx + 1.0f) * 13.0f;
        } else {
            int j = s - Sv;
            float coy = g_co[((size_t)b*Nv + n)*(2*KKv) + j*2 + 0];
            float cox = g_co[((size_t)b*Nv + n)*(2*KKv) + j*2 + 1];
            float cy = (float)ny + c_offm[j][0];
            float cx = (float)nx + c_offm[j][1];
            float cny = fminf(fmaxf(cy, 0.0f), 14.0f) * (2.0f/13.0f) - 1.0f;
            float cnx = fminf(fmaxf(cx, 0.0f), 14.0f) * (2.0f/13.0f) - 1.0f;
            py = (coy + cny + 1.0f) * 6.5f;
            px = (cox + cnx + 1.0f) * 6.5f;
            tpy = (coy - (float)ny + 1.0f) * 13.0f;
            tpx = (cox - (float)nx + 1.0f) * 13.0f;
        }
        float y0 = floorf(py), x0 = floorf(px);
        float wy1 = py - y0, wx1 = px - x0;
        const float* qkb = g_qk + (((size_t)(b*HEADS + h))*Nv + n)*Nv;
        float val = 0.0f;
        #pragma unroll
        for (int ccy = 0; ccy < 2; ccy++) {
            #pragma unroll
            for (int ccx = 0; ccx < 2; ccx++) {
                float yf = y0 + (float)ccy, xf = x0 + (float)ccx;
                float w = (ccy ? wy1 : 1.0f - wy1) * (ccx ? wx1 : 1.0f - wx1);
                bool valid = (yf >= 0.0f) && (yf <= 13.0f) && (xf >= 0.0f) && (xf <= 13.0f);
                if (!valid) w = 0.0f;
                int yi = (int)fminf(fmaxf(yf, 0.0f), 13.0f);
                int xi = (int)fminf(fmaxf(xf, 0.0f), 13.0f);
                int pix = yi*Wv_ + xi;
                val += w * qkb[pix];
                if (h == 0) { sp[s*4 + ccy*2 + ccx] = pix; swt[s*4 + ccy*2 + ccx] = w; }
            }
        }
        float by0 = floorf(tpy), bx0 = floorf(tpx);
        float bwy = tpy - by0, bwx = tpx - bx0;
        const float* tb = posembed + (size_t)h * (27*27);
        float bval = 0.0f;
        #pragma unroll
        for (int ccy = 0; ccy < 2; ccy++) {
            #pragma unroll
            for (int ccx = 0; ccx < 2; ccx++) {
                float yf = by0 + (float)ccy, xf = bx0 + (float)ccx;
                float w = (ccy ? bwy : 1.0f - bwy) * (ccx ? bwx : 1.0f - bwx);
                bool valid = (yf >= 0.0f) && (yf <= 26.0f) && (xf >= 0.0f) && (xf <= 26.0f);
                if (!valid) w = 0.0f;
                int yi = (int)fminf(fmaxf(yf, 0.0f), 26.0f);
                int xi = (int)fminf(fmaxf(xf, 0.0f), 26.0f);
                bval += w * tb[yi*27 + xi];
            }
        }
        sc[h*TS + s] = val + bval;
    }
    __syncthreads();

    const int wid = threadIdx.x >> 5, lane = threadIdx.x & 31;
    {
        float m = -1e30f;
        for (int s = lane; s < TS; s += 32) m = fmaxf(m, sc[wid*TS + s]);
        #pragma unroll
        for (int o = 16; o > 0; o >>= 1) m = fmaxf(m, __shfl_xor_sync(0xffffffffu, m, o));
        float sum = 0.0f;
        for (int s = lane; s < TS; s += 32) {
            float e = expf(sc[wid*TS + s] - m);
            sc[wid*TS + s] = e;
            sum += e;
        }
        #pragma unroll
        for (int o = 16; o > 0; o >>= 1) sum += __shfl_xor_sync(0xffffffffu, sum, o);
        float inv = 1.0f / sum;
        for (int s = lane; s < TS; s += 32) sc[wid*TS + s] *= inv;
    }
    for (int i = lane; i < TS*4; i += 32) {
        atomicAdd(&sA[wid][sp[i]], sc[wid*TS + (i >> 2)] * swt[i]);
    }
    __syncthreads();

    for (int idx = threadIdx.x; idx < HEADS*Nv; idx += blockDim.x) {
        int h = idx / Nv, p = idx - h * Nv;
        size_t o = ((size_t)(b*HEADS + h)*Nv + n)*AP + p;
        split_bf16(sA[h][p], g_Ahi[o], g_Alo[o]);
    }
}

// ================= av via HMMA: ao[n][c] = A @ V (+bv), seeds out with bp =================
__global__ __launch_bounds__(256, 4)
void av_hmma(const float* __restrict__ bvv, const float* __restrict__ bp, float* __restrict__ out)
{
    __shared__ __align__(16) __nv_bfloat16 sAh[64][40];
    __shared__ __align__(16) __nv_bfloat16 sAl[64][40];
    __shared__ __align__(16) __nv_bfloat16 sBh[32][40];
    __shared__ __align__(16) __nv_bfloat16 sBl[32][40];

    const int tid  = threadIdx.x;
    const int lane = tid & 31;
    const int w    = tid >> 5;
    const int wm   = w >> 1;        // 0..3
    const int wn   = w & 1;         // 0..1
    const int bm = blockIdx.x * 64;
    const int bh = blockIdx.y;
    const int b = bh / HEADS, h = bh - b * HEADS;
    const int gid = lane >> 2;
    const int tig = lane & 3;
    const int srow = tid >> 2, sc8 = (tid & 3) * 8;

    // seed out slab with proj bias
    for (int i = tid; i < 64 * HC; i += 256) {
        int nn = bm + (i & 63);
        int c  = h * HC + (i >> 6);
        if (nn < Nv) out[((size_t)(b * Cv + c)) * Nv + nn] = bp[c];
    }

    float acc[2][4];
    #pragma unroll
    for (int j = 0; j < 2; j++)
        #pragma unroll
        for (int q = 0; q < 4; q++) acc[j][q] = 0.0f;

    const __nv_bfloat16* Abh = g_Ahi + (size_t)bh * Nv * AP;
    const __nv_bfloat16* Abl = g_Alo + (size_t)bh * Nv * AP;
    const __nv_bfloat16* Vbh = g_vthi + (size_t)bh * HC * AP;
    const __nv_bfloat16* Vbl = g_vtlo + (size_t)bh * HC * AP;

    for (int p0 = 0; p0 < AP; p0 += 32) {
        {
            int m = bm + srow;
            uint4 vh = make_uint4(0u,0u,0u,0u), vl = vh;
            if (m < Nv) {
                size_t o = (size_t)m * AP + p0 + sc8;
                vh = *(const uint4*)&Abh[o];
                vl = *(const uint4*)&Abl[o];
            }
            *(uint4*)&sAh[srow][sc8] = vh;
            *(uint4*)&sAl[srow][sc8] = vl;
            if (srow < 32) {
                size_t o = (size_t)srow * AP + p0 + sc8;
                *(uint4*)&sBh[srow][sc8] = *(const uint4*)&Vbh[o];
                *(uint4*)&sBl[srow][sc8] = *(const uint4*)&Vbl[o];
            }
        }
        __syncthreads();
        #pragma unroll
        for (int kk = 0; kk < 32; kk += 16) {
            uint32_t ah[4], al[4], bh2[2][2], bl2[2][2];
            const int c = kk + tig * 2;
            {
                int r = wm * 16 + gid;
                ah[0] = *(const uint32_t*)&sAh[r][c];
                ah[1] = *(const uint32_t*)&sAh[r + 8][c];
                ah[2] = *(const uint32_t*)&sAh[r][c + 8];
                ah[3] = *(const uint32_t*)&sAh[r + 8][c + 8];
                al[0] = *(const uint32_t*)&sAl[r][c];
                al[1] = *(const uint32_t*)&sAl[r + 8][c];
                al[2] = *(const uint32_t*)&sAl[r][c + 8];
                al[3] = *(const uint32_t*)&sAl[r + 8][c + 8];
            }
            #pragma unroll
            for (int nt = 0; nt < 2; nt++) {
                int r = wn * 16 + nt * 8 + gid;
                bh2[nt][0] = *(const uint32_t*)&sBh[r][c];
                bh2[nt][1] = *(const uint32_t*)&sBh[r][c + 8];
                bl2[nt][0] = *(const uint32_t*)&sBl[r][c];
                bl2[nt][1] = *(const uint32_t*)&sBl[r][c + 8];
            }
            #pragma unroll
            for (int nt = 0; nt < 2; nt++) {
                mma16816(acc[nt], ah, bh2[nt]);
                mma16816(acc[nt], ah, bl2[nt]);
                mma16816(acc[nt], al, bh2[nt]);
            }
        }
        __syncthreads();
    }

    #pragma unroll
    for (int nt = 0; nt < 2; nt++) {
        int c0 = wn * 16 + nt * 8 + tig * 2;
        #pragma unroll
        for (int half = 0; half < 2; half++) {
            int n = bm + wm * 16 + gid + half * 8;
            if (n >= Nv) continue;
            #pragma unroll
            for (int jj = 0; jj < 2; jj++) {
                int c = c0 + jj;
                float v = acc[nt][half * 2 + jj] + bvv[h * HC + c];
                size_t o = ((size_t)(b*Nv + n))*Cv + h*HC + c;
                split_bf16(v, g_aohi[o], g_aolo[o]);
            }
        }
    }
}

extern "C" void kernel_launch(void* const* d_in, const int* in_sizes, int n_in,
                              void* d_out, int out_size)
{
    const float* x    = (const float*)d_in[0];
    const float* Wq   = (const float*)d_in[1];
    const float* bq   = (const float*)d_in[2];
    const float* Wk   = (const float*)d_in[3];
    // bk cancels in softmax — unused
    const float* Wvv  = (const float*)d_in[5];
    const float* bvv  = (const float*)d_in[6];
    const float* Wo1  = (const float*)d_in[7];
    const float* bo1  = (const float*)d_in[8];
    const float* Wdw  = (const float*)d_in[9];
    const float* bdw  = (const float*)d_in[10];
    const float* lng  = (const float*)d_in[11];
    const float* lnb  = (const float*)d_in[12];
    const float* Wo2  = (const float*)d_in[13];
    const float* Wco  = (const float*)d_in[14];
    const float* pos  = (const float*)d_in[15];
    const float* Wp   = (const float*)d_in[16];
    const float* bp   = (const float*)d_in[17];
    float* out = (float*)d_out;

    // 0) splits
    prep_kernel<<<1563, 256>>>(x, Wq, Wk, Wvv, Wo1, Wco, Wp, Wo2);
    // 1) qkv HMMA (q|xK -> g_qkvhi/lo, V -> g_vt transposed)
    qkv_hmma<<<dim3(18, 25), 256>>>(bq);
    // 2) fused HMMA: t1co + qk
    fused_t1qk_hmma<<<T1_BLOCKS + 16 * Bv * HEADS, 256>>>(bo1);
    // 3) offset net tail
    dwln_kernel<<<Bv*Sv, Cv>>>(Wdw, bdw, lng, lnb);
    off_hmma<<<dim3(7, 7, 2), 256>>>();
    // 4) scores -> probs -> dense bf16 A
    score_kernel<<<Bv*Nv, 384>>>(pos);
    // 5) AV via HMMA (+ seed out with proj bias)
    av_hmma<<<dim3(4, Bv*HEADS), 256>>>(bvv, bp, out);
    // 6) final projection HMMA (split-K x2, atomics into bias-seeded out)
    proj_hmma<<<dim3(25, 6, 2), 256>>>(out);
}

// round 15
// speedup vs baseline: 2.1790x; 1.0389x over previous
#include <cuda_runtime.h>
#include <cuda_bf16.h>
#include <math.h>
#include <stdint.h>

#define Bv   8
#define Cv   384
#define Hv   14
#define Wv_  14
#define HEADS 12
#define HC   32
#define Nv   196
#define Sv   49
#define rHv  7
#define rWv  7
#define KKv  9
#define TS   58
#define BNROWS (Bv*Nv)   // 1568
#define QKVC 1152
#define N2   448
#define AP   224

// fp32 scratch
__device__ __align__(16) float g_t1 [BNROWS*Cv];
__device__ __align__(16) float g_off [Bv*Sv*2*Nv];   // split-K partial 0
__device__ __align__(16) float g_off2[Bv*Sv*2*Nv];   // split-K partial 1
__device__ __align__(16) float g_co [BNROWS*2*KKv];
__device__ __align__(16) float g_qk [(size_t)Bv*HEADS*Nv*Nv];
// bf16 split operands
__device__ __align__(16) __nv_bfloat16 g_xhi[BNROWS*Cv];
__device__ __align__(16) __nv_bfloat16 g_xlo[BNROWS*Cv];
__device__ __align__(16) __nv_bfloat16 g_whi[QKVC*Cv];
__device__ __align__(16) __nv_bfloat16 g_wlo[QKVC*Cv];
__device__ __align__(16) __nv_bfloat16 g_qkvhi[BNROWS*QKVC];
__device__ __align__(16) __nv_bfloat16 g_qkvlo[BNROWS*QKVC];
__device__ __align__(16) __nv_bfloat16 g_w2hi[N2*Cv];
__device__ __align__(16) __nv_bfloat16 g_w2lo[N2*Cv];
__device__ __align__(16) __nv_bfloat16 g_wphi[Cv*Cv];
__device__ __align__(16) __nv_bfloat16 g_wplo[Cv*Cv];
__device__ __align__(16) __nv_bfloat16 g_wo2hi[(Bv*Sv)*Cv];
__device__ __align__(16) __nv_bfloat16 g_wo2lo[(Bv*Sv)*Cv];
__device__ __align__(16) __nv_bfloat16 g_t3hi[(Bv*Sv)*Cv];
__device__ __align__(16) __nv_bfloat16 g_t3lo[(Bv*Sv)*Cv];
__device__ __align__(16) __nv_bfloat16 g_aohi[BNROWS*Cv];
__device__ __align__(16) __nv_bfloat16 g_aolo[BNROWS*Cv];
__device__ __align__(16) __nv_bfloat16 g_Ahi[(size_t)Bv*HEADS*Nv*AP];
__device__ __align__(16) __nv_bfloat16 g_Alo[(size_t)Bv*HEADS*Nv*AP];
__device__ __align__(16) __nv_bfloat16 g_vthi[(size_t)Bv*HEADS*HC*AP];
__device__ __align__(16) __nv_bfloat16 g_vtlo[(size_t)Bv*HEADS*HC*AP];

__constant__ float c_offm[9][2] = {
    {0.f,-1.f},{-1.f,-1.f},{-1.f,0.f},{-1.f,1.f},{0.f,1.f},{1.f,1.f},{1.f,0.f},{1.f,-1.f},{0.f,0.f}
};

__device__ __forceinline__ float gelu_exact(float v) {
    return 0.5f * v * (1.0f + erff(v * 0.7071067811865476f));
}
__device__ __forceinline__ void mma16816(float* c, const uint32_t* a, const uint32_t* b) {
    asm volatile(
        "mma.sync.aligned.m16n8k16.row.col.f32.bf16.bf16.f32 "
        "{%0,%1,%2,%3}, {%4,%5,%6,%7}, {%8,%9}, {%0,%1,%2,%3};"
        : "+f"(c[0]), "+f"(c[1]), "+f"(c[2]), "+f"(c[3])
        : "r"(a[0]), "r"(a[1]), "r"(a[2]), "r"(a[3]), "r"(b[0]), "r"(b[1]));
}
__device__ __forceinline__ void split_bf16(float v, __nv_bfloat16& h, __nv_bfloat16& l) {
    h = __float2bfloat16(v);
    l = __float2bfloat16(v - __bfloat162float(h));
}
__device__ __forceinline__ uint32_t pack_bf16(__nv_bfloat16 a, __nv_bfloat16 b) {
    uint32_t r;
    unsigned short ua = *(unsigned short*)&a, ub = *(unsigned short*)&b;
    r = (uint32_t)ua | ((uint32_t)ub << 16);
    return r;
}

// ================= prep =================
__global__ void prep_kernel(const float* __restrict__ x,
                            const float* __restrict__ Wq, const float* __restrict__ Wk,
                            const float* __restrict__ Wvv, const float* __restrict__ Wo1,
                            const float* __restrict__ Wco, const float* __restrict__ Wp,
                            const float* __restrict__ Wo2)
{
    const int bid = blockIdx.x;
    const int tid = threadIdx.x;
    if (bid < 672) {
        int nt = bid % 7, ct = (bid / 7) % 12, b = bid / 84;
        __shared__ float tile[32][33];
        int tx = tid & 31, ty = tid >> 5;
        int c0 = ct * 32, n0 = nt * 32;
        for (int i = ty; i < 32; i += 8) {
            int c = c0 + i, n = n0 + tx;
            tile[i][tx] = (n < Nv) ? x[((size_t)b*Cv + c)*Nv + n] : 0.0f;
        }
        __syncthreads();
        for (int i = ty; i < 32; i += 8) {
            int n = n0 + i, c = c0 + tx;
            if (n < Nv) {
                size_t o = ((size_t)b*Nv + n)*Cv + c;
                split_bf16(tile[tx][i], g_xhi[o], g_xlo[o]);
            }
        }
    } else if (bid < 1104) {
        int idx = (bid - 672) * 256 + tid;
        if (idx < QKVC * (Cv/4)) {
            int r = idx / (Cv/4), c4 = idx - r * (Cv/4);
            const float* src = (r < Cv) ? &Wq[(size_t)r*Cv]
                              : (r < 2*Cv ? &Wk[(size_t)(r - Cv)*Cv] : &Wvv[(size_t)(r - 2*Cv)*Cv]);
            float4 v = *(const float4*)&src[c4*4];
            size_t o = (size_t)r*Cv + c4*4;
            float vv[4] = {v.x, v.y, v.z, v.w};
            #pragma unroll
            for (int j = 0; j < 4; j++) split_bf16(vv[j], g_whi[o + j], g_wlo[o + j]);
        }
    } else if (bid < 1272) {
        int idx = (bid - 1104) * 256 + tid;
        if (idx < N2 * (Cv/4)) {
            int r = idx / (Cv/4), c4 = idx - r * (Cv/4);
            float4 v = make_float4(0.f, 0.f, 0.f, 0.f);
            if (r < Cv) v = *(const float4*)&Wo1[(size_t)r*Cv + c4*4];
            else if (r < Cv + 2*KKv) v = *(const float4*)&Wco[(size_t)(r - Cv)*Cv + c4*4];
            size_t o = (size_t)r*Cv + c4*4;
            float vv[4] = {v.x, v.y, v.z, v.w};
            #pragma unroll
            for (int j = 0; j < 4; j++) split_bf16(vv[j], g_w2hi[o + j], g_w2lo[o + j]);
        }
    } else if (bid < 1416) {
        int idx = (bid - 1272) * 256 + tid;
        if (idx < Cv * (Cv/4)) {
            int r = idx / (Cv/4), c4 = idx - r * (Cv/4);
            float4 v = *(const float4*)&Wp[(size_t)r*Cv + c4*4];
            size_t o = (size_t)r*Cv + c4*4;
            float vv[4] = {v.x, v.y, v.z, v.w};
            #pragma unroll
            for (int j = 0; j < 4; j++) split_bf16(vv[j], g_wphi[o + j], g_wplo[o + j]);
        }
    } else {
        int idx = (bid - 1416) * 256 + tid;
        if (idx < (Bv*Sv) * (Cv/4)) {
            int r = idx / (Cv/4), c4 = idx - r * (Cv/4);
            float4 v = *(const float4*)&Wo2[(size_t)r*Cv + c4*4];
            size_t o = (size_t)r*Cv + c4*4;
            float vv[4] = {v.x, v.y, v.z, v.w};
            #pragma unroll
            for (int j = 0; j < 4; j++) split_bf16(vv[j], g_wo2hi[o + j], g_wo2lo[o + j]);
        }
    }
}

// ================= qkv via HMMA; q|xK -> g_qkvhi/lo, V -> transposed g_vthi/lo ============
__global__ __launch_bounds__(256, 4)
void qkv_hmma(const float* __restrict__ bq)
{
    __shared__ __align__(16) __nv_bfloat16 sAh[64][40];
    __shared__ __align__(16) __nv_bfloat16 sAl[64][40];
    __shared__ __align__(16) __nv_bfloat16 sBh[64][40];
    __shared__ __align__(16) __nv_bfloat16 sBl[64][40];

    const int tid  = threadIdx.x;
    const int lane = tid & 31;
    const int w    = tid >> 5;
    const int wm   = w >> 2;
    const int wn   = w & 3;
    const int bm = blockIdx.y * 64;
    const int bn = blockIdx.x * 64;
    const int gid = lane >> 2;
    const int tig = lane & 3;
    const int srow = tid >> 2, sc8 = (tid & 3) * 8;

    float acc[2][2][4];
    #pragma unroll
    for (int i = 0; i < 2; i++)
        #pragma unroll
        for (int j = 0; j < 2; j++)
            #pragma unroll
            for (int q = 0; q < 4; q++) acc[i][j][q] = 0.0f;

    for (int kc = 0; kc < 12; kc++) {
        const int k0 = kc * 32;
        {
            int m = bm + srow;
            uint4 vh = make_uint4(0u,0u,0u,0u), vl = vh;
            if (m < BNROWS) {
                size_t o = (size_t)m * Cv + k0 + sc8;
                vh = *(const uint4*)&g_xhi[o];
                vl = *(const uint4*)&g_xlo[o];
            }
            *(uint4*)&sAh[srow][sc8] = vh;
            *(uint4*)&sAl[srow][sc8] = vl;
            size_t ob = (size_t)(bn + srow) * Cv + k0 + sc8;
            *(uint4*)&sBh[srow][sc8] = *(const uint4*)&g_whi[ob];
            *(uint4*)&sBl[srow][sc8] = *(const uint4*)&g_wlo[ob];
        }
        __syncthreads();
        #pragma unroll
        for (int kk = 0; kk < 32; kk += 16) {
            uint32_t ah[2][4], al[2][4], bh[2][2], bl[2][2];
            const int c = kk + tig * 2;
            #pragma unroll
            for (int mt = 0; mt < 2; mt++) {
                int r = wm * 32 + mt * 16 + gid;
                ah[mt][0] = *(const uint32_t*)&sAh[r][c];
                ah[mt][1] = *(const uint32_t*)&sAh[r + 8][c];
                ah[mt][2] = *(const uint32_t*)&sAh[r][c + 8];
                ah[mt][3] = *(const uint32_t*)&sAh[r + 8][c + 8];
                al[mt][0] = *(const uint32_t*)&sAl[r][c];
                al[mt][1] = *(const uint32_t*)&sAl[r + 8][c];
                al[mt][2] = *(const uint32_t*)&sAl[r][c + 8];
                al[mt][3] = *(const uint32_t*)&sAl[r + 8][c + 8];
            }
            #pragma unroll
            for (int nt = 0; nt < 2; nt++) {
                int r = wn * 16 + nt * 8 + gid;
                bh[nt][0] = *(const uint32_t*)&sBh[r][c];
                bh[nt][1] = *(const uint32_t*)&sBh[r][c + 8];
                bl[nt][0] = *(const uint32_t*)&sBl[r][c];
                bl[nt][1] = *(const uint32_t*)&sBl[r][c + 8];
            }
            #pragma unroll
            for (int mt = 0; mt < 2; mt++)
                #pragma unroll
                for (int nt = 0; nt < 2; nt++) {
                    mma16816(acc[mt][nt], ah[mt], bh[nt]);
                    mma16816(acc[mt][nt], ah[mt], bl[nt]);
                    mma16816(acc[mt][nt], al[mt], bh[nt]);
                }
        }
        __syncthreads();
    }

    #pragma unroll
    for (int mt = 0; mt < 2; mt++) {
        #pragma unroll
        for (int nt = 0; nt < 2; nt++) {
            int n0 = bn + wn * 16 + nt * 8 + tig * 2;
            #pragma unroll
            for (int half = 0; half < 2; half++) {
                int m0 = bm + wm * 32 + mt * 16 + gid + half * 8;
                if (m0 >= BNROWS) continue;
                #pragma unroll
                for (int jj = 0; jj < 2; jj++) {
                    int n = n0 + jj;
                    float v = acc[mt][nt][half * 2 + jj];
                    if (n < Cv) v += bq[n];
                    if (n < 2 * Cv) {
                        size_t o = (size_t)m0 * QKVC + n;
                        split_bf16(v, g_qkvhi[o], g_qkvlo[o]);
                    } else {
                        int h = (n - 2 * Cv) >> 5, c = (n - 2 * Cv) & 31;
                        int b = m0 / Nv, p = m0 - b * Nv;
                        size_t o = ((size_t)(b * HEADS + h) * HC + c) * AP + p;
                        split_bf16(v, g_vthi[o], g_vtlo[o]);
                    }
                }
            }
        }
    }
}

// ================= fused HMMA: t1co (175 blocks) + qk (1536 blocks) =================
#define T1_BLOCKS 175
__global__ __launch_bounds__(256, 4)
void fused_t1qk_hmma(const float* __restrict__ bo1)
{
    __shared__ __align__(16) char smem_buf[20480];
    __nv_bfloat16 (*sAh)[40] = (__nv_bfloat16(*)[40])(smem_buf);
    __nv_bfloat16 (*sAl)[40] = (__nv_bfloat16(*)[40])(smem_buf + 5120);
    __nv_bfloat16 (*sBh)[40] = (__nv_bfloat16(*)[40])(smem_buf + 10240);
    __nv_bfloat16 (*sBl)[40] = (__nv_bfloat16(*)[40])(smem_buf + 15360);

    const int tid  = threadIdx.x;
    const int lane = tid & 31;
    const int w    = tid >> 5;
    const int wm   = w >> 2;
    const int wn   = w & 3;
    const int gid = lane >> 2;
    const int tig = lane & 3;
    const int srow = tid >> 2, sc8 = (tid & 3) * 8;

    float acc[2][2][4];
    #pragma unroll
    for (int i = 0; i < 2; i++)
        #pragma unroll
        for (int j = 0; j < 2; j++)
            #pragma unroll
            for (int q = 0; q < 4; q++) acc[i][j][q] = 0.0f;

    if (blockIdx.x < T1_BLOCKS) {
        const int bm = (blockIdx.x / 7) * 64;
        const int bn = (blockIdx.x % 7) * 64;
        for (int kc = 0; kc < 12; kc++) {
            const int k0 = kc * 32;
            {
                int m = bm + srow;
                uint4 vh = make_uint4(0u,0u,0u,0u), vl = vh;
                if (m < BNROWS) {
                    size_t o = (size_t)m * QKVC + k0 + sc8;
                    vh = *(const uint4*)&g_qkvhi[o];
                    vl = *(const uint4*)&g_qkvlo[o];
                }
                *(uint4*)&sAh[srow][sc8] = vh;
                *(uint4*)&sAl[srow][sc8] = vl;
                size_t ob = (size_t)(bn + srow) * Cv + k0 + sc8;
                *(uint4*)&sBh[srow][sc8] = *(const uint4*)&g_w2hi[ob];
                *(uint4*)&sBl[srow][sc8] = *(const uint4*)&g_w2lo[ob];
            }
            __syncthreads();
            #pragma unroll
            for (int kk = 0; kk < 32; kk += 16) {
                uint32_t ah[2][4], al[2][4], bh[2][2], bl[2][2];
                const int c = kk + tig * 2;
                #pragma unroll
                for (int mt = 0; mt < 2; mt++) {
                    int r = wm * 32 + mt * 16 + gid;
                    ah[mt][0] = *(const uint32_t*)&sAh[r][c];
                    ah[mt][1] = *(const uint32_t*)&sAh[r + 8][c];
                    ah[mt][2] = *(const uint32_t*)&sAh[r][c + 8];
                    ah[mt][3] = *(const uint32_t*)&sAh[r + 8][c + 8];
                    al[mt][0] = *(const uint32_t*)&sAl[r][c];
                    al[mt][1] = *(const uint32_t*)&sAl[r + 8][c];
                    al[mt][2] = *(const uint32_t*)&sAl[r][c + 8];
                    al[mt][3] = *(const uint32_t*)&sAl[r + 8][c + 8];
                }
                #pragma unroll
                for (int nt = 0; nt < 2; nt++) {
                    int r = wn * 16 + nt * 8 + gid;
                    bh[nt][0] = *(const uint32_t*)&sBh[r][c];
                    bh[nt][1] = *(const uint32_t*)&sBh[r][c + 8];
                    bl[nt][0] = *(const uint32_t*)&sBl[r][c];
                    bl[nt][1] = *(const uint32_t*)&sBl[r][c + 8];
                }
                #pragma unroll
                for (int mt = 0; mt < 2; mt++)
                    #pragma unroll
                    for (int nt = 0; nt < 2; nt++) {
                        mma16816(acc[mt][nt], ah[mt], bh[nt]);
                        mma16816(acc[mt][nt], ah[mt], bl[nt]);
                        mma16816(acc[mt][nt], al[mt], bh[nt]);
                    }
            }
            __syncthreads();
        }
        #pragma unroll
        for (int mt = 0; mt < 2; mt++) {
            #pragma unroll
            for (int nt = 0; nt < 2; nt++) {
                int n0 = bn + wn * 16 + nt * 8 + tig * 2;
                #pragma unroll
                for (int half = 0; half < 2; half++) {
                    int m0 = bm + wm * 32 + mt * 16 + gid + half * 8;
                    if (m0 >= BNROWS) continue;
                    #pragma unroll
                    for (int jj = 0; jj < 2; jj++) {
                        float v = acc[mt][nt][half * 2 + jj];
                        int n = n0 + jj;
                        if (n < Cv) {
                            g_t1[(size_t)m0 * Cv + n] = gelu_exact(v + bo1[n]);
                        } else if (n < Cv + 2 * KKv) {
                            g_co[(size_t)m0 * (2 * KKv) + (n - Cv)] = tanhf(v) * (1.0f / 14.0f);
                        }
                    }
                }
            }
        }
    } else {
        const int idx2 = blockIdx.x - T1_BLOCKS;
        const int bxq = idx2 & 3;
        const int byq = (idx2 >> 2) & 3;
        const int bh  = idx2 >> 4;
        const int b = bh / HEADS, h = bh - b * HEADS;
        const int n0b = byq * 64, p0b = bxq * 64;
        {
            int sc8q = (tid & 3) * 8;
            if (sc8q < 32) {
                int n = n0b + srow;
                uint4 vh = make_uint4(0u,0u,0u,0u), vl = vh;
                if (n < Nv) {
                    size_t o = ((size_t)(b*Nv + n))*QKVC + h*HC + sc8q;
                    vh = *(const uint4*)&g_qkvhi[o];
                    vl = *(const uint4*)&g_qkvlo[o];
                }
                *(uint4*)&sAh[srow][sc8q] = vh;
                *(uint4*)&sAl[srow][sc8q] = vl;
                int p = p0b + srow;
                uint4 wh = make_uint4(0u,0u,0u,0u), wl = wh;
                if (p < Nv) {
                    size_t o = ((size_t)(b*Nv + p))*QKVC + Cv + h*HC + sc8q;
                    wh = *(const uint4*)&g_qkvhi[o];
                    wl = *(const uint4*)&g_qkvlo[o];
                }
                *(uint4*)&sBh[srow][sc8q] = wh;
                *(uint4*)&sBl[srow][sc8q] = wl;
            }
        }
        __syncthreads();
        #pragma unroll
        for (int kk = 0; kk < 32; kk += 16) {
            uint32_t ah[2][4], al[2][4], bh2[2][2], bl2[2][2];
            const int c = kk + tig * 2;
            #pragma unroll
            for (int mt = 0; mt < 2; mt++) {
                int r = wm * 32 + mt * 16 + gid;
                ah[mt][0] = *(const uint32_t*)&sAh[r][c];
                ah[mt][1] = *(const uint32_t*)&sAh[r + 8][c];
                ah[mt][2] = *(const uint32_t*)&sAh[r][c + 8];
                ah[mt][3] = *(const uint32_t*)&sAh[r + 8][c + 8];
                al[mt][0] = *(const uint32_t*)&sAl[r][c];
                al[mt][1] = *(const uint32_t*)&sAl[r + 8][c];
                al[mt][2] = *(const uint32_t*)&sAl[r][c + 8];
                al[mt][3] = *(const uint32_t*)&sAl[r + 8][c + 8];
            }
            #pragma unroll
            for (int nt = 0; nt < 2; nt++) {
                int r = wn * 16 + nt * 8 + gid;
                bh2[nt][0] = *(const uint32_t*)&sBh[r][c];
                bh2[nt][1] = *(const uint32_t*)&sBh[r][c + 8];
                bl2[nt][0] = *(const uint32_t*)&sBl[r][c];
                bl2[nt][1] = *(const uint32_t*)&sBl[r][c + 8];
            }
            #pragma unroll
            for (int mt = 0; mt < 2; mt++)
                #pragma unroll
                for (int nt = 0; nt < 2; nt++) {
                    mma16816(acc[mt][nt], ah[mt], bh2[nt]);
                    mma16816(acc[mt][nt], ah[mt], bl2[nt]);
                    mma16816(acc[mt][nt], al[mt], bh2[nt]);
                }
        }
        float* qkb = g_qk + ((size_t)bh * Nv) * Nv;
        #pragma unroll
        for (int mt = 0; mt < 2; mt++) {
            #pragma unroll
            for (int nt = 0; nt < 2; nt++) {
                int p0 = p0b + wn * 16 + nt * 8 + tig * 2;
                #pragma unroll
                for (int half = 0; half < 2; half++) {
                    int n = n0b + wm * 32 + mt * 16 + gid + half * 8;
                    if (n >= Nv) continue;
                    if (p0 < Nv)     qkb[(size_t)n * Nv + p0]     = acc[mt][nt][half * 2 + 0];
                    if (p0 + 1 < Nv) qkb[(size_t)n * Nv + p0 + 1] = acc[mt][nt][half * 2 + 1];
                }
            }
        }
    }
}

// ================= gemm_off via HMMA (split-K x2, no atomics): partials to g_off/g_off2 ===
__global__ __launch_bounds__(256, 4)
void off_hmma()
{
    __shared__ __align__(16) __nv_bfloat16 sAh[64][40];
    __shared__ __align__(16) __nv_bfloat16 sAl[64][40];
    __shared__ __align__(16) __nv_bfloat16 sBh[64][40];
    __shared__ __align__(16) __nv_bfloat16 sBl[64][40];

    const int M = Bv * Sv;      // 392
    const int tid  = threadIdx.x;
    const int lane = tid & 31;
    const int w    = tid >> 5;
    const int wm   = w >> 2;
    const int wn   = w & 3;
    const int bm = blockIdx.y * 64;
    const int bn = blockIdx.x * 64;
    const int kbase = blockIdx.z * 192;
    float* outp = blockIdx.z ? g_off2 : g_off;
    const int gid = lane >> 2;
    const int tig = lane & 3;
    const int srow = tid >> 2, sc8 = (tid & 3) * 8;

    float acc[2][2][4];
    #pragma unroll
    for (int i = 0; i < 2; i++)
        #pragma unroll
        for (int j = 0; j < 2; j++)
            #pragma unroll
            for (int q = 0; q < 4; q++) acc[i][j][q] = 0.0f;

    for (int kc = 0; kc < 6; kc++) {
        const int k0 = kbase + kc * 32;
        {
            int m = bm + srow;
            uint4 vh = make_uint4(0u,0u,0u,0u), vl = vh;
            if (m < M) {
                size_t o = (size_t)m * Cv + k0 + sc8;
                vh = *(const uint4*)&g_t3hi[o];
                vl = *(const uint4*)&g_t3lo[o];
            }
            *(uint4*)&sAh[srow][sc8] = vh;
            *(uint4*)&sAl[srow][sc8] = vl;
            int n = bn + srow;
            uint4 wh = make_uint4(0u,0u,0u,0u), wl = wh;
            if (n < M) {
                size_t o = (size_t)n * Cv + k0 + sc8;
                wh = *(const uint4*)&g_wo2hi[o];
                wl = *(const uint4*)&g_wo2lo[o];
            }
            *(uint4*)&sBh[srow][sc8] = wh;
            *(uint4*)&sBl[srow][sc8] = wl;
        }
        __syncthreads();
        #pragma unroll
        for (int kk = 0; kk < 32; kk += 16) {
            uint32_t ah[2][4], al[2][4], bh[2][2], bl[2][2];
            const int c = kk + tig * 2;
            #pragma unroll
            for (int mt = 0; mt < 2; mt++) {
                int r = wm * 32 + mt * 16 + gid;
                ah[mt][0] = *(const uint32_t*)&sAh[r][c];
                ah[mt][1] = *(const uint32_t*)&sAh[r + 8][c];
                ah[mt][2] = *(const uint32_t*)&sAh[r][c + 8];
                ah[mt][3] = *(const uint32_t*)&sAh[r + 8][c + 8];
                al[mt][0] = *(const uint32_t*)&sAl[r][c];
                al[mt][1] = *(const uint32_t*)&sAl[r + 8][c];
                al[mt][2] = *(const uint32_t*)&sAl[r][c + 8];
                al[mt][3] = *(const uint32_t*)&sAl[r + 8][c + 8];
            }
            #pragma unroll
            for (int nt = 0; nt < 2; nt++) {
                int r = wn * 16 + nt * 8 + gid;
                bh[nt][0] = *(const uint32_t*)&sBh[r][c];
                bh[nt][1] = *(const uint32_t*)&sBh[r][c + 8];
                bl[nt][0] = *(const uint32_t*)&sBl[r][c];
                bl[nt][1] = *(const uint32_t*)&sBl[r][c + 8];
            }
            #pragma unroll
            for (int mt = 0; mt < 2; mt++)
                #pragma unroll
                for (int nt = 0; nt < 2; nt++) {
                    mma16816(acc[mt][nt], ah[mt], bh[nt]);
                    mma16816(acc[mt][nt], ah[mt], bl[nt]);
                    mma16816(acc[mt][nt], al[mt], bh[nt]);
                }
        }
        __syncthreads();
    }

    #pragma unroll
    for (int mt = 0; mt < 2; mt++) {
        #pragma unroll
        for (int nt = 0; nt < 2; nt++) {
            int n0 = bn + wn * 16 + nt * 8 + tig * 2;
            #pragma unroll
            for (int half = 0; half < 2; half++) {
                int m0 = bm + wm * 32 + mt * 16 + gid + half * 8;
                if (m0 >= M) continue;
                #pragma unroll
                for (int jj = 0; jj < 2; jj++) {
                    int n = n0 + jj;
                    if (n < M) outp[(size_t)m0 * (2*Nv) + n] = acc[mt][nt][half * 2 + jj];
                }
            }
        }
    }
}

// ================= proj HMMA (split-K x2): out += Wp @ ao^T =================
__global__ __launch_bounds__(256, 4)
void proj_hmma(float* __restrict__ out)
{
    __shared__ __align__(16) __nv_bfloat16 sAh[64][40];
    __shared__ __align__(16) __nv_bfloat16 sAl[64][40];
    __shared__ __align__(16) __nv_bfloat16 sBh[64][40];
    __shared__ __align__(16) __nv_bfloat16 sBl[64][40];

    const int tid  = threadIdx.x;
    const int lane = tid & 31;
    const int w    = tid >> 5;
    const int wm   = w >> 2;
    const int wn   = w & 3;
    const int bm = blockIdx.y * 64;
    const int bn = blockIdx.x * 64;
    const int kbase = blockIdx.z * 192;
    const int gid = lane >> 2;
    const int tig = lane & 3;
    const int srow = tid >> 2, sc8 = (tid & 3) * 8;

    float acc[2][2][4];
    #pragma unroll
    for (int i = 0; i < 2; i++)
        #pragma unroll
        for (int j = 0; j < 2; j++)
            #pragma unroll
            for (int q = 0; q < 4; q++) acc[i][j][q] = 0.0f;

    for (int kc = 0; kc < 6; kc++) {
        const int k0 = kbase + kc * 32;
        {
            size_t oa = (size_t)(bm + srow) * Cv + k0 + sc8;
            *(uint4*)&sAh[srow][sc8] = *(const uint4*)&g_wphi[oa];
            *(uint4*)&sAl[srow][sc8] = *(const uint4*)&g_wplo[oa];
            int n = bn + srow;
            uint4 vh = make_uint4(0u,0u,0u,0u), vl = vh;
            if (n < BNROWS) {
                size_t o = (size_t)n * Cv + k0 + sc8;
                vh = *(const uint4*)&g_aohi[o];
                vl = *(const uint4*)&g_aolo[o];
            }
            *(uint4*)&sBh[srow][sc8] = vh;
            *(uint4*)&sBl[srow][sc8] = vl;
        }
        __syncthreads();
        #pragma unroll
        for (int kk = 0; kk < 32; kk += 16) {
            uint32_t ah[2][4], al[2][4], bh[2][2], bl[2][2];
            const int c = kk + tig * 2;
            #pragma unroll
            for (int mt = 0; mt < 2; mt++) {
                int r = wm * 32 + mt * 16 + gid;
                ah[mt][0] = *(const uint32_t*)&sAh[r][c];
                ah[mt][1] = *(const uint32_t*)&sAh[r + 8][c];
                ah[mt][2] = *(const uint32_t*)&sAh[r][c + 8];
                ah[mt][3] = *(const uint32_t*)&sAh[r + 8][c + 8];
                al[mt][0] = *(const uint32_t*)&sAl[r][c];
                al[mt][1] = *(const uint32_t*)&sAl[r + 8][c];
                al[mt][2] = *(const uint32_t*)&sAl[r][c + 8];
                al[mt][3] = *(const uint32_t*)&sAl[r + 8][c + 8];
            }
            #pragma unroll
            for (int nt = 0; nt < 2; nt++) {
                int r = wn * 16 + nt * 8 + gid;
                bh[nt][0] = *(const uint32_t*)&sBh[r][c];
                bh[nt][1] = *(const uint32_t*)&sBh[r][c + 8];
                bl[nt][0] = *(const uint32_t*)&sBl[r][c];
                bl[nt][1] = *(const uint32_t*)&sBl[r][c + 8];
            }
            #pragma unroll
            for (int mt = 0; mt < 2; mt++)
                #pragma unroll
                for (int nt = 0; nt < 2; nt++) {
                    mma16816(acc[mt][nt], ah[mt], bh[nt]);
                    mma16816(acc[mt][nt], ah[mt], bl[nt]);
                    mma16816(acc[mt][nt], al[mt], bh[nt]);
                }
        }
        __syncthreads();
    }

    #pragma unroll
    for (int mt = 0; mt < 2; mt++) {
        #pragma unroll
        for (int nt = 0; nt < 2; nt++) {
            int n0 = bn + wn * 16 + nt * 8 + tig * 2;
            #pragma unroll
            for (int half = 0; half < 2; half++) {
                int m0 = bm + wm * 32 + mt * 16 + gid + half * 8;
                #pragma unroll
                for (int jj = 0; jj < 2; jj++) {
                    int n = n0 + jj;
                    if (n >= BNROWS) continue;
                    int b = n / Nv, nn = n - b * Nv;
                    atomicAdd(&out[((size_t)(b * Cv + m0)) * Nv + nn], acc[mt][nt][half * 2 + jj]);
                }
            }
        }
    }
}

// ================= dwln: depthwise conv + LN + GELU -> t3 hi/lo =================
__global__ void dwln_kernel(const float* __restrict__ Wdw, const float* __restrict__ bdw,
                            const float* __restrict__ lng, const float* __restrict__ lnb)
{
    int bs = blockIdx.x;
    int b = bs / Sv, s = bs % Sv;
    int oy = s / rWv, ox = s % rWv;
    int c = threadIdx.x;

    float acc = bdw[c];
    #pragma unroll
    for (int ky = 0; ky < 3; ky++) {
        int y = oy*2 - 1 + ky;
        if (y < 0 || y >= Hv) continue;
        #pragma unroll
        for (int kx = 0; kx < 3; kx++) {
            int x = ox*2 - 1 + kx;
            if (x < 0 || x >= Wv_) continue;
            acc = fmaf(g_t1[((size_t)b*Nv + y*Wv_ + x)*Cv + c], Wdw[c*9 + ky*3 + kx], acc);
        }
    }
    float s1 = acc, s2 = acc*acc;
    #pragma unroll
    for (int o = 16; o > 0; o >>= 1) {
        s1 += __shfl_xor_sync(0xffffffffu, s1, o);
        s2 += __shfl_xor_sync(0xffffffffu, s2, o);
    }
    __shared__ float w1[12], w2[12];
    __shared__ float s_mu, s_rstd;
    if ((c & 31) == 0) { w1[c >> 5] = s1; w2[c >> 5] = s2; }
    __syncthreads();
    if (c == 0) {
        float t1s = 0.f, t2s = 0.f;
        #pragma unroll
        for (int i = 0; i < 12; i++) { t1s += w1[i]; t2s += w2[i]; }
        float mu = t1s / (float)Cv;
        float var = t2s / (float)Cv - mu*mu;
        s_mu = mu; s_rstd = rsqrtf(var + 1e-5f);
    }
    __syncthreads();
    float v = gelu_exact((acc - s_mu) * s_rstd * lng[c] + lnb[c]);
    split_bf16(v, g_t3hi[(size_t)bs*Cv + c], g_t3lo[(size_t)bs*Cv + c]);
}

// ================= scores: hoisted coords + softmax -> dense bf16 prob matrix ============
__global__ void score_kernel(const float* __restrict__ posembed)
{
    const int bn = blockIdx.x;
    const int b = bn / Nv, n = bn % Nv;
    const int ny = n / Wv_, nx = n % Wv_;
    __shared__ float sc[HEADS*TS];
    __shared__ int   sp[TS*4];
    __shared__ float swt[TS*4];
    __shared__ int   stix[TS*4];
    __shared__ float stw[TS*4];
    __shared__ __align__(16) float sA[HEADS][Nv];

    for (int idx = threadIdx.x; idx < HEADS*Nv/4; idx += blockDim.x)
        ((float4*)sA)[idx] = make_float4(0.f, 0.f, 0.f, 0.f);

    // ---- phase A: 58 distinct coordinate computations ----
    if (threadIdx.x < TS) {
        const int s = threadIdx.x;
        float py, px, tpy, tpx;
        if (s < Sv) {
            int rh = s / rWv, rw = s % rWv;
            size_t ob = ((size_t)b*Sv + s)*(2*Nv);
            float offy = tanhf(g_off[ob + 0*Nv + n] + g_off2[ob + 0*Nv + n]) * (2.0f/14.0f);
            float offx = tanhf(g_off[ob + 1*Nv + n] + g_off2[ob + 1*Nv + n]) * (2.0f/14.0f);
            float refy = (float)(rh*2) * (2.0f/13.0f) - 1.0f;
            float refx = (float)(rw*2) * (2.0f/13.0f) - 1.0f;
            py = (offy + refy + 1.0f) * 6.5f;
            px = (offx + refx + 1.0f) * 6.5f;
            tpy = ((float)(2*rh - ny) * (1.0f/13.0f) - offy + 1.0f) * 13.0f;
            tpx = ((float)(2*rw - nx) * (1.0f/13.0f) - offx + 1.0f) * 13.0f;
        } else {
            int j = s - Sv;
            float coy = g_co[((size_t)b*Nv + n)*(2*KKv) + j*2 + 0];
            float cox = g_co[((size_t)b*Nv + n)*(2*KKv) + j*2 + 1];
            float cy = (float)ny + c_offm[j][0];
            float cx = (float)nx + c_offm[j][1];
            float cny = fminf(fmaxf(cy, 0.0f), 14.0f) * (2.0f/13.0f) - 1.0f;
            float cnx = fminf(fmaxf(cx, 0.0f), 14.0f) * (2.0f/13.0f) - 1.0f;
            py = (coy + cny + 1.0f) * 6.5f;
            px = (cox + cnx + 1.0f) * 6.5f;
            tpy = (coy - (float)ny + 1.0f) * 13.0f;
            tpx = (cox - (float)nx + 1.0f) * 13.0f;
        }
        // QK-map corners (14x14)
        {
            float y0 = floorf(py), x0 = floorf(px);
            float wy1 = py - y0, wx1 = px - x0;
            #pragma unroll
            for (int ccy = 0; ccy < 2; ccy++)
                #pragma unroll
                for (int ccx = 0; ccx < 2; ccx++) {
                    float yf = y0 + (float)ccy, xf = x0 + (float)ccx;
                    float w = (ccy ? wy1 : 1.0f - wy1) * (ccx ? wx1 : 1.0f - wx1);
                    bool valid = (yf >= 0.0f) && (yf <= 13.0f) && (xf >= 0.0f) && (xf <= 13.0f);
                    if (!valid) w = 0.0f;
                    int yi = (int)fminf(fmaxf(yf, 0.0f), 13.0f);
                    int xi = (int)fminf(fmaxf(xf, 0.0f), 13.0f);
                    sp [s*4 + ccy*2 + ccx] = yi*Wv_ + xi;
                    swt[s*4 + ccy*2 + ccx] = w;
                }
        }
        // pos-table corners (27x27)
        {
            float by0 = floorf(tpy), bx0 = floorf(tpx);
            float bwy = tpy - by0, bwx = tpx - bx0;
            #pragma unroll
            for (int ccy = 0; ccy < 2; ccy++)
                #pragma unroll
                for (int ccx = 0; ccx < 2; ccx++) {
                    float yf = by0 + (float)ccy, xf = bx0 + (float)ccx;
                    float w = (ccy ? bwy : 1.0f - bwy) * (ccx ? bwx : 1.0f - bwx);
                    bool valid = (yf >= 0.0f) && (yf <= 26.0f) && (xf >= 0.0f) && (xf <= 26.0f);
                    if (!valid) w = 0.0f;
                    int yi = (int)fminf(fmaxf(yf, 0.0f), 26.0f);
                    int xi = (int)fminf(fmaxf(xf, 0.0f), 26.0f);
                    stix[s*4 + ccy*2 + ccx] = yi*27 + xi;
                    stw [s*4 + ccy*2 + ccx] = w;
                }
        }
    }
    __syncthreads();

    // ---- phase B: per (h,s) score = QK bilinear + bias bilinear ----
    for (int item = threadIdx.x; item < HEADS*TS; item += blockDim.x) {
        const int h = item / TS, s = item % TS;
        const float* qkb = g_qk + (((size_t)(b*HEADS + h))*Nv + n)*Nv;
        const float* tb = posembed + (size_t)h * (27*27);
        float val = swt[s*4+0]*qkb[sp[s*4+0]] + swt[s*4+1]*qkb[sp[s*4+1]]
                  + swt[s*4+2]*qkb[sp[s*4+2]] + swt[s*4+3]*qkb[sp[s*4+3]];
        float bval = stw[s*4+0]*tb[stix[s*4+0]] + stw[s*4+1]*tb[stix[s*4+1]]
                   + stw[s*4+2]*tb[stix[s*4+2]] + stw[s*4+3]*tb[stix[s*4+3]];
        sc[h*TS + s] = val + bval;
    }
    __syncthreads();

    const int wid = threadIdx.x >> 5, lane = threadIdx.x & 31;
    {
        float m = -1e30f;
        for (int s = lane; s < TS; s += 32) m = fmaxf(m, sc[wid*TS + s]);
        #pragma unroll
        for (int o = 16; o > 0; o >>= 1) m = fmaxf(m, __shfl_xor_sync(0xffffffffu, m, o));
        float sum = 0.0f;
        for (int s = lane; s < TS; s += 32) {
            float e = expf(sc[wid*TS + s] - m);
            sc[wid*TS + s] = e;
            sum += e;
        }
        #pragma unroll
        for (int o = 16; o > 0; o >>= 1) sum += __shfl_xor_sync(0xffffffffu, sum, o);
        float inv = 1.0f / sum;
        for (int s = lane; s < TS; s += 32) sc[wid*TS + s] *= inv;
    }
    for (int i = lane; i < TS*4; i += 32) {
        atomicAdd(&sA[wid][sp[i]], sc[wid*TS + (i >> 2)] * swt[i]);
    }
    __syncthreads();

    // ---- writeback: packed uint32 stores of bf16 pairs ----
    for (int idx = threadIdx.x; idx < HEADS*(Nv/2); idx += blockDim.x) {
        int h = idx / (Nv/2), p2 = idx - h * (Nv/2);
        float v0 = sA[h][p2*2], v1 = sA[h][p2*2 + 1];
        __nv_bfloat16 h0, l0, h1, l1;
        split_bf16(v0, h0, l0);
        split_bf16(v1, h1, l1);
        size_t o = (((size_t)(b*HEADS + h)*Nv + n)*AP)/2 + p2;
        ((uint32_t*)g_Ahi)[o] = pack_bf16(h0, h1);
        ((uint32_t*)g_Alo)[o] = pack_bf16(l0, l1);
    }
}

// ================= av via HMMA: ao[n][c] = A @ V (+bv), seeds out with bp =================
__global__ __launch_bounds__(256, 4)
void av_hmma(const float* __restrict__ bvv, const float* __restrict__ bp, float* __restrict__ out)
{
    __shared__ __align__(16) __nv_bfloat16 sAh[64][40];
    __shared__ __align__(16) __nv_bfloat16 sAl[64][40];
    __shared__ __align__(16) __nv_bfloat16 sBh[32][40];
    __shared__ __align__(16) __nv_bfloat16 sBl[32][40];

    const int tid  = threadIdx.x;
    const int lane = tid & 31;
    const int w    = tid >> 5;
    const int wm   = w >> 1;
    const int wn   = w & 1;
    const int bm = blockIdx.x * 64;
    const int bh = blockIdx.y;
    const int b = bh / HEADS, h = bh - b * HEADS;
    const int gid = lane >> 2;
    const int tig = lane & 3;
    const int srow = tid >> 2, sc8 = (tid & 3) * 8;

    for (int i = tid; i < 64 * HC; i += 256) {
        int nn = bm + (i & 63);
        int c  = h * HC + (i >> 6);
        if (nn < Nv) out[((size_t)(b * Cv + c)) * Nv + nn] = bp[c];
    }

    float acc[2][4];
    #pragma unroll
    for (int j = 0; j < 2; j++)
        #pragma unroll
        for (int q = 0; q < 4; q++) acc[j][q] = 0.0f;

    const __nv_bfloat16* Abh = g_Ahi + (size_t)bh * Nv * AP;
    const __nv_bfloat16* Abl = g_Alo + (size_t)bh * Nv * AP;
    const __nv_bfloat16* Vbh = g_vthi + (size_t)bh * HC * AP;
    const __nv_bfloat16* Vbl = g_vtlo + (size_t)bh * HC * AP;

    for (int p0 = 0; p0 < AP; p0 += 32) {
        {
            int m = bm + srow;
            uint4 vh = make_uint4(0u,0u,0u,0u), vl = vh;
            if (m < Nv) {
                size_t o = (size_t)m * AP + p0 + sc8;
                vh = *(const uint4*)&Abh[o];
                vl = *(const uint4*)&Abl[o];
            }
            *(uint4*)&sAh[srow][sc8] = vh;
            *(uint4*)&sAl[srow][sc8] = vl;
            if (srow < 32) {
                size_t o = (size_t)srow * AP + p0 + sc8;
                *(uint4*)&sBh[srow][sc8] = *(const uint4*)&Vbh[o];
                *(uint4*)&sBl[srow][sc8] = *(const uint4*)&Vbl[o];
            }
        }
        __syncthreads();
        #pragma unroll
        for (int kk = 0; kk < 32; kk += 16) {
            uint32_t ah[4], al[4], bh2[2][2], bl2[2][2];
            const int c = kk + tig * 2;
            {
                int r = wm * 16 + gid;
                ah[0] = *(const uint32_t*)&sAh[r][c];
                ah[1] = *(const uint32_t*)&sAh[r + 8][c];
                ah[2] = *(const uint32_t*)&sAh[r][c + 8];
                ah[3] = *(const uint32_t*)&sAh[r + 8][c + 8];
                al[0] = *(const uint32_t*)&sAl[r][c];
                al[1] = *(const uint32_t*)&sAl[r + 8][c];
                al[2] = *(const uint32_t*)&sAl[r][c + 8];
                al[3] = *(const uint32_t*)&sAl[r + 8][c + 8];
            }
            #pragma unroll
            for (int nt = 0; nt < 2; nt++) {
                int r = wn * 16 + nt * 8 + gid;
                bh2[nt][0] = *(const uint32_t*)&sBh[r][c];
                bh2[nt][1] = *(const uint32_t*)&sBh[r][c + 8];
                bl2[nt][0] = *(const uint32_t*)&sBl[r][c];
                bl2[nt][1] = *(const uint32_t*)&sBl[r][c + 8];
            }
            #pragma unroll
            for (int nt = 0; nt < 2; nt++) {
                mma16816(acc[nt], ah, bh2[nt]);
                mma16816(acc[nt], ah, bl2[nt]);
                mma16816(acc[nt], al, bh2[nt]);
            }
        }
        __syncthreads();
    }

    #pragma unroll
    for (int nt = 0; nt < 2; nt++) {
        int c0 = wn * 16 + nt * 8 + tig * 2;
        #pragma unroll
        for (int half = 0; half < 2; half++) {
            int n = bm + wm * 16 + gid + half * 8;
            if (n >= Nv) continue;
            #pragma unroll
            for (int jj = 0; jj < 2; jj++) {
                int c = c0 + jj;
                float v = acc[nt][half * 2 + jj] + bvv[h * HC + c];
                size_t o = ((size_t)(b*Nv + n))*Cv + h*HC + c;
                split_bf16(v, g_aohi[o], g_aolo[o]);
            }
        }
    }
}

extern "C" void kernel_launch(void* const* d_in, const int* in_sizes, int n_in,
                              void* d_out, int out_size)
{
    const float* x    = (const float*)d_in[0];
    const float* Wq   = (const float*)d_in[1];
    const float* bq   = (const float*)d_in[2];
    const float* Wk   = (const float*)d_in[3];
    // bk cancels in softmax — unused
    const float* Wvv  = (const float*)d_in[5];
    const float* bvv  = (const float*)d_in[6];
    const float* Wo1  = (const float*)d_in[7];
    const float* bo1  = (const float*)d_in[8];
    const float* Wdw  = (const float*)d_in[9];
    const float* bdw  = (const float*)d_in[10];
    const float* lng  = (const float*)d_in[11];
    const float* lnb  = (const float*)d_in[12];
    const float* Wo2  = (const float*)d_in[13];
    const float* Wco  = (const float*)d_in[14];
    const float* pos  = (const float*)d_in[15];
    const float* Wp   = (const float*)d_in[16];
    const float* bp   = (const float*)d_in[17];
    float* out = (float*)d_out;

    prep_kernel<<<1563, 256>>>(x, Wq, Wk, Wvv, Wo1, Wco, Wp, Wo2);
    qkv_hmma<<<dim3(18, 25), 256>>>(bq);
    fused_t1qk_hmma<<<T1_BLOCKS + 16 * Bv * HEADS, 256>>>(bo1);
    dwln_kernel<<<Bv*Sv, Cv>>>(Wdw, bdw, lng, lnb);
    off_hmma<<<dim3(7, 7, 2), 256>>>();
    score_kernel<<<Bv*Nv, 384>>>(pos);
    av_hmma<<<dim3(4, Bv*HEADS), 256>>>(bvv, bp, out);
    proj_hmma<<<dim3(25, 6, 2), 256>>>(out);
}

// round 16
// speedup vs baseline: 2.2055x; 1.0122x over previous
#include <cuda_runtime.h>
#include <cuda_bf16.h>
#include <math.h>
#include <stdint.h>

#define Bv   8
#define Cv   384
#define Hv   14
#define Wv_  14
#define HEADS 12
#define HC   32
#define Nv   196
#define Sv   49
#define rHv  7
#define rWv  7
#define KKv  9
#define TS   58
#define BNROWS (Bv*Nv)   // 1568
#define QKVC 1152
#define N2   448
#define AP   224

// fp32 scratch
__device__ __align__(16) float g_t1 [BNROWS*Cv];
__device__ __align__(16) float g_off [Bv*Sv*2*Nv];   // split-K partial 0
__device__ __align__(16) float g_off2[Bv*Sv*2*Nv];   // split-K partial 1
__device__ __align__(16) float g_co [BNROWS*2*KKv];
__device__ __align__(16) float g_qk [(size_t)Bv*HEADS*Nv*Nv];
// bf16 split operands
__device__ __align__(16) __nv_bfloat16 g_xhi[BNROWS*Cv];
__device__ __align__(16) __nv_bfloat16 g_xlo[BNROWS*Cv];
__device__ __align__(16) __nv_bfloat16 g_whi[QKVC*Cv];
__device__ __align__(16) __nv_bfloat16 g_wlo[QKVC*Cv];
__device__ __align__(16) __nv_bfloat16 g_qkvhi[BNROWS*QKVC];
__device__ __align__(16) __nv_bfloat16 g_qkvlo[BNROWS*QKVC];
__device__ __align__(16) __nv_bfloat16 g_w2hi[N2*Cv];
__device__ __align__(16) __nv_bfloat16 g_w2lo[N2*Cv];
__device__ __align__(16) __nv_bfloat16 g_wphi[Cv*Cv];
__device__ __align__(16) __nv_bfloat16 g_wplo[Cv*Cv];
__device__ __align__(16) __nv_bfloat16 g_wo2hi[(Bv*Sv)*Cv];
__device__ __align__(16) __nv_bfloat16 g_wo2lo[(Bv*Sv)*Cv];
__device__ __align__(16) __nv_bfloat16 g_t3hi[(Bv*Sv)*Cv];
__device__ __align__(16) __nv_bfloat16 g_t3lo[(Bv*Sv)*Cv];
__device__ __align__(16) __nv_bfloat16 g_aohi[BNROWS*Cv];
__device__ __align__(16) __nv_bfloat16 g_aolo[BNROWS*Cv];
__device__ __align__(16) __nv_bfloat16 g_Ahi[(size_t)Bv*HEADS*Nv*AP];
__device__ __align__(16) __nv_bfloat16 g_Alo[(size_t)Bv*HEADS*Nv*AP];
__device__ __align__(16) __nv_bfloat16 g_vthi[(size_t)Bv*HEADS*HC*AP];
__device__ __align__(16) __nv_bfloat16 g_vtlo[(size_t)Bv*HEADS*HC*AP];

__constant__ float c_offm[9][2] = {
    {0.f,-1.f},{-1.f,-1.f},{-1.f,0.f},{-1.f,1.f},{0.f,1.f},{1.f,1.f},{1.f,0.f},{1.f,-1.f},{0.f,0.f}
};

__device__ __forceinline__ float gelu_exact(float v) {
    return 0.5f * v * (1.0f + erff(v * 0.7071067811865476f));
}
__device__ __forceinline__ void mma16816(float* c, const uint32_t* a, const uint32_t* b) {
    asm volatile(
        "mma.sync.aligned.m16n8k16.row.col.f32.bf16.bf16.f32 "
        "{%0,%1,%2,%3}, {%4,%5,%6,%7}, {%8,%9}, {%0,%1,%2,%3};"
        : "+f"(c[0]), "+f"(c[1]), "+f"(c[2]), "+f"(c[3])
        : "r"(a[0]), "r"(a[1]), "r"(a[2]), "r"(a[3]), "r"(b[0]), "r"(b[1]));
}
__device__ __forceinline__ void split_bf16(float v, __nv_bfloat16& h, __nv_bfloat16& l) {
    h = __float2bfloat16(v);
    l = __float2bfloat16(v - __bfloat162float(h));
}
__device__ __forceinline__ uint32_t pack_bf16(__nv_bfloat16 a, __nv_bfloat16 b) {
    uint32_t r;
    unsigned short ua = *(unsigned short*)&a, ub = *(unsigned short*)&b;
    r = (uint32_t)ua | ((uint32_t)ub << 16);
    return r;
}
// PDL: block until immediate stream predecessor has completed (its writes visible).
__device__ __forceinline__ void pdl_wait() {
    asm volatile("griddepcontrol.wait;" ::: "memory");
}

// ================= prep =================
__global__ void prep_kernel(const float* __restrict__ x,
                            const float* __restrict__ Wq, const float* __restrict__ Wk,
                            const float* __restrict__ Wvv, const float* __restrict__ Wo1,
                            const float* __restrict__ Wco, const float* __restrict__ Wp,
                            const float* __restrict__ Wo2)
{
    const int bid = blockIdx.x;
    const int tid = threadIdx.x;
    if (bid < 672) {
        int nt = bid % 7, ct = (bid / 7) % 12, b = bid / 84;
        __shared__ float tile[32][33];
        int tx = tid & 31, ty = tid >> 5;
        int c0 = ct * 32, n0 = nt * 32;
        for (int i = ty; i < 32; i += 8) {
            int c = c0 + i, n = n0 + tx;
            tile[i][tx] = (n < Nv) ? x[((size_t)b*Cv + c)*Nv + n] : 0.0f;
        }
        __syncthreads();
        for (int i = ty; i < 32; i += 8) {
            int n = n0 + i, c = c0 + tx;
            if (n < Nv) {
                size_t o = ((size_t)b*Nv + n)*Cv + c;
                split_bf16(tile[tx][i], g_xhi[o], g_xlo[o]);
            }
        }
    } else if (bid < 1104) {
        int idx = (bid - 672) * 256 + tid;
        if (idx < QKVC * (Cv/4)) {
            int r = idx / (Cv/4), c4 = idx - r * (Cv/4);
            const float* src = (r < Cv) ? &Wq[(size_t)r*Cv]
                              : (r < 2*Cv ? &Wk[(size_t)(r - Cv)*Cv] : &Wvv[(size_t)(r - 2*Cv)*Cv]);
            float4 v = *(const float4*)&src[c4*4];
            size_t o = (size_t)r*Cv + c4*4;
            float vv[4] = {v.x, v.y, v.z, v.w};
            #pragma unroll
            for (int j = 0; j < 4; j++) split_bf16(vv[j], g_whi[o + j], g_wlo[o + j]);
        }
    } else if (bid < 1272) {
        int idx = (bid - 1104) * 256 + tid;
        if (idx < N2 * (Cv/4)) {
            int r = idx / (Cv/4), c4 = idx - r * (Cv/4);
            float4 v = make_float4(0.f, 0.f, 0.f, 0.f);
            if (r < Cv) v = *(const float4*)&Wo1[(size_t)r*Cv + c4*4];
            else if (r < Cv + 2*KKv) v = *(const float4*)&Wco[(size_t)(r - Cv)*Cv + c4*4];
            size_t o = (size_t)r*Cv + c4*4;
            float vv[4] = {v.x, v.y, v.z, v.w};
            #pragma unroll
            for (int j = 0; j < 4; j++) split_bf16(vv[j], g_w2hi[o + j], g_w2lo[o + j]);
        }
    } else if (bid < 1416) {
        int idx = (bid - 1272) * 256 + tid;
        if (idx < Cv * (Cv/4)) {
            int r = idx / (Cv/4), c4 = idx - r * (Cv/4);
            float4 v = *(const float4*)&Wp[(size_t)r*Cv + c4*4];
            size_t o = (size_t)r*Cv + c4*4;
            float vv[4] = {v.x, v.y, v.z, v.w};
            #pragma unroll
            for (int j = 0; j < 4; j++) split_bf16(vv[j], g_wphi[o + j], g_wplo[o + j]);
        }
    } else {
        int idx = (bid - 1416) * 256 + tid;
        if (idx < (Bv*Sv) * (Cv/4)) {
            int r = idx / (Cv/4), c4 = idx - r * (Cv/4);
            float4 v = *(const float4*)&Wo2[(size_t)r*Cv + c4*4];
            size_t o = (size_t)r*Cv + c4*4;
            float vv[4] = {v.x, v.y, v.z, v.w};
            #pragma unroll
            for (int j = 0; j < 4; j++) split_bf16(vv[j], g_wo2hi[o + j], g_wo2lo[o + j]);
        }
    }
}

// ================= qkv via HMMA; q|xK -> g_qkvhi/lo, V -> transposed g_vthi/lo ============
__global__ __launch_bounds__(256, 4)
void qkv_hmma(const float* __restrict__ bq)
{
    __shared__ __align__(16) __nv_bfloat16 sAh[64][40];
    __shared__ __align__(16) __nv_bfloat16 sAl[64][40];
    __shared__ __align__(16) __nv_bfloat16 sBh[64][40];
    __shared__ __align__(16) __nv_bfloat16 sBl[64][40];

    const int tid  = threadIdx.x;
    const int lane = tid & 31;
    const int w    = tid >> 5;
    const int wm   = w >> 2;
    const int wn   = w & 3;
    const int bm = blockIdx.y * 64;
    const int bn = blockIdx.x * 64;
    const int gid = lane >> 2;
    const int tig = lane & 3;
    const int srow = tid >> 2, sc8 = (tid & 3) * 8;

    float acc[2][2][4];
    #pragma unroll
    for (int i = 0; i < 2; i++)
        #pragma unroll
        for (int j = 0; j < 2; j++)
            #pragma unroll
            for (int q = 0; q < 4; q++) acc[i][j][q] = 0.0f;

    pdl_wait();   // prep's g_xhi/g_whi must be visible

    for (int kc = 0; kc < 12; kc++) {
        const int k0 = kc * 32;
        {
            int m = bm + srow;
            uint4 vh = make_uint4(0u,0u,0u,0u), vl = vh;
            if (m < BNROWS) {
                size_t o = (size_t)m * Cv + k0 + sc8;
                vh = *(const uint4*)&g_xhi[o];
                vl = *(const uint4*)&g_xlo[o];
            }
            *(uint4*)&sAh[srow][sc8] = vh;
            *(uint4*)&sAl[srow][sc8] = vl;
            size_t ob = (size_t)(bn + srow) * Cv + k0 + sc8;
            *(uint4*)&sBh[srow][sc8] = *(const uint4*)&g_whi[ob];
            *(uint4*)&sBl[srow][sc8] = *(const uint4*)&g_wlo[ob];
        }
        __syncthreads();
        #pragma unroll
        for (int kk = 0; kk < 32; kk += 16) {
            uint32_t ah[2][4], al[2][4], bh[2][2], bl[2][2];
            const int c = kk + tig * 2;
            #pragma unroll
            for (int mt = 0; mt < 2; mt++) {
                int r = wm * 32 + mt * 16 + gid;
                ah[mt][0] = *(const uint32_t*)&sAh[r][c];
                ah[mt][1] = *(const uint32_t*)&sAh[r + 8][c];
                ah[mt][2] = *(const uint32_t*)&sAh[r][c + 8];
                ah[mt][3] = *(const uint32_t*)&sAh[r + 8][c + 8];
                al[mt][0] = *(const uint32_t*)&sAl[r][c];
                al[mt][1] = *(const uint32_t*)&sAl[r + 8][c];
                al[mt][2] = *(const uint32_t*)&sAl[r][c + 8];
                al[mt][3] = *(const uint32_t*)&sAl[r + 8][c + 8];
            }
            #pragma unroll
            for (int nt = 0; nt < 2; nt++) {
                int r = wn * 16 + nt * 8 + gid;
                bh[nt][0] = *(const uint32_t*)&sBh[r][c];
                bh[nt][1] = *(const uint32_t*)&sBh[r][c + 8];
                bl[nt][0] = *(const uint32_t*)&sBl[r][c];
                bl[nt][1] = *(const uint32_t*)&sBl[r][c + 8];
            }
            #pragma unroll
            for (int mt = 0; mt < 2; mt++)
                #pragma unroll
                for (int nt = 0; nt < 2; nt++) {
                    mma16816(acc[mt][nt], ah[mt], bh[nt]);
                    mma16816(acc[mt][nt], ah[mt], bl[nt]);
                    mma16816(acc[mt][nt], al[mt], bh[nt]);
                }
        }
        __syncthreads();
    }

    #pragma unroll
    for (int mt = 0; mt < 2; mt++) {
        #pragma unroll
        for (int nt = 0; nt < 2; nt++) {
            int n0 = bn + wn * 16 + nt * 8 + tig * 2;
            #pragma unroll
            for (int half = 0; half < 2; half++) {
                int m0 = bm + wm * 32 + mt * 16 + gid + half * 8;
                if (m0 >= BNROWS) continue;
                #pragma unroll
                for (int jj = 0; jj < 2; jj++) {
                    int n = n0 + jj;
                    float v = acc[mt][nt][half * 2 + jj];
                    if (n < Cv) v += bq[n];
                    if (n < 2 * Cv) {
                        size_t o = (size_t)m0 * QKVC + n;
                        split_bf16(v, g_qkvhi[o], g_qkvlo[o]);
                    } else {
                        int h = (n - 2 * Cv) >> 5, c = (n - 2 * Cv) & 31;
                        int b = m0 / Nv, p = m0 - b * Nv;
                        size_t o = ((size_t)(b * HEADS + h) * HC + c) * AP + p;
                        split_bf16(v, g_vthi[o], g_vtlo[o]);
                    }
                }
            }
        }
    }
}

// ================= fused HMMA: t1co (175 blocks) + qk (1536 blocks) =================
#define T1_BLOCKS 175
__global__ __launch_bounds__(256, 4)
void fused_t1qk_hmma(const float* __restrict__ bo1)
{
    __shared__ __align__(16) char smem_buf[20480];
    __nv_bfloat16 (*sAh)[40] = (__nv_bfloat16(*)[40])(smem_buf);
    __nv_bfloat16 (*sAl)[40] = (__nv_bfloat16(*)[40])(smem_buf + 5120);
    __nv_bfloat16 (*sBh)[40] = (__nv_bfloat16(*)[40])(smem_buf + 10240);
    __nv_bfloat16 (*sBl)[40] = (__nv_bfloat16(*)[40])(smem_buf + 15360);

    const int tid  = threadIdx.x;
    const int lane = tid & 31;
    const int w    = tid >> 5;
    const int wm   = w >> 2;
    const int wn   = w & 3;
    const int gid = lane >> 2;
    const int tig = lane & 3;
    const int srow = tid >> 2, sc8 = (tid & 3) * 8;

    float acc[2][2][4];
    #pragma unroll
    for (int i = 0; i < 2; i++)
        #pragma unroll
        for (int j = 0; j < 2; j++)
            #pragma unroll
            for (int q = 0; q < 4; q++) acc[i][j][q] = 0.0f;

    pdl_wait();   // qkv's g_qkvhi/lo must be visible

    if (blockIdx.x < T1_BLOCKS) {
        const int bm = (blockIdx.x / 7) * 64;
        const int bn = (blockIdx.x % 7) * 64;
        for (int kc = 0; kc < 12; kc++) {
            const int k0 = kc * 32;
            {
                int m = bm + srow;
                uint4 vh = make_uint4(0u,0u,0u,0u), vl = vh;
                if (m < BNROWS) {
                    size_t o = (size_t)m * QKVC + k0 + sc8;
                    vh = *(const uint4*)&g_qkvhi[o];
                    vl = *(const uint4*)&g_qkvlo[o];
                }
                *(uint4*)&sAh[srow][sc8] = vh;
                *(uint4*)&sAl[srow][sc8] = vl;
                size_t ob = (size_t)(bn + srow) * Cv + k0 + sc8;
                *(uint4*)&sBh[srow][sc8] = *(const uint4*)&g_w2hi[ob];
                *(uint4*)&sBl[srow][sc8] = *(const uint4*)&g_w2lo[ob];
            }
            __syncthreads();
            #pragma unroll
            for (int kk = 0; kk < 32; kk += 16) {
                uint32_t ah[2][4], al[2][4], bh[2][2], bl[2][2];
                const int c = kk + tig * 2;
                #pragma unroll
                for (int mt = 0; mt < 2; mt++) {
                    int r = wm * 32 + mt * 16 + gid;
                    ah[mt][0] = *(const uint32_t*)&sAh[r][c];
                    ah[mt][1] = *(const uint32_t*)&sAh[r + 8][c];
                    ah[mt][2] = *(const uint32_t*)&sAh[r][c + 8];
                    ah[mt][3] = *(const uint32_t*)&sAh[r + 8][c + 8];
                    al[mt][0] = *(const uint32_t*)&sAl[r][c];
                    al[mt][1] = *(const uint32_t*)&sAl[r + 8][c];
                    al[mt][2] = *(const uint32_t*)&sAl[r][c + 8];
                    al[mt][3] = *(const uint32_t*)&sAl[r + 8][c + 8];
                }
                #pragma unroll
                for (int nt = 0; nt < 2; nt++) {
                    int r = wn * 16 + nt * 8 + gid;
                    bh[nt][0] = *(const uint32_t*)&sBh[r][c];
                    bh[nt][1] = *(const uint32_t*)&sBh[r][c + 8];
                    bl[nt][0] = *(const uint32_t*)&sBl[r][c];
                    bl[nt][1] = *(const uint32_t*)&sBl[r][c + 8];
                }
                #pragma unroll
                for (int mt = 0; mt < 2; mt++)
                    #pragma unroll
                    for (int nt = 0; nt < 2; nt++) {
                        mma16816(acc[mt][nt], ah[mt], bh[nt]);
                        mma16816(acc[mt][nt], ah[mt], bl[nt]);
                        mma16816(acc[mt][nt], al[mt], bh[nt]);
                    }
            }
            __syncthreads();
        }
        #pragma unroll
        for (int mt = 0; mt < 2; mt++) {
            #pragma unroll
            for (int nt = 0; nt < 2; nt++) {
                int n0 = bn + wn * 16 + nt * 8 + tig * 2;
                #pragma unroll
                for (int half = 0; half < 2; half++) {
                    int m0 = bm + wm * 32 + mt * 16 + gid + half * 8;
                    if (m0 >= BNROWS) continue;
                    #pragma unroll
                    for (int jj = 0; jj < 2; jj++) {
                        float v = acc[mt][nt][half * 2 + jj];
                        int n = n0 + jj;
                        if (n < Cv) {
                            g_t1[(size_t)m0 * Cv + n] = gelu_exact(v + bo1[n]);
                        } else if (n < Cv + 2 * KKv) {
                            g_co[(size_t)m0 * (2 * KKv) + (n - Cv)] = tanhf(v) * (1.0f / 14.0f);
                        }
                    }
                }
            }
        }
    } else {
        const int idx2 = blockIdx.x - T1_BLOCKS;
        const int bxq = idx2 & 3;
        const int byq = (idx2 >> 2) & 3;
        const int bh  = idx2 >> 4;
        const int b = bh / HEADS, h = bh - b * HEADS;
        const int n0b = byq * 64, p0b = bxq * 64;
        {
            int sc8q = (tid & 3) * 8;
            if (sc8q < 32) {
                int n = n0b + srow;
                uint4 vh = make_uint4(0u,0u,0u,0u), vl = vh;
                if (n < Nv) {
                    size_t o = ((size_t)(b*Nv + n))*QKVC + h*HC + sc8q;
                    vh = *(const uint4*)&g_qkvhi[o];
                    vl = *(const uint4*)&g_qkvlo[o];
                }
                *(uint4*)&sAh[srow][sc8q] = vh;
                *(uint4*)&sAl[srow][sc8q] = vl;
                int p = p0b + srow;
                uint4 wh = make_uint4(0u,0u,0u,0u), wl = wh;
                if (p < Nv) {
                    size_t o = ((size_t)(b*Nv + p))*QKVC + Cv + h*HC + sc8q;
                    wh = *(const uint4*)&g_qkvhi[o];
                    wl = *(const uint4*)&g_qkvlo[o];
                }
                *(uint4*)&sBh[srow][sc8q] = wh;
                *(uint4*)&sBl[srow][sc8q] = wl;
            }
        }
        __syncthreads();
        #pragma unroll
        for (int kk = 0; kk < 32; kk += 16) {
            uint32_t ah[2][4], al[2][4], bh2[2][2], bl2[2][2];
            const int c = kk + tig * 2;
            #pragma unroll
            for (int mt = 0; mt < 2; mt++) {
                int r = wm * 32 + mt * 16 + gid;
                ah[mt][0] = *(const uint32_t*)&sAh[r][c];
                ah[mt][1] = *(const uint32_t*)&sAh[r + 8][c];
                ah[mt][2] = *(const uint32_t*)&sAh[r][c + 8];
                ah[mt][3] = *(const uint32_t*)&sAh[r + 8][c + 8];
                al[mt][0] = *(const uint32_t*)&sAl[r][c];
                al[mt][1] = *(const uint32_t*)&sAl[r + 8][c];
                al[mt][2] = *(const uint32_t*)&sAl[r][c + 8];
                al[mt][3] = *(const uint32_t*)&sAl[r + 8][c + 8];
            }
            #pragma unroll
            for (int nt = 0; nt < 2; nt++) {
                int r = wn * 16 + nt * 8 + gid;
                bh2[nt][0] = *(const uint32_t*)&sBh[r][c];
                bh2[nt][1] = *(const uint32_t*)&sBh[r][c + 8];
                bl2[nt][0] = *(const uint32_t*)&sBl[r][c];
                bl2[nt][1] = *(const uint32_t*)&sBl[r][c + 8];
            }
            #pragma unroll
            for (int mt = 0; mt < 2; mt++)
                #pragma unroll
                for (int nt = 0; nt < 2; nt++) {
                    mma16816(acc[mt][nt], ah[mt], bh2[nt]);
                    mma16816(acc[mt][nt], ah[mt], bl2[nt]);
                    mma16816(acc[mt][nt], al[mt], bh2[nt]);
                }
        }
        float* qkb = g_qk + ((size_t)bh * Nv) * Nv;
        #pragma unroll
        for (int mt = 0; mt < 2; mt++) {
            #pragma unroll
            for (int nt = 0; nt < 2; nt++) {
                int p0 = p0b + wn * 16 + nt * 8 + tig * 2;
                #pragma unroll
                for (int half = 0; half < 2; half++) {
                    int n = n0b + wm * 32 + mt * 16 + gid + half * 8;
                    if (n >= Nv) continue;
                    if (p0 < Nv)     qkb[(size_t)n * Nv + p0]     = acc[mt][nt][half * 2 + 0];
                    if (p0 + 1 < Nv) qkb[(size_t)n * Nv + p0 + 1] = acc[mt][nt][half * 2 + 1];
                }
            }
        }
    }
}

// ================= gemm_off via HMMA (split-K x2, no atomics): partials to g_off/g_off2 ===
__global__ __launch_bounds__(256, 4)
void off_hmma()
{
    __shared__ __align__(16) __nv_bfloat16 sAh[64][40];
    __shared__ __align__(16) __nv_bfloat16 sAl[64][40];
    __shared__ __align__(16) __nv_bfloat16 sBh[64][40];
    __shared__ __align__(16) __nv_bfloat16 sBl[64][40];

    const int M = Bv * Sv;      // 392
    const int tid  = threadIdx.x;
    const int lane = tid & 31;
    const int w    = tid >> 5;
    const int wm   = w >> 2;
    const int wn   = w & 3;
    const int bm = blockIdx.y * 64;
    const int bn = blockIdx.x * 64;
    const int kbase = blockIdx.z * 192;
    float* outp = blockIdx.z ? g_off2 : g_off;
    const int gid = lane >> 2;
    const int tig = lane & 3;
    const int srow = tid >> 2, sc8 = (tid & 3) * 8;

    float acc[2][2][4];
    #pragma unroll
    for (int i = 0; i < 2; i++)
        #pragma unroll
        for (int j = 0; j < 2; j++)
            #pragma unroll
            for (int q = 0; q < 4; q++) acc[i][j][q] = 0.0f;

    pdl_wait();   // dwln's g_t3hi/lo must be visible

    for (int kc = 0; kc < 6; kc++) {
        const int k0 = kbase + kc * 32;
        {
            int m = bm + srow;
            uint4 vh = make_uint4(0u,0u,0u,0u), vl = vh;
            if (m < M) {
                size_t o = (size_t)m * Cv + k0 + sc8;
                vh = *(const uint4*)&g_t3hi[o];
                vl = *(const uint4*)&g_t3lo[o];
            }
            *(uint4*)&sAh[srow][sc8] = vh;
            *(uint4*)&sAl[srow][sc8] = vl;
            int n = bn + srow;
            uint4 wh = make_uint4(0u,0u,0u,0u), wl = wh;
            if (n < M) {
                size_t o = (size_t)n * Cv + k0 + sc8;
                wh = *(const uint4*)&g_wo2hi[o];
                wl = *(const uint4*)&g_wo2lo[o];
            }
            *(uint4*)&sBh[srow][sc8] = wh;
            *(uint4*)&sBl[srow][sc8] = wl;
        }
        __syncthreads();
        #pragma unroll
        for (int kk = 0; kk < 32; kk += 16) {
            uint32_t ah[2][4], al[2][4], bh[2][2], bl[2][2];
            const int c = kk + tig * 2;
            #pragma unroll
            for (int mt = 0; mt < 2; mt++) {
                int r = wm * 32 + mt * 16 + gid;
                ah[mt][0] = *(const uint32_t*)&sAh[r][c];
                ah[mt][1] = *(const uint32_t*)&sAh[r + 8][c];
                ah[mt][2] = *(const uint32_t*)&sAh[r][c + 8];
                ah[mt][3] = *(const uint32_t*)&sAh[r + 8][c + 8];
                al[mt][0] = *(const uint32_t*)&sAl[r][c];
                al[mt][1] = *(const uint32_t*)&sAl[r + 8][c];
                al[mt][2] = *(const uint32_t*)&sAl[r][c + 8];
                al[mt][3] = *(const uint32_t*)&sAl[r + 8][c + 8];
            }
            #pragma unroll
            for (int nt = 0; nt < 2; nt++) {
                int r = wn * 16 + nt * 8 + gid;
                bh[nt][0] = *(const uint32_t*)&sBh[r][c];
                bh[nt][1] = *(const uint32_t*)&sBh[r][c + 8];
                bl[nt][0] = *(const uint32_t*)&sBl[r][c];
                bl[nt][1] = *(const uint32_t*)&sBl[r][c + 8];
            }
            #pragma unroll
            for (int mt = 0; mt < 2; mt++)
                #pragma unroll
                for (int nt = 0; nt < 2; nt++) {
                    mma16816(acc[mt][nt], ah[mt], bh[nt]);
                    mma16816(acc[mt][nt], ah[mt], bl[nt]);
                    mma16816(acc[mt][nt], al[mt], bh[nt]);
                }
        }
        __syncthreads();
    }

    #pragma unroll
    for (int mt = 0; mt < 2; mt++) {
        #pragma unroll
        for (int nt = 0; nt < 2; nt++) {
            int n0 = bn + wn * 16 + nt * 8 + tig * 2;
            #pragma unroll
            for (int half = 0; half < 2; half++) {
                int m0 = bm + wm * 32 + mt * 16 + gid + half * 8;
                if (m0 >= M) continue;
                #pragma unroll
                for (int jj = 0; jj < 2; jj++) {
                    int n = n0 + jj;
                    if (n < M) outp[(size_t)m0 * (2*Nv) + n] = acc[mt][nt][half * 2 + jj];
                }
            }
        }
    }
}

// ================= proj HMMA (split-K x2): out += Wp @ ao^T =================
__global__ __launch_bounds__(256, 4)
void proj_hmma(float* __restrict__ out)
{
    __shared__ __align__(16) __nv_bfloat16 sAh[64][40];
    __shared__ __align__(16) __nv_bfloat16 sAl[64][40];
    __shared__ __align__(16) __nv_bfloat16 sBh[64][40];
    __shared__ __align__(16) __nv_bfloat16 sBl[64][40];

    const int tid  = threadIdx.x;
    const int lane = tid & 31;
    const int w    = tid >> 5;
    const int wm   = w >> 2;
    const int wn   = w & 3;
    const int bm = blockIdx.y * 64;
    const int bn = blockIdx.x * 64;
    const int kbase = blockIdx.z * 192;
    const int gid = lane >> 2;
    const int tig = lane & 3;
    const int srow = tid >> 2, sc8 = (tid & 3) * 8;

    float acc[2][2][4];
    #pragma unroll
    for (int i = 0; i < 2; i++)
        #pragma unroll
        for (int j = 0; j < 2; j++)
            #pragma unroll
            for (int q = 0; q < 4; q++) acc[i][j][q] = 0.0f;

    pdl_wait();   // av's g_aohi/lo + out bias-seed must be visible

    for (int kc = 0; kc < 6; kc++) {
        const int k0 = kbase + kc * 32;
        {
            size_t oa = (size_t)(bm + srow) * Cv + k0 + sc8;
            *(uint4*)&sAh[srow][sc8] = *(const uint4*)&g_wphi[oa];
            *(uint4*)&sAl[srow][sc8] = *(const uint4*)&g_wplo[oa];
            int n = bn + srow;
            uint4 vh = make_uint4(0u,0u,0u,0u), vl = vh;
            if (n < BNROWS) {
                size_t o = (size_t)n * Cv + k0 + sc8;
                vh = *(const uint4*)&g_aohi[o];
                vl = *(const uint4*)&g_aolo[o];
            }
            *(uint4*)&sBh[srow][sc8] = vh;
            *(uint4*)&sBl[srow][sc8] = vl;
        }
        __syncthreads();
        #pragma unroll
        for (int kk = 0; kk < 32; kk += 16) {
            uint32_t ah[2][4], al[2][4], bh[2][2], bl[2][2];
            const int c = kk + tig * 2;
            #pragma unroll
            for (int mt = 0; mt < 2; mt++) {
                int r = wm * 32 + mt * 16 + gid;
                ah[mt][0] = *(const uint32_t*)&sAh[r][c];
                ah[mt][1] = *(const uint32_t*)&sAh[r + 8][c];
                ah[mt][2] = *(const uint32_t*)&sAh[r][c + 8];
                ah[mt][3] = *(const uint32_t*)&sAh[r + 8][c + 8];
                al[mt][0] = *(const uint32_t*)&sAl[r][c];
                al[mt][1] = *(const uint32_t*)&sAl[r + 8][c];
                al[mt][2] = *(const uint32_t*)&sAl[r][c + 8];
                al[mt][3] = *(const uint32_t*)&sAl[r + 8][c + 8];
            }
            #pragma unroll
            for (int nt = 0; nt < 2; nt++) {
                int r = wn * 16 + nt * 8 + gid;
                bh[nt][0] = *(const uint32_t*)&sBh[r][c];
                bh[nt][1] = *(const uint32_t*)&sBh[r][c + 8];
                bl[nt][0] = *(const uint32_t*)&sBl[r][c];
                bl[nt][1] = *(const uint32_t*)&sBl[r][c + 8];
            }
            #pragma unroll
            for (int mt = 0; mt < 2; mt++)
                #pragma unroll
                for (int nt = 0; nt < 2; nt++) {
                    mma16816(acc[mt][nt], ah[mt], bh[nt]);
                    mma16816(acc[mt][nt], ah[mt], bl[nt]);
                    mma16816(acc[mt][nt], al[mt], bh[nt]);
                }
        }
        __syncthreads();
    }

    #pragma unroll
    for (int mt = 0; mt < 2; mt++) {
        #pragma unroll
        for (int nt = 0; nt < 2; nt++) {
            int n0 = bn + wn * 16 + nt * 8 + tig * 2;
            #pragma unroll
            for (int half = 0; half < 2; half++) {
                int m0 = bm + wm * 32 + mt * 16 + gid + half * 8;
                #pragma unroll
                for (int jj = 0; jj < 2; jj++) {
                    int n = n0 + jj;
                    if (n >= BNROWS) continue;
                    int b = n / Nv, nn = n - b * Nv;
                    atomicAdd(&out[((size_t)(b * Cv + m0)) * Nv + nn], acc[mt][nt][half * 2 + jj]);
                }
            }
        }
    }
}

// ================= dwln: depthwise conv + LN + GELU -> t3 hi/lo =================
__global__ void dwln_kernel(const float* __restrict__ Wdw, const float* __restrict__ bdw,
                            const float* __restrict__ lng, const float* __restrict__ lnb)
{
    int bs = blockIdx.x;
    int b = bs / Sv, s = bs % Sv;
    int oy = s / rWv, ox = s % rWv;
    int c = threadIdx.x;

    float wreg[9];
    #pragma unroll
    for (int i = 0; i < 9; i++) wreg[i] = Wdw[c*9 + i];   // weights: safe pre-wait (input)
    float acc = bdw[c];

    pdl_wait();   // t1qk's g_t1 must be visible

    #pragma unroll
    for (int ky = 0; ky < 3; ky++) {
        int y = oy*2 - 1 + ky;
        if (y < 0 || y >= Hv) continue;
        #pragma unroll
        for (int kx = 0; kx < 3; kx++) {
            int x = ox*2 - 1 + kx;
            if (x < 0 || x >= Wv_) continue;
            acc = fmaf(g_t1[((size_t)b*Nv + y*Wv_ + x)*Cv + c], wreg[ky*3 + kx], acc);
        }
    }
    float s1 = acc, s2 = acc*acc;
    #pragma unroll
    for (int o = 16; o > 0; o >>= 1) {
        s1 += __shfl_xor_sync(0xffffffffu, s1, o);
        s2 += __shfl_xor_sync(0xffffffffu, s2, o);
    }
    __shared__ float w1[12], w2[12];
    __shared__ float s_mu, s_rstd;
    if ((c & 31) == 0) { w1[c >> 5] = s1; w2[c >> 5] = s2; }
    __syncthreads();
    if (c == 0) {
        float t1s = 0.f, t2s = 0.f;
        #pragma unroll
        for (int i = 0; i < 12; i++) { t1s += w1[i]; t2s += w2[i]; }
        float mu = t1s / (float)Cv;
        float var = t2s / (float)Cv - mu*mu;
        s_mu = mu; s_rstd = rsqrtf(var + 1e-5f);
    }
    __syncthreads();
    float v = gelu_exact((acc - s_mu) * s_rstd * lng[c] + lnb[c]);
    split_bf16(v, g_t3hi[(size_t)bs*Cv + c], g_t3lo[(size_t)bs*Cv + c]);
}

// ================= scores: hoisted coords + softmax -> dense bf16 prob matrix ============
__global__ void score_kernel(const float* __restrict__ posembed)
{
    const int bn = blockIdx.x;
    const int b = bn / Nv, n = bn % Nv;
    const int ny = n / Wv_, nx = n % Wv_;
    __shared__ float sc[HEADS*TS];
    __shared__ int   sp[TS*4];
    __shared__ float swt[TS*4];
    __shared__ int   stix[TS*4];
    __shared__ float stw[TS*4];
    __shared__ __align__(16) float sA[HEADS][Nv];

    // pre-wait prologue: zero sA (local), nothing dependent on predecessor
    for (int idx = threadIdx.x; idx < HEADS*Nv/4; idx += blockDim.x)
        ((float4*)sA)[idx] = make_float4(0.f, 0.f, 0.f, 0.f);

    pdl_wait();   // off_hmma's g_off/g_off2 must be visible

    if (threadIdx.x < TS) {
        const int s = threadIdx.x;
        float py, px, tpy, tpx;
        if (s < Sv) {
            int rh = s / rWv, rw = s % rWv;
            size_t ob = ((size_t)b*Sv + s)*(2*Nv);
            float offy = tanhf(g_off[ob + 0*Nv + n] + g_off2[ob + 0*Nv + n]) * (2.0f/14.0f);
            float offx = tanhf(g_off[ob + 1*Nv + n] + g_off2[ob + 1*Nv + n]) * (2.0f/14.0f);
            float refy = (float)(rh*2) * (2.0f/13.0f) - 1.0f;
            float refx = (float)(rw*2) * (2.0f/13.0f) - 1.0f;
            py = (offy + refy + 1.0f) * 6.5f;
            px = (offx + refx + 1.0f) * 6.5f;
            tpy = ((float)(2*rh - ny) * (1.0f/13.0f) - offy + 1.0f) * 13.0f;
            tpx = ((float)(2*rw - nx) * (1.0f/13.0f) - offx + 1.0f) * 13.0f;
        } else {
            int j = s - Sv;
            float coy = g_co[((size_t)b*Nv + n)*(2*KKv) + j*2 + 0];
            float cox = g_co[((size_t)b*Nv + n)*(2*KKv) + j*2 + 1];
            float cy = (float)ny + c_offm[j][0];
            float cx = (float)nx + c_offm[j][1];
            float cny = fminf(fmaxf(cy, 0.0f), 14.0f) * (2.0f/13.0f) - 1.0f;
            float cnx = fminf(fmaxf(cx, 0.0f), 14.0f) * (2.0f/13.0f) - 1.0f;
            py = (coy + cny + 1.0f) * 6.5f;
            px = (cox + cnx + 1.0f) * 6.5f;
            tpy = (coy - (float)ny + 1.0f) * 13.0f;
            tpx = (cox - (float)nx + 1.0f) * 13.0f;
        }
        {
            float y0 = floorf(py), x0 = floorf(px);
            float wy1 = py - y0, wx1 = px - x0;
            #pragma unroll
            for (int ccy = 0; ccy < 2; ccy++)
                #pragma unroll
                for (int ccx = 0; ccx < 2; ccx++) {
                    float yf = y0 + (float)ccy, xf = x0 + (float)ccx;
                    float w = (ccy ? wy1 : 1.0f - wy1) * (ccx ? wx1 : 1.0f - wx1);
                    bool valid = (yf >= 0.0f) && (yf <= 13.0f) && (xf >= 0.0f) && (xf <= 13.0f);
                    if (!valid) w = 0.0f;
                    int yi = (int)fminf(fmaxf(yf, 0.0f), 13.0f);
                    int xi = (int)fminf(fmaxf(xf, 0.0f), 13.0f);
                    sp [s*4 + ccy*2 + ccx] = yi*Wv_ + xi;
                    swt[s*4 + ccy*2 + ccx] = w;
                }
        }
        {
            float by0 = floorf(tpy), bx0 = floorf(tpx);
            float bwy = tpy - by0, bwx = tpx - bx0;
            #pragma unroll
            for (int ccy = 0; ccy < 2; ccy++)
                #pragma unroll
                for (int ccx = 0; ccx < 2; ccx++) {
                    float yf = by0 + (float)ccy, xf = bx0 + (float)ccx;
                    float w = (ccy ? bwy : 1.0f - bwy) * (ccx ? bwx : 1.0f - bwx);
                    bool valid = (yf >= 0.0f) && (yf <= 26.0f) && (xf >= 0.0f) && (xf <= 26.0f);
                    if (!valid) w = 0.0f;
                    int yi = (int)fminf(fmaxf(yf, 0.0f), 26.0f);
                    int xi = (int)fminf(fmaxf(xf, 0.0f), 26.0f);
                    stix[s*4 + ccy*2 + ccx] = yi*27 + xi;
                    stw [s*4 + ccy*2 + ccx] = w;
                }
        }
    }
    __syncthreads();

    for (int item = threadIdx.x; item < HEADS*TS; item += blockDim.x) {
        const int h = item / TS, s = item % TS;
        const float* qkb = g_qk + (((size_t)(b*HEADS + h))*Nv + n)*Nv;
        const float* tb = posembed + (size_t)h * (27*27);
        float val = swt[s*4+0]*qkb[sp[s*4+0]] + swt[s*4+1]*qkb[sp[s*4+1]]
                  + swt[s*4+2]*qkb[sp[s*4+2]] + swt[s*4+3]*qkb[sp[s*4+3]];
        float bval = stw[s*4+0]*tb[stix[s*4+0]] + stw[s*4+1]*tb[stix[s*4+1]]
                   + stw[s*4+2]*tb[stix[s*4+2]] + stw[s*4+3]*tb[stix[s*4+3]];
        sc[h*TS + s] = val + bval;
    }
    __syncthreads();

    const int wid = threadIdx.x >> 5, lane = threadIdx.x & 31;
    {
        float m = -1e30f;
        for (int s = lane; s < TS; s += 32) m = fmaxf(m, sc[wid*TS + s]);
        #pragma unroll
        for (int o = 16; o > 0; o >>= 1) m = fmaxf(m, __shfl_xor_sync(0xffffffffu, m, o));
        float sum = 0.0f;
        for (int s = lane; s < TS; s += 32) {
            float e = expf(sc[wid*TS + s] - m);
            sc[wid*TS + s] = e;
            sum += e;
        }
        #pragma unroll
        for (int o = 16; o > 0; o >>= 1) sum += __shfl_xor_sync(0xffffffffu, sum, o);
        float inv = 1.0f / sum;
        for (int s = lane; s < TS; s += 32) sc[wid*TS + s] *= inv;
    }
    for (int i = lane; i < TS*4; i += 32) {
        atomicAdd(&sA[wid][sp[i]], sc[wid*TS + (i >> 2)] * swt[i]);
    }
    __syncthreads();

    for (int idx = threadIdx.x; idx < HEADS*(Nv/2); idx += blockDim.x) {
        int h = idx / (Nv/2), p2 = idx - h * (Nv/2);
        float v0 = sA[h][p2*2], v1 = sA[h][p2*2 + 1];
        __nv_bfloat16 h0, l0, h1, l1;
        split_bf16(v0, h0, l0);
        split_bf16(v1, h1, l1);
        size_t o = (((size_t)(b*HEADS + h)*Nv + n)*AP)/2 + p2;
        ((uint32_t*)g_Ahi)[o] = pack_bf16(h0, h1);
        ((uint32_t*)g_Alo)[o] = pack_bf16(l0, l1);
    }
}

// ================= av via HMMA: ao[n][c] = A @ V (+bv), seeds out with bp =================
__global__ __launch_bounds__(256, 4)
void av_hmma(const float* __restrict__ bvv, const float* __restrict__ bp, float* __restrict__ out)
{
    __shared__ __align__(16) __nv_bfloat16 sAh[64][40];
    __shared__ __align__(16) __nv_bfloat16 sAl[64][40];
    __shared__ __align__(16) __nv_bfloat16 sBh[32][40];
    __shared__ __align__(16) __nv_bfloat16 sBl[32][40];

    const int tid  = threadIdx.x;
    const int lane = tid & 31;
    const int w    = tid >> 5;
    const int wm   = w >> 1;
    const int wn   = w & 1;
    const int bm = blockIdx.x * 64;
    const int bh = blockIdx.y;
    const int b = bh / HEADS, h = bh - b * HEADS;
    const int gid = lane >> 2;
    const int tig = lane & 3;
    const int srow = tid >> 2, sc8 = (tid & 3) * 8;

    // pre-wait prologue: bias-seed out (no predecessor writes this region)
    for (int i = tid; i < 64 * HC; i += 256) {
        int nn = bm + (i & 63);
        int c  = h * HC + (i >> 6);
        if (nn < Nv) out[((size_t)(b * Cv + c)) * Nv + nn] = bp[c];
    }

    float acc[2][4];
    #pragma unroll
    for (int j = 0; j < 2; j++)
        #pragma unroll
        for (int q = 0; q < 4; q++) acc[j][q] = 0.0f;

    const __nv_bfloat16* Abh = g_Ahi + (size_t)bh * Nv * AP;
    const __nv_bfloat16* Abl = g_Alo + (size_t)bh * Nv * AP;
    const __nv_bfloat16* Vbh = g_vthi + (size_t)bh * HC * AP;
    const __nv_bfloat16* Vbl = g_vtlo + (size_t)bh * HC * AP;

    pdl_wait();   // score's g_Ahi/lo must be visible

    for (int p0 = 0; p0 < AP; p0 += 32) {
        {
            int m = bm + srow;
            uint4 vh = make_uint4(0u,0u,0u,0u), vl = vh;
            if (m < Nv) {
                size_t o = (size_t)m * AP + p0 + sc8;
                vh = *(const uint4*)&Abh[o];
                vl = *(const uint4*)&Abl[o];
            }
            *(uint4*)&sAh[srow][sc8] = vh;
            *(uint4*)&sAl[srow][sc8] = vl;
            if (srow < 32) {
                size_t o = (size_t)srow * AP + p0 + sc8;
                *(uint4*)&sBh[srow][sc8] = *(const uint4*)&Vbh[o];
                *(uint4*)&sBl[srow][sc8] = *(const uint4*)&Vbl[o];
            }
        }
        __syncthreads();
        #pragma unroll
        for (int kk = 0; kk < 32; kk += 16) {
            uint32_t ah[4], al[4], bh2[2][2], bl2[2][2];
            const int c = kk + tig * 2;
            {
                int r = wm * 16 + gid;
                ah[0] = *(const uint32_t*)&sAh[r][c];
                ah[1] = *(const uint32_t*)&sAh[r + 8][c];
                ah[2] = *(const uint32_t*)&sAh[r][c + 8];
                ah[3] = *(const uint32_t*)&sAh[r + 8][c + 8];
                al[0] = *(const uint32_t*)&sAl[r][c];
                al[1] = *(const uint32_t*)&sAl[r + 8][c];
                al[2] = *(const uint32_t*)&sAl[r][c + 8];
                al[3] = *(const uint32_t*)&sAl[r + 8][c + 8];
            }
            #pragma unroll
            for (int nt = 0; nt < 2; nt++) {
                int r = wn * 16 + nt * 8 + gid;
                bh2[nt][0] = *(const uint32_t*)&sBh[r][c];
                bh2[nt][1] = *(const uint32_t*)&sBh[r][c + 8];
                bl2[nt][0] = *(const uint32_t*)&sBl[r][c];
                bl2[nt][1] = *(const uint32_t*)&sBl[r][c + 8];
            }
            #pragma unroll
            for (int nt = 0; nt < 2; nt++) {
                mma16816(acc[nt], ah, bh2[nt]);
                mma16816(acc[nt], ah, bl2[nt]);
                mma16816(acc[nt], al, bh2[nt]);
            }
        }
        __syncthreads();
    }

    #pragma unroll
    for (int nt = 0; nt < 2; nt++) {
        int c0 = wn * 16 + nt * 8 + tig * 2;
        #pragma unroll
        for (int half = 0; half < 2; half++) {
            int n = bm + wm * 16 + gid + half * 8;
            if (n >= Nv) continue;
            #pragma unroll
            for (int jj = 0; jj < 2; jj++) {
                int c = c0 + jj;
                float v = acc[nt][half * 2 + jj] + bvv[h * HC + c];
                size_t o = ((size_t)(b*Nv + n))*Cv + h*HC + c;
                split_bf16(v, g_aohi[o], g_aolo[o]);
            }
        }
    }
}

// ================= host: PDL launch helper =================
static inline void launch_pdl(const void* fn, dim3 g, dim3 b, void** args)
{
    cudaLaunchConfig_t cfg = {};
    cfg.gridDim = g;
    cfg.blockDim = b;
    cfg.dynamicSmemBytes = 0;
    cfg.stream = 0;
    cudaLaunchAttribute attr;
    attr.id = cudaLaunchAttributeProgrammaticStreamSerialization;
    attr.val.programmaticStreamSerializationAllowed = 1;
    cfg.attrs = &attr;
    cfg.numAttrs = 1;
    cudaLaunchKernelExC(&cfg, fn, args);
}

extern "C" void kernel_launch(void* const* d_in, const int* in_sizes, int n_in,
                              void* d_out, int out_size)
{
    const float* x    = (const float*)d_in[0];
    const float* Wq   = (const float*)d_in[1];
    const float* bq   = (const float*)d_in[2];
    const float* Wk   = (const float*)d_in[3];
    // bk cancels in softmax — unused
    const float* Wvv  = (const float*)d_in[5];
    const float* bvv  = (const float*)d_in[6];
    const float* Wo1  = (const float*)d_in[7];
    const float* bo1  = (const float*)d_in[8];
    const float* Wdw  = (const float*)d_in[9];
    const float* bdw  = (const float*)d_in[10];
    const float* lng  = (const float*)d_in[11];
    const float* lnb  = (const float*)d_in[12];
    const float* Wo2  = (const float*)d_in[13];
    const float* Wco  = (const float*)d_in[14];
    const float* pos  = (const float*)d_in[15];
    const float* Wp   = (const float*)d_in[16];
    const float* bp   = (const float*)d_in[17];
    float* out = (float*)d_out;

    // 0) prep (normal launch)
    prep_kernel<<<1563, 256>>>(x, Wq, Wk, Wvv, Wo1, Wco, Wp, Wo2);

    // 1..7) PDL chain
    { void* a[] = {(void*)&bq};
      launch_pdl((const void*)qkv_hmma, dim3(18, 25, 1), dim3(256, 1, 1), a); }
    { void* a[] = {(void*)&bo1};
      launch_pdl((const void*)fused_t1qk_hmma, dim3(T1_BLOCKS + 16 * Bv * HEADS, 1, 1), dim3(256, 1, 1), a); }
    { void* a[] = {(void*)&Wdw, (void*)&bdw, (void*)&lng, (void*)&lnb};
      launch_pdl((const void*)dwln_kernel, dim3(Bv * Sv, 1, 1), dim3(Cv, 1, 1), a); }
    { void* a[1] = {nullptr};
      launch_pdl((const void*)off_hmma, dim3(7, 7, 2), dim3(256, 1, 1), a); }
    { void* a[] = {(void*)&pos};
      launch_pdl((const void*)score_kernel, dim3(Bv * Nv, 1, 1), dim3(384, 1, 1), a); }
    { void* a[] = {(void*)&bvv, (void*)&bp, (void*)&out};
      launch_pdl((const void*)av_hmma, dim3(4, Bv * HEADS, 1), dim3(256, 1, 1), a); }
    { void* a[] = {(void*)&out};
      launch_pdl((const void*)proj_hmma, dim3(25, 6, 2), dim3(256, 1, 1), a); }
}